// round 1
// baseline (speedup 1.0000x reference)
#include <cuda_runtime.h>

// ---------------- problem constants ----------------
#define Bsz  8
#define Cdim 1024
#define Tdim 1024
#define Hn   8
#define DQKd 128
#define DFC1 128

// ---------------- scratch (device globals; no allocs allowed) ----------------
__device__ float g_q   [(size_t)Bsz*Hn*DQKd*Tdim];   //  33.5 MB
__device__ float g_k   [(size_t)Bsz*Hn*DQKd*Tdim];   //  33.5 MB
__device__ float g_v   [(size_t)Bsz*Hn*Cdim*Tdim];   // 268 MB
__device__ float g_attn[(size_t)Bsz*Hn*Tdim*Tdim];   // 268 MB
__device__ float g_hds [(size_t)Bsz*Hn*Tdim*Cdim];   // 268 MB (B,H,T,C) transposed heads
__device__ float g_y1  [(size_t)Bsz*Hn*Tdim*DFC1];   //  33.5 MB

// ---------------- shared 128x128x8 SGEMM mainloop ----------------
// C[m,n] = sum_k A(m,k) * B(k,n)
//   AM=true : A addr = k*lda + m   (m contiguous)
//   AM=false: A addr = m*lda + k   (k contiguous)
//   BN=true : B addr = k*ldb + n   (n contiguous)
//   BN=false: B addr = n*ldb + k   (k contiguous)
// 256 threads, each computes an 8x8 micro-tile split as 4+4 in both dims.
template<bool AM, bool BN>
__device__ __forceinline__ void sgemm_body(
    const float* __restrict__ A, const float* __restrict__ B,
    int K, int lda, int ldb, int mb, int nb,
    float (&acc)[8][8])
{
    __shared__ float As[8][132];
    __shared__ float Bs[8][132];
    const int tid = threadIdx.x;
    const int tx  = tid & 15;
    const int ty  = tid >> 4;

    for (int k0 = 0; k0 < K; k0 += 8) {
        #pragma unroll
        for (int j = 0; j < 4; j++) {
            int e = (j << 8) + tid;
            int m, kk;
            if (AM) { m = e & 127; kk = e >> 7; }
            else    { kk = e & 7;  m  = e >> 3; }
            size_t idx = AM ? (size_t)(k0 + kk) * lda + (size_t)(mb + m)
                            : (size_t)(mb + m) * lda + (size_t)(k0 + kk);
            As[kk][m] = A[idx];
        }
        #pragma unroll
        for (int j = 0; j < 4; j++) {
            int e = (j << 8) + tid;
            int n, kk;
            if (BN) { n = e & 127; kk = e >> 7; }
            else    { kk = e & 7;  n  = e >> 3; }
            size_t idx = BN ? (size_t)(k0 + kk) * ldb + (size_t)(nb + n)
                            : (size_t)(nb + n) * ldb + (size_t)(k0 + kk);
            Bs[kk][n] = B[idx];
        }
        __syncthreads();
        #pragma unroll
        for (int kk = 0; kk < 8; kk++) {
            float a[8], b[8];
            *(float4*)&a[0] = *(const float4*)&As[kk][ty * 4];
            *(float4*)&a[4] = *(const float4*)&As[kk][64 + ty * 4];
            *(float4*)&b[0] = *(const float4*)&Bs[kk][tx * 4];
            *(float4*)&b[4] = *(const float4*)&Bs[kk][64 + tx * 4];
            #pragma unroll
            for (int i = 0; i < 8; i++)
                #pragma unroll
                for (int jj = 0; jj < 8; jj++)
                    acc[i][jj] += a[i] * b[jj];
        }
        __syncthreads();
    }
}

// row index of micro-tile element i (i in [0,8))
__device__ __forceinline__ int tile_m(int mb, int ty, int i) {
    return mb + ty * 4 + ((i < 4) ? i : 60 + i);
}

// ---------------- kernel 1: per-head 1x1 conv  out[z,m,n] = sum_c W[h,m,c]*x[b,c,n] + bias[h,m]
__global__ __launch_bounds__(256) void k_conv(
    const float* __restrict__ W, const float* __restrict__ bias,
    const float* __restrict__ x, float* __restrict__ out, int M)
{
    const int z = blockIdx.z;            // z = b*H + h
    const int b = z >> 3, h = z & 7;
    const int mb = blockIdx.y * 128, nb = blockIdx.x * 128;
    const float* Ap = W + (size_t)h * M * Cdim;
    const float* Bp = x + (size_t)b * Cdim * Tdim;
    float acc[8][8] = {};
    sgemm_body<false, true>(Ap, Bp, Cdim, Cdim, Tdim, mb, nb, acc);

    const int tx = threadIdx.x & 15, ty = threadIdx.x >> 4;
    const float* bb = bias + h * M;
    float* o = out + (size_t)z * M * Tdim;
    #pragma unroll
    for (int i = 0; i < 8; i++) {
        int m = tile_m(mb, ty, i);
        float bvv = bb[m];
        float4 r0 = make_float4(acc[i][0]+bvv, acc[i][1]+bvv, acc[i][2]+bvv, acc[i][3]+bvv);
        float4 r1 = make_float4(acc[i][4]+bvv, acc[i][5]+bvv, acc[i][6]+bvv, acc[i][7]+bvv);
        *(float4*)&o[(size_t)m * Tdim + nb + tx * 4]      = r0;
        *(float4*)&o[(size_t)m * Tdim + nb + 64 + tx * 4] = r1;
    }
}

// ---------------- kernel 2: energy  E[z,t,s] = sum_o q[z,o,t]*k[z,o,s]
__global__ __launch_bounds__(256) void k_energy(
    const float* __restrict__ q, const float* __restrict__ kk,
    float* __restrict__ attn)
{
    const int z = blockIdx.z;
    const int mb = blockIdx.y * 128, nb = blockIdx.x * 128;
    const float* Ap = q  + (size_t)z * DQKd * Tdim;
    const float* Bp = kk + (size_t)z * DQKd * Tdim;
    float acc[8][8] = {};
    sgemm_body<true, true>(Ap, Bp, DQKd, Tdim, Tdim, mb, nb, acc);

    const int tx = threadIdx.x & 15, ty = threadIdx.x >> 4;
    float* o = attn + (size_t)z * Tdim * Tdim;
    #pragma unroll
    for (int i = 0; i < 8; i++) {
        int m = tile_m(mb, ty, i);
        float4 r0 = make_float4(acc[i][0], acc[i][1], acc[i][2], acc[i][3]);
        float4 r1 = make_float4(acc[i][4], acc[i][5], acc[i][6], acc[i][7]);
        *(float4*)&o[(size_t)m * Tdim + nb + tx * 4]      = r0;
        *(float4*)&o[(size_t)m * Tdim + nb + 64 + tx * 4] = r1;
    }
}

// ---------------- kernel 3: row softmax (in place), 1024-wide rows
__global__ __launch_bounds__(256) void k_softmax(float* __restrict__ attn)
{
    float* row = attn + (size_t)blockIdx.x * Tdim;
    const int tid = threadIdx.x;
    float4 v = *(float4*)&row[tid * 4];
    __shared__ float red[256];

    float mx = fmaxf(fmaxf(v.x, v.y), fmaxf(v.z, v.w));
    red[tid] = mx; __syncthreads();
    #pragma unroll
    for (int s = 128; s > 0; s >>= 1) {
        if (tid < s) red[tid] = fmaxf(red[tid], red[tid + s]);
        __syncthreads();
    }
    mx = red[0]; __syncthreads();

    v.x = __expf(v.x - mx); v.y = __expf(v.y - mx);
    v.z = __expf(v.z - mx); v.w = __expf(v.w - mx);
    red[tid] = v.x + v.y + v.z + v.w; __syncthreads();
    #pragma unroll
    for (int s = 128; s > 0; s >>= 1) {
        if (tid < s) red[tid] += red[tid + s];
        __syncthreads();
    }
    float inv = 1.0f / red[0];
    v.x *= inv; v.y *= inv; v.z *= inv; v.w *= inv;
    *(float4*)&row[tid * 4] = v;
}

// ---------------- kernel 4: heads_T[z,t,c] = gamma[h]*sum_s attn[z,t,s]*v[z,c,s] + x[b,c,t]
__global__ __launch_bounds__(256) void k_out_heads(
    const float* __restrict__ attn, const float* __restrict__ v,
    const float* __restrict__ gamma, const float* __restrict__ x,
    float* __restrict__ heads)
{
    const int z = blockIdx.z;
    const int b = z >> 3, h = z & 7;
    const int mb = blockIdx.y * 128, nb = blockIdx.x * 128;   // m=t, n=c
    const float* Ap = attn + (size_t)z * Tdim * Tdim;
    const float* Bp = v    + (size_t)z * Cdim * Tdim;
    float acc[8][8] = {};
    sgemm_body<false, false>(Ap, Bp, Tdim, Tdim, Tdim, mb, nb, acc);

    const int tx = threadIdx.x & 15, ty = threadIdx.x >> 4;
    const float g = gamma[h];
    const float* xb = x + (size_t)b * Cdim * Tdim;
    float* o = heads + (size_t)z * Tdim * Cdim;
    #pragma unroll
    for (int i = 0; i < 8; i++) {
        int m = tile_m(mb, ty, i);                 // t
        int n0 = nb + tx * 4, n1 = nb + 64 + tx * 4;
        float4 r0, r1;
        r0.x = g*acc[i][0] + xb[(size_t)(n0+0)*Tdim + m];
        r0.y = g*acc[i][1] + xb[(size_t)(n0+1)*Tdim + m];
        r0.z = g*acc[i][2] + xb[(size_t)(n0+2)*Tdim + m];
        r0.w = g*acc[i][3] + xb[(size_t)(n0+3)*Tdim + m];
        r1.x = g*acc[i][4] + xb[(size_t)(n1+0)*Tdim + m];
        r1.y = g*acc[i][5] + xb[(size_t)(n1+1)*Tdim + m];
        r1.z = g*acc[i][6] + xb[(size_t)(n1+2)*Tdim + m];
        r1.w = g*acc[i][7] + xb[(size_t)(n1+3)*Tdim + m];
        *(float4*)&o[(size_t)m * Cdim + n0] = r0;
        *(float4*)&o[(size_t)m * Cdim + n1] = r1;
    }
}

// ---------------- kernel 5: FC1  y1[r,f] = relu(sum_c heads[r,c]*W1[f,c] + b1[f])
__global__ __launch_bounds__(256) void k_fc1(
    const float* __restrict__ heads, const float* __restrict__ W1,
    const float* __restrict__ b1, float* __restrict__ y1)
{
    const int mb = blockIdx.y * 128;   // rows r, single N tile (128)
    float acc[8][8] = {};
    sgemm_body<false, false>(heads, W1, Cdim, Cdim, Cdim, mb, 0, acc);

    const int tx = threadIdx.x & 15, ty = threadIdx.x >> 4;
    #pragma unroll
    for (int i = 0; i < 8; i++) {
        int m = tile_m(mb, ty, i);
        int n0 = tx * 4, n1 = 64 + tx * 4;
        float4 r0, r1;
        r0.x = fmaxf(acc[i][0] + b1[n0+0], 0.f);
        r0.y = fmaxf(acc[i][1] + b1[n0+1], 0.f);
        r0.z = fmaxf(acc[i][2] + b1[n0+2], 0.f);
        r0.w = fmaxf(acc[i][3] + b1[n0+3], 0.f);
        r1.x = fmaxf(acc[i][4] + b1[n1+0], 0.f);
        r1.y = fmaxf(acc[i][5] + b1[n1+1], 0.f);
        r1.z = fmaxf(acc[i][6] + b1[n1+2], 0.f);
        r1.w = fmaxf(acc[i][7] + b1[n1+3], 0.f);
        *(float4*)&y1[(size_t)m * DFC1 + n0] = r0;
        *(float4*)&y1[(size_t)m * DFC1 + n1] = r1;
    }
}

// ---------------- kernel 6: FC2 + scatter + residual
// y2[r,d] = relu(sum_f y1[r,f]*W2[d,f] + b2[d]);  out[b, d*H+h, t] = y2 + x[b, d*H+h, t]
__global__ __launch_bounds__(256) void k_fc2(
    const float* __restrict__ y1, const float* __restrict__ W2,
    const float* __restrict__ b2, const float* __restrict__ x,
    float* __restrict__ out)
{
    const int mb = blockIdx.y * 128;
    float acc[8][8] = {};
    sgemm_body<false, false>(y1, W2, DFC1, DFC1, DFC1, mb, 0, acc);

    const int tx = threadIdx.x & 15, ty = threadIdx.x >> 4;
    #pragma unroll
    for (int i = 0; i < 8; i++) {
        int m = tile_m(mb, ty, i);           // r = (b*H + h)*T + t
        int b = m >> 13;                     // / (H*T) = /8192
        int h = (m >> 10) & 7;
        int t = m & 1023;
        size_t xbase = (size_t)b * Cdim * Tdim + t;
        #pragma unroll
        for (int j = 0; j < 8; j++) {
            int n = tx * 4 + ((j < 4) ? j : 60 + j);   // d
            int cp = n * Hn + h;
            size_t idx = xbase + (size_t)cp * Tdim;
            out[idx] = fmaxf(acc[i][j] + b2[n], 0.f) + x[idx];
        }
    }
}

// ---------------- launch ----------------
extern "C" void kernel_launch(void* const* d_in, const int* in_sizes, int n_in,
                              void* d_out, int out_size)
{
    (void)in_sizes; (void)n_in; (void)out_size;
    const float* x     = (const float*)d_in[0];
    const float* Wq    = (const float*)d_in[1];
    const float* bq    = (const float*)d_in[2];
    const float* Wk    = (const float*)d_in[3];
    const float* bk    = (const float*)d_in[4];
    const float* Wv    = (const float*)d_in[5];
    const float* bv    = (const float*)d_in[6];
    const float* gamma = (const float*)d_in[7];
    const float* W1    = (const float*)d_in[8];
    const float* b1    = (const float*)d_in[9];
    const float* W2    = (const float*)d_in[10];
    const float* b2    = (const float*)d_in[11];
    float* out = (float*)d_out;

    float *q, *k, *v, *attn, *heads, *y1;
    cudaGetSymbolAddress((void**)&q,     g_q);
    cudaGetSymbolAddress((void**)&k,     g_k);
    cudaGetSymbolAddress((void**)&v,     g_v);
    cudaGetSymbolAddress((void**)&attn,  g_attn);
    cudaGetSymbolAddress((void**)&heads, g_hds);
    cudaGetSymbolAddress((void**)&y1,    g_y1);

    const dim3 blk(256);
    const int ZB = Bsz * Hn;   // 64

    // q, k, v projections (per-head 1x1 conv)
    k_conv<<<dim3(Tdim/128, DQKd/128, ZB), blk>>>(Wq, bq, x, q, DQKd);
    k_conv<<<dim3(Tdim/128, DQKd/128, ZB), blk>>>(Wk, bk, x, k, DQKd);
    k_conv<<<dim3(Tdim/128, Cdim/128, ZB), blk>>>(Wv, bv, x, v, Cdim);

    // energy + softmax
    k_energy <<<dim3(Tdim/128, Tdim/128, ZB), blk>>>(q, k, attn);
    k_softmax<<<ZB * Tdim, blk>>>(attn);

    // o = v @ attn^T (stored transposed), fused gamma*o + x
    k_out_heads<<<dim3(Cdim/128, Tdim/128, ZB), blk>>>(attn, v, gamma, x, heads);

    // MLP: FC1 (relu) then FC2 (relu) + scatter + residual
    const int ROWS = Bsz * Hn * Tdim;   // 65536
    k_fc1<<<dim3(1, ROWS/128), blk>>>(heads, W1, b1, y1);
    k_fc2<<<dim3(1, ROWS/128), blk>>>(y1, W2, b2, x, out);
}

// round 3
// speedup vs baseline: 1.7935x; 1.7935x over previous
#include <cuda_runtime.h>
#include <cuda_bf16.h>
#include <cstdint>

// ---------------- problem constants ----------------
#define Bsz  8
#define Cdim 1024
#define Tdim 1024
#define Hn   8
#define DQKd 128
#define DFC1 128

// ---------------- scratch (device globals; no allocs allowed) ----------------
__device__ float g_q   [(size_t)Bsz*Hn*DQKd*Tdim];
__device__ float g_k   [(size_t)Bsz*Hn*DQKd*Tdim];
__device__ float g_attn[(size_t)Bsz*Hn*Tdim*Tdim];            // fp32 energy
__device__ __nv_bfloat16 g_attn_hi[(size_t)Bsz*Hn*Tdim*Tdim];
__device__ __nv_bfloat16 g_attn_lo[(size_t)Bsz*Hn*Tdim*Tdim];
__device__ __nv_bfloat16 g_v_hi[(size_t)Bsz*Hn*Cdim*Tdim];    // v (z,c,t)
__device__ __nv_bfloat16 g_v_lo[(size_t)Bsz*Hn*Cdim*Tdim];
__device__ __nv_bfloat16 g_wv_hi[(size_t)Hn*Cdim*Cdim];
__device__ __nv_bfloat16 g_wv_lo[(size_t)Hn*Cdim*Cdim];
__device__ __nv_bfloat16 g_xT_hi[(size_t)Bsz*Tdim*Cdim];      // x^T (b,t,c)
__device__ __nv_bfloat16 g_xT_lo[(size_t)Bsz*Tdim*Cdim];
__device__ float g_xT32[(size_t)Bsz*Tdim*Cdim];
__device__ float g_hds [(size_t)Bsz*Hn*Tdim*Cdim];            // heads (z,t,c)
__device__ float g_y1  [(size_t)Bsz*Hn*Tdim*DFC1];

// ============================================================================
// PTX helpers (sm_80-level — valid on compute_103)
// ============================================================================
__device__ __forceinline__ uint32_t s2u(const void* p) {
    uint32_t a;
    asm("{ .reg .u64 t; cvta.to.shared.u64 t, %1; cvt.u32.u64 %0, t; }"
        : "=r"(a) : "l"(p));
    return a;
}
__device__ __forceinline__ void ldsm_x4(uint32_t* r, uint32_t addr) {
    asm volatile("ldmatrix.sync.aligned.m8n8.x4.shared.b16 {%0,%1,%2,%3}, [%4];"
        : "=r"(r[0]), "=r"(r[1]), "=r"(r[2]), "=r"(r[3]) : "r"(addr));
}
__device__ __forceinline__ void ldsm_x2(uint32_t* r, uint32_t addr) {
    asm volatile("ldmatrix.sync.aligned.m8n8.x2.shared.b16 {%0,%1}, [%2];"
        : "=r"(r[0]), "=r"(r[1]) : "r"(addr));
}
__device__ __forceinline__ void mma16816(float* c, const uint32_t* a, const uint32_t* b) {
    asm volatile("mma.sync.aligned.m16n8k16.row.col.f32.bf16.bf16.f32 "
        "{%0,%1,%2,%3}, {%4,%5,%6,%7}, {%8,%9}, {%0,%1,%2,%3};"
        : "+f"(c[0]), "+f"(c[1]), "+f"(c[2]), "+f"(c[3])
        : "r"(a[0]), "r"(a[1]), "r"(a[2]), "r"(a[3]), "r"(b[0]), "r"(b[1]));
}
__device__ __forceinline__ void cpasync16(uint32_t dst, const void* src) {
    asm volatile("cp.async.cg.shared.global [%0], [%1], 16;" :: "r"(dst), "l"(src));
}

__device__ __forceinline__ void split_store(
    __nv_bfloat16* __restrict__ hi, __nv_bfloat16* __restrict__ lo,
    size_t off, float v0, float v1)
{
    __nv_bfloat16 h0 = __float2bfloat16_rn(v0);
    __nv_bfloat16 h1 = __float2bfloat16_rn(v1);
    __nv_bfloat162 hp; hp.x = h0; hp.y = h1;
    __nv_bfloat162 lp;
    lp.x = __float2bfloat16_rn(v0 - __bfloat162float(h0));
    lp.y = __float2bfloat16_rn(v1 - __bfloat162float(h1));
    *(__nv_bfloat162*)(hi + off) = hp;
    *(__nv_bfloat162*)(lo + off) = lp;
}

// ============================================================================
// bf16 split-precision tensor-core GEMM (TN): D[m,n] = sum_k A[m,k]*B[n,k]
// CTA tile 128x128, K-step 32, 2-stage cp.async pipeline, 8 warps (4M x 2N).
// acc += Ahi*Bhi + Alo*Bhi + Ahi*Blo  (fp32 accumulate)
// ============================================================================
#define PITCHB   80                  // bytes per smem row (40 bf16, conflict-free)
#define TILE_SB  (128*PITCHB)        // 10240 B per operand tile
#define STG_SB   (4*TILE_SB)         // Ahi, Alo, Bhi, Blo
#define MMA_SMEM (2*STG_SB)          // 81920 B

__device__ __forceinline__ void issue_stage(
    uint32_t sb, int s, int k0,
    const __nv_bfloat16* __restrict__ Ahi, const __nv_bfloat16* __restrict__ Alo,
    const __nv_bfloat16* __restrict__ Bhi, const __nv_bfloat16* __restrict__ Blo,
    int mb0, int nb0)
{
    const int tid  = threadIdx.x;
    const int lrow = tid >> 1;
    const int cb   = (tid & 1) * 32;   // byte offset within the 64-B k-slice
    const __nv_bfloat16* gp[4] = {
        Ahi + (size_t)(mb0 + lrow) * 1024,
        Alo + (size_t)(mb0 + lrow) * 1024,
        Bhi + (size_t)(nb0 + lrow) * 1024,
        Blo + (size_t)(nb0 + lrow) * 1024 };
    #pragma unroll
    for (int t = 0; t < 4; t++) {
        const char* src = (const char*)(gp[t] + k0) + cb;
        uint32_t dst = sb + s * STG_SB + t * TILE_SB + lrow * PITCHB + cb;
        cpasync16(dst,      src);
        cpasync16(dst + 16, src + 16);
    }
    asm volatile("cp.async.commit_group;" ::: "memory");
}

__device__ __forceinline__ void compute_stage(uint32_t sb, int s, float acc[2][8][4])
{
    const int lane = threadIdx.x & 31, wid = threadIdx.x >> 5;
    const int wm = wid & 3, wn = wid >> 2;
    const uint32_t ab_hi = sb + s * STG_SB;
    const uint32_t ab_lo = ab_hi + TILE_SB;
    const uint32_t bb_hi = ab_hi + 2 * TILE_SB;
    const uint32_t bb_lo = ab_hi + 3 * TILE_SB;
    #pragma unroll
    for (int k16 = 0; k16 < 2; k16++) {
        const uint32_t acol = k16 * 32 + (lane >> 4) * 16;
        uint32_t ah[2][4], al[2][4];
        #pragma unroll
        for (int mt = 0; mt < 2; mt++) {
            uint32_t arow = wm * 32 + mt * 16 + (lane & 15);
            ldsm_x4(ah[mt], ab_hi + arow * PITCHB + acol);
            ldsm_x4(al[mt], ab_lo + arow * PITCHB + acol);
        }
        const uint32_t bcol = k16 * 32 + ((lane >> 3) & 1) * 16;
        #pragma unroll
        for (int nt = 0; nt < 8; nt++) {
            uint32_t brow = wn * 64 + nt * 8 + (lane & 7);
            uint32_t bh[2], bl[2];
            ldsm_x2(bh, bb_hi + brow * PITCHB + bcol);
            ldsm_x2(bl, bb_lo + brow * PITCHB + bcol);
            #pragma unroll
            for (int mt = 0; mt < 2; mt++) {
                mma16816(acc[mt][nt], ah[mt], bh);
                mma16816(acc[mt][nt], al[mt], bh);
                mma16816(acc[mt][nt], ah[mt], bl);
            }
        }
    }
}

__device__ __forceinline__ void mma_mainloop(
    char* smem,
    const __nv_bfloat16* __restrict__ Ahi, const __nv_bfloat16* __restrict__ Alo,
    const __nv_bfloat16* __restrict__ Bhi, const __nv_bfloat16* __restrict__ Blo,
    int mb0, int nb0, float acc[2][8][4])
{
    uint32_t sb = s2u(smem);
    issue_stage(sb, 0, 0,  Ahi, Alo, Bhi, Blo, mb0, nb0);
    issue_stage(sb, 1, 32, Ahi, Alo, Bhi, Blo, mb0, nb0);
    #pragma unroll 1
    for (int st = 0; st < 32; st++) {
        if (st + 1 < 32) asm volatile("cp.async.wait_group 1;" ::: "memory");
        else             asm volatile("cp.async.wait_group 0;" ::: "memory");
        __syncthreads();
        compute_stage(sb, st & 1, acc);
        __syncthreads();
        if (st + 2 < 32)
            issue_stage(sb, st & 1, (st + 2) * 32, Ahi, Alo, Bhi, Blo, mb0, nb0);
    }
}

// ---------------- mma kernel 1: v[z,c,t] = Wv[h] @ x[b] + bv, split bf16 ----
__global__ __launch_bounds__(256, 1) void k_mma_vconv(
    const __nv_bfloat16* __restrict__ whi, const __nv_bfloat16* __restrict__ wlo,
    const __nv_bfloat16* __restrict__ xhi, const __nv_bfloat16* __restrict__ xlo,
    const float* __restrict__ bv,
    __nv_bfloat16* __restrict__ vhi, __nv_bfloat16* __restrict__ vlo)
{
    extern __shared__ char smem[];
    const int z = blockIdx.z, h = z & 7, b = z >> 3;
    const int mb0 = blockIdx.y * 128;    // c
    const int nb0 = blockIdx.x * 128;    // t
    float acc[2][8][4] = {};
    mma_mainloop(smem,
                 whi + (size_t)h * 1048576, wlo + (size_t)h * 1048576,
                 xhi + (size_t)b * 1048576, xlo + (size_t)b * 1048576,
                 mb0, nb0, acc);
    const int lane = threadIdx.x & 31, wid = threadIdx.x >> 5;
    const int wm = wid & 3, wn = wid >> 2;
    #pragma unroll
    for (int mt = 0; mt < 2; mt++) {
        int r0 = mb0 + wm * 32 + mt * 16 + (lane >> 2);
        float bias0 = bv[h * Cdim + r0];
        float bias1 = bv[h * Cdim + r0 + 8];
        size_t base = (size_t)z * 1048576 + (size_t)r0 * 1024;
        #pragma unroll
        for (int nt = 0; nt < 8; nt++) {
            int col = nb0 + wn * 64 + nt * 8 + (lane & 3) * 2;
            split_store(vhi, vlo, base + col,
                        acc[mt][nt][0] + bias0, acc[mt][nt][1] + bias0);
            split_store(vhi, vlo, base + 8 * 1024 + col,
                        acc[mt][nt][2] + bias1, acc[mt][nt][3] + bias1);
        }
    }
}

// ---------------- mma kernel 2: heads[z,t,c] = gamma*attn@v^T + x^T ---------
__global__ __launch_bounds__(256, 1) void k_mma_oheads(
    const __nv_bfloat16* __restrict__ ahi, const __nv_bfloat16* __restrict__ alo,
    const __nv_bfloat16* __restrict__ vhi, const __nv_bfloat16* __restrict__ vlo,
    const float* __restrict__ gamma, const float* __restrict__ xT32,
    float* __restrict__ heads)
{
    extern __shared__ char smem[];
    const int z = blockIdx.z, h = z & 7, b = z >> 3;
    const int mb0 = blockIdx.y * 128;    // t
    const int nb0 = blockIdx.x * 128;    // c
    float acc[2][8][4] = {};
    mma_mainloop(smem,
                 ahi + (size_t)z * 1048576, alo + (size_t)z * 1048576,
                 vhi + (size_t)z * 1048576, vlo + (size_t)z * 1048576,
                 mb0, nb0, acc);
    const int lane = threadIdx.x & 31, wid = threadIdx.x >> 5;
    const int wm = wid & 3, wn = wid >> 2;
    const float g = gamma[h];
    #pragma unroll
    for (int mt = 0; mt < 2; mt++) {
        int r0 = mb0 + wm * 32 + mt * 16 + (lane >> 2);
        size_t hb = (size_t)z * 1048576 + (size_t)r0 * 1024;
        size_t xb = (size_t)b * 1048576 + (size_t)r0 * 1024;
        #pragma unroll
        for (int nt = 0; nt < 8; nt++) {
            int col = nb0 + wn * 64 + nt * 8 + (lane & 3) * 2;
            float2 o0, o1;
            o0.x = g * acc[mt][nt][0] + xT32[xb + col];
            o0.y = g * acc[mt][nt][1] + xT32[xb + col + 1];
            o1.x = g * acc[mt][nt][2] + xT32[xb + 8 * 1024 + col];
            o1.y = g * acc[mt][nt][3] + xT32[xb + 8 * 1024 + col + 1];
            *(float2*)&heads[hb + col]            = o0;
            *(float2*)&heads[hb + 8 * 1024 + col] = o1;
        }
    }
}

// ============================================================================
// fp32 SGEMM path (q/k proj, energy, fc1, fc2)
// ============================================================================
template<bool AM, bool BN>
__device__ __forceinline__ void sgemm_body(
    const float* __restrict__ A, const float* __restrict__ B,
    int K, int lda, int ldb, int mb, int nb,
    float (&acc)[8][8])
{
    __shared__ float As[8][132];
    __shared__ float Bs[8][132];
    const int tid = threadIdx.x;
    const int tx  = tid & 15;
    const int ty  = tid >> 4;

    for (int k0 = 0; k0 < K; k0 += 8) {
        #pragma unroll
        for (int j = 0; j < 4; j++) {
            int e = (j << 8) + tid;
            int m, kk;
            if (AM) { m = e & 127; kk = e >> 7; }
            else    { kk = e & 7;  m  = e >> 3; }
            size_t idx = AM ? (size_t)(k0 + kk) * lda + (size_t)(mb + m)
                            : (size_t)(mb + m) * lda + (size_t)(k0 + kk);
            As[kk][m] = A[idx];
        }
        #pragma unroll
        for (int j = 0; j < 4; j++) {
            int e = (j << 8) + tid;
            int n, kk;
            if (BN) { n = e & 127; kk = e >> 7; }
            else    { kk = e & 7;  n  = e >> 3; }
            size_t idx = BN ? (size_t)(k0 + kk) * ldb + (size_t)(nb + n)
                            : (size_t)(nb + n) * ldb + (size_t)(k0 + kk);
            Bs[kk][n] = B[idx];
        }
        __syncthreads();
        #pragma unroll
        for (int kk = 0; kk < 8; kk++) {
            float a[8], bb[8];
            *(float4*)&a[0]  = *(const float4*)&As[kk][ty * 4];
            *(float4*)&a[4]  = *(const float4*)&As[kk][64 + ty * 4];
            *(float4*)&bb[0] = *(const float4*)&Bs[kk][tx * 4];
            *(float4*)&bb[4] = *(const float4*)&Bs[kk][64 + tx * 4];
            #pragma unroll
            for (int i = 0; i < 8; i++)
                #pragma unroll
                for (int jj = 0; jj < 8; jj++)
                    acc[i][jj] += a[i] * bb[jj];
        }
        __syncthreads();
    }
}

__device__ __forceinline__ int tile_m(int mb, int ty, int i) {
    return mb + ty * 4 + ((i < 4) ? i : 60 + i);
}

__global__ __launch_bounds__(256) void k_conv(
    const float* __restrict__ W, const float* __restrict__ bias,
    const float* __restrict__ x, float* __restrict__ out, int M)
{
    const int z = blockIdx.z;
    const int b = z >> 3, h = z & 7;
    const int mb = blockIdx.y * 128, nb = blockIdx.x * 128;
    const float* Ap = W + (size_t)h * M * Cdim;
    const float* Bp = x + (size_t)b * Cdim * Tdim;
    float acc[8][8] = {};
    sgemm_body<false, true>(Ap, Bp, Cdim, Cdim, Tdim, mb, nb, acc);

    const int tx = threadIdx.x & 15, ty = threadIdx.x >> 4;
    const float* bb = bias + h * M;
    float* o = out + (size_t)z * M * Tdim;
    #pragma unroll
    for (int i = 0; i < 8; i++) {
        int m = tile_m(mb, ty, i);
        float bvv = bb[m];
        float4 r0 = make_float4(acc[i][0]+bvv, acc[i][1]+bvv, acc[i][2]+bvv, acc[i][3]+bvv);
        float4 r1 = make_float4(acc[i][4]+bvv, acc[i][5]+bvv, acc[i][6]+bvv, acc[i][7]+bvv);
        *(float4*)&o[(size_t)m * Tdim + nb + tx * 4]      = r0;
        *(float4*)&o[(size_t)m * Tdim + nb + 64 + tx * 4] = r1;
    }
}

__global__ __launch_bounds__(256) void k_energy(
    const float* __restrict__ q, const float* __restrict__ kk,
    float* __restrict__ attn)
{
    const int z = blockIdx.z;
    const int mb = blockIdx.y * 128, nb = blockIdx.x * 128;
    const float* Ap = q  + (size_t)z * DQKd * Tdim;
    const float* Bp = kk + (size_t)z * DQKd * Tdim;
    float acc[8][8] = {};
    sgemm_body<true, true>(Ap, Bp, DQKd, Tdim, Tdim, mb, nb, acc);

    const int tx = threadIdx.x & 15, ty = threadIdx.x >> 4;
    float* o = attn + (size_t)z * Tdim * Tdim;
    #pragma unroll
    for (int i = 0; i < 8; i++) {
        int m = tile_m(mb, ty, i);
        float4 r0 = make_float4(acc[i][0], acc[i][1], acc[i][2], acc[i][3]);
        float4 r1 = make_float4(acc[i][4], acc[i][5], acc[i][6], acc[i][7]);
        *(float4*)&o[(size_t)m * Tdim + nb + tx * 4]      = r0;
        *(float4*)&o[(size_t)m * Tdim + nb + 64 + tx * 4] = r1;
    }
}

// softmax over 1024-wide rows; emits bf16 hi/lo split
__global__ __launch_bounds__(256) void k_softmax2(
    const float* __restrict__ E,
    __nv_bfloat16* __restrict__ ah, __nv_bfloat16* __restrict__ al)
{
    const float* row = E + (size_t)blockIdx.x * Tdim;
    const int tid = threadIdx.x;
    float4 v = *(const float4*)&row[tid * 4];
    __shared__ float red[256];

    float mx = fmaxf(fmaxf(v.x, v.y), fmaxf(v.z, v.w));
    red[tid] = mx; __syncthreads();
    #pragma unroll
    for (int s = 128; s > 0; s >>= 1) {
        if (tid < s) red[tid] = fmaxf(red[tid], red[tid + s]);
        __syncthreads();
    }
    mx = red[0]; __syncthreads();

    v.x = __expf(v.x - mx); v.y = __expf(v.y - mx);
    v.z = __expf(v.z - mx); v.w = __expf(v.w - mx);
    red[tid] = v.x + v.y + v.z + v.w; __syncthreads();
    #pragma unroll
    for (int s = 128; s > 0; s >>= 1) {
        if (tid < s) red[tid] += red[tid + s];
        __syncthreads();
    }
    float inv = 1.0f / red[0];
    v.x *= inv; v.y *= inv; v.z *= inv; v.w *= inv;

    size_t o = (size_t)blockIdx.x * Tdim + tid * 4;
    split_store(ah, al, o,     v.x, v.y);
    split_store(ah, al, o + 2, v.z, v.w);
}

__global__ __launch_bounds__(256) void k_fc1(
    const float* __restrict__ heads, const float* __restrict__ W1,
    const float* __restrict__ b1, float* __restrict__ y1)
{
    const int mb = blockIdx.y * 128;
    float acc[8][8] = {};
    sgemm_body<false, false>(heads, W1, Cdim, Cdim, Cdim, mb, 0, acc);

    const int tx = threadIdx.x & 15, ty = threadIdx.x >> 4;
    #pragma unroll
    for (int i = 0; i < 8; i++) {
        int m = tile_m(mb, ty, i);
        int n0 = tx * 4, n1 = 64 + tx * 4;
        float4 r0, r1;
        r0.x = fmaxf(acc[i][0] + b1[n0+0], 0.f);
        r0.y = fmaxf(acc[i][1] + b1[n0+1], 0.f);
        r0.z = fmaxf(acc[i][2] + b1[n0+2], 0.f);
        r0.w = fmaxf(acc[i][3] + b1[n0+3], 0.f);
        r1.x = fmaxf(acc[i][4] + b1[n1+0], 0.f);
        r1.y = fmaxf(acc[i][5] + b1[n1+1], 0.f);
        r1.z = fmaxf(acc[i][6] + b1[n1+2], 0.f);
        r1.w = fmaxf(acc[i][7] + b1[n1+3], 0.f);
        *(float4*)&y1[(size_t)m * DFC1 + n0] = r0;
        *(float4*)&y1[(size_t)m * DFC1 + n1] = r1;
    }
}

__global__ __launch_bounds__(256) void k_fc2(
    const float* __restrict__ y1, const float* __restrict__ W2,
    const float* __restrict__ b2, const float* __restrict__ x,
    float* __restrict__ out)
{
    const int mb = blockIdx.y * 128;
    float acc[8][8] = {};
    sgemm_body<false, false>(y1, W2, DFC1, DFC1, DFC1, mb, 0, acc);

    const int tx = threadIdx.x & 15, ty = threadIdx.x >> 4;
    #pragma unroll
    for (int i = 0; i < 8; i++) {
        int m = tile_m(mb, ty, i);           // r = (b*H + h)*T + t
        int b = m >> 13;
        int h = (m >> 10) & 7;
        int t = m & 1023;
        size_t xbase = (size_t)b * Cdim * Tdim + t;
        #pragma unroll
        for (int j = 0; j < 8; j++) {
            int n = tx * 4 + ((j < 4) ? j : 60 + j);
            int cp = n * Hn + h;
            size_t idx = xbase + (size_t)cp * Tdim;
            out[idx] = fmaxf(acc[i][j] + b2[n], 0.f) + x[idx];
        }
    }
}

// ---------------- prep kernels ----------------
__global__ __launch_bounds__(256) void k_wsplit(
    const float* __restrict__ w, __nv_bfloat16* __restrict__ hi,
    __nv_bfloat16* __restrict__ lo)
{
    size_t i = ((size_t)blockIdx.x * 256 + threadIdx.x) * 4;
    float4 v = *(const float4*)(w + i);
    split_store(hi, lo, i,     v.x, v.y);
    split_store(hi, lo, i + 2, v.z, v.w);
}

// transpose x (b,c,t) -> xT (b,t,c) as fp32 + bf16 hi/lo
__global__ void k_xprep(const float* __restrict__ x, float* __restrict__ xT32,
                        __nv_bfloat16* __restrict__ xh, __nv_bfloat16* __restrict__ xl)
{
    __shared__ float tile[32][33];
    const int b = blockIdx.z;
    const int c0 = blockIdx.y * 32, t0 = blockIdx.x * 32;
    for (int r = threadIdx.y; r < 32; r += 8)
        tile[r][threadIdx.x] = x[(size_t)b * Cdim * Tdim + (size_t)(c0 + r) * Tdim + t0 + threadIdx.x];
    __syncthreads();
    for (int r = threadIdx.y; r < 32; r += 8) {
        float v = tile[threadIdx.x][r];
        size_t o = (size_t)b * Tdim * Cdim + (size_t)(t0 + r) * Cdim + c0 + threadIdx.x;
        xT32[o] = v;
        __nv_bfloat16 h = __float2bfloat16_rn(v);
        xh[o] = h;
        xl[o] = __float2bfloat16_rn(v - __bfloat162float(h));
    }
}

// ============================================================================
// launch
// ============================================================================
extern "C" void kernel_launch(void* const* d_in, const int* in_sizes, int n_in,
                              void* d_out, int out_size)
{
    (void)in_sizes; (void)n_in; (void)out_size;
    const float* x     = (const float*)d_in[0];
    const float* Wq    = (const float*)d_in[1];
    const float* bq    = (const float*)d_in[2];
    const float* Wk    = (const float*)d_in[3];
    const float* bk    = (const float*)d_in[4];
    const float* Wv    = (const float*)d_in[5];
    const float* bv    = (const float*)d_in[6];
    const float* gamma = (const float*)d_in[7];
    const float* W1    = (const float*)d_in[8];
    const float* b1    = (const float*)d_in[9];
    const float* W2    = (const float*)d_in[10];
    const float* b2    = (const float*)d_in[11];
    float* out = (float*)d_out;

    float *q, *k, *attn, *heads, *y1, *xT32;
    __nv_bfloat16 *ahi, *alo, *vhi, *vlo, *whi, *wlo, *xhi, *xlo;
    cudaGetSymbolAddress((void**)&q,     g_q);
    cudaGetSymbolAddress((void**)&k,     g_k);
    cudaGetSymbolAddress((void**)&attn,  g_attn);
    cudaGetSymbolAddress((void**)&ahi,   g_attn_hi);
    cudaGetSymbolAddress((void**)&alo,   g_attn_lo);
    cudaGetSymbolAddress((void**)&vhi,   g_v_hi);
    cudaGetSymbolAddress((void**)&vlo,   g_v_lo);
    cudaGetSymbolAddress((void**)&whi,   g_wv_hi);
    cudaGetSymbolAddress((void**)&wlo,   g_wv_lo);
    cudaGetSymbolAddress((void**)&xhi,   g_xT_hi);
    cudaGetSymbolAddress((void**)&xlo,   g_xT_lo);
    cudaGetSymbolAddress((void**)&xT32,  g_xT32);
    cudaGetSymbolAddress((void**)&heads, g_hds);
    cudaGetSymbolAddress((void**)&y1,    g_y1);

    static bool attr_set = false;
    if (!attr_set) {
        cudaFuncSetAttribute(k_mma_vconv,  cudaFuncAttributeMaxDynamicSharedMemorySize, MMA_SMEM);
        cudaFuncSetAttribute(k_mma_oheads, cudaFuncAttributeMaxDynamicSharedMemorySize, MMA_SMEM);
        attr_set = true;
    }

    const dim3 blk(256);
    const int ZB = Bsz * Hn;   // 64

    // q, k projections (fp32 SGEMM)
    k_conv<<<dim3(Tdim/128, DQKd/128, ZB), blk>>>(Wq, bq, x, q, DQKd);
    k_conv<<<dim3(Tdim/128, DQKd/128, ZB), blk>>>(Wk, bk, x, k, DQKd);

    // bf16 split preps
    k_wsplit<<<(Hn*Cdim*Cdim)/1024, 256>>>(Wv, whi, wlo);
    k_xprep<<<dim3(Tdim/32, Cdim/32, Bsz), dim3(32, 8)>>>(x, xT32, xhi, xlo);

    // v projection (tensor-core split-bf16): v[z,c,t]
    k_mma_vconv<<<dim3(Tdim/128, Cdim/128, ZB), blk, MMA_SMEM>>>(
        whi, wlo, xhi, xlo, bv, vhi, vlo);

    // energy + softmax (softmax emits attn hi/lo)
    k_energy  <<<dim3(Tdim/128, Tdim/128, ZB), blk>>>(q, k, attn);
    k_softmax2<<<ZB * Tdim, blk>>>(attn, ahi, alo);

    // heads[z,t,c] = gamma * (attn @ v^T) + x^T  (tensor-core split-bf16)
    k_mma_oheads<<<dim3(Cdim/128, Tdim/128, ZB), blk, MMA_SMEM>>>(
        ahi, alo, vhi, vlo, gamma, xT32, heads);

    // MLP
    const int ROWS = Bsz * Hn * Tdim;
    k_fc1<<<dim3(1, ROWS/128), blk>>>(heads, W1, b1, y1);
    k_fc2<<<dim3(1, ROWS/128), blk>>>(y1, W2, b2, x, out);
}

// round 4
// speedup vs baseline: 2.1932x; 1.2229x over previous
#include <cuda_runtime.h>
#include <cuda_bf16.h>
#include <cstdint>

// ---------------- problem constants ----------------
#define Bsz  8
#define Cdim 1024
#define Tdim 1024
#define Hn   8
#define DQKd 128
#define DFC1 128

// ---------------- scratch (device globals; no allocs allowed) ----------------
__device__ float g_attn[(size_t)Bsz*Hn*Tdim*Tdim];            // fp32 energy
__device__ __nv_bfloat16 g_attn_hi[(size_t)Bsz*Hn*Tdim*Tdim];
__device__ __nv_bfloat16 g_attn_lo[(size_t)Bsz*Hn*Tdim*Tdim];
__device__ __nv_bfloat16 g_v_hi[(size_t)Bsz*Hn*Cdim*Tdim];    // v (z,c,t)
__device__ __nv_bfloat16 g_v_lo[(size_t)Bsz*Hn*Cdim*Tdim];
__device__ __nv_bfloat16 g_wv_hi[(size_t)Hn*Cdim*Cdim];
__device__ __nv_bfloat16 g_wv_lo[(size_t)Hn*Cdim*Cdim];
__device__ __nv_bfloat16 g_wq_hi[(size_t)Hn*DQKd*Cdim];
__device__ __nv_bfloat16 g_wq_lo[(size_t)Hn*DQKd*Cdim];
__device__ __nv_bfloat16 g_wk_hi[(size_t)Hn*DQKd*Cdim];
__device__ __nv_bfloat16 g_wk_lo[(size_t)Hn*DQKd*Cdim];
__device__ __nv_bfloat16 g_w1_hi[(size_t)DFC1*Cdim];
__device__ __nv_bfloat16 g_w1_lo[(size_t)DFC1*Cdim];
__device__ __nv_bfloat16 g_w2_hi[(size_t)DFC1*DFC1];
__device__ __nv_bfloat16 g_w2_lo[(size_t)DFC1*DFC1];
__device__ __nv_bfloat16 g_xT_hi[(size_t)Bsz*Tdim*Cdim];      // x^T (b,t,c)
__device__ __nv_bfloat16 g_xT_lo[(size_t)Bsz*Tdim*Cdim];
__device__ float g_xT32[(size_t)Bsz*Tdim*Cdim];
__device__ __nv_bfloat16 g_q_hi[(size_t)Bsz*Hn*Tdim*DQKd];    // q (z,t,o)
__device__ __nv_bfloat16 g_q_lo[(size_t)Bsz*Hn*Tdim*DQKd];
__device__ __nv_bfloat16 g_k_hi[(size_t)Bsz*Hn*Tdim*DQKd];
__device__ __nv_bfloat16 g_k_lo[(size_t)Bsz*Hn*Tdim*DQKd];
__device__ __nv_bfloat16 g_h_hi[(size_t)Bsz*Hn*Tdim*Cdim];    // heads (z,t,c)
__device__ __nv_bfloat16 g_h_lo[(size_t)Bsz*Hn*Tdim*Cdim];
__device__ __nv_bfloat16 g_y1_hi[(size_t)Bsz*Hn*Tdim*DFC1];
__device__ __nv_bfloat16 g_y1_lo[(size_t)Bsz*Hn*Tdim*DFC1];

// ============================================================================
// PTX helpers (sm_80-level — valid on compute_103)
// ============================================================================
__device__ __forceinline__ uint32_t s2u(const void* p) {
    uint32_t a;
    asm("{ .reg .u64 t; cvta.to.shared.u64 t, %1; cvt.u32.u64 %0, t; }"
        : "=r"(a) : "l"(p));
    return a;
}
__device__ __forceinline__ void ldsm_x4(uint32_t* r, uint32_t addr) {
    asm volatile("ldmatrix.sync.aligned.m8n8.x4.shared.b16 {%0,%1,%2,%3}, [%4];"
        : "=r"(r[0]), "=r"(r[1]), "=r"(r[2]), "=r"(r[3]) : "r"(addr));
}
__device__ __forceinline__ void ldsm_x2(uint32_t* r, uint32_t addr) {
    asm volatile("ldmatrix.sync.aligned.m8n8.x2.shared.b16 {%0,%1}, [%2];"
        : "=r"(r[0]), "=r"(r[1]) : "r"(addr));
}
__device__ __forceinline__ void mma16816(float* c, const uint32_t* a, const uint32_t* b) {
    asm volatile("mma.sync.aligned.m16n8k16.row.col.f32.bf16.bf16.f32 "
        "{%0,%1,%2,%3}, {%4,%5,%6,%7}, {%8,%9}, {%0,%1,%2,%3};"
        : "+f"(c[0]), "+f"(c[1]), "+f"(c[2]), "+f"(c[3])
        : "r"(a[0]), "r"(a[1]), "r"(a[2]), "r"(a[3]), "r"(b[0]), "r"(b[1]));
}
__device__ __forceinline__ void cpasync16(uint32_t dst, const void* src) {
    asm volatile("cp.async.cg.shared.global [%0], [%1], 16;" :: "r"(dst), "l"(src));
}

__device__ __forceinline__ void split_store(
    __nv_bfloat16* __restrict__ hi, __nv_bfloat16* __restrict__ lo,
    size_t off, float v0, float v1)
{
    __nv_bfloat16 h0 = __float2bfloat16_rn(v0);
    __nv_bfloat16 h1 = __float2bfloat16_rn(v1);
    __nv_bfloat162 hp; hp.x = h0; hp.y = h1;
    __nv_bfloat162 lp;
    lp.x = __float2bfloat16_rn(v0 - __bfloat162float(h0));
    lp.y = __float2bfloat16_rn(v1 - __bfloat162float(h1));
    *(__nv_bfloat162*)(hi + off) = hp;
    *(__nv_bfloat162*)(lo + off) = lp;
}

// ============================================================================
// bf16 split-precision tensor-core GEMM (TN): D[m,n] = sum_k A[m,k]*B[n,k]
// CTA tile 128x128, K-step 32, 3-stage cp.async pipeline, 8 warps (4M x 2N).
// acc += Ahi*Bhi + Alo*Bhi + Ahi*Blo  (fp32 accumulate)
// ============================================================================
#define PITCHB   80                  // bytes per smem row (40 bf16, conflict-free)
#define TILE_SB  (128*PITCHB)        // 10240 B per operand tile
#define STG_SB   (4*TILE_SB)         // Ahi, Alo, Bhi, Blo
#define NPIPE    3
#define MMA_SMEM (NPIPE*STG_SB)      // 122880 B

__device__ __forceinline__ void issue_stage(
    uint32_t sb, int buf, int k0,
    const __nv_bfloat16* __restrict__ Ahi, const __nv_bfloat16* __restrict__ Alo,
    const __nv_bfloat16* __restrict__ Bhi, const __nv_bfloat16* __restrict__ Blo,
    int lda, int ldb, int mb0, int nb0)
{
    const int tid  = threadIdx.x;
    const int lrow = tid >> 1;
    const int cb   = (tid & 1) * 32;   // byte offset within the 64-B k-slice
    const __nv_bfloat16* gp[4] = {
        Ahi + (size_t)(mb0 + lrow) * lda,
        Alo + (size_t)(mb0 + lrow) * lda,
        Bhi + (size_t)(nb0 + lrow) * ldb,
        Blo + (size_t)(nb0 + lrow) * ldb };
    #pragma unroll
    for (int t = 0; t < 4; t++) {
        const char* src = (const char*)(gp[t] + k0) + cb;
        uint32_t dst = sb + buf * STG_SB + t * TILE_SB + lrow * PITCHB + cb;
        cpasync16(dst,      src);
        cpasync16(dst + 16, src + 16);
    }
    asm volatile("cp.async.commit_group;" ::: "memory");
}

__device__ __forceinline__ void compute_stage(uint32_t sb, int buf, float acc[2][8][4])
{
    const int lane = threadIdx.x & 31, wid = threadIdx.x >> 5;
    const int wm = wid & 3, wn = wid >> 2;
    const uint32_t ab_hi = sb + buf * STG_SB;
    const uint32_t ab_lo = ab_hi + TILE_SB;
    const uint32_t bb_hi = ab_hi + 2 * TILE_SB;
    const uint32_t bb_lo = ab_hi + 3 * TILE_SB;
    #pragma unroll
    for (int k16 = 0; k16 < 2; k16++) {
        const uint32_t acol = k16 * 32 + (lane >> 4) * 16;
        uint32_t ah[2][4], al[2][4];
        #pragma unroll
        for (int mt = 0; mt < 2; mt++) {
            uint32_t arow = wm * 32 + mt * 16 + (lane & 15);
            ldsm_x4(ah[mt], ab_hi + arow * PITCHB + acol);
            ldsm_x4(al[mt], ab_lo + arow * PITCHB + acol);
        }
        const uint32_t bcol = k16 * 32 + ((lane >> 3) & 1) * 16;
        #pragma unroll
        for (int nt = 0; nt < 8; nt++) {
            uint32_t brow = wn * 64 + nt * 8 + (lane & 7);
            uint32_t bh[2], bl[2];
            ldsm_x2(bh, bb_hi + brow * PITCHB + bcol);
            ldsm_x2(bl, bb_lo + brow * PITCHB + bcol);
            #pragma unroll
            for (int mt = 0; mt < 2; mt++) {
                mma16816(acc[mt][nt], ah[mt], bh);
                mma16816(acc[mt][nt], al[mt], bh);
                mma16816(acc[mt][nt], ah[mt], bl);
            }
        }
    }
}

__device__ __forceinline__ void mma_mainloop(
    char* smem,
    const __nv_bfloat16* __restrict__ Ahi, const __nv_bfloat16* __restrict__ Alo,
    const __nv_bfloat16* __restrict__ Bhi, const __nv_bfloat16* __restrict__ Blo,
    int lda, int ldb, int mb0, int nb0, int nst, float acc[2][8][4])
{
    uint32_t sb = s2u(smem);
    issue_stage(sb, 0, 0,  Ahi, Alo, Bhi, Blo, lda, ldb, mb0, nb0);
    issue_stage(sb, 1, 32, Ahi, Alo, Bhi, Blo, lda, ldb, mb0, nb0);
    #pragma unroll 1
    for (int st = 0; st < nst; st++) {
        if (st + 2 < nst) {
            int nx = st + 2;
            issue_stage(sb, nx % NPIPE, nx * 32, Ahi, Alo, Bhi, Blo, lda, ldb, mb0, nb0);
        }
        int rem = nst - 1 - st;
        if      (rem >= 2) asm volatile("cp.async.wait_group 2;" ::: "memory");
        else if (rem == 1) asm volatile("cp.async.wait_group 1;" ::: "memory");
        else               asm volatile("cp.async.wait_group 0;" ::: "memory");
        __syncthreads();
        compute_stage(sb, st % NPIPE, acc);
        __syncthreads();
    }
}

// epilogue index helpers (shared by all mma kernels)
struct EpiIdx { int r0; int lane, wm, wn; };
__device__ __forceinline__ EpiIdx epi_idx(int mb0, int mt) {
    EpiIdx e;
    e.lane = threadIdx.x & 31;
    int wid = threadIdx.x >> 5;
    e.wm = wid & 3; e.wn = wid >> 2;
    e.r0 = mb0 + e.wm * 32 + mt * 16 + (e.lane >> 2);
    return e;
}

// ---------------- q/k projection: P[z,t,o] = xT[b] @ W[h]^T + bias, split ---
__global__ __launch_bounds__(256, 1) void k_mma_proj(
    const __nv_bfloat16* __restrict__ xhi, const __nv_bfloat16* __restrict__ xlo,
    const __nv_bfloat16* __restrict__ whi, const __nv_bfloat16* __restrict__ wlo,
    const float* __restrict__ bias,
    __nv_bfloat16* __restrict__ phi, __nv_bfloat16* __restrict__ plo)
{
    extern __shared__ char smem[];
    const int z = blockIdx.z, h = z & 7, b = z >> 3;
    const int mb0 = blockIdx.y * 128;    // t
    float acc[2][8][4] = {};
    mma_mainloop(smem,
                 xhi + (size_t)b * 1048576, xlo + (size_t)b * 1048576,
                 whi + (size_t)h * 131072,  wlo + (size_t)h * 131072,
                 1024, 1024, mb0, 0, 32, acc);
    #pragma unroll
    for (int mt = 0; mt < 2; mt++) {
        EpiIdx e = epi_idx(mb0, mt);
        size_t base = (size_t)z * 131072 + (size_t)e.r0 * 128;
        #pragma unroll
        for (int nt = 0; nt < 8; nt++) {
            int col = e.wn * 64 + nt * 8 + (e.lane & 3) * 2;
            float bc0 = bias[h * DQKd + col], bc1 = bias[h * DQKd + col + 1];
            split_store(phi, plo, base + col,
                        acc[mt][nt][0] + bc0, acc[mt][nt][1] + bc1);
            split_store(phi, plo, base + 8 * 128 + col,
                        acc[mt][nt][2] + bc0, acc[mt][nt][3] + bc1);
        }
    }
}

// ---------------- energy: E[z,t,s] = q[z,t,:] . k[z,s,:]  (fp32 out) --------
__global__ __launch_bounds__(256, 1) void k_mma_energy(
    const __nv_bfloat16* __restrict__ qhi, const __nv_bfloat16* __restrict__ qlo,
    const __nv_bfloat16* __restrict__ khi, const __nv_bfloat16* __restrict__ klo,
    float* __restrict__ attn)
{
    extern __shared__ char smem[];
    const int z = blockIdx.z;
    const int mb0 = blockIdx.y * 128;    // t
    const int nb0 = blockIdx.x * 128;    // s
    float acc[2][8][4] = {};
    mma_mainloop(smem,
                 qhi + (size_t)z * 131072, qlo + (size_t)z * 131072,
                 khi + (size_t)z * 131072, klo + (size_t)z * 131072,
                 128, 128, mb0, nb0, 4, acc);
    #pragma unroll
    for (int mt = 0; mt < 2; mt++) {
        EpiIdx e = epi_idx(mb0, mt);
        size_t base = (size_t)z * 1048576 + (size_t)e.r0 * 1024;
        #pragma unroll
        for (int nt = 0; nt < 8; nt++) {
            int col = nb0 + e.wn * 64 + nt * 8 + (e.lane & 3) * 2;
            *(float2*)&attn[base + col] = make_float2(acc[mt][nt][0], acc[mt][nt][1]);
            *(float2*)&attn[base + 8 * 1024 + col] = make_float2(acc[mt][nt][2], acc[mt][nt][3]);
        }
    }
}

// ---------------- v projection: v[z,c,t] = Wv[h] @ x[b] + bv, split ---------
__global__ __launch_bounds__(256, 1) void k_mma_vconv(
    const __nv_bfloat16* __restrict__ whi, const __nv_bfloat16* __restrict__ wlo,
    const __nv_bfloat16* __restrict__ xhi, const __nv_bfloat16* __restrict__ xlo,
    const float* __restrict__ bv,
    __nv_bfloat16* __restrict__ vhi, __nv_bfloat16* __restrict__ vlo)
{
    extern __shared__ char smem[];
    const int z = blockIdx.z, h = z & 7, b = z >> 3;
    const int mb0 = blockIdx.y * 128;    // c
    const int nb0 = blockIdx.x * 128;    // t
    float acc[2][8][4] = {};
    mma_mainloop(smem,
                 whi + (size_t)h * 1048576, wlo + (size_t)h * 1048576,
                 xhi + (size_t)b * 1048576, xlo + (size_t)b * 1048576,
                 1024, 1024, mb0, nb0, 32, acc);
    #pragma unroll
    for (int mt = 0; mt < 2; mt++) {
        EpiIdx e = epi_idx(mb0, mt);
        float bias0 = bv[h * Cdim + e.r0];
        float bias1 = bv[h * Cdim + e.r0 + 8];
        size_t base = (size_t)z * 1048576 + (size_t)e.r0 * 1024;
        #pragma unroll
        for (int nt = 0; nt < 8; nt++) {
            int col = nb0 + e.wn * 64 + nt * 8 + (e.lane & 3) * 2;
            split_store(vhi, vlo, base + col,
                        acc[mt][nt][0] + bias0, acc[mt][nt][1] + bias0);
            split_store(vhi, vlo, base + 8 * 1024 + col,
                        acc[mt][nt][2] + bias1, acc[mt][nt][3] + bias1);
        }
    }
}

// ---------------- heads[z,t,c] = gamma*attn@v^T + x^T (split bf16 out) ------
__global__ __launch_bounds__(256, 1) void k_mma_oheads(
    const __nv_bfloat16* __restrict__ ahi, const __nv_bfloat16* __restrict__ alo,
    const __nv_bfloat16* __restrict__ vhi, const __nv_bfloat16* __restrict__ vlo,
    const float* __restrict__ gamma, const float* __restrict__ xT32,
    __nv_bfloat16* __restrict__ hhi, __nv_bfloat16* __restrict__ hlo)
{
    extern __shared__ char smem[];
    const int z = blockIdx.z, h = z & 7, b = z >> 3;
    const int mb0 = blockIdx.y * 128;    // t
    const int nb0 = blockIdx.x * 128;    // c
    float acc[2][8][4] = {};
    mma_mainloop(smem,
                 ahi + (size_t)z * 1048576, alo + (size_t)z * 1048576,
                 vhi + (size_t)z * 1048576, vlo + (size_t)z * 1048576,
                 1024, 1024, mb0, nb0, 32, acc);
    const float g = gamma[h];
    #pragma unroll
    for (int mt = 0; mt < 2; mt++) {
        EpiIdx e = epi_idx(mb0, mt);
        size_t hb = (size_t)z * 1048576 + (size_t)e.r0 * 1024;
        size_t xb = (size_t)b * 1048576 + (size_t)e.r0 * 1024;
        #pragma unroll
        for (int nt = 0; nt < 8; nt++) {
            int col = nb0 + e.wn * 64 + nt * 8 + (e.lane & 3) * 2;
            split_store(hhi, hlo, hb + col,
                        g * acc[mt][nt][0] + xT32[xb + col],
                        g * acc[mt][nt][1] + xT32[xb + col + 1]);
            split_store(hhi, hlo, hb + 8 * 1024 + col,
                        g * acc[mt][nt][2] + xT32[xb + 8 * 1024 + col],
                        g * acc[mt][nt][3] + xT32[xb + 8 * 1024 + col + 1]);
        }
    }
}

// ---------------- fc1: y1[r,f] = relu(heads[r,:] . W1[f,:] + b1), split -----
__global__ __launch_bounds__(256, 1) void k_mma_fc1(
    const __nv_bfloat16* __restrict__ hhi, const __nv_bfloat16* __restrict__ hlo,
    const __nv_bfloat16* __restrict__ whi, const __nv_bfloat16* __restrict__ wlo,
    const float* __restrict__ b1,
    __nv_bfloat16* __restrict__ y1hi, __nv_bfloat16* __restrict__ y1lo)
{
    extern __shared__ char smem[];
    const int mb0 = blockIdx.y * 128;    // r
    float acc[2][8][4] = {};
    mma_mainloop(smem, hhi, hlo, whi, wlo, 1024, 1024, mb0, 0, 32, acc);
    #pragma unroll
    for (int mt = 0; mt < 2; mt++) {
        EpiIdx e = epi_idx(mb0, mt);
        size_t base = (size_t)e.r0 * 128;
        #pragma unroll
        for (int nt = 0; nt < 8; nt++) {
            int col = e.wn * 64 + nt * 8 + (e.lane & 3) * 2;
            float bc0 = b1[col], bc1 = b1[col + 1];
            split_store(y1hi, y1lo, base + col,
                        fmaxf(acc[mt][nt][0] + bc0, 0.f), fmaxf(acc[mt][nt][1] + bc1, 0.f));
            split_store(y1hi, y1lo, base + 8 * 128 + col,
                        fmaxf(acc[mt][nt][2] + bc0, 0.f), fmaxf(acc[mt][nt][3] + bc1, 0.f));
        }
    }
}

// ---------------- fc2: out scatter + relu + residual ------------------------
__global__ __launch_bounds__(256, 1) void k_mma_fc2(
    const __nv_bfloat16* __restrict__ y1hi, const __nv_bfloat16* __restrict__ y1lo,
    const __nv_bfloat16* __restrict__ whi, const __nv_bfloat16* __restrict__ wlo,
    const float* __restrict__ b2, const float* __restrict__ x,
    float* __restrict__ out)
{
    extern __shared__ char smem[];
    const int mb0 = blockIdx.y * 128;    // r
    float acc[2][8][4] = {};
    mma_mainloop(smem, y1hi, y1lo, whi, wlo, 128, 128, mb0, 0, 4, acc);
    #pragma unroll
    for (int mt = 0; mt < 2; mt++) {
        EpiIdx e = epi_idx(mb0, mt);
        #pragma unroll
        for (int rr = 0; rr < 2; rr++) {
            int r = e.r0 + rr * 8;               // r = (b*H + h)*T + t
            int b = r >> 13;
            int h = (r >> 10) & 7;
            int t = r & 1023;
            size_t xbase = (size_t)b * 1048576 + t;
            #pragma unroll
            for (int nt = 0; nt < 8; nt++) {
                int col = e.wn * 64 + nt * 8 + (e.lane & 3) * 2;
                #pragma unroll
                for (int jj = 0; jj < 2; jj++) {
                    int d = col + jj;
                    size_t idx = xbase + (size_t)(d * Hn + h) * 1024;
                    out[idx] = fmaxf(acc[mt][nt][rr * 2 + jj] + b2[d], 0.f) + x[idx];
                }
            }
        }
    }
}

// ---------------- softmax over 1024-wide rows; emits bf16 hi/lo split -------
__global__ __launch_bounds__(256) void k_softmax2(
    const float* __restrict__ E,
    __nv_bfloat16* __restrict__ ah, __nv_bfloat16* __restrict__ al)
{
    const float* row = E + (size_t)blockIdx.x * Tdim;
    const int tid = threadIdx.x;
    float4 v = *(const float4*)&row[tid * 4];
    __shared__ float red[256];

    float mx = fmaxf(fmaxf(v.x, v.y), fmaxf(v.z, v.w));
    red[tid] = mx; __syncthreads();
    #pragma unroll
    for (int s = 128; s > 0; s >>= 1) {
        if (tid < s) red[tid] = fmaxf(red[tid], red[tid + s]);
        __syncthreads();
    }
    mx = red[0]; __syncthreads();

    v.x = __expf(v.x - mx); v.y = __expf(v.y - mx);
    v.z = __expf(v.z - mx); v.w = __expf(v.w - mx);
    red[tid] = v.x + v.y + v.z + v.w; __syncthreads();
    #pragma unroll
    for (int s = 128; s > 0; s >>= 1) {
        if (tid < s) red[tid] += red[tid + s];
        __syncthreads();
    }
    float inv = 1.0f / red[0];
    v.x *= inv; v.y *= inv; v.z *= inv; v.w *= inv;

    size_t o = (size_t)blockIdx.x * Tdim + tid * 4;
    split_store(ah, al, o,     v.x, v.y);
    split_store(ah, al, o + 2, v.z, v.w);
}

// ---------------- prep kernels ----------------
__global__ __launch_bounds__(256) void k_wsplit(
    const float* __restrict__ w, __nv_bfloat16* __restrict__ hi,
    __nv_bfloat16* __restrict__ lo)
{
    size_t i = ((size_t)blockIdx.x * 256 + threadIdx.x) * 4;
    float4 v = *(const float4*)(w + i);
    split_store(hi, lo, i,     v.x, v.y);
    split_store(hi, lo, i + 2, v.z, v.w);
}

// transpose x (b,c,t) -> xT (b,t,c) as fp32 + bf16 hi/lo
__global__ void k_xprep(const float* __restrict__ x, float* __restrict__ xT32,
                        __nv_bfloat16* __restrict__ xh, __nv_bfloat16* __restrict__ xl)
{
    __shared__ float tile[32][33];
    const int b = blockIdx.z;
    const int c0 = blockIdx.y * 32, t0 = blockIdx.x * 32;
    for (int r = threadIdx.y; r < 32; r += 8)
        tile[r][threadIdx.x] = x[(size_t)b * Cdim * Tdim + (size_t)(c0 + r) * Tdim + t0 + threadIdx.x];
    __syncthreads();
    for (int r = threadIdx.y; r < 32; r += 8) {
        float v = tile[threadIdx.x][r];
        size_t o = (size_t)b * Tdim * Cdim + (size_t)(t0 + r) * Cdim + c0 + threadIdx.x;
        xT32[o] = v;
        __nv_bfloat16 h = __float2bfloat16_rn(v);
        xh[o] = h;
        xl[o] = __float2bfloat16_rn(v - __bfloat162float(h));
    }
}

// ============================================================================
// launch
// ============================================================================
extern "C" void kernel_launch(void* const* d_in, const int* in_sizes, int n_in,
                              void* d_out, int out_size)
{
    (void)in_sizes; (void)n_in; (void)out_size;
    const float* x     = (const float*)d_in[0];
    const float* Wq    = (const float*)d_in[1];
    const float* bq    = (const float*)d_in[2];
    const float* Wk    = (const float*)d_in[3];
    const float* bk    = (const float*)d_in[4];
    const float* Wv    = (const float*)d_in[5];
    const float* bv    = (const float*)d_in[6];
    const float* gamma = (const float*)d_in[7];
    const float* W1    = (const float*)d_in[8];
    const float* b1    = (const float*)d_in[9];
    const float* W2    = (const float*)d_in[10];
    const float* b2    = (const float*)d_in[11];
    float* out = (float*)d_out;

    float *attn, *xT32;
    __nv_bfloat16 *ahi, *alo, *vhi, *vlo, *wvhi, *wvlo, *wqhi, *wqlo, *wkhi, *wklo;
    __nv_bfloat16 *w1hi, *w1lo, *w2hi, *w2lo, *xhi, *xlo;
    __nv_bfloat16 *qhi, *qlo, *khi, *klo, *hhi, *hlo, *y1hi, *y1lo;
    cudaGetSymbolAddress((void**)&attn,  g_attn);
    cudaGetSymbolAddress((void**)&ahi,   g_attn_hi);
    cudaGetSymbolAddress((void**)&alo,   g_attn_lo);
    cudaGetSymbolAddress((void**)&vhi,   g_v_hi);
    cudaGetSymbolAddress((void**)&vlo,   g_v_lo);
    cudaGetSymbolAddress((void**)&wvhi,  g_wv_hi);
    cudaGetSymbolAddress((void**)&wvlo,  g_wv_lo);
    cudaGetSymbolAddress((void**)&wqhi,  g_wq_hi);
    cudaGetSymbolAddress((void**)&wqlo,  g_wq_lo);
    cudaGetSymbolAddress((void**)&wkhi,  g_wk_hi);
    cudaGetSymbolAddress((void**)&wklo,  g_wk_lo);
    cudaGetSymbolAddress((void**)&w1hi,  g_w1_hi);
    cudaGetSymbolAddress((void**)&w1lo,  g_w1_lo);
    cudaGetSymbolAddress((void**)&w2hi,  g_w2_hi);
    cudaGetSymbolAddress((void**)&w2lo,  g_w2_lo);
    cudaGetSymbolAddress((void**)&xhi,   g_xT_hi);
    cudaGetSymbolAddress((void**)&xlo,   g_xT_lo);
    cudaGetSymbolAddress((void**)&xT32,  g_xT32);
    cudaGetSymbolAddress((void**)&qhi,   g_q_hi);
    cudaGetSymbolAddress((void**)&qlo,   g_q_lo);
    cudaGetSymbolAddress((void**)&khi,   g_k_hi);
    cudaGetSymbolAddress((void**)&klo,   g_k_lo);
    cudaGetSymbolAddress((void**)&hhi,   g_h_hi);
    cudaGetSymbolAddress((void**)&hlo,   g_h_lo);
    cudaGetSymbolAddress((void**)&y1hi,  g_y1_hi);
    cudaGetSymbolAddress((void**)&y1lo,  g_y1_lo);

    static bool attr_set = false;
    if (!attr_set) {
        cudaFuncSetAttribute(k_mma_proj,   cudaFuncAttributeMaxDynamicSharedMemorySize, MMA_SMEM);
        cudaFuncSetAttribute(k_mma_energy, cudaFuncAttributeMaxDynamicSharedMemorySize, MMA_SMEM);
        cudaFuncSetAttribute(k_mma_vconv,  cudaFuncAttributeMaxDynamicSharedMemorySize, MMA_SMEM);
        cudaFuncSetAttribute(k_mma_oheads, cudaFuncAttributeMaxDynamicSharedMemorySize, MMA_SMEM);
        cudaFuncSetAttribute(k_mma_fc1,    cudaFuncAttributeMaxDynamicSharedMemorySize, MMA_SMEM);
        cudaFuncSetAttribute(k_mma_fc2,    cudaFuncAttributeMaxDynamicSharedMemorySize, MMA_SMEM);
        attr_set = true;
    }

    const dim3 blk(256);
    const int ZB = Bsz * Hn;   // 64

    // preps: weight splits + x transpose/split
    k_wsplit<<<(Hn*Cdim*Cdim)/1024, 256>>>(Wv, wvhi, wvlo);
    k_wsplit<<<(Hn*DQKd*Cdim)/1024, 256>>>(Wq, wqhi, wqlo);
    k_wsplit<<<(Hn*DQKd*Cdim)/1024, 256>>>(Wk, wkhi, wklo);
    k_wsplit<<<(DFC1*Cdim)/1024,    256>>>(W1, w1hi, w1lo);
    k_wsplit<<<(DFC1*DFC1)/1024,    256>>>(W2, w2hi, w2lo);
    k_xprep<<<dim3(Tdim/32, Cdim/32, Bsz), dim3(32, 8)>>>(x, xT32, xhi, xlo);

    // q/k projections (tensor core): q[z,t,o], k[z,t,o] split
    k_mma_proj<<<dim3(1, Tdim/128, ZB), blk, MMA_SMEM>>>(xhi, xlo, wqhi, wqlo, bq, qhi, qlo);
    k_mma_proj<<<dim3(1, Tdim/128, ZB), blk, MMA_SMEM>>>(xhi, xlo, wkhi, wklo, bk, khi, klo);

    // v projection: v[z,c,t] split
    k_mma_vconv<<<dim3(Tdim/128, Cdim/128, ZB), blk, MMA_SMEM>>>(
        wvhi, wvlo, xhi, xlo, bv, vhi, vlo);

    // energy (fp32 out) + softmax (emits attn hi/lo)
    k_mma_energy<<<dim3(Tdim/128, Tdim/128, ZB), blk, MMA_SMEM>>>(qhi, qlo, khi, klo, attn);
    k_softmax2<<<ZB * Tdim, blk>>>(attn, ahi, alo);

    // heads[z,t,c] = gamma * (attn @ v^T) + x^T  (split bf16 out)
    k_mma_oheads<<<dim3(Cdim/128, Tdim/128, ZB), blk, MMA_SMEM>>>(
        ahi, alo, vhi, vlo, gamma, xT32, hhi, hlo);

    // MLP
    const int ROWS = Bsz * Hn * Tdim;   // 65536
    k_mma_fc1<<<dim3(1, ROWS/128), blk, MMA_SMEM>>>(hhi, hlo, w1hi, w1lo, b1, y1hi, y1lo);
    k_mma_fc2<<<dim3(1, ROWS/128), blk, MMA_SMEM>>>(y1hi, y1lo, w2hi, w2lo, b2, x, out);
}

// round 5
// speedup vs baseline: 2.7053x; 1.2335x over previous
#include <cuda_runtime.h>
#include <cuda_bf16.h>
#include <cstdint>

// ---------------- problem constants ----------------
#define Bsz  8
#define Cdim 1024
#define Tdim 1024
#define Hn   8
#define DQKd 128
#define DFC1 128

// ---------------- scratch (device globals; no allocs allowed) ----------------
__device__ float g_attn[(size_t)Bsz*Hn*Tdim*Tdim];            // fp32 energy
__device__ __nv_bfloat16 g_attn_hi[(size_t)Bsz*Hn*Tdim*Tdim];
__device__ __nv_bfloat16 g_attn_lo[(size_t)Bsz*Hn*Tdim*Tdim];
__device__ __nv_bfloat16 g_v_hi[(size_t)Bsz*Hn*Cdim*Tdim];    // v (z,c,t)
__device__ __nv_bfloat16 g_v_lo[(size_t)Bsz*Hn*Cdim*Tdim];
__device__ __nv_bfloat16 g_wv_hi[(size_t)Hn*Cdim*Cdim];
__device__ __nv_bfloat16 g_wv_lo[(size_t)Hn*Cdim*Cdim];
__device__ __nv_bfloat16 g_wq_hi[(size_t)Hn*DQKd*Cdim];
__device__ __nv_bfloat16 g_wq_lo[(size_t)Hn*DQKd*Cdim];
__device__ __nv_bfloat16 g_wk_hi[(size_t)Hn*DQKd*Cdim];
__device__ __nv_bfloat16 g_wk_lo[(size_t)Hn*DQKd*Cdim];
__device__ __nv_bfloat16 g_w1_hi[(size_t)DFC1*Cdim];
__device__ __nv_bfloat16 g_w1_lo[(size_t)DFC1*Cdim];
__device__ __nv_bfloat16 g_w2_hi[(size_t)DFC1*DFC1];
__device__ __nv_bfloat16 g_w2_lo[(size_t)DFC1*DFC1];
__device__ __nv_bfloat16 g_xT_hi[(size_t)Bsz*Tdim*Cdim];      // x^T (b,t,c)
__device__ __nv_bfloat16 g_xT_lo[(size_t)Bsz*Tdim*Cdim];
__device__ float g_xT32[(size_t)Bsz*Tdim*Cdim];
__device__ __nv_bfloat16 g_q_hi[(size_t)Bsz*Hn*Tdim*DQKd];    // q (z,t,o)
__device__ __nv_bfloat16 g_q_lo[(size_t)Bsz*Hn*Tdim*DQKd];
__device__ __nv_bfloat16 g_k_hi[(size_t)Bsz*Hn*Tdim*DQKd];
__device__ __nv_bfloat16 g_k_lo[(size_t)Bsz*Hn*Tdim*DQKd];
__device__ __nv_bfloat16 g_h_hi[(size_t)Bsz*Hn*Tdim*Cdim];    // heads (z,t,c)
__device__ __nv_bfloat16 g_h_lo[(size_t)Bsz*Hn*Tdim*Cdim];
__device__ __nv_bfloat16 g_y1_hi[(size_t)Bsz*Hn*Tdim*DFC1];
__device__ __nv_bfloat16 g_y1_lo[(size_t)Bsz*Hn*Tdim*DFC1];

// ============================================================================
// PTX helpers (sm_80-level — valid on compute_103)
// ============================================================================
__device__ __forceinline__ uint32_t s2u(const void* p) {
    uint32_t a;
    asm("{ .reg .u64 t; cvta.to.shared.u64 t, %1; cvt.u32.u64 %0, t; }"
        : "=r"(a) : "l"(p));
    return a;
}
__device__ __forceinline__ void ldsm_x4(uint32_t* r, uint32_t addr) {
    asm volatile("ldmatrix.sync.aligned.m8n8.x4.shared.b16 {%0,%1,%2,%3}, [%4];"
        : "=r"(r[0]), "=r"(r[1]), "=r"(r[2]), "=r"(r[3]) : "r"(addr));
}
__device__ __forceinline__ void mma16816(float* c, const uint32_t* a, const uint32_t* b) {
    asm volatile("mma.sync.aligned.m16n8k16.row.col.f32.bf16.bf16.f32 "
        "{%0,%1,%2,%3}, {%4,%5,%6,%7}, {%8,%9}, {%0,%1,%2,%3};"
        : "+f"(c[0]), "+f"(c[1]), "+f"(c[2]), "+f"(c[3])
        : "r"(a[0]), "r"(a[1]), "r"(a[2]), "r"(a[3]), "r"(b[0]), "r"(b[1]));
}
__device__ __forceinline__ void cpasync16(uint32_t dst, const void* src) {
    asm volatile("cp.async.cg.shared.global [%0], [%1], 16;" :: "r"(dst), "l"(src));
}

__device__ __forceinline__ void split_store(
    __nv_bfloat16* __restrict__ hi, __nv_bfloat16* __restrict__ lo,
    size_t off, float v0, float v1)
{
    __nv_bfloat16 h0 = __float2bfloat16_rn(v0);
    __nv_bfloat16 h1 = __float2bfloat16_rn(v1);
    __nv_bfloat162 hp; hp.x = h0; hp.y = h1;
    __nv_bfloat162 lp;
    lp.x = __float2bfloat16_rn(v0 - __bfloat162float(h0));
    lp.y = __float2bfloat16_rn(v1 - __bfloat162float(h1));
    *(__nv_bfloat162*)(hi + off) = hp;
    *(__nv_bfloat162*)(lo + off) = lp;
}

// ============================================================================
// bf16 split-precision tensor-core GEMM (TN): D[m,n] = sum_k A[m,k]*B[n,k]
// CTA tile 256x128, K-step 32, 3-stage cp.async pipeline.
// 8 warps as 4M x 2N, each warp computes 64x64 (4 mt x 8 nt of m16n8).
// acc += Ahi*Bhi + Alo*Bhi + Ahi*Blo  (fp32 accumulate)
// ============================================================================
#define PITCHB   80                  // bytes per smem row (32 bf16 + pad)
#define A_ROWS   256
#define B_ROWS   128
#define A_SB     (A_ROWS*PITCHB)     // 20480
#define B_SB     (B_ROWS*PITCHB)     // 10240
#define STG_SB   (2*A_SB + 2*B_SB)   // 61440
#define NPIPE    3
#define MMA_SMEM (NPIPE*STG_SB)      // 184320

__device__ __forceinline__ void issue_stage(
    uint32_t sb, int buf, int k0,
    const __nv_bfloat16* __restrict__ Ahi, const __nv_bfloat16* __restrict__ Alo,
    const __nv_bfloat16* __restrict__ Bhi, const __nv_bfloat16* __restrict__ Blo,
    int lda, int ldb, int mb0, int nb0)
{
    const int tid  = threadIdx.x;
    const int row4 = tid >> 2;
    const int cb   = (tid & 3) * 16;
    const uint32_t base = sb + buf * STG_SB;
    #pragma unroll
    for (int r0 = 0; r0 < A_ROWS; r0 += 64) {
        int row = r0 + row4;
        const char* sh = (const char*)(Ahi + (size_t)(mb0 + row) * lda + k0) + cb;
        const char* sl = (const char*)(Alo + (size_t)(mb0 + row) * lda + k0) + cb;
        cpasync16(base + row * PITCHB + cb, sh);
        cpasync16(base + A_SB + row * PITCHB + cb, sl);
    }
    #pragma unroll
    for (int r0 = 0; r0 < B_ROWS; r0 += 64) {
        int row = r0 + row4;
        const char* sh = (const char*)(Bhi + (size_t)(nb0 + row) * ldb + k0) + cb;
        const char* sl = (const char*)(Blo + (size_t)(nb0 + row) * ldb + k0) + cb;
        cpasync16(base + 2 * A_SB + row * PITCHB + cb, sh);
        cpasync16(base + 2 * A_SB + B_SB + row * PITCHB + cb, sl);
    }
    asm volatile("cp.async.commit_group;" ::: "memory");
}

__device__ __forceinline__ void compute_stage(uint32_t sb, int buf, float acc[4][8][4])
{
    const int lane = threadIdx.x & 31, wid = threadIdx.x >> 5;
    const int wm = wid & 3, wn = wid >> 2;
    const uint32_t ab_hi = sb + buf * STG_SB;
    const uint32_t ab_lo = ab_hi + A_SB;
    const uint32_t bb_hi = ab_hi + 2 * A_SB;
    const uint32_t bb_lo = bb_hi + B_SB;
    #pragma unroll
    for (int k16 = 0; k16 < 2; k16++) {
        const uint32_t acol = k16 * 32 + (lane >> 4) * 16;
        uint32_t ah[4][4], al[4][4];
        #pragma unroll
        for (int mt = 0; mt < 4; mt++) {
            uint32_t arow = wm * 64 + mt * 16 + (lane & 15);
            ldsm_x4(ah[mt], ab_hi + arow * PITCHB + acol);
            ldsm_x4(al[mt], ab_lo + arow * PITCHB + acol);
        }
        const uint32_t bcol = k16 * 32 + ((lane >> 3) & 1) * 16;
        #pragma unroll
        for (int ntp = 0; ntp < 4; ntp++) {
            // paired-nt ldmatrix: matrices 0,1 -> nt=2*ntp; 2,3 -> nt=2*ntp+1
            uint32_t brow = wn * 64 + ntp * 16 + ((lane >> 4) & 1) * 8 + (lane & 7);
            uint32_t bh[4], bl[4];
            ldsm_x4(bh, bb_hi + brow * PITCHB + bcol);
            ldsm_x4(bl, bb_lo + brow * PITCHB + bcol);
            #pragma unroll
            for (int mt = 0; mt < 4; mt++) {
                mma16816(acc[mt][2*ntp],   ah[mt], bh);
                mma16816(acc[mt][2*ntp],   al[mt], bh);
                mma16816(acc[mt][2*ntp],   ah[mt], bl);
                mma16816(acc[mt][2*ntp+1], ah[mt], bh + 2);
                mma16816(acc[mt][2*ntp+1], al[mt], bh + 2);
                mma16816(acc[mt][2*ntp+1], ah[mt], bl + 2);
            }
        }
    }
}

__device__ __forceinline__ void mma_mainloop(
    char* smem,
    const __nv_bfloat16* __restrict__ Ahi, const __nv_bfloat16* __restrict__ Alo,
    const __nv_bfloat16* __restrict__ Bhi, const __nv_bfloat16* __restrict__ Blo,
    int lda, int ldb, int mb0, int nb0, int nst, float acc[4][8][4])
{
    uint32_t sb = s2u(smem);
    issue_stage(sb, 0, 0,  Ahi, Alo, Bhi, Blo, lda, ldb, mb0, nb0);
    issue_stage(sb, 1, 32, Ahi, Alo, Bhi, Blo, lda, ldb, mb0, nb0);
    #pragma unroll 1
    for (int st = 0; st < nst; st++) {
        if (st + 2 < nst) {
            int nx = st + 2;
            issue_stage(sb, nx % NPIPE, nx * 32, Ahi, Alo, Bhi, Blo, lda, ldb, mb0, nb0);
        }
        int rem = nst - 1 - st;
        if      (rem >= 2) asm volatile("cp.async.wait_group 2;" ::: "memory");
        else if (rem == 1) asm volatile("cp.async.wait_group 1;" ::: "memory");
        else               asm volatile("cp.async.wait_group 0;" ::: "memory");
        __syncthreads();
        compute_stage(sb, st % NPIPE, acc);
        __syncthreads();
    }
}

// epilogue index helper
struct EpiIdx { int r0; int lane, wm, wn; };
__device__ __forceinline__ EpiIdx epi_idx(int mb0, int mt) {
    EpiIdx e;
    e.lane = threadIdx.x & 31;
    int wid = threadIdx.x >> 5;
    e.wm = wid & 3; e.wn = wid >> 2;
    e.r0 = mb0 + e.wm * 64 + mt * 16 + (e.lane >> 2);
    return e;
}

// ---------------- q/k projection: P[z,t,o] = xT[b] @ W[h]^T + bias, split ---
__global__ __launch_bounds__(256, 1) void k_mma_proj(
    const __nv_bfloat16* __restrict__ xhi, const __nv_bfloat16* __restrict__ xlo,
    const __nv_bfloat16* __restrict__ whi, const __nv_bfloat16* __restrict__ wlo,
    const float* __restrict__ bias,
    __nv_bfloat16* __restrict__ phi, __nv_bfloat16* __restrict__ plo)
{
    extern __shared__ char smem[];
    const int z = blockIdx.z, h = z & 7, b = z >> 3;
    const int mb0 = blockIdx.y * 256;    // t
    float acc[4][8][4] = {};
    mma_mainloop(smem,
                 xhi + (size_t)b * 1048576, xlo + (size_t)b * 1048576,
                 whi + (size_t)h * 131072,  wlo + (size_t)h * 131072,
                 1024, 1024, mb0, 0, 32, acc);
    #pragma unroll
    for (int mt = 0; mt < 4; mt++) {
        EpiIdx e = epi_idx(mb0, mt);
        size_t base = (size_t)z * 131072 + (size_t)e.r0 * 128;
        #pragma unroll
        for (int nt = 0; nt < 8; nt++) {
            int col = e.wn * 64 + nt * 8 + (e.lane & 3) * 2;
            float bc0 = bias[h * DQKd + col], bc1 = bias[h * DQKd + col + 1];
            split_store(phi, plo, base + col,
                        acc[mt][nt][0] + bc0, acc[mt][nt][1] + bc1);
            split_store(phi, plo, base + 8 * 128 + col,
                        acc[mt][nt][2] + bc0, acc[mt][nt][3] + bc1);
        }
    }
}

// ---------------- energy: E[z,t,s] = q[z,t,:] . k[z,s,:]  (fp32 out) --------
__global__ __launch_bounds__(256, 1) void k_mma_energy(
    const __nv_bfloat16* __restrict__ qhi, const __nv_bfloat16* __restrict__ qlo,
    const __nv_bfloat16* __restrict__ khi, const __nv_bfloat16* __restrict__ klo,
    float* __restrict__ attn)
{
    extern __shared__ char smem[];
    const int z = blockIdx.z;
    const int mb0 = blockIdx.y * 256;    // t
    const int nb0 = blockIdx.x * 128;    // s
    float acc[4][8][4] = {};
    mma_mainloop(smem,
                 qhi + (size_t)z * 131072, qlo + (size_t)z * 131072,
                 khi + (size_t)z * 131072, klo + (size_t)z * 131072,
                 128, 128, mb0, nb0, 4, acc);
    #pragma unroll
    for (int mt = 0; mt < 4; mt++) {
        EpiIdx e = epi_idx(mb0, mt);
        size_t base = (size_t)z * 1048576 + (size_t)e.r0 * 1024;
        #pragma unroll
        for (int nt = 0; nt < 8; nt++) {
            int col = nb0 + e.wn * 64 + nt * 8 + (e.lane & 3) * 2;
            *(float2*)&attn[base + col] = make_float2(acc[mt][nt][0], acc[mt][nt][1]);
            *(float2*)&attn[base + 8 * 1024 + col] = make_float2(acc[mt][nt][2], acc[mt][nt][3]);
        }
    }
}

// ---------------- v projection: v[z,c,t] = Wv[h] @ x[b] + bv, split ---------
__global__ __launch_bounds__(256, 1) void k_mma_vconv(
    const __nv_bfloat16* __restrict__ whi, const __nv_bfloat16* __restrict__ wlo,
    const __nv_bfloat16* __restrict__ xhi, const __nv_bfloat16* __restrict__ xlo,
    const float* __restrict__ bv,
    __nv_bfloat16* __restrict__ vhi, __nv_bfloat16* __restrict__ vlo)
{
    extern __shared__ char smem[];
    const int z = blockIdx.z, h = z & 7, b = z >> 3;
    const int mb0 = blockIdx.y * 256;    // c
    const int nb0 = blockIdx.x * 128;    // t
    float acc[4][8][4] = {};
    mma_mainloop(smem,
                 whi + (size_t)h * 1048576, wlo + (size_t)h * 1048576,
                 xhi + (size_t)b * 1048576, xlo + (size_t)b * 1048576,
                 1024, 1024, mb0, nb0, 32, acc);
    #pragma unroll
    for (int mt = 0; mt < 4; mt++) {
        EpiIdx e = epi_idx(mb0, mt);
        float bias0 = bv[h * Cdim + e.r0];
        float bias1 = bv[h * Cdim + e.r0 + 8];
        size_t base = (size_t)z * 1048576 + (size_t)e.r0 * 1024;
        #pragma unroll
        for (int nt = 0; nt < 8; nt++) {
            int col = nb0 + e.wn * 64 + nt * 8 + (e.lane & 3) * 2;
            split_store(vhi, vlo, base + col,
                        acc[mt][nt][0] + bias0, acc[mt][nt][1] + bias0);
            split_store(vhi, vlo, base + 8 * 1024 + col,
                        acc[mt][nt][2] + bias1, acc[mt][nt][3] + bias1);
        }
    }
}

// ---------------- heads[z,t,c] = gamma*attn@v^T + x^T (split bf16 out) ------
__global__ __launch_bounds__(256, 1) void k_mma_oheads(
    const __nv_bfloat16* __restrict__ ahi, const __nv_bfloat16* __restrict__ alo,
    const __nv_bfloat16* __restrict__ vhi, const __nv_bfloat16* __restrict__ vlo,
    const float* __restrict__ gamma, const float* __restrict__ xT32,
    __nv_bfloat16* __restrict__ hhi, __nv_bfloat16* __restrict__ hlo)
{
    extern __shared__ char smem[];
    const int z = blockIdx.z, h = z & 7, b = z >> 3;
    const int mb0 = blockIdx.y * 256;    // t
    const int nb0 = blockIdx.x * 128;    // c
    float acc[4][8][4] = {};
    mma_mainloop(smem,
                 ahi + (size_t)z * 1048576, alo + (size_t)z * 1048576,
                 vhi + (size_t)z * 1048576, vlo + (size_t)z * 1048576,
                 1024, 1024, mb0, nb0, 32, acc);
    const float g = gamma[h];
    #pragma unroll
    for (int mt = 0; mt < 4; mt++) {
        EpiIdx e = epi_idx(mb0, mt);
        size_t hb = (size_t)z * 1048576 + (size_t)e.r0 * 1024;
        size_t xb = (size_t)b * 1048576 + (size_t)e.r0 * 1024;
        #pragma unroll
        for (int nt = 0; nt < 8; nt++) {
            int col = nb0 + e.wn * 64 + nt * 8 + (e.lane & 3) * 2;
            split_store(hhi, hlo, hb + col,
                        g * acc[mt][nt][0] + xT32[xb + col],
                        g * acc[mt][nt][1] + xT32[xb + col + 1]);
            split_store(hhi, hlo, hb + 8 * 1024 + col,
                        g * acc[mt][nt][2] + xT32[xb + 8 * 1024 + col],
                        g * acc[mt][nt][3] + xT32[xb + 8 * 1024 + col + 1]);
        }
    }
}

// ---------------- fc1: y1[r,f] = relu(heads[r,:] . W1[f,:] + b1), split -----
__global__ __launch_bounds__(256, 1) void k_mma_fc1(
    const __nv_bfloat16* __restrict__ hhi, const __nv_bfloat16* __restrict__ hlo,
    const __nv_bfloat16* __restrict__ whi, const __nv_bfloat16* __restrict__ wlo,
    const float* __restrict__ b1,
    __nv_bfloat16* __restrict__ y1hi, __nv_bfloat16* __restrict__ y1lo)
{
    extern __shared__ char smem[];
    const int mb0 = blockIdx.y * 256;    // r
    float acc[4][8][4] = {};
    mma_mainloop(smem, hhi, hlo, whi, wlo, 1024, 1024, mb0, 0, 32, acc);
    #pragma unroll
    for (int mt = 0; mt < 4; mt++) {
        EpiIdx e = epi_idx(mb0, mt);
        size_t base = (size_t)e.r0 * 128;
        #pragma unroll
        for (int nt = 0; nt < 8; nt++) {
            int col = e.wn * 64 + nt * 8 + (e.lane & 3) * 2;
            float bc0 = b1[col], bc1 = b1[col + 1];
            split_store(y1hi, y1lo, base + col,
                        fmaxf(acc[mt][nt][0] + bc0, 0.f), fmaxf(acc[mt][nt][1] + bc1, 0.f));
            split_store(y1hi, y1lo, base + 8 * 128 + col,
                        fmaxf(acc[mt][nt][2] + bc0, 0.f), fmaxf(acc[mt][nt][3] + bc1, 0.f));
        }
    }
}

// ---------------- fc2: out scatter + relu + residual ------------------------
__global__ __launch_bounds__(256, 1) void k_mma_fc2(
    const __nv_bfloat16* __restrict__ y1hi, const __nv_bfloat16* __restrict__ y1lo,
    const __nv_bfloat16* __restrict__ whi, const __nv_bfloat16* __restrict__ wlo,
    const float* __restrict__ b2, const float* __restrict__ x,
    float* __restrict__ out)
{
    extern __shared__ char smem[];
    const int mb0 = blockIdx.y * 256;    // r
    float acc[4][8][4] = {};
    mma_mainloop(smem, y1hi, y1lo, whi, wlo, 128, 128, mb0, 0, 4, acc);
    #pragma unroll
    for (int mt = 0; mt < 4; mt++) {
        EpiIdx e = epi_idx(mb0, mt);
        #pragma unroll
        for (int rr = 0; rr < 2; rr++) {
            int r = e.r0 + rr * 8;               // r = (b*H + h)*T + t
            int b = r >> 13;
            int h = (r >> 10) & 7;
            int t = r & 1023;
            size_t xbase = (size_t)b * 1048576 + t;
            #pragma unroll
            for (int nt = 0; nt < 8; nt++) {
                int col = e.wn * 64 + nt * 8 + (e.lane & 3) * 2;
                #pragma unroll
                for (int jj = 0; jj < 2; jj++) {
                    int d = col + jj;
                    size_t idx = xbase + (size_t)(d * Hn + h) * 1024;
                    out[idx] = fmaxf(acc[mt][nt][rr * 2 + jj] + b2[d], 0.f) + x[idx];
                }
            }
        }
    }
}

// ---------------- softmax over 1024-wide rows; emits bf16 hi/lo split -------
__global__ __launch_bounds__(256) void k_softmax2(
    const float* __restrict__ E,
    __nv_bfloat16* __restrict__ ah, __nv_bfloat16* __restrict__ al)
{
    const float* row = E + (size_t)blockIdx.x * Tdim;
    const int tid = threadIdx.x;
    float4 v = *(const float4*)&row[tid * 4];
    __shared__ float red[256];

    float mx = fmaxf(fmaxf(v.x, v.y), fmaxf(v.z, v.w));
    red[tid] = mx; __syncthreads();
    #pragma unroll
    for (int s = 128; s > 0; s >>= 1) {
        if (tid < s) red[tid] = fmaxf(red[tid], red[tid + s]);
        __syncthreads();
    }
    mx = red[0]; __syncthreads();

    v.x = __expf(v.x - mx); v.y = __expf(v.y - mx);
    v.z = __expf(v.z - mx); v.w = __expf(v.w - mx);
    red[tid] = v.x + v.y + v.z + v.w; __syncthreads();
    #pragma unroll
    for (int s = 128; s > 0; s >>= 1) {
        if (tid < s) red[tid] += red[tid + s];
        __syncthreads();
    }
    float inv = 1.0f / red[0];
    v.x *= inv; v.y *= inv; v.z *= inv; v.w *= inv;

    size_t o = (size_t)blockIdx.x * Tdim + tid * 4;
    split_store(ah, al, o,     v.x, v.y);
    split_store(ah, al, o + 2, v.z, v.w);
}

// ---------------- prep kernels ----------------
__global__ __launch_bounds__(256) void k_wsplit(
    const float* __restrict__ w, __nv_bfloat16* __restrict__ hi,
    __nv_bfloat16* __restrict__ lo)
{
    size_t i = ((size_t)blockIdx.x * 256 + threadIdx.x) * 4;
    float4 v = *(const float4*)(w + i);
    split_store(hi, lo, i,     v.x, v.y);
    split_store(hi, lo, i + 2, v.z, v.w);
}

// transpose x (b,c,t) -> xT (b,t,c) as fp32 + bf16 hi/lo
__global__ void k_xprep(const float* __restrict__ x, float* __restrict__ xT32,
                        __nv_bfloat16* __restrict__ xh, __nv_bfloat16* __restrict__ xl)
{
    __shared__ float tile[32][33];
    const int b = blockIdx.z;
    const int c0 = blockIdx.y * 32, t0 = blockIdx.x * 32;
    for (int r = threadIdx.y; r < 32; r += 8)
        tile[r][threadIdx.x] = x[(size_t)b * Cdim * Tdim + (size_t)(c0 + r) * Tdim + t0 + threadIdx.x];
    __syncthreads();
    for (int r = threadIdx.y; r < 32; r += 8) {
        float v = tile[threadIdx.x][r];
        size_t o = (size_t)b * Tdim * Cdim + (size_t)(t0 + r) * Cdim + c0 + threadIdx.x;
        xT32[o] = v;
        __nv_bfloat16 h = __float2bfloat16_rn(v);
        xh[o] = h;
        xl[o] = __float2bfloat16_rn(v - __bfloat162float(h));
    }
}

// ============================================================================
// launch
// ============================================================================
extern "C" void kernel_launch(void* const* d_in, const int* in_sizes, int n_in,
                              void* d_out, int out_size)
{
    (void)in_sizes; (void)n_in; (void)out_size;
    const float* x     = (const float*)d_in[0];
    const float* Wq    = (const float*)d_in[1];
    const float* bq    = (const float*)d_in[2];
    const float* Wk    = (const float*)d_in[3];
    const float* bk    = (const float*)d_in[4];
    const float* Wv    = (const float*)d_in[5];
    const float* bv    = (const float*)d_in[6];
    const float* gamma = (const float*)d_in[7];
    const float* W1    = (const float*)d_in[8];
    const float* b1    = (const float*)d_in[9];
    const float* W2    = (const float*)d_in[10];
    const float* b2    = (const float*)d_in[11];
    float* out = (float*)d_out;

    float *attn, *xT32;
    __nv_bfloat16 *ahi, *alo, *vhi, *vlo, *wvhi, *wvlo, *wqhi, *wqlo, *wkhi, *wklo;
    __nv_bfloat16 *w1hi, *w1lo, *w2hi, *w2lo, *xhi, *xlo;
    __nv_bfloat16 *qhi, *qlo, *khi, *klo, *hhi, *hlo, *y1hi, *y1lo;
    cudaGetSymbolAddress((void**)&attn,  g_attn);
    cudaGetSymbolAddress((void**)&ahi,   g_attn_hi);
    cudaGetSymbolAddress((void**)&alo,   g_attn_lo);
    cudaGetSymbolAddress((void**)&vhi,   g_v_hi);
    cudaGetSymbolAddress((void**)&vlo,   g_v_lo);
    cudaGetSymbolAddress((void**)&wvhi,  g_wv_hi);
    cudaGetSymbolAddress((void**)&wvlo,  g_wv_lo);
    cudaGetSymbolAddress((void**)&wqhi,  g_wq_hi);
    cudaGetSymbolAddress((void**)&wqlo,  g_wq_lo);
    cudaGetSymbolAddress((void**)&wkhi,  g_wk_hi);
    cudaGetSymbolAddress((void**)&wklo,  g_wk_lo);
    cudaGetSymbolAddress((void**)&w1hi,  g_w1_hi);
    cudaGetSymbolAddress((void**)&w1lo,  g_w1_lo);
    cudaGetSymbolAddress((void**)&w2hi,  g_w2_hi);
    cudaGetSymbolAddress((void**)&w2lo,  g_w2_lo);
    cudaGetSymbolAddress((void**)&xhi,   g_xT_hi);
    cudaGetSymbolAddress((void**)&xlo,   g_xT_lo);
    cudaGetSymbolAddress((void**)&xT32,  g_xT32);
    cudaGetSymbolAddress((void**)&qhi,   g_q_hi);
    cudaGetSymbolAddress((void**)&qlo,   g_q_lo);
    cudaGetSymbolAddress((void**)&khi,   g_k_hi);
    cudaGetSymbolAddress((void**)&klo,   g_k_lo);
    cudaGetSymbolAddress((void**)&hhi,   g_h_hi);
    cudaGetSymbolAddress((void**)&hlo,   g_h_lo);
    cudaGetSymbolAddress((void**)&y1hi,  g_y1_hi);
    cudaGetSymbolAddress((void**)&y1lo,  g_y1_lo);

    static bool attr_set = false;
    if (!attr_set) {
        cudaFuncSetAttribute(k_mma_proj,   cudaFuncAttributeMaxDynamicSharedMemorySize, MMA_SMEM);
        cudaFuncSetAttribute(k_mma_energy, cudaFuncAttributeMaxDynamicSharedMemorySize, MMA_SMEM);
        cudaFuncSetAttribute(k_mma_vconv,  cudaFuncAttributeMaxDynamicSharedMemorySize, MMA_SMEM);
        cudaFuncSetAttribute(k_mma_oheads, cudaFuncAttributeMaxDynamicSharedMemorySize, MMA_SMEM);
        cudaFuncSetAttribute(k_mma_fc1,    cudaFuncAttributeMaxDynamicSharedMemorySize, MMA_SMEM);
        cudaFuncSetAttribute(k_mma_fc2,    cudaFuncAttributeMaxDynamicSharedMemorySize, MMA_SMEM);
        attr_set = true;
    }

    const dim3 blk(256);
    const int ZB = Bsz * Hn;   // 64

    // preps: weight splits + x transpose/split
    k_wsplit<<<(Hn*Cdim*Cdim)/1024, 256>>>(Wv, wvhi, wvlo);
    k_wsplit<<<(Hn*DQKd*Cdim)/1024, 256>>>(Wq, wqhi, wqlo);
    k_wsplit<<<(Hn*DQKd*Cdim)/1024, 256>>>(Wk, wkhi, wklo);
    k_wsplit<<<(DFC1*Cdim)/1024,    256>>>(W1, w1hi, w1lo);
    k_wsplit<<<(DFC1*DFC1)/1024,    256>>>(W2, w2hi, w2lo);
    k_xprep<<<dim3(Tdim/32, Cdim/32, Bsz), dim3(32, 8)>>>(x, xT32, xhi, xlo);

    // q/k projections: q[z,t,o], k[z,t,o] split
    k_mma_proj<<<dim3(1, Tdim/256, ZB), blk, MMA_SMEM>>>(xhi, xlo, wqhi, wqlo, bq, qhi, qlo);
    k_mma_proj<<<dim3(1, Tdim/256, ZB), blk, MMA_SMEM>>>(xhi, xlo, wkhi, wklo, bk, khi, klo);

    // v projection: v[z,c,t] split
    k_mma_vconv<<<dim3(Tdim/128, Cdim/256, ZB), blk, MMA_SMEM>>>(
        wvhi, wvlo, xhi, xlo, bv, vhi, vlo);

    // energy (fp32 out) + softmax (emits attn hi/lo)
    k_mma_energy<<<dim3(Tdim/128, Tdim/256, ZB), blk, MMA_SMEM>>>(qhi, qlo, khi, klo, attn);
    k_softmax2<<<ZB * Tdim, blk>>>(attn, ahi, alo);

    // heads[z,t,c] = gamma * (attn @ v^T) + x^T  (split bf16 out)
    k_mma_oheads<<<dim3(Cdim/128, Tdim/256, ZB), blk, MMA_SMEM>>>(
        ahi, alo, vhi, vlo, gamma, xT32, hhi, hlo);

    // MLP
    const int ROWS = Bsz * Hn * Tdim;   // 65536
    k_mma_fc1<<<dim3(1, ROWS/256), blk, MMA_SMEM>>>(hhi, hlo, w1hi, w1lo, b1, y1hi, y1lo);
    k_mma_fc2<<<dim3(1, ROWS/256), blk, MMA_SMEM>>>(y1hi, y1lo, w2hi, w2lo, b2, x, out);
}

// round 6
// speedup vs baseline: 3.4476x; 1.2744x over previous
#include <cuda_runtime.h>
#include <cuda_bf16.h>
#include <cuda_fp16.h>
#include <cstdint>

// ---------------- problem constants ----------------
#define Bsz  8
#define Cdim 1024
#define Tdim 1024
#define Hn   8
#define DQKd 128
#define DFC1 128

// ---------------- scratch (device globals; no allocs allowed) ----------------
__device__ float g_attn[(size_t)Bsz*Hn*Tdim*Tdim];            // fp32 energy
__device__ __half g_attn_hi[(size_t)Bsz*Hn*Tdim*Tdim];        // softmax out, fp16 split
__device__ __half g_attn_lo[(size_t)Bsz*Hn*Tdim*Tdim];
__device__ __half g_v16 [(size_t)Bsz*Hn*Cdim*Tdim];           // v (z,c,t) single fp16
__device__ __half g_wv_hi[(size_t)Hn*Cdim*Cdim];              // Wv fp16 split
__device__ __half g_wv_lo[(size_t)Hn*Cdim*Cdim];
__device__ __nv_bfloat16 g_wq_hi[(size_t)Hn*DQKd*Cdim];
__device__ __nv_bfloat16 g_wq_lo[(size_t)Hn*DQKd*Cdim];
__device__ __nv_bfloat16 g_wk_hi[(size_t)Hn*DQKd*Cdim];
__device__ __nv_bfloat16 g_wk_lo[(size_t)Hn*DQKd*Cdim];
__device__ __half g_w1_16[(size_t)DFC1*Cdim];                 // W1 single fp16
__device__ __half g_w2_16[(size_t)DFC1*DFC1];                 // W2 single fp16
__device__ __nv_bfloat16 g_xT_hi[(size_t)Bsz*Tdim*Cdim];      // x^T (b,t,c) bf16 split
__device__ __nv_bfloat16 g_xT_lo[(size_t)Bsz*Tdim*Cdim];
__device__ __half g_xT16[(size_t)Bsz*Tdim*Cdim];              // x^T single fp16
__device__ float g_xT32[(size_t)Bsz*Tdim*Cdim];
__device__ __nv_bfloat16 g_q_hi[(size_t)Bsz*Hn*Tdim*DQKd];    // q (z,t,o) bf16 split
__device__ __nv_bfloat16 g_q_lo[(size_t)Bsz*Hn*Tdim*DQKd];
__device__ __nv_bfloat16 g_k_hi[(size_t)Bsz*Hn*Tdim*DQKd];
__device__ __nv_bfloat16 g_k_lo[(size_t)Bsz*Hn*Tdim*DQKd];
__device__ __half g_h_hi[(size_t)Bsz*Hn*Tdim*Cdim];           // heads (z,t,c) fp16 split
__device__ __half g_h_lo[(size_t)Bsz*Hn*Tdim*Cdim];
__device__ __half g_y1_hi[(size_t)Bsz*Hn*Tdim*DFC1];
__device__ __half g_y1_lo[(size_t)Bsz*Hn*Tdim*DFC1];

// ============================================================================
// PTX helpers (sm_80-level — valid on compute_103)
// ============================================================================
__device__ __forceinline__ uint32_t s2u(const void* p) {
    uint32_t a;
    asm("{ .reg .u64 t; cvta.to.shared.u64 t, %1; cvt.u32.u64 %0, t; }"
        : "=r"(a) : "l"(p));
    return a;
}
__device__ __forceinline__ void ldsm_x4(uint32_t* r, uint32_t addr) {
    asm volatile("ldmatrix.sync.aligned.m8n8.x4.shared.b16 {%0,%1,%2,%3}, [%4];"
        : "=r"(r[0]), "=r"(r[1]), "=r"(r[2]), "=r"(r[3]) : "r"(addr));
}
__device__ __forceinline__ void mma_bf(float* c, const uint32_t* a, const uint32_t* b) {
    asm volatile("mma.sync.aligned.m16n8k16.row.col.f32.bf16.bf16.f32 "
        "{%0,%1,%2,%3}, {%4,%5,%6,%7}, {%8,%9}, {%0,%1,%2,%3};"
        : "+f"(c[0]), "+f"(c[1]), "+f"(c[2]), "+f"(c[3])
        : "r"(a[0]), "r"(a[1]), "r"(a[2]), "r"(a[3]), "r"(b[0]), "r"(b[1]));
}
__device__ __forceinline__ void mma_fp(float* c, const uint32_t* a, const uint32_t* b) {
    asm volatile("mma.sync.aligned.m16n8k16.row.col.f32.f16.f16.f32 "
        "{%0,%1,%2,%3}, {%4,%5,%6,%7}, {%8,%9}, {%0,%1,%2,%3};"
        : "+f"(c[0]), "+f"(c[1]), "+f"(c[2]), "+f"(c[3])
        : "r"(a[0]), "r"(a[1]), "r"(a[2]), "r"(a[3]), "r"(b[0]), "r"(b[1]));
}
__device__ __forceinline__ void cpasync16(uint32_t dst, const void* src) {
    asm volatile("cp.async.cg.shared.global [%0], [%1], 16;" :: "r"(dst), "l"(src));
}

__device__ __forceinline__ void split_store_b(
    __nv_bfloat16* __restrict__ hi, __nv_bfloat16* __restrict__ lo,
    size_t off, float v0, float v1)
{
    __nv_bfloat16 h0 = __float2bfloat16_rn(v0);
    __nv_bfloat16 h1 = __float2bfloat16_rn(v1);
    __nv_bfloat162 hp; hp.x = h0; hp.y = h1;
    __nv_bfloat162 lp;
    lp.x = __float2bfloat16_rn(v0 - __bfloat162float(h0));
    lp.y = __float2bfloat16_rn(v1 - __bfloat162float(h1));
    *(__nv_bfloat162*)(hi + off) = hp;
    *(__nv_bfloat162*)(lo + off) = lp;
}
__device__ __forceinline__ void split_store_h(
    __half* __restrict__ hi, __half* __restrict__ lo,
    size_t off, float v0, float v1)
{
    __half h0 = __float2half_rn(v0);
    __half h1 = __float2half_rn(v1);
    __half2 hp; hp.x = h0; hp.y = h1;
    __half2 lp;
    lp.x = __float2half_rn(v0 - __half2float(h0));
    lp.y = __float2half_rn(v1 - __half2float(h1));
    *(__half2*)(hi + off) = hp;
    *(__half2*)(lo + off) = lp;
}

// ============================================================================
// Tensor-core GEMM mainloops (TN): D[m,n] = sum_k A[m,k]*B[n,k]
// CTA tile 256x128, K-step 32, 3-stage cp.async pipeline, single sync/stage.
// 8 warps as 4M x 2N, each warp 64x64.
// Variant 3 (bf16): acc += Ahi*Bhi + Alo*Bhi + Ahi*Blo
// Variant 2 (fp16): acc += Ahi*B + Alo*B
// ============================================================================
#define PITCHB   80
#define A_ROWS   256
#define B_ROWS   128
#define A_SB     (A_ROWS*PITCHB)     // 20480
#define B_SB     (B_ROWS*PITCHB)     // 10240
#define STG3_SB  (2*A_SB + 2*B_SB)   // 61440
#define STG2_SB  (2*A_SB + B_SB)     // 51200
#define NPIPE    3
#define MMA3_SMEM (NPIPE*STG3_SB)    // 184320
#define MMA2_SMEM (NPIPE*STG2_SB)    // 153600

// ---- variant 3 (bf16, A split + B split) ----
__device__ __forceinline__ void issue3(
    uint32_t sb, int buf, int k0,
    const __nv_bfloat16* __restrict__ Ahi, const __nv_bfloat16* __restrict__ Alo,
    const __nv_bfloat16* __restrict__ Bhi, const __nv_bfloat16* __restrict__ Blo,
    int lda, int ldb, int mb0, int nb0)
{
    const int tid  = threadIdx.x;
    const int row4 = tid >> 2;
    const int cb   = (tid & 3) * 16;
    const uint32_t base = sb + buf * STG3_SB;
    #pragma unroll
    for (int r0 = 0; r0 < A_ROWS; r0 += 64) {
        int row = r0 + row4;
        cpasync16(base + row * PITCHB + cb,
                  (const char*)(Ahi + (size_t)(mb0 + row) * lda + k0) + cb);
        cpasync16(base + A_SB + row * PITCHB + cb,
                  (const char*)(Alo + (size_t)(mb0 + row) * lda + k0) + cb);
    }
    #pragma unroll
    for (int r0 = 0; r0 < B_ROWS; r0 += 64) {
        int row = r0 + row4;
        cpasync16(base + 2 * A_SB + row * PITCHB + cb,
                  (const char*)(Bhi + (size_t)(nb0 + row) * ldb + k0) + cb);
        cpasync16(base + 2 * A_SB + B_SB + row * PITCHB + cb,
                  (const char*)(Blo + (size_t)(nb0 + row) * ldb + k0) + cb);
    }
    asm volatile("cp.async.commit_group;" ::: "memory");
}

__device__ __forceinline__ void compute3(uint32_t sb, int buf, float acc[4][8][4])
{
    const int lane = threadIdx.x & 31, wid = threadIdx.x >> 5;
    const int wm = wid & 3, wn = wid >> 2;
    const uint32_t ab_hi = sb + buf * STG3_SB;
    const uint32_t ab_lo = ab_hi + A_SB;
    const uint32_t bb_hi = ab_hi + 2 * A_SB;
    const uint32_t bb_lo = bb_hi + B_SB;
    #pragma unroll
    for (int k16 = 0; k16 < 2; k16++) {
        const uint32_t acol = k16 * 32 + (lane >> 4) * 16;
        uint32_t ah[4][4], al[4][4];
        #pragma unroll
        for (int mt = 0; mt < 4; mt++) {
            uint32_t arow = wm * 64 + mt * 16 + (lane & 15);
            ldsm_x4(ah[mt], ab_hi + arow * PITCHB + acol);
            ldsm_x4(al[mt], ab_lo + arow * PITCHB + acol);
        }
        const uint32_t bcol = k16 * 32 + ((lane >> 3) & 1) * 16;
        #pragma unroll
        for (int ntp = 0; ntp < 4; ntp++) {
            uint32_t brow = wn * 64 + ntp * 16 + ((lane >> 4) & 1) * 8 + (lane & 7);
            uint32_t bh[4], bl[4];
            ldsm_x4(bh, bb_hi + brow * PITCHB + bcol);
            ldsm_x4(bl, bb_lo + brow * PITCHB + bcol);
            #pragma unroll
            for (int mt = 0; mt < 4; mt++) {
                mma_bf(acc[mt][2*ntp],   ah[mt], bh);
                mma_bf(acc[mt][2*ntp],   al[mt], bh);
                mma_bf(acc[mt][2*ntp],   ah[mt], bl);
                mma_bf(acc[mt][2*ntp+1], ah[mt], bh + 2);
                mma_bf(acc[mt][2*ntp+1], al[mt], bh + 2);
                mma_bf(acc[mt][2*ntp+1], ah[mt], bl + 2);
            }
        }
    }
}

__device__ __forceinline__ void mainloop3(
    char* smem,
    const __nv_bfloat16* __restrict__ Ahi, const __nv_bfloat16* __restrict__ Alo,
    const __nv_bfloat16* __restrict__ Bhi, const __nv_bfloat16* __restrict__ Blo,
    int lda, int ldb, int mb0, int nb0, int nst, float acc[4][8][4])
{
    uint32_t sb = s2u(smem);
    issue3(sb, 0, 0,  Ahi, Alo, Bhi, Blo, lda, ldb, mb0, nb0);
    issue3(sb, 1, 32, Ahi, Alo, Bhi, Blo, lda, ldb, mb0, nb0);
    #pragma unroll 1
    for (int st = 0; st < nst; st++) {
        if (st + 1 < nst) asm volatile("cp.async.wait_group 1;" ::: "memory");
        else              asm volatile("cp.async.wait_group 0;" ::: "memory");
        __syncthreads();
        if (st + 2 < nst)
            issue3(sb, (st + 2) % NPIPE, (st + 2) * 32, Ahi, Alo, Bhi, Blo, lda, ldb, mb0, nb0);
        compute3(sb, st % NPIPE, acc);
    }
}

// ---- variant 2 (fp16, A split + B single) ----
__device__ __forceinline__ void issue2(
    uint32_t sb, int buf, int k0,
    const __half* __restrict__ Ahi, const __half* __restrict__ Alo,
    const __half* __restrict__ B,
    int lda, int ldb, int mb0, int nb0)
{
    const int tid  = threadIdx.x;
    const int row4 = tid >> 2;
    const int cb   = (tid & 3) * 16;
    const uint32_t base = sb + buf * STG2_SB;
    #pragma unroll
    for (int r0 = 0; r0 < A_ROWS; r0 += 64) {
        int row = r0 + row4;
        cpasync16(base + row * PITCHB + cb,
                  (const char*)(Ahi + (size_t)(mb0 + row) * lda + k0) + cb);
        cpasync16(base + A_SB + row * PITCHB + cb,
                  (const char*)(Alo + (size_t)(mb0 + row) * lda + k0) + cb);
    }
    #pragma unroll
    for (int r0 = 0; r0 < B_ROWS; r0 += 64) {
        int row = r0 + row4;
        cpasync16(base + 2 * A_SB + row * PITCHB + cb,
                  (const char*)(B + (size_t)(nb0 + row) * ldb + k0) + cb);
    }
    asm volatile("cp.async.commit_group;" ::: "memory");
}

__device__ __forceinline__ void compute2(uint32_t sb, int buf, float acc[4][8][4])
{
    const int lane = threadIdx.x & 31, wid = threadIdx.x >> 5;
    const int wm = wid & 3, wn = wid >> 2;
    const uint32_t ab_hi = sb + buf * STG2_SB;
    const uint32_t ab_lo = ab_hi + A_SB;
    const uint32_t bb    = ab_hi + 2 * A_SB;
    #pragma unroll
    for (int k16 = 0; k16 < 2; k16++) {
        const uint32_t acol = k16 * 32 + (lane >> 4) * 16;
        uint32_t ah[4][4], al[4][4];
        #pragma unroll
        for (int mt = 0; mt < 4; mt++) {
            uint32_t arow = wm * 64 + mt * 16 + (lane & 15);
            ldsm_x4(ah[mt], ab_hi + arow * PITCHB + acol);
            ldsm_x4(al[mt], ab_lo + arow * PITCHB + acol);
        }
        const uint32_t bcol = k16 * 32 + ((lane >> 3) & 1) * 16;
        #pragma unroll
        for (int ntp = 0; ntp < 4; ntp++) {
            uint32_t brow = wn * 64 + ntp * 16 + ((lane >> 4) & 1) * 8 + (lane & 7);
            uint32_t bh[4];
            ldsm_x4(bh, bb + brow * PITCHB + bcol);
            #pragma unroll
            for (int mt = 0; mt < 4; mt++) {
                mma_fp(acc[mt][2*ntp],   ah[mt], bh);
                mma_fp(acc[mt][2*ntp],   al[mt], bh);
                mma_fp(acc[mt][2*ntp+1], ah[mt], bh + 2);
                mma_fp(acc[mt][2*ntp+1], al[mt], bh + 2);
            }
        }
    }
}

__device__ __forceinline__ void mainloop2(
    char* smem,
    const __half* __restrict__ Ahi, const __half* __restrict__ Alo,
    const __half* __restrict__ B,
    int lda, int ldb, int mb0, int nb0, int nst, float acc[4][8][4])
{
    uint32_t sb = s2u(smem);
    issue2(sb, 0, 0,  Ahi, Alo, B, lda, ldb, mb0, nb0);
    issue2(sb, 1, 32, Ahi, Alo, B, lda, ldb, mb0, nb0);
    #pragma unroll 1
    for (int st = 0; st < nst; st++) {
        if (st + 1 < nst) asm volatile("cp.async.wait_group 1;" ::: "memory");
        else              asm volatile("cp.async.wait_group 0;" ::: "memory");
        __syncthreads();
        if (st + 2 < nst)
            issue2(sb, (st + 2) % NPIPE, (st + 2) * 32, Ahi, Alo, B, lda, ldb, mb0, nb0);
        compute2(sb, st % NPIPE, acc);
    }
}

// epilogue index helper
struct EpiIdx { int r0; int lane, wm, wn; };
__device__ __forceinline__ EpiIdx epi_idx(int mb0, int mt) {
    EpiIdx e;
    e.lane = threadIdx.x & 31;
    int wid = threadIdx.x >> 5;
    e.wm = wid & 3; e.wn = wid >> 2;
    e.r0 = mb0 + e.wm * 64 + mt * 16 + (e.lane >> 2);
    return e;
}

// ---------------- q/k projection (bf16 3-term): P[z,t,o], split bf16 --------
__global__ __launch_bounds__(256, 1) void k_mma_proj(
    const __nv_bfloat16* __restrict__ xhi, const __nv_bfloat16* __restrict__ xlo,
    const __nv_bfloat16* __restrict__ whi, const __nv_bfloat16* __restrict__ wlo,
    const float* __restrict__ bias,
    __nv_bfloat16* __restrict__ phi, __nv_bfloat16* __restrict__ plo)
{
    extern __shared__ char smem[];
    const int z = blockIdx.z, h = z & 7, b = z >> 3;
    const int mb0 = blockIdx.y * 256;    // t
    float acc[4][8][4] = {};
    mainloop3(smem,
              xhi + (size_t)b * 1048576, xlo + (size_t)b * 1048576,
              whi + (size_t)h * 131072,  wlo + (size_t)h * 131072,
              1024, 1024, mb0, 0, 32, acc);
    #pragma unroll
    for (int mt = 0; mt < 4; mt++) {
        EpiIdx e = epi_idx(mb0, mt);
        size_t base = (size_t)z * 131072 + (size_t)e.r0 * 128;
        #pragma unroll
        for (int nt = 0; nt < 8; nt++) {
            int col = e.wn * 64 + nt * 8 + (e.lane & 3) * 2;
            float bc0 = bias[h * DQKd + col], bc1 = bias[h * DQKd + col + 1];
            split_store_b(phi, plo, base + col,
                          acc[mt][nt][0] + bc0, acc[mt][nt][1] + bc1);
            split_store_b(phi, plo, base + 8 * 128 + col,
                          acc[mt][nt][2] + bc0, acc[mt][nt][3] + bc1);
        }
    }
}

// ---------------- energy (bf16 3-term): E fp32 ------------------------------
__global__ __launch_bounds__(256, 1) void k_mma_energy(
    const __nv_bfloat16* __restrict__ qhi, const __nv_bfloat16* __restrict__ qlo,
    const __nv_bfloat16* __restrict__ khi, const __nv_bfloat16* __restrict__ klo,
    float* __restrict__ attn)
{
    extern __shared__ char smem[];
    const int z = blockIdx.z;
    const int mb0 = blockIdx.y * 256;    // t
    const int nb0 = blockIdx.x * 128;    // s
    float acc[4][8][4] = {};
    mainloop3(smem,
              qhi + (size_t)z * 131072, qlo + (size_t)z * 131072,
              khi + (size_t)z * 131072, klo + (size_t)z * 131072,
              128, 128, mb0, nb0, 4, acc);
    #pragma unroll
    for (int mt = 0; mt < 4; mt++) {
        EpiIdx e = epi_idx(mb0, mt);
        size_t base = (size_t)z * 1048576 + (size_t)e.r0 * 1024;
        #pragma unroll
        for (int nt = 0; nt < 8; nt++) {
            int col = nb0 + e.wn * 64 + nt * 8 + (e.lane & 3) * 2;
            *(float2*)&attn[base + col] = make_float2(acc[mt][nt][0], acc[mt][nt][1]);
            *(float2*)&attn[base + 8 * 1024 + col] = make_float2(acc[mt][nt][2], acc[mt][nt][3]);
        }
    }
}

// ---------------- v projection (fp16 2-term): v[z,c,t] single fp16 ----------
__global__ __launch_bounds__(256, 1) void k_mma_vconv(
    const __half* __restrict__ whi, const __half* __restrict__ wlo,
    const __half* __restrict__ x16,
    const float* __restrict__ bv, __half* __restrict__ v16)
{
    extern __shared__ char smem[];
    const int z = blockIdx.z, h = z & 7, b = z >> 3;
    const int mb0 = blockIdx.y * 256;    // c
    const int nb0 = blockIdx.x * 128;    // t
    float acc[4][8][4] = {};
    mainloop2(smem,
              whi + (size_t)h * 1048576, wlo + (size_t)h * 1048576,
              x16 + (size_t)b * 1048576,
              1024, 1024, mb0, nb0, 32, acc);
    #pragma unroll
    for (int mt = 0; mt < 4; mt++) {
        EpiIdx e = epi_idx(mb0, mt);
        float bias0 = bv[h * Cdim + e.r0];
        float bias1 = bv[h * Cdim + e.r0 + 8];
        size_t base = (size_t)z * 1048576 + (size_t)e.r0 * 1024;
        #pragma unroll
        for (int nt = 0; nt < 8; nt++) {
            int col = nb0 + e.wn * 64 + nt * 8 + (e.lane & 3) * 2;
            __half2 p0, p1;
            p0.x = __float2half_rn(acc[mt][nt][0] + bias0);
            p0.y = __float2half_rn(acc[mt][nt][1] + bias0);
            p1.x = __float2half_rn(acc[mt][nt][2] + bias1);
            p1.y = __float2half_rn(acc[mt][nt][3] + bias1);
            *(__half2*)(v16 + base + col) = p0;
            *(__half2*)(v16 + base + 8 * 1024 + col) = p1;
        }
    }
}

// ---------------- heads (fp16 2-term): gamma*attn@v^T + x^T, split fp16 -----
__global__ __launch_bounds__(256, 1) void k_mma_oheads(
    const __half* __restrict__ ahi, const __half* __restrict__ alo,
    const __half* __restrict__ v16,
    const float* __restrict__ gamma, const float* __restrict__ xT32,
    __half* __restrict__ hhi, __half* __restrict__ hlo)
{
    extern __shared__ char smem[];
    const int z = blockIdx.z, h = z & 7, b = z >> 3;
    const int mb0 = blockIdx.y * 256;    // t
    const int nb0 = blockIdx.x * 128;    // c
    float acc[4][8][4] = {};
    mainloop2(smem,
              ahi + (size_t)z * 1048576, alo + (size_t)z * 1048576,
              v16 + (size_t)z * 1048576,
              1024, 1024, mb0, nb0, 32, acc);
    const float g = gamma[h];
    #pragma unroll
    for (int mt = 0; mt < 4; mt++) {
        EpiIdx e = epi_idx(mb0, mt);
        size_t hb = (size_t)z * 1048576 + (size_t)e.r0 * 1024;
        size_t xb = (size_t)b * 1048576 + (size_t)e.r0 * 1024;
        #pragma unroll
        for (int nt = 0; nt < 8; nt++) {
            int col = nb0 + e.wn * 64 + nt * 8 + (e.lane & 3) * 2;
            split_store_h(hhi, hlo, hb + col,
                          g * acc[mt][nt][0] + xT32[xb + col],
                          g * acc[mt][nt][1] + xT32[xb + col + 1]);
            split_store_h(hhi, hlo, hb + 8 * 1024 + col,
                          g * acc[mt][nt][2] + xT32[xb + 8 * 1024 + col],
                          g * acc[mt][nt][3] + xT32[xb + 8 * 1024 + col + 1]);
        }
    }
}

// ---------------- fc1 (fp16 2-term): y1 = relu(heads.W1^T + b1), split ------
__global__ __launch_bounds__(256, 1) void k_mma_fc1(
    const __half* __restrict__ hhi, const __half* __restrict__ hlo,
    const __half* __restrict__ w1, const float* __restrict__ b1,
    __half* __restrict__ y1hi, __half* __restrict__ y1lo)
{
    extern __shared__ char smem[];
    const int mb0 = blockIdx.y * 256;    // r
    float acc[4][8][4] = {};
    mainloop2(smem, hhi, hlo, w1, 1024, 1024, mb0, 0, 32, acc);
    #pragma unroll
    for (int mt = 0; mt < 4; mt++) {
        EpiIdx e = epi_idx(mb0, mt);
        size_t base = (size_t)e.r0 * 128;
        #pragma unroll
        for (int nt = 0; nt < 8; nt++) {
            int col = e.wn * 64 + nt * 8 + (e.lane & 3) * 2;
            float bc0 = b1[col], bc1 = b1[col + 1];
            split_store_h(y1hi, y1lo, base + col,
                          fmaxf(acc[mt][nt][0] + bc0, 0.f), fmaxf(acc[mt][nt][1] + bc1, 0.f));
            split_store_h(y1hi, y1lo, base + 8 * 128 + col,
                          fmaxf(acc[mt][nt][2] + bc0, 0.f), fmaxf(acc[mt][nt][3] + bc1, 0.f));
        }
    }
}

// ---------------- fc2 (fp16 2-term): out scatter + relu + residual ----------
__global__ __launch_bounds__(256, 1) void k_mma_fc2(
    const __half* __restrict__ y1hi, const __half* __restrict__ y1lo,
    const __half* __restrict__ w2, const float* __restrict__ b2,
    const float* __restrict__ x, float* __restrict__ out)
{
    extern __shared__ char smem[];
    const int mb0 = blockIdx.y * 256;    // r
    float acc[4][8][4] = {};
    mainloop2(smem, y1hi, y1lo, w2, 128, 128, mb0, 0, 4, acc);
    #pragma unroll
    for (int mt = 0; mt < 4; mt++) {
        EpiIdx e = epi_idx(mb0, mt);
        #pragma unroll
        for (int rr = 0; rr < 2; rr++) {
            int r = e.r0 + rr * 8;               // r = (b*H + h)*T + t
            int b = r >> 13;
            int h = (r >> 10) & 7;
            int t = r & 1023;
            size_t xbase = (size_t)b * 1048576 + t;
            #pragma unroll
            for (int nt = 0; nt < 8; nt++) {
                int col = e.wn * 64 + nt * 8 + (e.lane & 3) * 2;
                #pragma unroll
                for (int jj = 0; jj < 2; jj++) {
                    int d = col + jj;
                    size_t idx = xbase + (size_t)(d * Hn + h) * 1024;
                    out[idx] = fmaxf(acc[mt][nt][rr * 2 + jj] + b2[d], 0.f) + x[idx];
                }
            }
        }
    }
}

// ---------------- softmax: emits fp16 hi/lo split ---------------------------
__global__ __launch_bounds__(256) void k_softmax2(
    const float* __restrict__ E,
    __half* __restrict__ ah, __half* __restrict__ al)
{
    const float* row = E + (size_t)blockIdx.x * Tdim;
    const int tid = threadIdx.x;
    float4 v = *(const float4*)&row[tid * 4];
    __shared__ float red[256];

    float mx = fmaxf(fmaxf(v.x, v.y), fmaxf(v.z, v.w));
    red[tid] = mx; __syncthreads();
    #pragma unroll
    for (int s = 128; s > 0; s >>= 1) {
        if (tid < s) red[tid] = fmaxf(red[tid], red[tid + s]);
        __syncthreads();
    }
    mx = red[0]; __syncthreads();

    v.x = __expf(v.x - mx); v.y = __expf(v.y - mx);
    v.z = __expf(v.z - mx); v.w = __expf(v.w - mx);
    red[tid] = v.x + v.y + v.z + v.w; __syncthreads();
    #pragma unroll
    for (int s = 128; s > 0; s >>= 1) {
        if (tid < s) red[tid] += red[tid + s];
        __syncthreads();
    }
    float inv = 1.0f / red[0];
    v.x *= inv; v.y *= inv; v.z *= inv; v.w *= inv;

    size_t o = (size_t)blockIdx.x * Tdim + tid * 4;
    split_store_h(ah, al, o,     v.x, v.y);
    split_store_h(ah, al, o + 2, v.z, v.w);
}

// ---------------- prep kernels ----------------
__global__ __launch_bounds__(256) void k_wsplit_b(
    const float* __restrict__ w, __nv_bfloat16* __restrict__ hi,
    __nv_bfloat16* __restrict__ lo)
{
    size_t i = ((size_t)blockIdx.x * 256 + threadIdx.x) * 4;
    float4 v = *(const float4*)(w + i);
    split_store_b(hi, lo, i,     v.x, v.y);
    split_store_b(hi, lo, i + 2, v.z, v.w);
}
__global__ __launch_bounds__(256) void k_wsplit_h(
    const float* __restrict__ w, __half* __restrict__ hi, __half* __restrict__ lo)
{
    size_t i = ((size_t)blockIdx.x * 256 + threadIdx.x) * 4;
    float4 v = *(const float4*)(w + i);
    split_store_h(hi, lo, i,     v.x, v.y);
    split_store_h(hi, lo, i + 2, v.z, v.w);
}
__global__ __launch_bounds__(256) void k_wround_h(
    const float* __restrict__ w, __half* __restrict__ o)
{
    size_t i = ((size_t)blockIdx.x * 256 + threadIdx.x) * 4;
    float4 v = *(const float4*)(w + i);
    __half2 p;
    p.x = __float2half_rn(v.x); p.y = __float2half_rn(v.y);
    *(__half2*)(o + i) = p;
    p.x = __float2half_rn(v.z); p.y = __float2half_rn(v.w);
    *(__half2*)(o + i + 2) = p;
}

// transpose x (b,c,t) -> xT (b,t,c) as fp32 + bf16 hi/lo + fp16 single
__global__ void k_xprep(const float* __restrict__ x, float* __restrict__ xT32,
                        __nv_bfloat16* __restrict__ xh, __nv_bfloat16* __restrict__ xl,
                        __half* __restrict__ x16)
{
    __shared__ float tile[32][33];
    const int b = blockIdx.z;
    const int c0 = blockIdx.y * 32, t0 = blockIdx.x * 32;
    for (int r = threadIdx.y; r < 32; r += 8)
        tile[r][threadIdx.x] = x[(size_t)b * Cdim * Tdim + (size_t)(c0 + r) * Tdim + t0 + threadIdx.x];
    __syncthreads();
    for (int r = threadIdx.y; r < 32; r += 8) {
        float v = tile[threadIdx.x][r];
        size_t o = (size_t)b * Tdim * Cdim + (size_t)(t0 + r) * Cdim + c0 + threadIdx.x;
        xT32[o] = v;
        __nv_bfloat16 h = __float2bfloat16_rn(v);
        xh[o] = h;
        xl[o] = __float2bfloat16_rn(v - __bfloat162float(h));
        x16[o] = __float2half_rn(v);
    }
}

// ============================================================================
// launch
// ============================================================================
extern "C" void kernel_launch(void* const* d_in, const int* in_sizes, int n_in,
                              void* d_out, int out_size)
{
    (void)in_sizes; (void)n_in; (void)out_size;
    const float* x     = (const float*)d_in[0];
    const float* Wq    = (const float*)d_in[1];
    const float* bq    = (const float*)d_in[2];
    const float* Wk    = (const float*)d_in[3];
    const float* bk    = (const float*)d_in[4];
    const float* Wv    = (const float*)d_in[5];
    const float* bv    = (const float*)d_in[6];
    const float* gamma = (const float*)d_in[7];
    const float* W1    = (const float*)d_in[8];
    const float* b1    = (const float*)d_in[9];
    const float* W2    = (const float*)d_in[10];
    const float* b2    = (const float*)d_in[11];
    float* out = (float*)d_out;

    float *attn, *xT32;
    __half *ahi, *alo, *v16, *wvhi, *wvlo, *w116, *w216, *x16;
    __half *hhi, *hlo, *y1hi, *y1lo;
    __nv_bfloat16 *wqhi, *wqlo, *wkhi, *wklo, *xhi, *xlo, *qhi, *qlo, *khi, *klo;
    cudaGetSymbolAddress((void**)&attn,  g_attn);
    cudaGetSymbolAddress((void**)&ahi,   g_attn_hi);
    cudaGetSymbolAddress((void**)&alo,   g_attn_lo);
    cudaGetSymbolAddress((void**)&v16,   g_v16);
    cudaGetSymbolAddress((void**)&wvhi,  g_wv_hi);
    cudaGetSymbolAddress((void**)&wvlo,  g_wv_lo);
    cudaGetSymbolAddress((void**)&wqhi,  g_wq_hi);
    cudaGetSymbolAddress((void**)&wqlo,  g_wq_lo);
    cudaGetSymbolAddress((void**)&wkhi,  g_wk_hi);
    cudaGetSymbolAddress((void**)&wklo,  g_wk_lo);
    cudaGetSymbolAddress((void**)&w116,  g_w1_16);
    cudaGetSymbolAddress((void**)&w216,  g_w2_16);
    cudaGetSymbolAddress((void**)&xhi,   g_xT_hi);
    cudaGetSymbolAddress((void**)&xlo,   g_xT_lo);
    cudaGetSymbolAddress((void**)&x16,   g_xT16);
    cudaGetSymbolAddress((void**)&xT32,  g_xT32);
    cudaGetSymbolAddress((void**)&qhi,   g_q_hi);
    cudaGetSymbolAddress((void**)&qlo,   g_q_lo);
    cudaGetSymbolAddress((void**)&khi,   g_k_hi);
    cudaGetSymbolAddress((void**)&klo,   g_k_lo);
    cudaGetSymbolAddress((void**)&hhi,   g_h_hi);
    cudaGetSymbolAddress((void**)&hlo,   g_h_lo);
    cudaGetSymbolAddress((void**)&y1hi,  g_y1_hi);
    cudaGetSymbolAddress((void**)&y1lo,  g_y1_lo);

    static bool attr_set = false;
    if (!attr_set) {
        cudaFuncSetAttribute(k_mma_proj,   cudaFuncAttributeMaxDynamicSharedMemorySize, MMA3_SMEM);
        cudaFuncSetAttribute(k_mma_energy, cudaFuncAttributeMaxDynamicSharedMemorySize, MMA3_SMEM);
        cudaFuncSetAttribute(k_mma_vconv,  cudaFuncAttributeMaxDynamicSharedMemorySize, MMA2_SMEM);
        cudaFuncSetAttribute(k_mma_oheads, cudaFuncAttributeMaxDynamicSharedMemorySize, MMA2_SMEM);
        cudaFuncSetAttribute(k_mma_fc1,    cudaFuncAttributeMaxDynamicSharedMemorySize, MMA2_SMEM);
        cudaFuncSetAttribute(k_mma_fc2,    cudaFuncAttributeMaxDynamicSharedMemorySize, MMA2_SMEM);
        attr_set = true;
    }

    const dim3 blk(256);
    const int ZB = Bsz * Hn;   // 64

    // preps
    k_wsplit_h<<<(Hn*Cdim*Cdim)/1024, 256>>>(Wv, wvhi, wvlo);
    k_wsplit_b<<<(Hn*DQKd*Cdim)/1024, 256>>>(Wq, wqhi, wqlo);
    k_wsplit_b<<<(Hn*DQKd*Cdim)/1024, 256>>>(Wk, wkhi, wklo);
    k_wround_h<<<(DFC1*Cdim)/1024,    256>>>(W1, w116);
    k_wround_h<<<(DFC1*DFC1)/1024,    256>>>(W2, w216);
    k_xprep<<<dim3(Tdim/32, Cdim/32, Bsz), dim3(32, 8)>>>(x, xT32, xhi, xlo, x16);

    // q/k projections (bf16 3-term)
    k_mma_proj<<<dim3(1, Tdim/256, ZB), blk, MMA3_SMEM>>>(xhi, xlo, wqhi, wqlo, bq, qhi, qlo);
    k_mma_proj<<<dim3(1, Tdim/256, ZB), blk, MMA3_SMEM>>>(xhi, xlo, wkhi, wklo, bk, khi, klo);

    // v projection (fp16 2-term): v[z,c,t] single fp16
    k_mma_vconv<<<dim3(Tdim/128, Cdim/256, ZB), blk, MMA2_SMEM>>>(wvhi, wvlo, x16, bv, v16);

    // energy (bf16 3-term, fp32 out) + softmax (fp16 split out)
    k_mma_energy<<<dim3(Tdim/128, Tdim/256, ZB), blk, MMA3_SMEM>>>(qhi, qlo, khi, klo, attn);
    k_softmax2<<<ZB * Tdim, blk>>>(attn, ahi, alo);

    // heads (fp16 2-term)
    k_mma_oheads<<<dim3(Cdim/128, Tdim/256, ZB), blk, MMA2_SMEM>>>(
        ahi, alo, v16, gamma, xT32, hhi, hlo);

    // MLP (fp16 2-term)
    const int ROWS = Bsz * Hn * Tdim;   // 65536
    k_mma_fc1<<<dim3(1, ROWS/256), blk, MMA2_SMEM>>>(hhi, hlo, w116, b1, y1hi, y1lo);
    k_mma_fc2<<<dim3(1, ROWS/256), blk, MMA2_SMEM>>>(y1hi, y1lo, w216, b2, x, out);
}

// round 7
// speedup vs baseline: 4.7047x; 1.3647x over previous
#include <cuda_runtime.h>
#include <cuda_bf16.h>
#include <cuda_fp16.h>
#include <cstdint>

// ---------------- problem constants ----------------
#define Bsz  8
#define Cdim 1024
#define Tdim 1024
#define Hn   8
#define DQKd 128
#define DFC1 128

// ---------------- scratch (device globals; no allocs allowed) ----------------
__device__ float g_attn[(size_t)Bsz*Hn*Tdim*Tdim];            // fp32 energy
__device__ __half g_attn16[(size_t)Bsz*Hn*Tdim*Tdim];         // softmax out, single fp16
__device__ __half g_v16 [(size_t)Bsz*Hn*Cdim*Tdim];           // v (z,c,t) single fp16
__device__ __half g_wv_16[(size_t)Hn*Cdim*Cdim];              // Wv single fp16
__device__ __nv_bfloat16 g_wq_hi[(size_t)Hn*DQKd*Cdim];
__device__ __nv_bfloat16 g_wq_lo[(size_t)Hn*DQKd*Cdim];
__device__ __nv_bfloat16 g_wk_hi[(size_t)Hn*DQKd*Cdim];
__device__ __nv_bfloat16 g_wk_lo[(size_t)Hn*DQKd*Cdim];
__device__ __half g_w1_16[(size_t)DFC1*Cdim];                 // W1 single fp16
__device__ __half g_w2_16[(size_t)DFC1*DFC1];                 // W2 single fp16
__device__ __nv_bfloat16 g_xT_hi[(size_t)Bsz*Tdim*Cdim];      // x^T (b,t,c) bf16 split
__device__ __nv_bfloat16 g_xT_lo[(size_t)Bsz*Tdim*Cdim];
__device__ __half g_xT16[(size_t)Bsz*Tdim*Cdim];              // x^T single fp16
__device__ float g_xT32[(size_t)Bsz*Tdim*Cdim];
__device__ __nv_bfloat16 g_q_hi[(size_t)Bsz*Hn*Tdim*DQKd];    // q (z,t,o) bf16 split
__device__ __nv_bfloat16 g_q_lo[(size_t)Bsz*Hn*Tdim*DQKd];
__device__ __nv_bfloat16 g_k_hi[(size_t)Bsz*Hn*Tdim*DQKd];
__device__ __nv_bfloat16 g_k_lo[(size_t)Bsz*Hn*Tdim*DQKd];
__device__ __half g_h_hi[(size_t)Bsz*Hn*Tdim*Cdim];           // heads (z,t,c) fp16 split
__device__ __half g_h_lo[(size_t)Bsz*Hn*Tdim*Cdim];
__device__ __half g_y1_hi[(size_t)Bsz*Hn*Tdim*DFC1];
__device__ __half g_y1_lo[(size_t)Bsz*Hn*Tdim*DFC1];

// ============================================================================
// PTX helpers (sm_80-level — valid on compute_103)
// ============================================================================
__device__ __forceinline__ uint32_t s2u(const void* p) {
    uint32_t a;
    asm("{ .reg .u64 t; cvta.to.shared.u64 t, %1; cvt.u32.u64 %0, t; }"
        : "=r"(a) : "l"(p));
    return a;
}
__device__ __forceinline__ void ldsm_x4(uint32_t* r, uint32_t addr) {
    asm volatile("ldmatrix.sync.aligned.m8n8.x4.shared.b16 {%0,%1,%2,%3}, [%4];"
        : "=r"(r[0]), "=r"(r[1]), "=r"(r[2]), "=r"(r[3]) : "r"(addr));
}
__device__ __forceinline__ void mma_bf(float* c, const uint32_t* a, const uint32_t* b) {
    asm volatile("mma.sync.aligned.m16n8k16.row.col.f32.bf16.bf16.f32 "
        "{%0,%1,%2,%3}, {%4,%5,%6,%7}, {%8,%9}, {%0,%1,%2,%3};"
        : "+f"(c[0]), "+f"(c[1]), "+f"(c[2]), "+f"(c[3])
        : "r"(a[0]), "r"(a[1]), "r"(a[2]), "r"(a[3]), "r"(b[0]), "r"(b[1]));
}
__device__ __forceinline__ void mma_fp(float* c, const uint32_t* a, const uint32_t* b) {
    asm volatile("mma.sync.aligned.m16n8k16.row.col.f32.f16.f16.f32 "
        "{%0,%1,%2,%3}, {%4,%5,%6,%7}, {%8,%9}, {%0,%1,%2,%3};"
        : "+f"(c[0]), "+f"(c[1]), "+f"(c[2]), "+f"(c[3])
        : "r"(a[0]), "r"(a[1]), "r"(a[2]), "r"(a[3]), "r"(b[0]), "r"(b[1]));
}
__device__ __forceinline__ void cpasync16(uint32_t dst, const void* src) {
    asm volatile("cp.async.cg.shared.global [%0], [%1], 16;" :: "r"(dst), "l"(src));
}

__device__ __forceinline__ void split_store_b(
    __nv_bfloat16* __restrict__ hi, __nv_bfloat16* __restrict__ lo,
    size_t off, float v0, float v1)
{
    __nv_bfloat16 h0 = __float2bfloat16_rn(v0);
    __nv_bfloat16 h1 = __float2bfloat16_rn(v1);
    __nv_bfloat162 hp; hp.x = h0; hp.y = h1;
    __nv_bfloat162 lp;
    lp.x = __float2bfloat16_rn(v0 - __bfloat162float(h0));
    lp.y = __float2bfloat16_rn(v1 - __bfloat162float(h1));
    *(__nv_bfloat162*)(hi + off) = hp;
    *(__nv_bfloat162*)(lo + off) = lp;
}
__device__ __forceinline__ void split_store_h(
    __half* __restrict__ hi, __half* __restrict__ lo,
    size_t off, float v0, float v1)
{
    __half h0 = __float2half_rn(v0);
    __half h1 = __float2half_rn(v1);
    __half2 hp; hp.x = h0; hp.y = h1;
    __half2 lp;
    lp.x = __float2half_rn(v0 - __half2float(h0));
    lp.y = __float2half_rn(v1 - __half2float(h1));
    *(__half2*)(hi + off) = hp;
    *(__half2*)(lo + off) = lp;
}

// ============================================================================
// Tensor-core GEMM mainloops (TN): D[m,n] = sum_k A[m,k]*B[n,k]
// CTA tile 256x128, K-step 32, 3-stage cp.async pipeline, single sync/stage.
// 8 warps as 4M x 2N, each warp 64x64.
// Variant 3 (bf16): acc += Ahi*Bhi + Alo*Bhi + Ahi*Blo
// Variant 2 (fp16): acc += Ahi*B + Alo*B
// Variant 1 (fp16): acc += A*B
// ============================================================================
#define PITCHB   80
#define A_ROWS   256
#define B_ROWS   128
#define A_SB     (A_ROWS*PITCHB)     // 20480
#define B_SB     (B_ROWS*PITCHB)     // 10240
#define STG3_SB  (2*A_SB + 2*B_SB)   // 61440
#define STG2_SB  (2*A_SB + B_SB)     // 51200
#define STG1_SB  (A_SB + B_SB)       // 30720
#define NPIPE    3
#define MMA3_SMEM (NPIPE*STG3_SB)    // 184320
#define MMA2_SMEM (NPIPE*STG2_SB)    // 153600
#define MMA1_SMEM (NPIPE*STG1_SB)    // 92160

// ---- variant 3 (bf16, A split + B split) ----
__device__ __forceinline__ void issue3(
    uint32_t sb, int buf, int k0,
    const __nv_bfloat16* __restrict__ Ahi, const __nv_bfloat16* __restrict__ Alo,
    const __nv_bfloat16* __restrict__ Bhi, const __nv_bfloat16* __restrict__ Blo,
    int lda, int ldb, int mb0, int nb0)
{
    const int tid  = threadIdx.x;
    const int row4 = tid >> 2;
    const int cb   = (tid & 3) * 16;
    const uint32_t base = sb + buf * STG3_SB;
    #pragma unroll
    for (int r0 = 0; r0 < A_ROWS; r0 += 64) {
        int row = r0 + row4;
        cpasync16(base + row * PITCHB + cb,
                  (const char*)(Ahi + (size_t)(mb0 + row) * lda + k0) + cb);
        cpasync16(base + A_SB + row * PITCHB + cb,
                  (const char*)(Alo + (size_t)(mb0 + row) * lda + k0) + cb);
    }
    #pragma unroll
    for (int r0 = 0; r0 < B_ROWS; r0 += 64) {
        int row = r0 + row4;
        cpasync16(base + 2 * A_SB + row * PITCHB + cb,
                  (const char*)(Bhi + (size_t)(nb0 + row) * ldb + k0) + cb);
        cpasync16(base + 2 * A_SB + B_SB + row * PITCHB + cb,
                  (const char*)(Blo + (size_t)(nb0 + row) * ldb + k0) + cb);
    }
    asm volatile("cp.async.commit_group;" ::: "memory");
}

__device__ __forceinline__ void compute3(uint32_t sb, int buf, float acc[4][8][4])
{
    const int lane = threadIdx.x & 31, wid = threadIdx.x >> 5;
    const int wm = wid & 3, wn = wid >> 2;
    const uint32_t ab_hi = sb + buf * STG3_SB;
    const uint32_t ab_lo = ab_hi + A_SB;
    const uint32_t bb_hi = ab_hi + 2 * A_SB;
    const uint32_t bb_lo = bb_hi + B_SB;
    #pragma unroll
    for (int k16 = 0; k16 < 2; k16++) {
        const uint32_t acol = k16 * 32 + (lane >> 4) * 16;
        uint32_t ah[4][4], al[4][4];
        #pragma unroll
        for (int mt = 0; mt < 4; mt++) {
            uint32_t arow = wm * 64 + mt * 16 + (lane & 15);
            ldsm_x4(ah[mt], ab_hi + arow * PITCHB + acol);
            ldsm_x4(al[mt], ab_lo + arow * PITCHB + acol);
        }
        const uint32_t bcol = k16 * 32 + ((lane >> 3) & 1) * 16;
        #pragma unroll
        for (int ntp = 0; ntp < 4; ntp++) {
            uint32_t brow = wn * 64 + ntp * 16 + ((lane >> 4) & 1) * 8 + (lane & 7);
            uint32_t bh[4], bl[4];
            ldsm_x4(bh, bb_hi + brow * PITCHB + bcol);
            ldsm_x4(bl, bb_lo + brow * PITCHB + bcol);
            #pragma unroll
            for (int mt = 0; mt < 4; mt++) {
                mma_bf(acc[mt][2*ntp],   ah[mt], bh);
                mma_bf(acc[mt][2*ntp],   al[mt], bh);
                mma_bf(acc[mt][2*ntp],   ah[mt], bl);
                mma_bf(acc[mt][2*ntp+1], ah[mt], bh + 2);
                mma_bf(acc[mt][2*ntp+1], al[mt], bh + 2);
                mma_bf(acc[mt][2*ntp+1], ah[mt], bl + 2);
            }
        }
    }
}

__device__ __forceinline__ void mainloop3(
    char* smem,
    const __nv_bfloat16* __restrict__ Ahi, const __nv_bfloat16* __restrict__ Alo,
    const __nv_bfloat16* __restrict__ Bhi, const __nv_bfloat16* __restrict__ Blo,
    int lda, int ldb, int mb0, int nb0, int nst, float acc[4][8][4])
{
    uint32_t sb = s2u(smem);
    issue3(sb, 0, 0,  Ahi, Alo, Bhi, Blo, lda, ldb, mb0, nb0);
    issue3(sb, 1, 32, Ahi, Alo, Bhi, Blo, lda, ldb, mb0, nb0);
    #pragma unroll 1
    for (int st = 0; st < nst; st++) {
        if (st + 1 < nst) asm volatile("cp.async.wait_group 1;" ::: "memory");
        else              asm volatile("cp.async.wait_group 0;" ::: "memory");
        __syncthreads();
        if (st + 2 < nst)
            issue3(sb, (st + 2) % NPIPE, (st + 2) * 32, Ahi, Alo, Bhi, Blo, lda, ldb, mb0, nb0);
        compute3(sb, st % NPIPE, acc);
    }
}

// ---- variant 2 (fp16, A split + B single) ----
__device__ __forceinline__ void issue2(
    uint32_t sb, int buf, int k0,
    const __half* __restrict__ Ahi, const __half* __restrict__ Alo,
    const __half* __restrict__ B,
    int lda, int ldb, int mb0, int nb0)
{
    const int tid  = threadIdx.x;
    const int row4 = tid >> 2;
    const int cb   = (tid & 3) * 16;
    const uint32_t base = sb + buf * STG2_SB;
    #pragma unroll
    for (int r0 = 0; r0 < A_ROWS; r0 += 64) {
        int row = r0 + row4;
        cpasync16(base + row * PITCHB + cb,
                  (const char*)(Ahi + (size_t)(mb0 + row) * lda + k0) + cb);
        cpasync16(base + A_SB + row * PITCHB + cb,
                  (const char*)(Alo + (size_t)(mb0 + row) * lda + k0) + cb);
    }
    #pragma unroll
    for (int r0 = 0; r0 < B_ROWS; r0 += 64) {
        int row = r0 + row4;
        cpasync16(base + 2 * A_SB + row * PITCHB + cb,
                  (const char*)(B + (size_t)(nb0 + row) * ldb + k0) + cb);
    }
    asm volatile("cp.async.commit_group;" ::: "memory");
}

__device__ __forceinline__ void compute2(uint32_t sb, int buf, float acc[4][8][4])
{
    const int lane = threadIdx.x & 31, wid = threadIdx.x >> 5;
    const int wm = wid & 3, wn = wid >> 2;
    const uint32_t ab_hi = sb + buf * STG2_SB;
    const uint32_t ab_lo = ab_hi + A_SB;
    const uint32_t bb    = ab_hi + 2 * A_SB;
    #pragma unroll
    for (int k16 = 0; k16 < 2; k16++) {
        const uint32_t acol = k16 * 32 + (lane >> 4) * 16;
        uint32_t ah[4][4], al[4][4];
        #pragma unroll
        for (int mt = 0; mt < 4; mt++) {
            uint32_t arow = wm * 64 + mt * 16 + (lane & 15);
            ldsm_x4(ah[mt], ab_hi + arow * PITCHB + acol);
            ldsm_x4(al[mt], ab_lo + arow * PITCHB + acol);
        }
        const uint32_t bcol = k16 * 32 + ((lane >> 3) & 1) * 16;
        #pragma unroll
        for (int ntp = 0; ntp < 4; ntp++) {
            uint32_t brow = wn * 64 + ntp * 16 + ((lane >> 4) & 1) * 8 + (lane & 7);
            uint32_t bh[4];
            ldsm_x4(bh, bb + brow * PITCHB + bcol);
            #pragma unroll
            for (int mt = 0; mt < 4; mt++) {
                mma_fp(acc[mt][2*ntp],   ah[mt], bh);
                mma_fp(acc[mt][2*ntp],   al[mt], bh);
                mma_fp(acc[mt][2*ntp+1], ah[mt], bh + 2);
                mma_fp(acc[mt][2*ntp+1], al[mt], bh + 2);
            }
        }
    }
}

__device__ __forceinline__ void mainloop2(
    char* smem,
    const __half* __restrict__ Ahi, const __half* __restrict__ Alo,
    const __half* __restrict__ B,
    int lda, int ldb, int mb0, int nb0, int nst, float acc[4][8][4])
{
    uint32_t sb = s2u(smem);
    issue2(sb, 0, 0,  Ahi, Alo, B, lda, ldb, mb0, nb0);
    issue2(sb, 1, 32, Ahi, Alo, B, lda, ldb, mb0, nb0);
    #pragma unroll 1
    for (int st = 0; st < nst; st++) {
        if (st + 1 < nst) asm volatile("cp.async.wait_group 1;" ::: "memory");
        else              asm volatile("cp.async.wait_group 0;" ::: "memory");
        __syncthreads();
        if (st + 2 < nst)
            issue2(sb, (st + 2) % NPIPE, (st + 2) * 32, Ahi, Alo, B, lda, ldb, mb0, nb0);
        compute2(sb, st % NPIPE, acc);
    }
}

// ---- variant 1 (fp16, A single + B single) ----
__device__ __forceinline__ void issue1(
    uint32_t sb, int buf, int k0,
    const __half* __restrict__ A, const __half* __restrict__ B,
    int lda, int ldb, int mb0, int nb0)
{
    const int tid  = threadIdx.x;
    const int row4 = tid >> 2;
    const int cb   = (tid & 3) * 16;
    const uint32_t base = sb + buf * STG1_SB;
    #pragma unroll
    for (int r0 = 0; r0 < A_ROWS; r0 += 64) {
        int row = r0 + row4;
        cpasync16(base + row * PITCHB + cb,
                  (const char*)(A + (size_t)(mb0 + row) * lda + k0) + cb);
    }
    #pragma unroll
    for (int r0 = 0; r0 < B_ROWS; r0 += 64) {
        int row = r0 + row4;
        cpasync16(base + A_SB + row * PITCHB + cb,
                  (const char*)(B + (size_t)(nb0 + row) * ldb + k0) + cb);
    }
    asm volatile("cp.async.commit_group;" ::: "memory");
}

__device__ __forceinline__ void compute1(uint32_t sb, int buf, float acc[4][8][4])
{
    const int lane = threadIdx.x & 31, wid = threadIdx.x >> 5;
    const int wm = wid & 3, wn = wid >> 2;
    const uint32_t ab = sb + buf * STG1_SB;
    const uint32_t bb = ab + A_SB;
    #pragma unroll
    for (int k16 = 0; k16 < 2; k16++) {
        const uint32_t acol = k16 * 32 + (lane >> 4) * 16;
        uint32_t ah[4][4];
        #pragma unroll
        for (int mt = 0; mt < 4; mt++) {
            uint32_t arow = wm * 64 + mt * 16 + (lane & 15);
            ldsm_x4(ah[mt], ab + arow * PITCHB + acol);
        }
        const uint32_t bcol = k16 * 32 + ((lane >> 3) & 1) * 16;
        #pragma unroll
        for (int ntp = 0; ntp < 4; ntp++) {
            uint32_t brow = wn * 64 + ntp * 16 + ((lane >> 4) & 1) * 8 + (lane & 7);
            uint32_t bh[4];
            ldsm_x4(bh, bb + brow * PITCHB + bcol);
            #pragma unroll
            for (int mt = 0; mt < 4; mt++) {
                mma_fp(acc[mt][2*ntp],   ah[mt], bh);
                mma_fp(acc[mt][2*ntp+1], ah[mt], bh + 2);
            }
        }
    }
}

__device__ __forceinline__ void mainloop1(
    char* smem,
    const __half* __restrict__ A, const __half* __restrict__ B,
    int lda, int ldb, int mb0, int nb0, int nst, float acc[4][8][4])
{
    uint32_t sb = s2u(smem);
    issue1(sb, 0, 0,  A, B, lda, ldb, mb0, nb0);
    issue1(sb, 1, 32, A, B, lda, ldb, mb0, nb0);
    #pragma unroll 1
    for (int st = 0; st < nst; st++) {
        if (st + 1 < nst) asm volatile("cp.async.wait_group 1;" ::: "memory");
        else              asm volatile("cp.async.wait_group 0;" ::: "memory");
        __syncthreads();
        if (st + 2 < nst)
            issue1(sb, (st + 2) % NPIPE, (st + 2) * 32, A, B, lda, ldb, mb0, nb0);
        compute1(sb, st % NPIPE, acc);
    }
}

// epilogue index helper
struct EpiIdx { int r0; int lane, wm, wn; };
__device__ __forceinline__ EpiIdx epi_idx(int mb0, int mt) {
    EpiIdx e;
    e.lane = threadIdx.x & 31;
    int wid = threadIdx.x >> 5;
    e.wm = wid & 3; e.wn = wid >> 2;
    e.r0 = mb0 + e.wm * 64 + mt * 16 + (e.lane >> 2);
    return e;
}

// ---------------- q/k projection (bf16 3-term): P[z,t,o], split bf16 --------
__global__ __launch_bounds__(256, 1) void k_mma_proj(
    const __nv_bfloat16* __restrict__ xhi, const __nv_bfloat16* __restrict__ xlo,
    const __nv_bfloat16* __restrict__ whi, const __nv_bfloat16* __restrict__ wlo,
    const float* __restrict__ bias,
    __nv_bfloat16* __restrict__ phi, __nv_bfloat16* __restrict__ plo)
{
    extern __shared__ char smem[];
    const int z = blockIdx.z, h = z & 7, b = z >> 3;
    const int mb0 = blockIdx.y * 256;    // t
    float acc[4][8][4] = {};
    mainloop3(smem,
              xhi + (size_t)b * 1048576, xlo + (size_t)b * 1048576,
              whi + (size_t)h * 131072,  wlo + (size_t)h * 131072,
              1024, 1024, mb0, 0, 32, acc);
    #pragma unroll
    for (int mt = 0; mt < 4; mt++) {
        EpiIdx e = epi_idx(mb0, mt);
        size_t base = (size_t)z * 131072 + (size_t)e.r0 * 128;
        #pragma unroll
        for (int nt = 0; nt < 8; nt++) {
            int col = e.wn * 64 + nt * 8 + (e.lane & 3) * 2;
            float bc0 = bias[h * DQKd + col], bc1 = bias[h * DQKd + col + 1];
            split_store_b(phi, plo, base + col,
                          acc[mt][nt][0] + bc0, acc[mt][nt][1] + bc1);
            split_store_b(phi, plo, base + 8 * 128 + col,
                          acc[mt][nt][2] + bc0, acc[mt][nt][3] + bc1);
        }
    }
}

// ---------------- energy (bf16 3-term): E fp32 ------------------------------
__global__ __launch_bounds__(256, 1) void k_mma_energy(
    const __nv_bfloat16* __restrict__ qhi, const __nv_bfloat16* __restrict__ qlo,
    const __nv_bfloat16* __restrict__ khi, const __nv_bfloat16* __restrict__ klo,
    float* __restrict__ attn)
{
    extern __shared__ char smem[];
    const int z = blockIdx.z;
    const int mb0 = blockIdx.y * 256;    // t
    const int nb0 = blockIdx.x * 128;    // s
    float acc[4][8][4] = {};
    mainloop3(smem,
              qhi + (size_t)z * 131072, qlo + (size_t)z * 131072,
              khi + (size_t)z * 131072, klo + (size_t)z * 131072,
              128, 128, mb0, nb0, 4, acc);
    #pragma unroll
    for (int mt = 0; mt < 4; mt++) {
        EpiIdx e = epi_idx(mb0, mt);
        size_t base = (size_t)z * 1048576 + (size_t)e.r0 * 1024;
        #pragma unroll
        for (int nt = 0; nt < 8; nt++) {
            int col = nb0 + e.wn * 64 + nt * 8 + (e.lane & 3) * 2;
            *(float2*)&attn[base + col] = make_float2(acc[mt][nt][0], acc[mt][nt][1]);
            *(float2*)&attn[base + 8 * 1024 + col] = make_float2(acc[mt][nt][2], acc[mt][nt][3]);
        }
    }
}

// ---------------- v projection (fp16 1-term): v[z,c,t] single fp16 ----------
__global__ __launch_bounds__(256, 1) void k_mma_vconv(
    const __half* __restrict__ wv, const __half* __restrict__ x16,
    const float* __restrict__ bv, __half* __restrict__ v16)
{
    extern __shared__ char smem[];
    const int z = blockIdx.z, h = z & 7, b = z >> 3;
    const int mb0 = blockIdx.y * 256;    // c
    const int nb0 = blockIdx.x * 128;    // t
    float acc[4][8][4] = {};
    mainloop1(smem,
              wv + (size_t)h * 1048576, x16 + (size_t)b * 1048576,
              1024, 1024, mb0, nb0, 32, acc);
    #pragma unroll
    for (int mt = 0; mt < 4; mt++) {
        EpiIdx e = epi_idx(mb0, mt);
        float bias0 = bv[h * Cdim + e.r0];
        float bias1 = bv[h * Cdim + e.r0 + 8];
        size_t base = (size_t)z * 1048576 + (size_t)e.r0 * 1024;
        #pragma unroll
        for (int nt = 0; nt < 8; nt++) {
            int col = nb0 + e.wn * 64 + nt * 8 + (e.lane & 3) * 2;
            __half2 p0, p1;
            p0.x = __float2half_rn(acc[mt][nt][0] + bias0);
            p0.y = __float2half_rn(acc[mt][nt][1] + bias0);
            p1.x = __float2half_rn(acc[mt][nt][2] + bias1);
            p1.y = __float2half_rn(acc[mt][nt][3] + bias1);
            *(__half2*)(v16 + base + col) = p0;
            *(__half2*)(v16 + base + 8 * 1024 + col) = p1;
        }
    }
}

// ---------------- heads (fp16 1-term): gamma*attn@v^T + x^T, split fp16 -----
__global__ __launch_bounds__(256, 1) void k_mma_oheads(
    const __half* __restrict__ a16, const __half* __restrict__ v16,
    const float* __restrict__ gamma, const float* __restrict__ xT32,
    __half* __restrict__ hhi, __half* __restrict__ hlo)
{
    extern __shared__ char smem[];
    const int z = blockIdx.z, h = z & 7, b = z >> 3;
    const int mb0 = blockIdx.y * 256;    // t
    const int nb0 = blockIdx.x * 128;    // c
    float acc[4][8][4] = {};
    mainloop1(smem,
              a16 + (size_t)z * 1048576, v16 + (size_t)z * 1048576,
              1024, 1024, mb0, nb0, 32, acc);
    const float g = gamma[h];
    #pragma unroll
    for (int mt = 0; mt < 4; mt++) {
        EpiIdx e = epi_idx(mb0, mt);
        size_t hb = (size_t)z * 1048576 + (size_t)e.r0 * 1024;
        size_t xb = (size_t)b * 1048576 + (size_t)e.r0 * 1024;
        #pragma unroll
        for (int nt = 0; nt < 8; nt++) {
            int col = nb0 + e.wn * 64 + nt * 8 + (e.lane & 3) * 2;
            split_store_h(hhi, hlo, hb + col,
                          g * acc[mt][nt][0] + xT32[xb + col],
                          g * acc[mt][nt][1] + xT32[xb + col + 1]);
            split_store_h(hhi, hlo, hb + 8 * 1024 + col,
                          g * acc[mt][nt][2] + xT32[xb + 8 * 1024 + col],
                          g * acc[mt][nt][3] + xT32[xb + 8 * 1024 + col + 1]);
        }
    }
}

// ---------------- fc1 (fp16 2-term): y1 = relu(heads.W1^T + b1), split ------
__global__ __launch_bounds__(256, 1) void k_mma_fc1(
    const __half* __restrict__ hhi, const __half* __restrict__ hlo,
    const __half* __restrict__ w1, const float* __restrict__ b1,
    __half* __restrict__ y1hi, __half* __restrict__ y1lo)
{
    extern __shared__ char smem[];
    const int mb0 = blockIdx.y * 256;    // r
    float acc[4][8][4] = {};
    mainloop2(smem, hhi, hlo, w1, 1024, 1024, mb0, 0, 32, acc);
    #pragma unroll
    for (int mt = 0; mt < 4; mt++) {
        EpiIdx e = epi_idx(mb0, mt);
        size_t base = (size_t)e.r0 * 128;
        #pragma unroll
        for (int nt = 0; nt < 8; nt++) {
            int col = e.wn * 64 + nt * 8 + (e.lane & 3) * 2;
            float bc0 = b1[col], bc1 = b1[col + 1];
            split_store_h(y1hi, y1lo, base + col,
                          fmaxf(acc[mt][nt][0] + bc0, 0.f), fmaxf(acc[mt][nt][1] + bc1, 0.f));
            split_store_h(y1hi, y1lo, base + 8 * 128 + col,
                          fmaxf(acc[mt][nt][2] + bc0, 0.f), fmaxf(acc[mt][nt][3] + bc1, 0.f));
        }
    }
}

// ---------------- fc2 (fp16 2-term): out scatter + relu + residual ----------
__global__ __launch_bounds__(256, 1) void k_mma_fc2(
    const __half* __restrict__ y1hi, const __half* __restrict__ y1lo,
    const __half* __restrict__ w2, const float* __restrict__ b2,
    const float* __restrict__ x, float* __restrict__ out)
{
    extern __shared__ char smem[];
    const int mb0 = blockIdx.y * 256;    // r
    float acc[4][8][4] = {};
    mainloop2(smem, y1hi, y1lo, w2, 128, 128, mb0, 0, 4, acc);
    #pragma unroll
    for (int mt = 0; mt < 4; mt++) {
        EpiIdx e = epi_idx(mb0, mt);
        #pragma unroll
        for (int rr = 0; rr < 2; rr++) {
            int r = e.r0 + rr * 8;               // r = (b*H + h)*T + t
            int b = r >> 13;
            int h = (r >> 10) & 7;
            int t = r & 1023;
            size_t xbase = (size_t)b * 1048576 + t;
            #pragma unroll
            for (int nt = 0; nt < 8; nt++) {
                int col = e.wn * 64 + nt * 8 + (e.lane & 3) * 2;
                #pragma unroll
                for (int jj = 0; jj < 2; jj++) {
                    int d = col + jj;
                    size_t idx = xbase + (size_t)(d * Hn + h) * 1024;
                    out[idx] = fmaxf(acc[mt][nt][rr * 2 + jj] + b2[d], 0.f) + x[idx];
                }
            }
        }
    }
}

// ---------------- softmax: emits single fp16 --------------------------------
__global__ __launch_bounds__(256) void k_softmax2(
    const float* __restrict__ E, __half* __restrict__ a16)
{
    const float* row = E + (size_t)blockIdx.x * Tdim;
    const int tid = threadIdx.x;
    float4 v = *(const float4*)&row[tid * 4];
    __shared__ float red[256];

    float mx = fmaxf(fmaxf(v.x, v.y), fmaxf(v.z, v.w));
    red[tid] = mx; __syncthreads();
    #pragma unroll
    for (int s = 128; s > 0; s >>= 1) {
        if (tid < s) red[tid] = fmaxf(red[tid], red[tid + s]);
        __syncthreads();
    }
    mx = red[0]; __syncthreads();

    v.x = __expf(v.x - mx); v.y = __expf(v.y - mx);
    v.z = __expf(v.z - mx); v.w = __expf(v.w - mx);
    red[tid] = v.x + v.y + v.z + v.w; __syncthreads();
    #pragma unroll
    for (int s = 128; s > 0; s >>= 1) {
        if (tid < s) red[tid] += red[tid + s];
        __syncthreads();
    }
    float inv = 1.0f / red[0];

    size_t o = (size_t)blockIdx.x * Tdim + tid * 4;
    __half2 p;
    p.x = __float2half_rn(v.x * inv); p.y = __float2half_rn(v.y * inv);
    *(__half2*)(a16 + o) = p;
    p.x = __float2half_rn(v.z * inv); p.y = __float2half_rn(v.w * inv);
    *(__half2*)(a16 + o + 2) = p;
}

// ---------------- prep kernels ----------------
__global__ __launch_bounds__(256) void k_wsplit_b(
    const float* __restrict__ w, __nv_bfloat16* __restrict__ hi,
    __nv_bfloat16* __restrict__ lo)
{
    size_t i = ((size_t)blockIdx.x * 256 + threadIdx.x) * 4;
    float4 v = *(const float4*)(w + i);
    split_store_b(hi, lo, i,     v.x, v.y);
    split_store_b(hi, lo, i + 2, v.z, v.w);
}
__global__ __launch_bounds__(256) void k_wround_h(
    const float* __restrict__ w, __half* __restrict__ o)
{
    size_t i = ((size_t)blockIdx.x * 256 + threadIdx.x) * 4;
    float4 v = *(const float4*)(w + i);
    __half2 p;
    p.x = __float2half_rn(v.x); p.y = __float2half_rn(v.y);
    *(__half2*)(o + i) = p;
    p.x = __float2half_rn(v.z); p.y = __float2half_rn(v.w);
    *(__half2*)(o + i + 2) = p;
}

// transpose x (b,c,t) -> xT (b,t,c) as fp32 + bf16 hi/lo + fp16 single
__global__ void k_xprep(const float* __restrict__ x, float* __restrict__ xT32,
                        __nv_bfloat16* __restrict__ xh, __nv_bfloat16* __restrict__ xl,
                        __half* __restrict__ x16)
{
    __shared__ float tile[32][33];
    const int b = blockIdx.z;
    const int c0 = blockIdx.y * 32, t0 = blockIdx.x * 32;
    for (int r = threadIdx.y; r < 32; r += 8)
        tile[r][threadIdx.x] = x[(size_t)b * Cdim * Tdim + (size_t)(c0 + r) * Tdim + t0 + threadIdx.x];
    __syncthreads();
    for (int r = threadIdx.y; r < 32; r += 8) {
        float v = tile[threadIdx.x][r];
        size_t o = (size_t)b * Tdim * Cdim + (size_t)(t0 + r) * Cdim + c0 + threadIdx.x;
        xT32[o] = v;
        __nv_bfloat16 h = __float2bfloat16_rn(v);
        xh[o] = h;
        xl[o] = __float2bfloat16_rn(v - __bfloat162float(h));
        x16[o] = __float2half_rn(v);
    }
}

// ============================================================================
// launch
// ============================================================================
extern "C" void kernel_launch(void* const* d_in, const int* in_sizes, int n_in,
                              void* d_out, int out_size)
{
    (void)in_sizes; (void)n_in; (void)out_size;
    const float* x     = (const float*)d_in[0];
    const float* Wq    = (const float*)d_in[1];
    const float* bq    = (const float*)d_in[2];
    const float* Wk    = (const float*)d_in[3];
    const float* bk    = (const float*)d_in[4];
    const float* Wv    = (const float*)d_in[5];
    const float* bv    = (const float*)d_in[6];
    const float* gamma = (const float*)d_in[7];
    const float* W1    = (const float*)d_in[8];
    const float* b1    = (const float*)d_in[9];
    const float* W2    = (const float*)d_in[10];
    const float* b2    = (const float*)d_in[11];
    float* out = (float*)d_out;

    float *attn, *xT32;
    __half *a16, *v16, *wv16, *w116, *w216, *x16;
    __half *hhi, *hlo, *y1hi, *y1lo;
    __nv_bfloat16 *wqhi, *wqlo, *wkhi, *wklo, *xhi, *xlo, *qhi, *qlo, *khi, *klo;
    cudaGetSymbolAddress((void**)&attn,  g_attn);
    cudaGetSymbolAddress((void**)&a16,   g_attn16);
    cudaGetSymbolAddress((void**)&v16,   g_v16);
    cudaGetSymbolAddress((void**)&wv16,  g_wv_16);
    cudaGetSymbolAddress((void**)&wqhi,  g_wq_hi);
    cudaGetSymbolAddress((void**)&wqlo,  g_wq_lo);
    cudaGetSymbolAddress((void**)&wkhi,  g_wk_hi);
    cudaGetSymbolAddress((void**)&wklo,  g_wk_lo);
    cudaGetSymbolAddress((void**)&w116,  g_w1_16);
    cudaGetSymbolAddress((void**)&w216,  g_w2_16);
    cudaGetSymbolAddress((void**)&xhi,   g_xT_hi);
    cudaGetSymbolAddress((void**)&xlo,   g_xT_lo);
    cudaGetSymbolAddress((void**)&x16,   g_xT16);
    cudaGetSymbolAddress((void**)&xT32,  g_xT32);
    cudaGetSymbolAddress((void**)&qhi,   g_q_hi);
    cudaGetSymbolAddress((void**)&qlo,   g_q_lo);
    cudaGetSymbolAddress((void**)&khi,   g_k_hi);
    cudaGetSymbolAddress((void**)&klo,   g_k_lo);
    cudaGetSymbolAddress((void**)&hhi,   g_h_hi);
    cudaGetSymbolAddress((void**)&hlo,   g_h_lo);
    cudaGetSymbolAddress((void**)&y1hi,  g_y1_hi);
    cudaGetSymbolAddress((void**)&y1lo,  g_y1_lo);

    static bool attr_set = false;
    if (!attr_set) {
        cudaFuncSetAttribute(k_mma_proj,   cudaFuncAttributeMaxDynamicSharedMemorySize, MMA3_SMEM);
        cudaFuncSetAttribute(k_mma_energy, cudaFuncAttributeMaxDynamicSharedMemorySize, MMA3_SMEM);
        cudaFuncSetAttribute(k_mma_vconv,  cudaFuncAttributeMaxDynamicSharedMemorySize, MMA1_SMEM);
        cudaFuncSetAttribute(k_mma_oheads, cudaFuncAttributeMaxDynamicSharedMemorySize, MMA1_SMEM);
        cudaFuncSetAttribute(k_mma_fc1,    cudaFuncAttributeMaxDynamicSharedMemorySize, MMA2_SMEM);
        cudaFuncSetAttribute(k_mma_fc2,    cudaFuncAttributeMaxDynamicSharedMemorySize, MMA2_SMEM);
        attr_set = true;
    }

    const dim3 blk(256);
    const int ZB = Bsz * Hn;   // 64

    // preps
    k_wround_h<<<(Hn*Cdim*Cdim)/1024, 256>>>(Wv, wv16);
    k_wsplit_b<<<(Hn*DQKd*Cdim)/1024, 256>>>(Wq, wqhi, wqlo);
    k_wsplit_b<<<(Hn*DQKd*Cdim)/1024, 256>>>(Wk, wkhi, wklo);
    k_wround_h<<<(DFC1*Cdim)/1024,    256>>>(W1, w116);
    k_wround_h<<<(DFC1*DFC1)/1024,    256>>>(W2, w216);
    k_xprep<<<dim3(Tdim/32, Cdim/32, Bsz), dim3(32, 8)>>>(x, xT32, xhi, xlo, x16);

    // q/k projections (bf16 3-term)
    k_mma_proj<<<dim3(1, Tdim/256, ZB), blk, MMA3_SMEM>>>(xhi, xlo, wqhi, wqlo, bq, qhi, qlo);
    k_mma_proj<<<dim3(1, Tdim/256, ZB), blk, MMA3_SMEM>>>(xhi, xlo, wkhi, wklo, bk, khi, klo);

    // v projection (fp16 1-term): v[z,c,t] single fp16
    k_mma_vconv<<<dim3(Tdim/128, Cdim/256, ZB), blk, MMA1_SMEM>>>(wv16, x16, bv, v16);

    // energy (bf16 3-term, fp32 out) + softmax (single fp16 out)
    k_mma_energy<<<dim3(Tdim/128, Tdim/256, ZB), blk, MMA3_SMEM>>>(qhi, qlo, khi, klo, attn);
    k_softmax2<<<ZB * Tdim, blk>>>(attn, a16);

    // heads (fp16 1-term)
    k_mma_oheads<<<dim3(Cdim/128, Tdim/256, ZB), blk, MMA1_SMEM>>>(
        a16, v16, gamma, xT32, hhi, hlo);

    // MLP (fp16 2-term)
    const int ROWS = Bsz * Hn * Tdim;   // 65536
    k_mma_fc1<<<dim3(1, ROWS/256), blk, MMA2_SMEM>>>(hhi, hlo, w116, b1, y1hi, y1lo);
    k_mma_fc2<<<dim3(1, ROWS/256), blk, MMA2_SMEM>>>(y1hi, y1lo, w216, b2, x, out);
}

// round 8
// speedup vs baseline: 5.0263x; 1.0683x over previous
#include <cuda_runtime.h>
#include <cuda_fp16.h>
#include <cstdint>

// ---------------- problem constants ----------------
#define Bsz  8
#define Cdim 1024
#define Tdim 1024
#define Hn   8
#define DQKd 128
#define DFC1 128

// ---------------- scratch (device globals; no allocs allowed) ----------------
__device__ __half g_attn16[(size_t)Bsz*Hn*Tdim*Tdim];         // logits -> attn (in-place)
__device__ __half g_v16 [(size_t)Bsz*Hn*Cdim*Tdim];           // v (z,c,t) single fp16
__device__ __half g_wv16[(size_t)Hn*Cdim*Cdim];
__device__ __half g_wq16[(size_t)Hn*DQKd*Cdim];
__device__ __half g_wk16[(size_t)Hn*DQKd*Cdim];
__device__ __half g_w116[(size_t)DFC1*Cdim];
__device__ __half g_w216[(size_t)DFC1*DFC1];
__device__ __half g_xT_hi[(size_t)Bsz*Tdim*Cdim];             // x^T (b,t,c) fp16 split
__device__ __half g_xT_lo[(size_t)Bsz*Tdim*Cdim];
__device__ float  g_xT32[(size_t)Bsz*Tdim*Cdim];
__device__ __half g_q_hi[(size_t)Bsz*Hn*Tdim*DQKd];           // q (z,t,o) fp16 split
__device__ __half g_q_lo[(size_t)Bsz*Hn*Tdim*DQKd];
__device__ __half g_k_hi[(size_t)Bsz*Hn*Tdim*DQKd];
__device__ __half g_k_lo[(size_t)Bsz*Hn*Tdim*DQKd];
__device__ __half g_h_hi[(size_t)Bsz*Hn*Tdim*Cdim];           // heads (z,t,c) fp16 split
__device__ __half g_h_lo[(size_t)Bsz*Hn*Tdim*Cdim];
__device__ __half g_y1_hi[(size_t)Bsz*Hn*Tdim*DFC1];
__device__ __half g_y1_lo[(size_t)Bsz*Hn*Tdim*DFC1];

// ============================================================================
// PTX helpers (sm_80-level — valid on compute_103)
// ============================================================================
__device__ __forceinline__ uint32_t s2u(const void* p) {
    uint32_t a;
    asm("{ .reg .u64 t; cvta.to.shared.u64 t, %1; cvt.u32.u64 %0, t; }"
        : "=r"(a) : "l"(p));
    return a;
}
__device__ __forceinline__ void ldsm_x4(uint32_t* r, uint32_t addr) {
    asm volatile("ldmatrix.sync.aligned.m8n8.x4.shared.b16 {%0,%1,%2,%3}, [%4];"
        : "=r"(r[0]), "=r"(r[1]), "=r"(r[2]), "=r"(r[3]) : "r"(addr));
}
__device__ __forceinline__ void mma_fp(float* c, const uint32_t* a, const uint32_t* b) {
    asm volatile("mma.sync.aligned.m16n8k16.row.col.f32.f16.f16.f32 "
        "{%0,%1,%2,%3}, {%4,%5,%6,%7}, {%8,%9}, {%0,%1,%2,%3};"
        : "+f"(c[0]), "+f"(c[1]), "+f"(c[2]), "+f"(c[3])
        : "r"(a[0]), "r"(a[1]), "r"(a[2]), "r"(a[3]), "r"(b[0]), "r"(b[1]));
}
__device__ __forceinline__ void cpasync16(uint32_t dst, const void* src) {
    asm volatile("cp.async.cg.shared.global [%0], [%1], 16;" :: "r"(dst), "l"(src));
}
__device__ __forceinline__ void split_store_h(
    __half* __restrict__ hi, __half* __restrict__ lo,
    size_t off, float v0, float v1)
{
    __half h0 = __float2half_rn(v0);
    __half h1 = __float2half_rn(v1);
    __half2 hp; hp.x = h0; hp.y = h1;
    __half2 lp;
    lp.x = __float2half_rn(v0 - __half2float(h0));
    lp.y = __float2half_rn(v1 - __half2float(h1));
    *(__half2*)(hi + off) = hp;
    *(__half2*)(lo + off) = lp;
}

// ============================================================================
// fp16 tensor-core GEMM mainloops (TN): D[m,n] = sum_k A[m,k]*B[n,k]
// CTA tile 256x128, K-step 32, 4-stage cp.async pipeline (prefetch dist 3),
// single __syncthreads per stage. 8 warps as 4M x 2N, each warp 64x64.
// Variant 2: acc += Ahi*B + Alo*B   Variant 1: acc += A*B
// ============================================================================
#define PITCHB   80
#define A_ROWS   256
#define B_ROWS   128
#define A_SB     (A_ROWS*PITCHB)     // 20480
#define B_SB     (B_ROWS*PITCHB)     // 10240
#define STG2_SB  (2*A_SB + B_SB)     // 51200
#define STG1_SB  (A_SB + B_SB)       // 30720
#define NPIPE    4
#define MMA2_SMEM (NPIPE*STG2_SB)    // 204800
#define MMA1_SMEM (NPIPE*STG1_SB)    // 122880

#define WAIT_PEND(nst, st) do {                                         \
    int _p = (nst) - (st) - 1;                                          \
    if      (_p >= 2) asm volatile("cp.async.wait_group 2;" ::: "memory"); \
    else if (_p == 1) asm volatile("cp.async.wait_group 1;" ::: "memory"); \
    else              asm volatile("cp.async.wait_group 0;" ::: "memory"); \
} while (0)

// ---- variant 2 (A split + B single) ----
__device__ __forceinline__ void issue2(
    uint32_t sb, int buf, int k0,
    const __half* __restrict__ Ahi, const __half* __restrict__ Alo,
    const __half* __restrict__ B,
    int lda, int ldb, int mb0, int nb0)
{
    const int tid  = threadIdx.x;
    const int row4 = tid >> 2;
    const int cb   = (tid & 3) * 16;
    const uint32_t base = sb + buf * STG2_SB;
    #pragma unroll
    for (int r0 = 0; r0 < A_ROWS; r0 += 64) {
        int row = r0 + row4;
        cpasync16(base + row * PITCHB + cb,
                  (const char*)(Ahi + (size_t)(mb0 + row) * lda + k0) + cb);
        cpasync16(base + A_SB + row * PITCHB + cb,
                  (const char*)(Alo + (size_t)(mb0 + row) * lda + k0) + cb);
    }
    #pragma unroll
    for (int r0 = 0; r0 < B_ROWS; r0 += 64) {
        int row = r0 + row4;
        cpasync16(base + 2 * A_SB + row * PITCHB + cb,
                  (const char*)(B + (size_t)(nb0 + row) * ldb + k0) + cb);
    }
    asm volatile("cp.async.commit_group;" ::: "memory");
}

__device__ __forceinline__ void compute2(uint32_t sb, int buf, float acc[4][8][4])
{
    const int lane = threadIdx.x & 31, wid = threadIdx.x >> 5;
    const int wm = wid & 3, wn = wid >> 2;
    const uint32_t ab_hi = sb + buf * STG2_SB;
    const uint32_t ab_lo = ab_hi + A_SB;
    const uint32_t bb    = ab_hi + 2 * A_SB;
    #pragma unroll
    for (int k16 = 0; k16 < 2; k16++) {
        const uint32_t acol = k16 * 32 + (lane >> 4) * 16;
        uint32_t ah[4][4], al[4][4];
        #pragma unroll
        for (int mt = 0; mt < 4; mt++) {
            uint32_t arow = wm * 64 + mt * 16 + (lane & 15);
            ldsm_x4(ah[mt], ab_hi + arow * PITCHB + acol);
            ldsm_x4(al[mt], ab_lo + arow * PITCHB + acol);
        }
        const uint32_t bcol = k16 * 32 + ((lane >> 3) & 1) * 16;
        #pragma unroll
        for (int ntp = 0; ntp < 4; ntp++) {
            uint32_t brow = wn * 64 + ntp * 16 + ((lane >> 4) & 1) * 8 + (lane & 7);
            uint32_t bh[4];
            ldsm_x4(bh, bb + brow * PITCHB + bcol);
            #pragma unroll
            for (int mt = 0; mt < 4; mt++) {
                mma_fp(acc[mt][2*ntp],   ah[mt], bh);
                mma_fp(acc[mt][2*ntp],   al[mt], bh);
                mma_fp(acc[mt][2*ntp+1], ah[mt], bh + 2);
                mma_fp(acc[mt][2*ntp+1], al[mt], bh + 2);
            }
        }
    }
}

__device__ __forceinline__ void mainloop2(
    char* smem,
    const __half* __restrict__ Ahi, const __half* __restrict__ Alo,
    const __half* __restrict__ B,
    int lda, int ldb, int mb0, int nb0, int nst, float acc[4][8][4])
{
    uint32_t sb = s2u(smem);
    issue2(sb, 0, 0,  Ahi, Alo, B, lda, ldb, mb0, nb0);
    issue2(sb, 1, 32, Ahi, Alo, B, lda, ldb, mb0, nb0);
    issue2(sb, 2, 64, Ahi, Alo, B, lda, ldb, mb0, nb0);
    #pragma unroll 1
    for (int st = 0; st < nst; st++) {
        WAIT_PEND(nst, st);
        __syncthreads();
        if (st + 3 < nst)
            issue2(sb, (st + 3) & 3, (st + 3) * 32, Ahi, Alo, B, lda, ldb, mb0, nb0);
        compute2(sb, st & 3, acc);
    }
}

// ---- variant 1 (A single + B single) ----
__device__ __forceinline__ void issue1(
    uint32_t sb, int buf, int k0,
    const __half* __restrict__ A, const __half* __restrict__ B,
    int lda, int ldb, int mb0, int nb0)
{
    const int tid  = threadIdx.x;
    const int row4 = tid >> 2;
    const int cb   = (tid & 3) * 16;
    const uint32_t base = sb + buf * STG1_SB;
    #pragma unroll
    for (int r0 = 0; r0 < A_ROWS; r0 += 64) {
        int row = r0 + row4;
        cpasync16(base + row * PITCHB + cb,
                  (const char*)(A + (size_t)(mb0 + row) * lda + k0) + cb);
    }
    #pragma unroll
    for (int r0 = 0; r0 < B_ROWS; r0 += 64) {
        int row = r0 + row4;
        cpasync16(base + A_SB + row * PITCHB + cb,
                  (const char*)(B + (size_t)(nb0 + row) * ldb + k0) + cb);
    }
    asm volatile("cp.async.commit_group;" ::: "memory");
}

__device__ __forceinline__ void compute1(uint32_t sb, int buf, float acc[4][8][4])
{
    const int lane = threadIdx.x & 31, wid = threadIdx.x >> 5;
    const int wm = wid & 3, wn = wid >> 2;
    const uint32_t ab = sb + buf * STG1_SB;
    const uint32_t bb = ab + A_SB;
    #pragma unroll
    for (int k16 = 0; k16 < 2; k16++) {
        const uint32_t acol = k16 * 32 + (lane >> 4) * 16;
        uint32_t ah[4][4];
        #pragma unroll
        for (int mt = 0; mt < 4; mt++) {
            uint32_t arow = wm * 64 + mt * 16 + (lane & 15);
            ldsm_x4(ah[mt], ab + arow * PITCHB + acol);
        }
        const uint32_t bcol = k16 * 32 + ((lane >> 3) & 1) * 16;
        #pragma unroll
        for (int ntp = 0; ntp < 4; ntp++) {
            uint32_t brow = wn * 64 + ntp * 16 + ((lane >> 4) & 1) * 8 + (lane & 7);
            uint32_t bh[4];
            ldsm_x4(bh, bb + brow * PITCHB + bcol);
            #pragma unroll
            for (int mt = 0; mt < 4; mt++) {
                mma_fp(acc[mt][2*ntp],   ah[mt], bh);
                mma_fp(acc[mt][2*ntp+1], ah[mt], bh + 2);
            }
        }
    }
}

__device__ __forceinline__ void mainloop1(
    char* smem,
    const __half* __restrict__ A, const __half* __restrict__ B,
    int lda, int ldb, int mb0, int nb0, int nst, float acc[4][8][4])
{
    uint32_t sb = s2u(smem);
    issue1(sb, 0, 0,  A, B, lda, ldb, mb0, nb0);
    issue1(sb, 1, 32, A, B, lda, ldb, mb0, nb0);
    issue1(sb, 2, 64, A, B, lda, ldb, mb0, nb0);
    #pragma unroll 1
    for (int st = 0; st < nst; st++) {
        WAIT_PEND(nst, st);
        __syncthreads();
        if (st + 3 < nst)
            issue1(sb, (st + 3) & 3, (st + 3) * 32, A, B, lda, ldb, mb0, nb0);
        compute1(sb, st & 3, acc);
    }
}

// epilogue index helper
struct EpiIdx { int r0; int lane, wm, wn; };
__device__ __forceinline__ EpiIdx epi_idx(int mb0, int mt) {
    EpiIdx e;
    e.lane = threadIdx.x & 31;
    int wid = threadIdx.x >> 5;
    e.wm = wid & 3; e.wn = wid >> 2;
    e.r0 = mb0 + e.wm * 64 + mt * 16 + (e.lane >> 2);
    return e;
}

// ---------------- q/k projection (fp16 2-term): P[z,t,o], split fp16 --------
__global__ __launch_bounds__(256, 1) void k_mma_proj(
    const __half* __restrict__ xhi, const __half* __restrict__ xlo,
    const __half* __restrict__ w16, const float* __restrict__ bias,
    __half* __restrict__ phi, __half* __restrict__ plo)
{
    extern __shared__ char smem[];
    const int z = blockIdx.z, h = z & 7, b = z >> 3;
    const int mb0 = blockIdx.y * 256;    // t
    float acc[4][8][4] = {};
    mainloop2(smem,
              xhi + (size_t)b * 1048576, xlo + (size_t)b * 1048576,
              w16 + (size_t)h * 131072,
              1024, 1024, mb0, 0, 32, acc);
    #pragma unroll
    for (int mt = 0; mt < 4; mt++) {
        EpiIdx e = epi_idx(mb0, mt);
        size_t base = (size_t)z * 131072 + (size_t)e.r0 * 128;
        #pragma unroll
        for (int nt = 0; nt < 8; nt++) {
            int col = e.wn * 64 + nt * 8 + (e.lane & 3) * 2;
            float bc0 = bias[h * DQKd + col], bc1 = bias[h * DQKd + col + 1];
            split_store_h(phi, plo, base + col,
                          acc[mt][nt][0] + bc0, acc[mt][nt][1] + bc1);
            split_store_h(phi, plo, base + 8 * 128 + col,
                          acc[mt][nt][2] + bc0, acc[mt][nt][3] + bc1);
        }
    }
}

// ---------------- energy (fp16 2-term): logits fp16 out ---------------------
__global__ __launch_bounds__(256, 1) void k_mma_energy(
    const __half* __restrict__ qhi, const __half* __restrict__ qlo,
    const __half* __restrict__ khi, __half* __restrict__ logits)
{
    extern __shared__ char smem[];
    const int z = blockIdx.z;
    const int mb0 = blockIdx.y * 256;    // t
    const int nb0 = blockIdx.x * 128;    // s
    float acc[4][8][4] = {};
    mainloop2(smem,
              qhi + (size_t)z * 131072, qlo + (size_t)z * 131072,
              khi + (size_t)z * 131072,
              128, 128, mb0, nb0, 4, acc);
    #pragma unroll
    for (int mt = 0; mt < 4; mt++) {
        EpiIdx e = epi_idx(mb0, mt);
        size_t base = (size_t)z * 1048576 + (size_t)e.r0 * 1024;
        #pragma unroll
        for (int nt = 0; nt < 8; nt++) {
            int col = nb0 + e.wn * 64 + nt * 8 + (e.lane & 3) * 2;
            __half2 p0, p1;
            p0.x = __float2half_rn(acc[mt][nt][0]);
            p0.y = __float2half_rn(acc[mt][nt][1]);
            p1.x = __float2half_rn(acc[mt][nt][2]);
            p1.y = __float2half_rn(acc[mt][nt][3]);
            *(__half2*)(logits + base + col) = p0;
            *(__half2*)(logits + base + 8 * 1024 + col) = p1;
        }
    }
}

// ---------------- v projection (fp16 1-term): v[z,c,t] single fp16 ----------
__global__ __launch_bounds__(256, 1) void k_mma_vconv(
    const __half* __restrict__ wv, const __half* __restrict__ x16,
    const float* __restrict__ bv, __half* __restrict__ v16)
{
    extern __shared__ char smem[];
    const int z = blockIdx.z, h = z & 7, b = z >> 3;
    const int mb0 = blockIdx.y * 256;    // c
    const int nb0 = blockIdx.x * 128;    // t
    float acc[4][8][4] = {};
    mainloop1(smem,
              wv + (size_t)h * 1048576, x16 + (size_t)b * 1048576,
              1024, 1024, mb0, nb0, 32, acc);
    #pragma unroll
    for (int mt = 0; mt < 4; mt++) {
        EpiIdx e = epi_idx(mb0, mt);
        float bias0 = bv[h * Cdim + e.r0];
        float bias1 = bv[h * Cdim + e.r0 + 8];
        size_t base = (size_t)z * 1048576 + (size_t)e.r0 * 1024;
        #pragma unroll
        for (int nt = 0; nt < 8; nt++) {
            int col = nb0 + e.wn * 64 + nt * 8 + (e.lane & 3) * 2;
            __half2 p0, p1;
            p0.x = __float2half_rn(acc[mt][nt][0] + bias0);
            p0.y = __float2half_rn(acc[mt][nt][1] + bias0);
            p1.x = __float2half_rn(acc[mt][nt][2] + bias1);
            p1.y = __float2half_rn(acc[mt][nt][3] + bias1);
            *(__half2*)(v16 + base + col) = p0;
            *(__half2*)(v16 + base + 8 * 1024 + col) = p1;
        }
    }
}

// ---------------- heads (fp16 1-term): gamma*attn@v^T + x^T, split fp16 -----
__global__ __launch_bounds__(256, 1) void k_mma_oheads(
    const __half* __restrict__ a16, const __half* __restrict__ v16,
    const float* __restrict__ gamma, const float* __restrict__ xT32,
    __half* __restrict__ hhi, __half* __restrict__ hlo)
{
    extern __shared__ char smem[];
    const int z = blockIdx.z, h = z & 7, b = z >> 3;
    const int mb0 = blockIdx.y * 256;    // t
    const int nb0 = blockIdx.x * 128;    // c
    float acc[4][8][4] = {};
    mainloop1(smem,
              a16 + (size_t)z * 1048576, v16 + (size_t)z * 1048576,
              1024, 1024, mb0, nb0, 32, acc);
    const float g = gamma[h];
    #pragma unroll
    for (int mt = 0; mt < 4; mt++) {
        EpiIdx e = epi_idx(mb0, mt);
        size_t hb = (size_t)z * 1048576 + (size_t)e.r0 * 1024;
        size_t xb = (size_t)b * 1048576 + (size_t)e.r0 * 1024;
        #pragma unroll
        for (int nt = 0; nt < 8; nt++) {
            int col = nb0 + e.wn * 64 + nt * 8 + (e.lane & 3) * 2;
            split_store_h(hhi, hlo, hb + col,
                          g * acc[mt][nt][0] + xT32[xb + col],
                          g * acc[mt][nt][1] + xT32[xb + col + 1]);
            split_store_h(hhi, hlo, hb + 8 * 1024 + col,
                          g * acc[mt][nt][2] + xT32[xb + 8 * 1024 + col],
                          g * acc[mt][nt][3] + xT32[xb + 8 * 1024 + col + 1]);
        }
    }
}

// ---------------- fc1 (fp16 2-term): y1 = relu(heads.W1^T + b1), split ------
__global__ __launch_bounds__(256, 1) void k_mma_fc1(
    const __half* __restrict__ hhi, const __half* __restrict__ hlo,
    const __half* __restrict__ w1, const float* __restrict__ b1,
    __half* __restrict__ y1hi, __half* __restrict__ y1lo)
{
    extern __shared__ char smem[];
    const int mb0 = blockIdx.y * 256;    // r
    float acc[4][8][4] = {};
    mainloop2(smem, hhi, hlo, w1, 1024, 1024, mb0, 0, 32, acc);
    #pragma unroll
    for (int mt = 0; mt < 4; mt++) {
        EpiIdx e = epi_idx(mb0, mt);
        size_t base = (size_t)e.r0 * 128;
        #pragma unroll
        for (int nt = 0; nt < 8; nt++) {
            int col = e.wn * 64 + nt * 8 + (e.lane & 3) * 2;
            float bc0 = b1[col], bc1 = b1[col + 1];
            split_store_h(y1hi, y1lo, base + col,
                          fmaxf(acc[mt][nt][0] + bc0, 0.f), fmaxf(acc[mt][nt][1] + bc1, 0.f));
            split_store_h(y1hi, y1lo, base + 8 * 128 + col,
                          fmaxf(acc[mt][nt][2] + bc0, 0.f), fmaxf(acc[mt][nt][3] + bc1, 0.f));
        }
    }
}

// ---------------- fc2 (fp16 2-term): out scatter + relu + residual ----------
__global__ __launch_bounds__(256, 1) void k_mma_fc2(
    const __half* __restrict__ y1hi, const __half* __restrict__ y1lo,
    const __half* __restrict__ w2, const float* __restrict__ b2,
    const float* __restrict__ x, float* __restrict__ out)
{
    extern __shared__ char smem[];
    const int mb0 = blockIdx.y * 256;    // r
    float acc[4][8][4] = {};
    mainloop2(smem, y1hi, y1lo, w2, 128, 128, mb0, 0, 4, acc);
    #pragma unroll
    for (int mt = 0; mt < 4; mt++) {
        EpiIdx e = epi_idx(mb0, mt);
        #pragma unroll
        for (int rr = 0; rr < 2; rr++) {
            int r = e.r0 + rr * 8;               // r = (b*H + h)*T + t
            int b = r >> 13;
            int h = (r >> 10) & 7;
            int t = r & 1023;
            size_t xbase = (size_t)b * 1048576 + t;
            #pragma unroll
            for (int nt = 0; nt < 8; nt++) {
                int col = e.wn * 64 + nt * 8 + (e.lane & 3) * 2;
                #pragma unroll
                for (int jj = 0; jj < 2; jj++) {
                    int d = col + jj;
                    size_t idx = xbase + (size_t)(d * Hn + h) * 1024;
                    out[idx] = fmaxf(acc[mt][nt][rr * 2 + jj] + b2[d], 0.f) + x[idx];
                }
            }
        }
    }
}

// ---------------- softmax: fp16 logits in, fp16 attn out (in-place) ---------
__global__ __launch_bounds__(256) void k_softmax(__half* __restrict__ a)
{
    __half* row = a + (size_t)blockIdx.x * Tdim;
    const int tid = threadIdx.x;
    __half2 h01 = *(__half2*)&row[tid * 4];
    __half2 h23 = *(__half2*)&row[tid * 4 + 2];
    float v0 = __half2float(h01.x), v1 = __half2float(h01.y);
    float v2 = __half2float(h23.x), v3 = __half2float(h23.y);
    __shared__ float red[256];

    float mx = fmaxf(fmaxf(v0, v1), fmaxf(v2, v3));
    red[tid] = mx; __syncthreads();
    #pragma unroll
    for (int s = 128; s > 0; s >>= 1) {
        if (tid < s) red[tid] = fmaxf(red[tid], red[tid + s]);
        __syncthreads();
    }
    mx = red[0]; __syncthreads();

    v0 = __expf(v0 - mx); v1 = __expf(v1 - mx);
    v2 = __expf(v2 - mx); v3 = __expf(v3 - mx);
    red[tid] = v0 + v1 + v2 + v3; __syncthreads();
    #pragma unroll
    for (int s = 128; s > 0; s >>= 1) {
        if (tid < s) red[tid] += red[tid + s];
        __syncthreads();
    }
    float inv = 1.0f / red[0];

    __half2 p;
    p.x = __float2half_rn(v0 * inv); p.y = __float2half_rn(v1 * inv);
    *(__half2*)&row[tid * 4] = p;
    p.x = __float2half_rn(v2 * inv); p.y = __float2half_rn(v3 * inv);
    *(__half2*)&row[tid * 4 + 2] = p;
}

// ---------------- prep kernels ----------------
__global__ __launch_bounds__(256) void k_wround_h(
    const float* __restrict__ w, __half* __restrict__ o)
{
    size_t i = ((size_t)blockIdx.x * 256 + threadIdx.x) * 4;
    float4 v = *(const float4*)(w + i);
    __half2 p;
    p.x = __float2half_rn(v.x); p.y = __float2half_rn(v.y);
    *(__half2*)(o + i) = p;
    p.x = __float2half_rn(v.z); p.y = __float2half_rn(v.w);
    *(__half2*)(o + i + 2) = p;
}

// transpose x (b,c,t) -> xT (b,t,c) as fp32 + fp16 hi/lo
__global__ void k_xprep(const float* __restrict__ x, float* __restrict__ xT32,
                        __half* __restrict__ xh, __half* __restrict__ xl)
{
    __shared__ float tile[32][33];
    const int b = blockIdx.z;
    const int c0 = blockIdx.y * 32, t0 = blockIdx.x * 32;
    for (int r = threadIdx.y; r < 32; r += 8)
        tile[r][threadIdx.x] = x[(size_t)b * Cdim * Tdim + (size_t)(c0 + r) * Tdim + t0 + threadIdx.x];
    __syncthreads();
    for (int r = threadIdx.y; r < 32; r += 8) {
        float v = tile[threadIdx.x][r];
        size_t o = (size_t)b * Tdim * Cdim + (size_t)(t0 + r) * Cdim + c0 + threadIdx.x;
        xT32[o] = v;
        __half h = __float2half_rn(v);
        xh[o] = h;
        xl[o] = __float2half_rn(v - __half2float(h));
    }
}

// ============================================================================
// launch
// ============================================================================
extern "C" void kernel_launch(void* const* d_in, const int* in_sizes, int n_in,
                              void* d_out, int out_size)
{
    (void)in_sizes; (void)n_in; (void)out_size;
    const float* x     = (const float*)d_in[0];
    const float* Wq    = (const float*)d_in[1];
    const float* bq    = (const float*)d_in[2];
    const float* Wk    = (const float*)d_in[3];
    const float* bk    = (const float*)d_in[4];
    const float* Wv    = (const float*)d_in[5];
    const float* bv    = (const float*)d_in[6];
    const float* gamma = (const float*)d_in[7];
    const float* W1    = (const float*)d_in[8];
    const float* b1    = (const float*)d_in[9];
    const float* W2    = (const float*)d_in[10];
    const float* b2    = (const float*)d_in[11];
    float* out = (float*)d_out;

    float *xT32;
    __half *a16, *v16, *wv16, *wq16, *wk16, *w116, *w216;
    __half *xhi, *xlo, *qhi, *qlo, *khi, *klo, *hhi, *hlo, *y1hi, *y1lo;
    cudaGetSymbolAddress((void**)&a16,   g_attn16);
    cudaGetSymbolAddress((void**)&v16,   g_v16);
    cudaGetSymbolAddress((void**)&wv16,  g_wv16);
    cudaGetSymbolAddress((void**)&wq16,  g_wq16);
    cudaGetSymbolAddress((void**)&wk16,  g_wk16);
    cudaGetSymbolAddress((void**)&w116,  g_w116);
    cudaGetSymbolAddress((void**)&w216,  g_w216);
    cudaGetSymbolAddress((void**)&xhi,   g_xT_hi);
    cudaGetSymbolAddress((void**)&xlo,   g_xT_lo);
    cudaGetSymbolAddress((void**)&xT32,  g_xT32);
    cudaGetSymbolAddress((void**)&qhi,   g_q_hi);
    cudaGetSymbolAddress((void**)&qlo,   g_q_lo);
    cudaGetSymbolAddress((void**)&khi,   g_k_hi);
    cudaGetSymbolAddress((void**)&klo,   g_k_lo);
    cudaGetSymbolAddress((void**)&hhi,   g_h_hi);
    cudaGetSymbolAddress((void**)&hlo,   g_h_lo);
    cudaGetSymbolAddress((void**)&y1hi,  g_y1_hi);
    cudaGetSymbolAddress((void**)&y1lo,  g_y1_lo);

    static bool attr_set = false;
    if (!attr_set) {
        cudaFuncSetAttribute(k_mma_proj,   cudaFuncAttributeMaxDynamicSharedMemorySize, MMA2_SMEM);
        cudaFuncSetAttribute(k_mma_energy, cudaFuncAttributeMaxDynamicSharedMemorySize, MMA2_SMEM);
        cudaFuncSetAttribute(k_mma_vconv,  cudaFuncAttributeMaxDynamicSharedMemorySize, MMA1_SMEM);
        cudaFuncSetAttribute(k_mma_oheads, cudaFuncAttributeMaxDynamicSharedMemorySize, MMA1_SMEM);
        cudaFuncSetAttribute(k_mma_fc1,    cudaFuncAttributeMaxDynamicSharedMemorySize, MMA2_SMEM);
        cudaFuncSetAttribute(k_mma_fc2,    cudaFuncAttributeMaxDynamicSharedMemorySize, MMA2_SMEM);
        attr_set = true;
    }

    const dim3 blk(256);
    const int ZB = Bsz * Hn;   // 64

    // preps (ordered so launch index 5 = k_mma_vconv for ncu -s 5 -c 1)
    k_wround_h<<<(Hn*Cdim*Cdim)/1024, 256>>>(Wv, wv16);                 // 0
    k_wround_h<<<(Hn*DQKd*Cdim)/1024, 256>>>(Wq, wq16);                 // 1
    k_wround_h<<<(Hn*DQKd*Cdim)/1024, 256>>>(Wk, wk16);                 // 2
    k_wround_h<<<(DFC1*Cdim)/1024,    256>>>(W1, w116);                 // 3
    k_xprep<<<dim3(Tdim/32, Cdim/32, Bsz), dim3(32, 8)>>>(x, xT32, xhi, xlo);  // 4

    // v projection (fp16 1-term): v[z,c,t]
    k_mma_vconv<<<dim3(Tdim/128, Cdim/256, ZB), blk, MMA1_SMEM>>>(wv16, xhi, bv, v16);  // 5

    // q/k projections (fp16 2-term)
    k_mma_proj<<<dim3(1, Tdim/256, ZB), blk, MMA2_SMEM>>>(xhi, xlo, wq16, bq, qhi, qlo);
    k_mma_proj<<<dim3(1, Tdim/256, ZB), blk, MMA2_SMEM>>>(xhi, xlo, wk16, bk, khi, klo);

    // energy (fp16 2-term, fp16 logits) + softmax (in-place fp16)
    k_mma_energy<<<dim3(Tdim/128, Tdim/256, ZB), blk, MMA2_SMEM>>>(qhi, qlo, khi, a16);
    k_softmax<<<ZB * Tdim, blk>>>(a16);

    // heads (fp16 1-term)
    k_mma_oheads<<<dim3(Cdim/128, Tdim/256, ZB), blk, MMA1_SMEM>>>(
        a16, v16, gamma, xT32, hhi, hlo);

    // MLP (fp16 2-term)
    const int ROWS = Bsz * Hn * Tdim;   // 65536
    k_mma_fc1<<<dim3(1, ROWS/256), blk, MMA2_SMEM>>>(hhi, hlo, w116, b1, y1hi, y1lo);
    k_wround_h<<<(DFC1*DFC1)/1024, 256>>>(W2, w216);
    k_mma_fc2<<<dim3(1, ROWS/256), blk, MMA2_SMEM>>>(y1hi, y1lo, w216, b2, x, out);
}

// round 9
// speedup vs baseline: 5.5543x; 1.1051x over previous
#include <cuda_runtime.h>
#include <cuda_fp16.h>
#include <cstdint>

// ---------------- problem constants ----------------
#define Bsz  8
#define Cdim 1024
#define Tdim 1024
#define Hn   8
#define DQKd 128
#define DFC1 128

// ---------------- scratch (device globals; no allocs allowed) ----------------
__device__ __half g_attn16[(size_t)Bsz*Hn*Tdim*Tdim];         // logits -> attn (in-place)
__device__ __half g_v16 [(size_t)Bsz*Hn*Cdim*Tdim];           // v (z,c,t) single fp16
__device__ __half g_wv16[(size_t)Hn*Cdim*Cdim];
__device__ __half g_wq16[(size_t)Hn*DQKd*Cdim];
__device__ __half g_wk16[(size_t)Hn*DQKd*Cdim];
__device__ __half g_w116[(size_t)DFC1*Cdim];
__device__ __half g_w216[(size_t)DFC1*DFC1];
__device__ __half g_x16 [(size_t)Bsz*Tdim*Cdim];              // x^T (b,t,c) single fp16
__device__ float  g_xT32[(size_t)Bsz*Tdim*Cdim];
__device__ __half g_q16[(size_t)Bsz*Hn*Tdim*DQKd];            // q (z,t,o) single fp16
__device__ __half g_k16[(size_t)Bsz*Hn*Tdim*DQKd];
__device__ __half g_h_hi[(size_t)Bsz*Hn*Tdim*Cdim];           // heads (z,t,c) fp16 split
__device__ __half g_h_lo[(size_t)Bsz*Hn*Tdim*Cdim];
__device__ __half g_y1_hi[(size_t)Bsz*Hn*Tdim*DFC1];
__device__ __half g_y1_lo[(size_t)Bsz*Hn*Tdim*DFC1];

// ============================================================================
// PTX helpers (sm_80-level — valid on compute_103)
// ============================================================================
__device__ __forceinline__ uint32_t s2u(const void* p) {
    uint32_t a;
    asm("{ .reg .u64 t; cvta.to.shared.u64 t, %1; cvt.u32.u64 %0, t; }"
        : "=r"(a) : "l"(p));
    return a;
}
__device__ __forceinline__ void ldsm_x4(uint32_t* r, uint32_t addr) {
    asm volatile("ldmatrix.sync.aligned.m8n8.x4.shared.b16 {%0,%1,%2,%3}, [%4];"
        : "=r"(r[0]), "=r"(r[1]), "=r"(r[2]), "=r"(r[3]) : "r"(addr));
}
__device__ __forceinline__ void mma_fp(float* c, const uint32_t* a, const uint32_t* b) {
    asm volatile("mma.sync.aligned.m16n8k16.row.col.f32.f16.f16.f32 "
        "{%0,%1,%2,%3}, {%4,%5,%6,%7}, {%8,%9}, {%0,%1,%2,%3};"
        : "+f"(c[0]), "+f"(c[1]), "+f"(c[2]), "+f"(c[3])
        : "r"(a[0]), "r"(a[1]), "r"(a[2]), "r"(a[3]), "r"(b[0]), "r"(b[1]));
}
__device__ __forceinline__ void cpasync16(uint32_t dst, const void* src) {
    asm volatile("cp.async.cg.shared.global [%0], [%1], 16;" :: "r"(dst), "l"(src));
}
__device__ __forceinline__ void split_store_h(
    __half* __restrict__ hi, __half* __restrict__ lo,
    size_t off, float v0, float v1)
{
    __half h0 = __float2half_rn(v0);
    __half h1 = __float2half_rn(v1);
    __half2 hp; hp.x = h0; hp.y = h1;
    __half2 lp;
    lp.x = __float2half_rn(v0 - __half2float(h0));
    lp.y = __float2half_rn(v1 - __half2float(h1));
    *(__half2*)(hi + off) = hp;
    *(__half2*)(lo + off) = lp;
}

// ============================================================================
// fp16 tensor-core GEMM mainloops (TN): D[m,n] = sum_k A[m,k]*B[n,k]
// CTA tile 256x128, K-step 32, 4-stage cp.async pipeline (prefetch dist 3),
// single __syncthreads per stage. 8 warps as 4M x 2N, each warp 64x64.
// Variant 2: acc += Ahi*B + Alo*B   Variant 1: acc += A*B
// ============================================================================
#define PITCHB   80
#define A_ROWS   256
#define B_ROWS   128
#define A_SB     (A_ROWS*PITCHB)     // 20480
#define B_SB     (B_ROWS*PITCHB)     // 10240
#define STG2_SB  (2*A_SB + B_SB)     // 51200
#define STG1_SB  (A_SB + B_SB)       // 30720
#define NPIPE    4
#define MMA2_SMEM (NPIPE*STG2_SB)    // 204800
#define MMA1_SMEM (NPIPE*STG1_SB)    // 122880

#define WAIT_PEND(nst, st) do {                                         \
    int _p = (nst) - (st) - 1;                                          \
    if      (_p >= 2) asm volatile("cp.async.wait_group 2;" ::: "memory"); \
    else if (_p == 1) asm volatile("cp.async.wait_group 1;" ::: "memory"); \
    else              asm volatile("cp.async.wait_group 0;" ::: "memory"); \
} while (0)

// ---- variant 2 (A split + B single) ----
__device__ __forceinline__ void issue2(
    uint32_t sb, int buf, int k0,
    const __half* __restrict__ Ahi, const __half* __restrict__ Alo,
    const __half* __restrict__ B,
    int lda, int ldb, int mb0, int nb0)
{
    const int tid  = threadIdx.x;
    const int row4 = tid >> 2;
    const int cb   = (tid & 3) * 16;
    const uint32_t base = sb + buf * STG2_SB;
    #pragma unroll
    for (int r0 = 0; r0 < A_ROWS; r0 += 64) {
        int row = r0 + row4;
        cpasync16(base + row * PITCHB + cb,
                  (const char*)(Ahi + (size_t)(mb0 + row) * lda + k0) + cb);
        cpasync16(base + A_SB + row * PITCHB + cb,
                  (const char*)(Alo + (size_t)(mb0 + row) * lda + k0) + cb);
    }
    #pragma unroll
    for (int r0 = 0; r0 < B_ROWS; r0 += 64) {
        int row = r0 + row4;
        cpasync16(base + 2 * A_SB + row * PITCHB + cb,
                  (const char*)(B + (size_t)(nb0 + row) * ldb + k0) + cb);
    }
    asm volatile("cp.async.commit_group;" ::: "memory");
}

__device__ __forceinline__ void compute2(uint32_t sb, int buf, float acc[4][8][4])
{
    const int lane = threadIdx.x & 31, wid = threadIdx.x >> 5;
    const int wm = wid & 3, wn = wid >> 2;
    const uint32_t ab_hi = sb + buf * STG2_SB;
    const uint32_t ab_lo = ab_hi + A_SB;
    const uint32_t bb    = ab_hi + 2 * A_SB;
    #pragma unroll
    for (int k16 = 0; k16 < 2; k16++) {
        const uint32_t acol = k16 * 32 + (lane >> 4) * 16;
        uint32_t ah[4][4], al[4][4];
        #pragma unroll
        for (int mt = 0; mt < 4; mt++) {
            uint32_t arow = wm * 64 + mt * 16 + (lane & 15);
            ldsm_x4(ah[mt], ab_hi + arow * PITCHB + acol);
            ldsm_x4(al[mt], ab_lo + arow * PITCHB + acol);
        }
        const uint32_t bcol = k16 * 32 + ((lane >> 3) & 1) * 16;
        #pragma unroll
        for (int ntp = 0; ntp < 4; ntp++) {
            uint32_t brow = wn * 64 + ntp * 16 + ((lane >> 4) & 1) * 8 + (lane & 7);
            uint32_t bh[4];
            ldsm_x4(bh, bb + brow * PITCHB + bcol);
            #pragma unroll
            for (int mt = 0; mt < 4; mt++) {
                mma_fp(acc[mt][2*ntp],   ah[mt], bh);
                mma_fp(acc[mt][2*ntp],   al[mt], bh);
                mma_fp(acc[mt][2*ntp+1], ah[mt], bh + 2);
                mma_fp(acc[mt][2*ntp+1], al[mt], bh + 2);
            }
        }
    }
}

__device__ __forceinline__ void mainloop2(
    char* smem,
    const __half* __restrict__ Ahi, const __half* __restrict__ Alo,
    const __half* __restrict__ B,
    int lda, int ldb, int mb0, int nb0, int nst, float acc[4][8][4])
{
    uint32_t sb = s2u(smem);
    issue2(sb, 0, 0,  Ahi, Alo, B, lda, ldb, mb0, nb0);
    issue2(sb, 1, 32, Ahi, Alo, B, lda, ldb, mb0, nb0);
    issue2(sb, 2, 64, Ahi, Alo, B, lda, ldb, mb0, nb0);
    #pragma unroll 1
    for (int st = 0; st < nst; st++) {
        WAIT_PEND(nst, st);
        __syncthreads();
        if (st + 3 < nst)
            issue2(sb, (st + 3) & 3, (st + 3) * 32, Ahi, Alo, B, lda, ldb, mb0, nb0);
        compute2(sb, st & 3, acc);
    }
}

// ---- variant 1 (A single + B single) ----
__device__ __forceinline__ void issue1(
    uint32_t sb, int buf, int k0,
    const __half* __restrict__ A, const __half* __restrict__ B,
    int lda, int ldb, int mb0, int nb0)
{
    const int tid  = threadIdx.x;
    const int row4 = tid >> 2;
    const int cb   = (tid & 3) * 16;
    const uint32_t base = sb + buf * STG1_SB;
    #pragma unroll
    for (int r0 = 0; r0 < A_ROWS; r0 += 64) {
        int row = r0 + row4;
        cpasync16(base + row * PITCHB + cb,
                  (const char*)(A + (size_t)(mb0 + row) * lda + k0) + cb);
    }
    #pragma unroll
    for (int r0 = 0; r0 < B_ROWS; r0 += 64) {
        int row = r0 + row4;
        cpasync16(base + A_SB + row * PITCHB + cb,
                  (const char*)(B + (size_t)(nb0 + row) * ldb + k0) + cb);
    }
    asm volatile("cp.async.commit_group;" ::: "memory");
}

__device__ __forceinline__ void compute1(uint32_t sb, int buf, float acc[4][8][4])
{
    const int lane = threadIdx.x & 31, wid = threadIdx.x >> 5;
    const int wm = wid & 3, wn = wid >> 2;
    const uint32_t ab = sb + buf * STG1_SB;
    const uint32_t bb = ab + A_SB;
    #pragma unroll
    for (int k16 = 0; k16 < 2; k16++) {
        const uint32_t acol = k16 * 32 + (lane >> 4) * 16;
        uint32_t ah[4][4];
        #pragma unroll
        for (int mt = 0; mt < 4; mt++) {
            uint32_t arow = wm * 64 + mt * 16 + (lane & 15);
            ldsm_x4(ah[mt], ab + arow * PITCHB + acol);
        }
        const uint32_t bcol = k16 * 32 + ((lane >> 3) & 1) * 16;
        #pragma unroll
        for (int ntp = 0; ntp < 4; ntp++) {
            uint32_t brow = wn * 64 + ntp * 16 + ((lane >> 4) & 1) * 8 + (lane & 7);
            uint32_t bh[4];
            ldsm_x4(bh, bb + brow * PITCHB + bcol);
            #pragma unroll
            for (int mt = 0; mt < 4; mt++) {
                mma_fp(acc[mt][2*ntp],   ah[mt], bh);
                mma_fp(acc[mt][2*ntp+1], ah[mt], bh + 2);
            }
        }
    }
}

__device__ __forceinline__ void mainloop1(
    char* smem,
    const __half* __restrict__ A, const __half* __restrict__ B,
    int lda, int ldb, int mb0, int nb0, int nst, float acc[4][8][4])
{
    uint32_t sb = s2u(smem);
    issue1(sb, 0, 0,  A, B, lda, ldb, mb0, nb0);
    issue1(sb, 1, 32, A, B, lda, ldb, mb0, nb0);
    issue1(sb, 2, 64, A, B, lda, ldb, mb0, nb0);
    #pragma unroll 1
    for (int st = 0; st < nst; st++) {
        WAIT_PEND(nst, st);
        __syncthreads();
        if (st + 3 < nst)
            issue1(sb, (st + 3) & 3, (st + 3) * 32, A, B, lda, ldb, mb0, nb0);
        compute1(sb, st & 3, acc);
    }
}

// epilogue index helper
struct EpiIdx { int r0; int lane, wm, wn; };
__device__ __forceinline__ EpiIdx epi_idx(int mb0, int mt) {
    EpiIdx e;
    e.lane = threadIdx.x & 31;
    int wid = threadIdx.x >> 5;
    e.wm = wid & 3; e.wn = wid >> 2;
    e.r0 = mb0 + e.wm * 64 + mt * 16 + (e.lane >> 2);
    return e;
}

// ---------------- q/k projection (fp16 1-term): P[z,t,o] single fp16 --------
__global__ __launch_bounds__(256, 1) void k_mma_proj(
    const __half* __restrict__ x16, const __half* __restrict__ w16,
    const float* __restrict__ bias, __half* __restrict__ p16)
{
    extern __shared__ char smem[];
    const int z = blockIdx.z, h = z & 7, b = z >> 3;
    const int mb0 = blockIdx.y * 256;    // t
    float acc[4][8][4] = {};
    mainloop1(smem,
              x16 + (size_t)b * 1048576, w16 + (size_t)h * 131072,
              1024, 1024, mb0, 0, 32, acc);
    #pragma unroll
    for (int mt = 0; mt < 4; mt++) {
        EpiIdx e = epi_idx(mb0, mt);
        size_t base = (size_t)z * 131072 + (size_t)e.r0 * 128;
        #pragma unroll
        for (int nt = 0; nt < 8; nt++) {
            int col = e.wn * 64 + nt * 8 + (e.lane & 3) * 2;
            float bc0 = bias[h * DQKd + col], bc1 = bias[h * DQKd + col + 1];
            __half2 p0, p1;
            p0.x = __float2half_rn(acc[mt][nt][0] + bc0);
            p0.y = __float2half_rn(acc[mt][nt][1] + bc1);
            p1.x = __float2half_rn(acc[mt][nt][2] + bc0);
            p1.y = __float2half_rn(acc[mt][nt][3] + bc1);
            *(__half2*)(p16 + base + col) = p0;
            *(__half2*)(p16 + base + 8 * 128 + col) = p1;
        }
    }
}

// ---------------- energy (fp16 1-term): logits fp16 out ---------------------
__global__ __launch_bounds__(256, 1) void k_mma_energy(
    const __half* __restrict__ q16, const __half* __restrict__ k16,
    __half* __restrict__ logits)
{
    extern __shared__ char smem[];
    const int z = blockIdx.z;
    const int mb0 = blockIdx.y * 256;    // t
    const int nb0 = blockIdx.x * 128;    // s
    float acc[4][8][4] = {};
    mainloop1(smem,
              q16 + (size_t)z * 131072, k16 + (size_t)z * 131072,
              128, 128, mb0, nb0, 4, acc);
    #pragma unroll
    for (int mt = 0; mt < 4; mt++) {
        EpiIdx e = epi_idx(mb0, mt);
        size_t base = (size_t)z * 1048576 + (size_t)e.r0 * 1024;
        #pragma unroll
        for (int nt = 0; nt < 8; nt++) {
            int col = nb0 + e.wn * 64 + nt * 8 + (e.lane & 3) * 2;
            __half2 p0, p1;
            p0.x = __float2half_rn(acc[mt][nt][0]);
            p0.y = __float2half_rn(acc[mt][nt][1]);
            p1.x = __float2half_rn(acc[mt][nt][2]);
            p1.y = __float2half_rn(acc[mt][nt][3]);
            *(__half2*)(logits + base + col) = p0;
            *(__half2*)(logits + base + 8 * 1024 + col) = p1;
        }
    }
}

// ---------------- v projection (fp16 1-term): v[z,c,t] single fp16 ----------
__global__ __launch_bounds__(256, 1) void k_mma_vconv(
    const __half* __restrict__ wv, const __half* __restrict__ x16,
    const float* __restrict__ bv, __half* __restrict__ v16)
{
    extern __shared__ char smem[];
    const int z = blockIdx.z, h = z & 7, b = z >> 3;
    const int mb0 = blockIdx.y * 256;    // c
    const int nb0 = blockIdx.x * 128;    // t
    float acc[4][8][4] = {};
    mainloop1(smem,
              wv + (size_t)h * 1048576, x16 + (size_t)b * 1048576,
              1024, 1024, mb0, nb0, 32, acc);
    #pragma unroll
    for (int mt = 0; mt < 4; mt++) {
        EpiIdx e = epi_idx(mb0, mt);
        float bias0 = bv[h * Cdim + e.r0];
        float bias1 = bv[h * Cdim + e.r0 + 8];
        size_t base = (size_t)z * 1048576 + (size_t)e.r0 * 1024;
        #pragma unroll
        for (int nt = 0; nt < 8; nt++) {
            int col = nb0 + e.wn * 64 + nt * 8 + (e.lane & 3) * 2;
            __half2 p0, p1;
            p0.x = __float2half_rn(acc[mt][nt][0] + bias0);
            p0.y = __float2half_rn(acc[mt][nt][1] + bias0);
            p1.x = __float2half_rn(acc[mt][nt][2] + bias1);
            p1.y = __float2half_rn(acc[mt][nt][3] + bias1);
            *(__half2*)(v16 + base + col) = p0;
            *(__half2*)(v16 + base + 8 * 1024 + col) = p1;
        }
    }
}

// ---------------- heads (fp16 1-term): gamma*attn@v^T + x^T, split fp16 -----
__global__ __launch_bounds__(256, 1) void k_mma_oheads(
    const __half* __restrict__ a16, const __half* __restrict__ v16,
    const float* __restrict__ gamma, const float* __restrict__ xT32,
    __half* __restrict__ hhi, __half* __restrict__ hlo)
{
    extern __shared__ char smem[];
    const int z = blockIdx.z, h = z & 7, b = z >> 3;
    const int mb0 = blockIdx.y * 256;    // t
    const int nb0 = blockIdx.x * 128;    // c
    float acc[4][8][4] = {};
    mainloop1(smem,
              a16 + (size_t)z * 1048576, v16 + (size_t)z * 1048576,
              1024, 1024, mb0, nb0, 32, acc);
    const float g = gamma[h];
    #pragma unroll
    for (int mt = 0; mt < 4; mt++) {
        EpiIdx e = epi_idx(mb0, mt);
        size_t hb = (size_t)z * 1048576 + (size_t)e.r0 * 1024;
        size_t xb = (size_t)b * 1048576 + (size_t)e.r0 * 1024;
        #pragma unroll
        for (int nt = 0; nt < 8; nt++) {
            int col = nb0 + e.wn * 64 + nt * 8 + (e.lane & 3) * 2;
            split_store_h(hhi, hlo, hb + col,
                          g * acc[mt][nt][0] + xT32[xb + col],
                          g * acc[mt][nt][1] + xT32[xb + col + 1]);
            split_store_h(hhi, hlo, hb + 8 * 1024 + col,
                          g * acc[mt][nt][2] + xT32[xb + 8 * 1024 + col],
                          g * acc[mt][nt][3] + xT32[xb + 8 * 1024 + col + 1]);
        }
    }
}

// ---------------- fc1 (fp16 2-term): y1 = relu(heads.W1^T + b1), split ------
__global__ __launch_bounds__(256, 1) void k_mma_fc1(
    const __half* __restrict__ hhi, const __half* __restrict__ hlo,
    const __half* __restrict__ w1, const float* __restrict__ b1,
    __half* __restrict__ y1hi, __half* __restrict__ y1lo)
{
    extern __shared__ char smem[];
    const int mb0 = blockIdx.y * 256;    // r
    float acc[4][8][4] = {};
    mainloop2(smem, hhi, hlo, w1, 1024, 1024, mb0, 0, 32, acc);
    #pragma unroll
    for (int mt = 0; mt < 4; mt++) {
        EpiIdx e = epi_idx(mb0, mt);
        size_t base = (size_t)e.r0 * 128;
        #pragma unroll
        for (int nt = 0; nt < 8; nt++) {
            int col = e.wn * 64 + nt * 8 + (e.lane & 3) * 2;
            float bc0 = b1[col], bc1 = b1[col + 1];
            split_store_h(y1hi, y1lo, base + col,
                          fmaxf(acc[mt][nt][0] + bc0, 0.f), fmaxf(acc[mt][nt][1] + bc1, 0.f));
            split_store_h(y1hi, y1lo, base + 8 * 128 + col,
                          fmaxf(acc[mt][nt][2] + bc0, 0.f), fmaxf(acc[mt][nt][3] + bc1, 0.f));
        }
    }
}

// ---------------- fc2 (fp16 2-term): out scatter + relu + residual ----------
__global__ __launch_bounds__(256, 1) void k_mma_fc2(
    const __half* __restrict__ y1hi, const __half* __restrict__ y1lo,
    const __half* __restrict__ w2, const float* __restrict__ b2,
    const float* __restrict__ x, float* __restrict__ out)
{
    extern __shared__ char smem[];
    const int mb0 = blockIdx.y * 256;    // r
    float acc[4][8][4] = {};
    mainloop2(smem, y1hi, y1lo, w2, 128, 128, mb0, 0, 4, acc);
    #pragma unroll
    for (int mt = 0; mt < 4; mt++) {
        EpiIdx e = epi_idx(mb0, mt);
        #pragma unroll
        for (int rr = 0; rr < 2; rr++) {
            int r = e.r0 + rr * 8;               // r = (b*H + h)*T + t
            int b = r >> 13;
            int h = (r >> 10) & 7;
            int t = r & 1023;
            size_t xbase = (size_t)b * 1048576 + t;
            #pragma unroll
            for (int nt = 0; nt < 8; nt++) {
                int col = e.wn * 64 + nt * 8 + (e.lane & 3) * 2;
                #pragma unroll
                for (int jj = 0; jj < 2; jj++) {
                    int d = col + jj;
                    size_t idx = xbase + (size_t)(d * Hn + h) * 1024;
                    out[idx] = fmaxf(acc[mt][nt][rr * 2 + jj] + b2[d], 0.f) + x[idx];
                }
            }
        }
    }
}

// ---------------- softmax: fp16 logits in, fp16 attn out (in-place) ---------
__global__ __launch_bounds__(256) void k_softmax(__half* __restrict__ a)
{
    __half* row = a + (size_t)blockIdx.x * Tdim;
    const int tid = threadIdx.x;
    __half2 h01 = *(__half2*)&row[tid * 4];
    __half2 h23 = *(__half2*)&row[tid * 4 + 2];
    float v0 = __half2float(h01.x), v1 = __half2float(h01.y);
    float v2 = __half2float(h23.x), v3 = __half2float(h23.y);
    __shared__ float red[256];

    float mx = fmaxf(fmaxf(v0, v1), fmaxf(v2, v3));
    red[tid] = mx; __syncthreads();
    #pragma unroll
    for (int s = 128; s > 0; s >>= 1) {
        if (tid < s) red[tid] = fmaxf(red[tid], red[tid + s]);
        __syncthreads();
    }
    mx = red[0]; __syncthreads();

    v0 = __expf(v0 - mx); v1 = __expf(v1 - mx);
    v2 = __expf(v2 - mx); v3 = __expf(v3 - mx);
    red[tid] = v0 + v1 + v2 + v3; __syncthreads();
    #pragma unroll
    for (int s = 128; s > 0; s >>= 1) {
        if (tid < s) red[tid] += red[tid + s];
        __syncthreads();
    }
    float inv = 1.0f / red[0];

    __half2 p;
    p.x = __float2half_rn(v0 * inv); p.y = __float2half_rn(v1 * inv);
    *(__half2*)&row[tid * 4] = p;
    p.x = __float2half_rn(v2 * inv); p.y = __float2half_rn(v3 * inv);
    *(__half2*)&row[tid * 4 + 2] = p;
}

// ---------------- prep kernels ----------------
__global__ __launch_bounds__(256) void k_wround_h(
    const float* __restrict__ w, __half* __restrict__ o)
{
    size_t i = ((size_t)blockIdx.x * 256 + threadIdx.x) * 4;
    float4 v = *(const float4*)(w + i);
    __half2 p;
    p.x = __float2half_rn(v.x); p.y = __float2half_rn(v.y);
    *(__half2*)(o + i) = p;
    p.x = __float2half_rn(v.z); p.y = __float2half_rn(v.w);
    *(__half2*)(o + i + 2) = p;
}

// transpose x (b,c,t) -> xT (b,t,c) as fp32 + fp16
__global__ void k_xprep(const float* __restrict__ x, float* __restrict__ xT32,
                        __half* __restrict__ x16)
{
    __shared__ float tile[32][33];
    const int b = blockIdx.z;
    const int c0 = blockIdx.y * 32, t0 = blockIdx.x * 32;
    for (int r = threadIdx.y; r < 32; r += 8)
        tile[r][threadIdx.x] = x[(size_t)b * Cdim * Tdim + (size_t)(c0 + r) * Tdim + t0 + threadIdx.x];
    __syncthreads();
    for (int r = threadIdx.y; r < 32; r += 8) {
        float v = tile[threadIdx.x][r];
        size_t o = (size_t)b * Tdim * Cdim + (size_t)(t0 + r) * Cdim + c0 + threadIdx.x;
        xT32[o] = v;
        x16[o] = __float2half_rn(v);
    }
}

// ============================================================================
// launch
// ============================================================================
extern "C" void kernel_launch(void* const* d_in, const int* in_sizes, int n_in,
                              void* d_out, int out_size)
{
    (void)in_sizes; (void)n_in; (void)out_size;
    const float* x     = (const float*)d_in[0];
    const float* Wq    = (const float*)d_in[1];
    const float* bq    = (const float*)d_in[2];
    const float* Wk    = (const float*)d_in[3];
    const float* bk    = (const float*)d_in[4];
    const float* Wv    = (const float*)d_in[5];
    const float* bv    = (const float*)d_in[6];
    const float* gamma = (const float*)d_in[7];
    const float* W1    = (const float*)d_in[8];
    const float* b1    = (const float*)d_in[9];
    const float* W2    = (const float*)d_in[10];
    const float* b2    = (const float*)d_in[11];
    float* out = (float*)d_out;

    float *xT32;
    __half *a16, *v16, *wv16, *wq16, *wk16, *w116, *w216, *x16;
    __half *q16, *k16, *hhi, *hlo, *y1hi, *y1lo;
    cudaGetSymbolAddress((void**)&a16,   g_attn16);
    cudaGetSymbolAddress((void**)&v16,   g_v16);
    cudaGetSymbolAddress((void**)&wv16,  g_wv16);
    cudaGetSymbolAddress((void**)&wq16,  g_wq16);
    cudaGetSymbolAddress((void**)&wk16,  g_wk16);
    cudaGetSymbolAddress((void**)&w116,  g_w116);
    cudaGetSymbolAddress((void**)&w216,  g_w216);
    cudaGetSymbolAddress((void**)&x16,   g_x16);
    cudaGetSymbolAddress((void**)&xT32,  g_xT32);
    cudaGetSymbolAddress((void**)&q16,   g_q16);
    cudaGetSymbolAddress((void**)&k16,   g_k16);
    cudaGetSymbolAddress((void**)&hhi,   g_h_hi);
    cudaGetSymbolAddress((void**)&hlo,   g_h_lo);
    cudaGetSymbolAddress((void**)&y1hi,  g_y1_hi);
    cudaGetSymbolAddress((void**)&y1lo,  g_y1_lo);

    static cudaStream_t s1 = nullptr;
    static cudaEvent_t evFork = nullptr, evV = nullptr;
    static bool init_done = false;
    if (!init_done) {
        cudaFuncSetAttribute(k_mma_proj,   cudaFuncAttributeMaxDynamicSharedMemorySize, MMA1_SMEM);
        cudaFuncSetAttribute(k_mma_energy, cudaFuncAttributeMaxDynamicSharedMemorySize, MMA1_SMEM);
        cudaFuncSetAttribute(k_mma_vconv,  cudaFuncAttributeMaxDynamicSharedMemorySize, MMA1_SMEM);
        cudaFuncSetAttribute(k_mma_oheads, cudaFuncAttributeMaxDynamicSharedMemorySize, MMA1_SMEM);
        cudaFuncSetAttribute(k_mma_fc1,    cudaFuncAttributeMaxDynamicSharedMemorySize, MMA2_SMEM);
        cudaFuncSetAttribute(k_mma_fc2,    cudaFuncAttributeMaxDynamicSharedMemorySize, MMA2_SMEM);
        cudaStreamCreateWithFlags(&s1, cudaStreamNonBlocking);
        cudaEventCreateWithFlags(&evFork, cudaEventDisableTiming);
        cudaEventCreateWithFlags(&evV,    cudaEventDisableTiming);
        init_done = true;
    }

    const dim3 blk(256);
    const int ZB = Bsz * Hn;   // 64

    // -------- stream 0 (default, capture stream): x prep --------
    k_xprep<<<dim3(Tdim/32, Cdim/32, Bsz), dim3(32, 8)>>>(x, xT32, x16);
    cudaEventRecord(evFork, 0);

    // -------- stream 1: Wv prep -> vconv -> W2 prep --------
    cudaStreamWaitEvent(s1, evFork, 0);
    k_wround_h<<<(Hn*Cdim*Cdim)/1024, 256, 0, s1>>>(Wv, wv16);
    k_mma_vconv<<<dim3(Tdim/128, Cdim/256, ZB), blk, MMA1_SMEM, s1>>>(wv16, x16, bv, v16);
    k_wround_h<<<(DFC1*DFC1)/1024, 256, 0, s1>>>(W2, w216);
    cudaEventRecord(evV, s1);

    // -------- stream 0: q/k chain --------
    k_wround_h<<<(Hn*DQKd*Cdim)/1024, 256>>>(Wq, wq16);
    k_wround_h<<<(Hn*DQKd*Cdim)/1024, 256>>>(Wk, wk16);
    k_wround_h<<<(DFC1*Cdim)/1024,    256>>>(W1, w116);
    k_mma_proj<<<dim3(1, Tdim/256, ZB), blk, MMA1_SMEM>>>(x16, wq16, bq, q16);
    k_mma_proj<<<dim3(1, Tdim/256, ZB), blk, MMA1_SMEM>>>(x16, wk16, bk, k16);
    k_mma_energy<<<dim3(Tdim/128, Tdim/256, ZB), blk, MMA1_SMEM>>>(q16, k16, a16);
    k_softmax<<<ZB * Tdim, blk>>>(a16);

    // join: oheads needs attn (s0) and v (s1)
    cudaStreamWaitEvent(0, evV, 0);
    k_mma_oheads<<<dim3(Cdim/128, Tdim/256, ZB), blk, MMA1_SMEM>>>(
        a16, v16, gamma, xT32, hhi, hlo);

    // MLP (fp16 2-term)
    const int ROWS = Bsz * Hn * Tdim;   // 65536
    k_mma_fc1<<<dim3(1, ROWS/256), blk, MMA2_SMEM>>>(hhi, hlo, w116, b1, y1hi, y1lo);
    k_mma_fc2<<<dim3(1, ROWS/256), blk, MMA2_SMEM>>>(y1hi, y1lo, w216, b2, x, out);
}

// round 10
// speedup vs baseline: 5.9325x; 1.0681x over previous
#include <cuda_runtime.h>
#include <cuda_fp16.h>
#include <cstdint>

// ---------------- problem constants ----------------
#define Bsz  8
#define Cdim 1024
#define Tdim 1024
#define Hn   8
#define DQKd 128
#define DFC1 128

// ---------------- scratch (device globals; no allocs allowed) ----------------
__device__ __half g_attn16[(size_t)Bsz*Hn*Tdim*Tdim];         // logits -> attn (in-place)
__device__ __half g_v16 [(size_t)Bsz*Hn*Cdim*Tdim];           // v (z,c,t)
__device__ __half g_wv16[(size_t)Hn*Cdim*Cdim];
__device__ __half g_wq16[(size_t)Hn*DQKd*Cdim];
__device__ __half g_wk16[(size_t)Hn*DQKd*Cdim];
__device__ __half g_w116[(size_t)DFC1*Cdim];
__device__ __half g_w216[(size_t)DFC1*DFC1];
__device__ __half g_x16 [(size_t)Bsz*Tdim*Cdim];              // x^T (b,t,c)
__device__ float  g_xT32[(size_t)Bsz*Tdim*Cdim];
__device__ __half g_q16[(size_t)Bsz*Hn*Tdim*DQKd];            // q (z,t,o)
__device__ __half g_k16[(size_t)Bsz*Hn*Tdim*DQKd];
__device__ __half g_h16[(size_t)Bsz*Hn*Tdim*Cdim];            // heads (z,t,c)
__device__ __half g_y116[(size_t)Bsz*Hn*Tdim*DFC1];

// ============================================================================
// PTX helpers (sm_80-level — valid on compute_103)
// ============================================================================
__device__ __forceinline__ uint32_t s2u(const void* p) {
    uint32_t a;
    asm("{ .reg .u64 t; cvta.to.shared.u64 t, %1; cvt.u32.u64 %0, t; }"
        : "=r"(a) : "l"(p));
    return a;
}
__device__ __forceinline__ void ldsm_x4(uint32_t* r, uint32_t addr) {
    asm volatile("ldmatrix.sync.aligned.m8n8.x4.shared.b16 {%0,%1,%2,%3}, [%4];"
        : "=r"(r[0]), "=r"(r[1]), "=r"(r[2]), "=r"(r[3]) : "r"(addr));
}
__device__ __forceinline__ void mma_fp(float* c, const uint32_t* a, const uint32_t* b) {
    asm volatile("mma.sync.aligned.m16n8k16.row.col.f32.f16.f16.f32 "
        "{%0,%1,%2,%3}, {%4,%5,%6,%7}, {%8,%9}, {%0,%1,%2,%3};"
        : "+f"(c[0]), "+f"(c[1]), "+f"(c[2]), "+f"(c[3])
        : "r"(a[0]), "r"(a[1]), "r"(a[2]), "r"(a[3]), "r"(b[0]), "r"(b[1]));
}
__device__ __forceinline__ void cpasync16(uint32_t dst, const void* src) {
    asm volatile("cp.async.cg.shared.global [%0], [%1], 16;" :: "r"(dst), "l"(src));
}

// ============================================================================
// fp16 1-term tensor-core GEMM (TN): D[m,n] = sum_k A[m,k]*B[n,k]
// CTA tile 256x128, K-step 32, 4-stage cp.async pipeline (prefetch dist 3),
// single __syncthreads per stage. 8 warps as 4M x 2N, each warp 64x64.
// ============================================================================
#define PITCHB   80
#define A_ROWS   256
#define B_ROWS   128
#define A_SB     (A_ROWS*PITCHB)     // 20480
#define B_SB     (B_ROWS*PITCHB)     // 10240
#define STG_SB   (A_SB + B_SB)       // 30720
#define NPIPE    4
#define MMA_SMEM (NPIPE*STG_SB)      // 122880

#define WAIT_PEND(nst, st) do {                                         \
    int _p = (nst) - (st) - 1;                                          \
    if      (_p >= 2) asm volatile("cp.async.wait_group 2;" ::: "memory"); \
    else if (_p == 1) asm volatile("cp.async.wait_group 1;" ::: "memory"); \
    else              asm volatile("cp.async.wait_group 0;" ::: "memory"); \
} while (0)

__device__ __forceinline__ void issue1(
    uint32_t sb, int buf, int k0,
    const __half* __restrict__ A, const __half* __restrict__ B,
    int lda, int ldb, int mb0, int nb0)
{
    const int tid  = threadIdx.x;
    const int row4 = tid >> 2;
    const int cb   = (tid & 3) * 16;
    const uint32_t base = sb + buf * STG_SB;
    #pragma unroll
    for (int r0 = 0; r0 < A_ROWS; r0 += 64) {
        int row = r0 + row4;
        cpasync16(base + row * PITCHB + cb,
                  (const char*)(A + (size_t)(mb0 + row) * lda + k0) + cb);
    }
    #pragma unroll
    for (int r0 = 0; r0 < B_ROWS; r0 += 64) {
        int row = r0 + row4;
        cpasync16(base + A_SB + row * PITCHB + cb,
                  (const char*)(B + (size_t)(nb0 + row) * ldb + k0) + cb);
    }
    asm volatile("cp.async.commit_group;" ::: "memory");
}

__device__ __forceinline__ void compute1(uint32_t sb, int buf, float acc[4][8][4])
{
    const int lane = threadIdx.x & 31, wid = threadIdx.x >> 5;
    const int wm = wid & 3, wn = wid >> 2;
    const uint32_t ab = sb + buf * STG_SB;
    const uint32_t bb = ab + A_SB;
    #pragma unroll
    for (int k16 = 0; k16 < 2; k16++) {
        const uint32_t acol = k16 * 32 + (lane >> 4) * 16;
        uint32_t ah[4][4];
        #pragma unroll
        for (int mt = 0; mt < 4; mt++) {
            uint32_t arow = wm * 64 + mt * 16 + (lane & 15);
            ldsm_x4(ah[mt], ab + arow * PITCHB + acol);
        }
        const uint32_t bcol = k16 * 32 + ((lane >> 3) & 1) * 16;
        #pragma unroll
        for (int ntp = 0; ntp < 4; ntp++) {
            uint32_t brow = wn * 64 + ntp * 16 + ((lane >> 4) & 1) * 8 + (lane & 7);
            uint32_t bh[4];
            ldsm_x4(bh, bb + brow * PITCHB + bcol);
            #pragma unroll
            for (int mt = 0; mt < 4; mt++) {
                mma_fp(acc[mt][2*ntp],   ah[mt], bh);
                mma_fp(acc[mt][2*ntp+1], ah[mt], bh + 2);
            }
        }
    }
}

__device__ __forceinline__ void mainloop1(
    char* smem,
    const __half* __restrict__ A, const __half* __restrict__ B,
    int lda, int ldb, int mb0, int nb0, int nst, float acc[4][8][4])
{
    uint32_t sb = s2u(smem);
    issue1(sb, 0, 0,  A, B, lda, ldb, mb0, nb0);
    issue1(sb, 1, 32, A, B, lda, ldb, mb0, nb0);
    issue1(sb, 2, 64, A, B, lda, ldb, mb0, nb0);
    #pragma unroll 1
    for (int st = 0; st < nst; st++) {
        WAIT_PEND(nst, st);
        __syncthreads();
        if (st + 3 < nst)
            issue1(sb, (st + 3) & 3, (st + 3) * 32, A, B, lda, ldb, mb0, nb0);
        compute1(sb, st & 3, acc);
    }
}

// epilogue index helper
struct EpiIdx { int r0; int lane, wm, wn; };
__device__ __forceinline__ EpiIdx epi_idx(int mb0, int mt) {
    EpiIdx e;
    e.lane = threadIdx.x & 31;
    int wid = threadIdx.x >> 5;
    e.wm = wid & 3; e.wn = wid >> 2;
    e.r0 = mb0 + e.wm * 64 + mt * 16 + (e.lane >> 2);
    return e;
}

// ---------------- q/k projection: P[z,t,o] single fp16 ----------------------
__global__ __launch_bounds__(256, 1) void k_mma_proj(
    const __half* __restrict__ x16, const __half* __restrict__ w16,
    const float* __restrict__ bias, __half* __restrict__ p16)
{
    extern __shared__ char smem[];
    const int z = blockIdx.z, h = z & 7, b = z >> 3;
    const int mb0 = blockIdx.y * 256;    // t
    float acc[4][8][4] = {};
    mainloop1(smem,
              x16 + (size_t)b * 1048576, w16 + (size_t)h * 131072,
              1024, 1024, mb0, 0, 32, acc);
    #pragma unroll
    for (int mt = 0; mt < 4; mt++) {
        EpiIdx e = epi_idx(mb0, mt);
        size_t base = (size_t)z * 131072 + (size_t)e.r0 * 128;
        #pragma unroll
        for (int nt = 0; nt < 8; nt++) {
            int col = e.wn * 64 + nt * 8 + (e.lane & 3) * 2;
            float bc0 = bias[h * DQKd + col], bc1 = bias[h * DQKd + col + 1];
            __half2 p0, p1;
            p0.x = __float2half_rn(acc[mt][nt][0] + bc0);
            p0.y = __float2half_rn(acc[mt][nt][1] + bc1);
            p1.x = __float2half_rn(acc[mt][nt][2] + bc0);
            p1.y = __float2half_rn(acc[mt][nt][3] + bc1);
            *(__half2*)(p16 + base + col) = p0;
            *(__half2*)(p16 + base + 8 * 128 + col) = p1;
        }
    }
}

// ---------------- energy: logits fp16 out ------------------------------------
__global__ __launch_bounds__(256, 1) void k_mma_energy(
    const __half* __restrict__ q16, const __half* __restrict__ k16,
    __half* __restrict__ logits)
{
    extern __shared__ char smem[];
    const int z = blockIdx.z;
    const int mb0 = blockIdx.y * 256;    // t
    const int nb0 = blockIdx.x * 128;    // s
    float acc[4][8][4] = {};
    mainloop1(smem,
              q16 + (size_t)z * 131072, k16 + (size_t)z * 131072,
              128, 128, mb0, nb0, 4, acc);
    #pragma unroll
    for (int mt = 0; mt < 4; mt++) {
        EpiIdx e = epi_idx(mb0, mt);
        size_t base = (size_t)z * 1048576 + (size_t)e.r0 * 1024;
        #pragma unroll
        for (int nt = 0; nt < 8; nt++) {
            int col = nb0 + e.wn * 64 + nt * 8 + (e.lane & 3) * 2;
            __half2 p0, p1;
            p0.x = __float2half_rn(acc[mt][nt][0]);
            p0.y = __float2half_rn(acc[mt][nt][1]);
            p1.x = __float2half_rn(acc[mt][nt][2]);
            p1.y = __float2half_rn(acc[mt][nt][3]);
            *(__half2*)(logits + base + col) = p0;
            *(__half2*)(logits + base + 8 * 1024 + col) = p1;
        }
    }
}

// ---------------- v projection: v[z,c,t] single fp16 ------------------------
__global__ __launch_bounds__(256, 1) void k_mma_vconv(
    const __half* __restrict__ wv, const __half* __restrict__ x16,
    const float* __restrict__ bv, __half* __restrict__ v16)
{
    extern __shared__ char smem[];
    const int z = blockIdx.z, h = z & 7, b = z >> 3;
    const int mb0 = blockIdx.y * 256;    // c
    const int nb0 = blockIdx.x * 128;    // t
    float acc[4][8][4] = {};
    mainloop1(smem,
              wv + (size_t)h * 1048576, x16 + (size_t)b * 1048576,
              1024, 1024, mb0, nb0, 32, acc);
    #pragma unroll
    for (int mt = 0; mt < 4; mt++) {
        EpiIdx e = epi_idx(mb0, mt);
        float bias0 = bv[h * Cdim + e.r0];
        float bias1 = bv[h * Cdim + e.r0 + 8];
        size_t base = (size_t)z * 1048576 + (size_t)e.r0 * 1024;
        #pragma unroll
        for (int nt = 0; nt < 8; nt++) {
            int col = nb0 + e.wn * 64 + nt * 8 + (e.lane & 3) * 2;
            __half2 p0, p1;
            p0.x = __float2half_rn(acc[mt][nt][0] + bias0);
            p0.y = __float2half_rn(acc[mt][nt][1] + bias0);
            p1.x = __float2half_rn(acc[mt][nt][2] + bias1);
            p1.y = __float2half_rn(acc[mt][nt][3] + bias1);
            *(__half2*)(v16 + base + col) = p0;
            *(__half2*)(v16 + base + 8 * 1024 + col) = p1;
        }
    }
}

// ---------------- heads: gamma*attn@v^T + x^T, single fp16 ------------------
__global__ __launch_bounds__(256, 1) void k_mma_oheads(
    const __half* __restrict__ a16, const __half* __restrict__ v16,
    const float* __restrict__ gamma, const float* __restrict__ xT32,
    __half* __restrict__ h16)
{
    extern __shared__ char smem[];
    const int z = blockIdx.z, h = z & 7, b = z >> 3;
    const int mb0 = blockIdx.y * 256;    // t
    const int nb0 = blockIdx.x * 128;    // c
    float acc[4][8][4] = {};
    mainloop1(smem,
              a16 + (size_t)z * 1048576, v16 + (size_t)z * 1048576,
              1024, 1024, mb0, nb0, 32, acc);
    const float g = gamma[h];
    #pragma unroll
    for (int mt = 0; mt < 4; mt++) {
        EpiIdx e = epi_idx(mb0, mt);
        size_t hb = (size_t)z * 1048576 + (size_t)e.r0 * 1024;
        size_t xb = (size_t)b * 1048576 + (size_t)e.r0 * 1024;
        #pragma unroll
        for (int nt = 0; nt < 8; nt++) {
            int col = nb0 + e.wn * 64 + nt * 8 + (e.lane & 3) * 2;
            __half2 p0, p1;
            p0.x = __float2half_rn(g * acc[mt][nt][0] + xT32[xb + col]);
            p0.y = __float2half_rn(g * acc[mt][nt][1] + xT32[xb + col + 1]);
            p1.x = __float2half_rn(g * acc[mt][nt][2] + xT32[xb + 8 * 1024 + col]);
            p1.y = __float2half_rn(g * acc[mt][nt][3] + xT32[xb + 8 * 1024 + col + 1]);
            *(__half2*)(h16 + hb + col) = p0;
            *(__half2*)(h16 + hb + 8 * 1024 + col) = p1;
        }
    }
}

// ---------------- fc1: y1 = relu(heads.W1^T + b1), single fp16 --------------
__global__ __launch_bounds__(256, 1) void k_mma_fc1(
    const __half* __restrict__ h16, const __half* __restrict__ w1,
    const float* __restrict__ b1, __half* __restrict__ y116)
{
    extern __shared__ char smem[];
    const int mb0 = blockIdx.y * 256;    // r
    float acc[4][8][4] = {};
    mainloop1(smem, h16, w1, 1024, 1024, mb0, 0, 32, acc);
    #pragma unroll
    for (int mt = 0; mt < 4; mt++) {
        EpiIdx e = epi_idx(mb0, mt);
        size_t base = (size_t)e.r0 * 128;
        #pragma unroll
        for (int nt = 0; nt < 8; nt++) {
            int col = e.wn * 64 + nt * 8 + (e.lane & 3) * 2;
            float bc0 = b1[col], bc1 = b1[col + 1];
            __half2 p0, p1;
            p0.x = __float2half_rn(fmaxf(acc[mt][nt][0] + bc0, 0.f));
            p0.y = __float2half_rn(fmaxf(acc[mt][nt][1] + bc1, 0.f));
            p1.x = __float2half_rn(fmaxf(acc[mt][nt][2] + bc0, 0.f));
            p1.y = __float2half_rn(fmaxf(acc[mt][nt][3] + bc1, 0.f));
            *(__half2*)(y116 + base + col) = p0;
            *(__half2*)(y116 + base + 8 * 128 + col) = p1;
        }
    }
}

// ---------------- fc2: out scatter + relu + residual ------------------------
__global__ __launch_bounds__(256, 1) void k_mma_fc2(
    const __half* __restrict__ y116, const __half* __restrict__ w2,
    const float* __restrict__ b2, const float* __restrict__ x,
    float* __restrict__ out)
{
    extern __shared__ char smem[];
    const int mb0 = blockIdx.y * 256;    // r
    float acc[4][8][4] = {};
    mainloop1(smem, y116, w2, 128, 128, mb0, 0, 4, acc);
    #pragma unroll
    for (int mt = 0; mt < 4; mt++) {
        EpiIdx e = epi_idx(mb0, mt);
        #pragma unroll
        for (int rr = 0; rr < 2; rr++) {
            int r = e.r0 + rr * 8;               // r = (b*H + h)*T + t
            int b = r >> 13;
            int h = (r >> 10) & 7;
            int t = r & 1023;
            size_t xbase = (size_t)b * 1048576 + t;
            #pragma unroll
            for (int nt = 0; nt < 8; nt++) {
                int col = e.wn * 64 + nt * 8 + (e.lane & 3) * 2;
                #pragma unroll
                for (int jj = 0; jj < 2; jj++) {
                    int d = col + jj;
                    size_t idx = xbase + (size_t)(d * Hn + h) * 1024;
                    out[idx] = fmaxf(acc[mt][nt][rr * 2 + jj] + b2[d], 0.f) + x[idx];
                }
            }
        }
    }
}

// ---------------- softmax: fp16 logits in, fp16 attn out (in-place) ---------
__global__ __launch_bounds__(256) void k_softmax(__half* __restrict__ a)
{
    __half* row = a + (size_t)blockIdx.x * Tdim;
    const int tid = threadIdx.x;
    __half2 h01 = *(__half2*)&row[tid * 4];
    __half2 h23 = *(__half2*)&row[tid * 4 + 2];
    float v0 = __half2float(h01.x), v1 = __half2float(h01.y);
    float v2 = __half2float(h23.x), v3 = __half2float(h23.y);
    __shared__ float red[256];

    float mx = fmaxf(fmaxf(v0, v1), fmaxf(v2, v3));
    red[tid] = mx; __syncthreads();
    #pragma unroll
    for (int s = 128; s > 0; s >>= 1) {
        if (tid < s) red[tid] = fmaxf(red[tid], red[tid + s]);
        __syncthreads();
    }
    mx = red[0]; __syncthreads();

    v0 = __expf(v0 - mx); v1 = __expf(v1 - mx);
    v2 = __expf(v2 - mx); v3 = __expf(v3 - mx);
    red[tid] = v0 + v1 + v2 + v3; __syncthreads();
    #pragma unroll
    for (int s = 128; s > 0; s >>= 1) {
        if (tid < s) red[tid] += red[tid + s];
        __syncthreads();
    }
    float inv = 1.0f / red[0];

    __half2 p;
    p.x = __float2half_rn(v0 * inv); p.y = __float2half_rn(v1 * inv);
    *(__half2*)&row[tid * 4] = p;
    p.x = __float2half_rn(v2 * inv); p.y = __float2half_rn(v3 * inv);
    *(__half2*)&row[tid * 4 + 2] = p;
}

// ---------------- prep kernels ----------------
__global__ __launch_bounds__(256) void k_wround_h(
    const float* __restrict__ w, __half* __restrict__ o)
{
    size_t i = ((size_t)blockIdx.x * 256 + threadIdx.x) * 4;
    float4 v = *(const float4*)(w + i);
    __half2 p;
    p.x = __float2half_rn(v.x); p.y = __float2half_rn(v.y);
    *(__half2*)(o + i) = p;
    p.x = __float2half_rn(v.z); p.y = __float2half_rn(v.w);
    *(__half2*)(o + i + 2) = p;
}

// transpose x (b,c,t) -> xT (b,t,c) as fp32 + fp16
__global__ void k_xprep(const float* __restrict__ x, float* __restrict__ xT32,
                        __half* __restrict__ x16)
{
    __shared__ float tile[32][33];
    const int b = blockIdx.z;
    const int c0 = blockIdx.y * 32, t0 = blockIdx.x * 32;
    for (int r = threadIdx.y; r < 32; r += 8)
        tile[r][threadIdx.x] = x[(size_t)b * Cdim * Tdim + (size_t)(c0 + r) * Tdim + t0 + threadIdx.x];
    __syncthreads();
    for (int r = threadIdx.y; r < 32; r += 8) {
        float v = tile[threadIdx.x][r];
        size_t o = (size_t)b * Tdim * Cdim + (size_t)(t0 + r) * Cdim + c0 + threadIdx.x;
        xT32[o] = v;
        x16[o] = __float2half_rn(v);
    }
}

// ============================================================================
// launch
// ============================================================================
extern "C" void kernel_launch(void* const* d_in, const int* in_sizes, int n_in,
                              void* d_out, int out_size)
{
    (void)in_sizes; (void)n_in; (void)out_size;
    const float* x     = (const float*)d_in[0];
    const float* Wq    = (const float*)d_in[1];
    const float* bq    = (const float*)d_in[2];
    const float* Wk    = (const float*)d_in[3];
    const float* bk    = (const float*)d_in[4];
    const float* Wv    = (const float*)d_in[5];
    const float* bv    = (const float*)d_in[6];
    const float* gamma = (const float*)d_in[7];
    const float* W1    = (const float*)d_in[8];
    const float* b1    = (const float*)d_in[9];
    const float* W2    = (const float*)d_in[10];
    const float* b2    = (const float*)d_in[11];
    float* out = (float*)d_out;

    float *xT32;
    __half *a16, *v16, *wv16, *wq16, *wk16, *w116, *w216, *x16;
    __half *q16, *k16, *h16, *y116;
    cudaGetSymbolAddress((void**)&a16,   g_attn16);
    cudaGetSymbolAddress((void**)&v16,   g_v16);
    cudaGetSymbolAddress((void**)&wv16,  g_wv16);
    cudaGetSymbolAddress((void**)&wq16,  g_wq16);
    cudaGetSymbolAddress((void**)&wk16,  g_wk16);
    cudaGetSymbolAddress((void**)&w116,  g_w116);
    cudaGetSymbolAddress((void**)&w216,  g_w216);
    cudaGetSymbolAddress((void**)&x16,   g_x16);
    cudaGetSymbolAddress((void**)&xT32,  g_xT32);
    cudaGetSymbolAddress((void**)&q16,   g_q16);
    cudaGetSymbolAddress((void**)&k16,   g_k16);
    cudaGetSymbolAddress((void**)&h16,   g_h16);
    cudaGetSymbolAddress((void**)&y116,  g_y116);

    static cudaStream_t s1 = nullptr;
    static cudaEvent_t evFork = nullptr, evV = nullptr;
    static bool init_done = false;
    if (!init_done) {
        cudaFuncSetAttribute(k_mma_proj,   cudaFuncAttributeMaxDynamicSharedMemorySize, MMA_SMEM);
        cudaFuncSetAttribute(k_mma_energy, cudaFuncAttributeMaxDynamicSharedMemorySize, MMA_SMEM);
        cudaFuncSetAttribute(k_mma_vconv,  cudaFuncAttributeMaxDynamicSharedMemorySize, MMA_SMEM);
        cudaFuncSetAttribute(k_mma_oheads, cudaFuncAttributeMaxDynamicSharedMemorySize, MMA_SMEM);
        cudaFuncSetAttribute(k_mma_fc1,    cudaFuncAttributeMaxDynamicSharedMemorySize, MMA_SMEM);
        cudaFuncSetAttribute(k_mma_fc2,    cudaFuncAttributeMaxDynamicSharedMemorySize, MMA_SMEM);
        cudaStreamCreateWithFlags(&s1, cudaStreamNonBlocking);
        cudaEventCreateWithFlags(&evFork, cudaEventDisableTiming);
        cudaEventCreateWithFlags(&evV,    cudaEventDisableTiming);
        init_done = true;
    }

    const dim3 blk(256);
    const int ZB = Bsz * Hn;   // 64

    // -------- stream 0 (default, capture stream): x prep --------
    k_xprep<<<dim3(Tdim/32, Cdim/32, Bsz), dim3(32, 8)>>>(x, xT32, x16);
    cudaEventRecord(evFork, 0);

    // -------- stream 1: Wv prep -> vconv -> W2 prep --------
    cudaStreamWaitEvent(s1, evFork, 0);
    k_wround_h<<<(Hn*Cdim*Cdim)/1024, 256, 0, s1>>>(Wv, wv16);
    k_mma_vconv<<<dim3(Tdim/128, Cdim/256, ZB), blk, MMA_SMEM, s1>>>(wv16, x16, bv, v16);
    k_wround_h<<<(DFC1*DFC1)/1024, 256, 0, s1>>>(W2, w216);
    cudaEventRecord(evV, s1);

    // -------- stream 0: q/k chain --------
    k_wround_h<<<(Hn*DQKd*Cdim)/1024, 256>>>(Wq, wq16);
    k_wround_h<<<(Hn*DQKd*Cdim)/1024, 256>>>(Wk, wk16);
    k_wround_h<<<(DFC1*Cdim)/1024,    256>>>(W1, w116);
    k_mma_proj<<<dim3(1, Tdim/256, ZB), blk, MMA_SMEM>>>(x16, wq16, bq, q16);
    k_mma_proj<<<dim3(1, Tdim/256, ZB), blk, MMA_SMEM>>>(x16, wk16, bk, k16);
    k_mma_energy<<<dim3(Tdim/128, Tdim/256, ZB), blk, MMA_SMEM>>>(q16, k16, a16);
    k_softmax<<<ZB * Tdim, blk>>>(a16);

    // join: oheads needs attn (s0) and v (s1)
    cudaStreamWaitEvent(0, evV, 0);
    k_mma_oheads<<<dim3(Cdim/128, Tdim/256, ZB), blk, MMA_SMEM>>>(
        a16, v16, gamma, xT32, h16);

    // MLP (fp16 1-term)
    const int ROWS = Bsz * Hn * Tdim;   // 65536
    k_mma_fc1<<<dim3(1, ROWS/256), blk, MMA_SMEM>>>(h16, w116, b1, y116);
    k_mma_fc2<<<dim3(1, ROWS/256), blk, MMA_SMEM>>>(y116, w216, b2, x, out);
}

// round 11
// speedup vs baseline: 6.9013x; 1.1633x over previous
#include <cuda_runtime.h>
#include <cuda_fp16.h>
#include <cstdint>

// ---------------- problem constants ----------------
#define Bsz  8
#define Cdim 1024
#define Tdim 1024
#define Hn   8
#define DQKd 128
#define DFC1 128

// ---------------- scratch (device globals; no allocs allowed) ----------------
__device__ __half g_attn16[(size_t)Bsz*Hn*Tdim*Tdim];         // logits -> attn (in-place)
__device__ __half g_v16 [(size_t)Bsz*Hn*Cdim*Tdim];           // v (z,c,t)
__device__ __half g_wv16[(size_t)Hn*Cdim*Cdim];
__device__ __half g_wq16[(size_t)Hn*DQKd*Cdim];
__device__ __half g_wk16[(size_t)Hn*DQKd*Cdim];
__device__ __half g_w116[(size_t)DFC1*Cdim];
__device__ __half g_w216[(size_t)DFC1*DFC1];
__device__ __half g_x16 [(size_t)Bsz*Tdim*Cdim];              // x^T (b,t,c)
__device__ __half g_q16[(size_t)Bsz*Hn*Tdim*DQKd];            // q (z,t,o)
__device__ __half g_k16[(size_t)Bsz*Hn*Tdim*DQKd];
__device__ __half g_h16[(size_t)Bsz*Hn*Tdim*Cdim];            // heads (z,t,c)
__device__ __half g_y116[(size_t)Bsz*Hn*Tdim*DFC1];

// ============================================================================
// PTX helpers (sm_80-level — valid on compute_103)
// ============================================================================
__device__ __forceinline__ uint32_t s2u(const void* p) {
    uint32_t a;
    asm("{ .reg .u64 t; cvta.to.shared.u64 t, %1; cvt.u32.u64 %0, t; }"
        : "=r"(a) : "l"(p));
    return a;
}
__device__ __forceinline__ void ldsm_x4(uint32_t* r, uint32_t addr) {
    asm volatile("ldmatrix.sync.aligned.m8n8.x4.shared.b16 {%0,%1,%2,%3}, [%4];"
        : "=r"(r[0]), "=r"(r[1]), "=r"(r[2]), "=r"(r[3]) : "r"(addr));
}
__device__ __forceinline__ void mma_fp(float* c, const uint32_t* a, const uint32_t* b) {
    asm volatile("mma.sync.aligned.m16n8k16.row.col.f32.f16.f16.f32 "
        "{%0,%1,%2,%3}, {%4,%5,%6,%7}, {%8,%9}, {%0,%1,%2,%3};"
        : "+f"(c[0]), "+f"(c[1]), "+f"(c[2]), "+f"(c[3])
        : "r"(a[0]), "r"(a[1]), "r"(a[2]), "r"(a[3]), "r"(b[0]), "r"(b[1]));
}
__device__ __forceinline__ void cpasync16(uint32_t dst, const void* src) {
    asm volatile("cp.async.cg.shared.global [%0], [%1], 16;" :: "r"(dst), "l"(src));
}

// ============================================================================
// fp16 1-term tensor-core GEMM (TN): D[m,n] = sum_k A[m,k]*B[n,k]
// CTA tile 256x128, K-step 64, 3-stage cp.async pipeline (prefetch dist 2),
// single __syncthreads per stage. 8 warps as 4M x 2N, each warp 64x64.
// ============================================================================
#define PITCHB   144                 // 64 fp16 (128 B) + 16 B pad (conflict-free)
#define A_ROWS   256
#define B_ROWS   128
#define A_SB     (A_ROWS*PITCHB)     // 36864
#define B_SB     (B_ROWS*PITCHB)     // 18432
#define STG_SB   (A_SB + B_SB)       // 55296
#define NPIPE    3
#define MMA_SMEM (NPIPE*STG_SB)      // 165888

__device__ __forceinline__ void issue1(
    uint32_t sb, int buf, int k0,
    const __half* __restrict__ A, const __half* __restrict__ B,
    int lda, int ldb, int mb0, int nb0)
{
    const int tid   = threadIdx.x;
    const int rgrp  = tid >> 3;          // 0..31
    const int cb    = (tid & 7) * 16;    // byte offset within 128-B k-slice
    const uint32_t base = sb + buf * STG_SB;
    #pragma unroll
    for (int i = 0; i < 8; i++) {        // 256 A rows
        int row = i * 32 + rgrp;
        cpasync16(base + row * PITCHB + cb,
                  (const char*)(A + (size_t)(mb0 + row) * lda + k0) + cb);
    }
    #pragma unroll
    for (int i = 0; i < 4; i++) {        // 128 B rows
        int row = i * 32 + rgrp;
        cpasync16(base + A_SB + row * PITCHB + cb,
                  (const char*)(B + (size_t)(nb0 + row) * ldb + k0) + cb);
    }
    asm volatile("cp.async.commit_group;" ::: "memory");
}

__device__ __forceinline__ void compute1(uint32_t sb, int buf, float acc[4][8][4])
{
    const int lane = threadIdx.x & 31, wid = threadIdx.x >> 5;
    const int wm = wid & 3, wn = wid >> 2;
    const uint32_t ab = sb + buf * STG_SB;
    const uint32_t bb = ab + A_SB;
    #pragma unroll
    for (int k16 = 0; k16 < 4; k16++) {
        const uint32_t acol = k16 * 32 + (lane >> 4) * 16;
        uint32_t ah[4][4];
        #pragma unroll
        for (int mt = 0; mt < 4; mt++) {
            uint32_t arow = wm * 64 + mt * 16 + (lane & 15);
            ldsm_x4(ah[mt], ab + arow * PITCHB + acol);
        }
        const uint32_t bcol = k16 * 32 + ((lane >> 3) & 1) * 16;
        #pragma unroll
        for (int ntp = 0; ntp < 4; ntp++) {
            uint32_t brow = wn * 64 + ntp * 16 + ((lane >> 4) & 1) * 8 + (lane & 7);
            uint32_t bh[4];
            ldsm_x4(bh, bb + brow * PITCHB + bcol);
            #pragma unroll
            for (int mt = 0; mt < 4; mt++) {
                mma_fp(acc[mt][2*ntp],   ah[mt], bh);
                mma_fp(acc[mt][2*ntp+1], ah[mt], bh + 2);
            }
        }
    }
}

__device__ __forceinline__ void mainloop1(
    char* smem,
    const __half* __restrict__ A, const __half* __restrict__ B,
    int lda, int ldb, int mb0, int nb0, int nst, float acc[4][8][4])
{
    uint32_t sb = s2u(smem);
    issue1(sb, 0, 0,  A, B, lda, ldb, mb0, nb0);
    issue1(sb, 1, 64, A, B, lda, ldb, mb0, nb0);
    #pragma unroll 1
    for (int st = 0; st < nst; st++) {
        if (st + 1 < nst) asm volatile("cp.async.wait_group 1;" ::: "memory");
        else              asm volatile("cp.async.wait_group 0;" ::: "memory");
        __syncthreads();
        if (st + 2 < nst) {
            int nx = st + 2;
            issue1(sb, nx % NPIPE, nx * 64, A, B, lda, ldb, mb0, nb0);
        }
        compute1(sb, st % NPIPE, acc);
    }
}

// epilogue index helper
struct EpiIdx { int r0; int lane, wm, wn; };
__device__ __forceinline__ EpiIdx epi_idx(int mb0, int mt) {
    EpiIdx e;
    e.lane = threadIdx.x & 31;
    int wid = threadIdx.x >> 5;
    e.wm = wid & 3; e.wn = wid >> 2;
    e.r0 = mb0 + e.wm * 64 + mt * 16 + (e.lane >> 2);
    return e;
}

// ---------------- q+k projection (fused): P[z,t,o] single fp16 --------------
__global__ __launch_bounds__(256, 1) void k_mma_proj(
    const __half* __restrict__ x16,
    const __half* __restrict__ wq16, const __half* __restrict__ wk16,
    const float* __restrict__ bq, const float* __restrict__ bk,
    __half* __restrict__ q16, __half* __restrict__ k16)
{
    extern __shared__ char smem[];
    const int zz = blockIdx.z;            // 0..127; >=64 -> k path
    const int z = zz & 63, h = z & 7, b = z >> 3;
    const bool is_k = zz >= 64;
    const __half* w16 = is_k ? wk16 : wq16;
    const float* bias = is_k ? bk : bq;
    __half* p16 = is_k ? k16 : q16;
    const int mb0 = blockIdx.y * 256;    // t
    float acc[4][8][4] = {};
    mainloop1(smem,
              x16 + (size_t)b * 1048576, w16 + (size_t)h * 131072,
              1024, 1024, mb0, 0, 16, acc);
    #pragma unroll
    for (int mt = 0; mt < 4; mt++) {
        EpiIdx e = epi_idx(mb0, mt);
        size_t base = (size_t)z * 131072 + (size_t)e.r0 * 128;
        #pragma unroll
        for (int nt = 0; nt < 8; nt++) {
            int col = e.wn * 64 + nt * 8 + (e.lane & 3) * 2;
            float bc0 = bias[h * DQKd + col], bc1 = bias[h * DQKd + col + 1];
            __half2 p0, p1;
            p0.x = __float2half_rn(acc[mt][nt][0] + bc0);
            p0.y = __float2half_rn(acc[mt][nt][1] + bc1);
            p1.x = __float2half_rn(acc[mt][nt][2] + bc0);
            p1.y = __float2half_rn(acc[mt][nt][3] + bc1);
            *(__half2*)(p16 + base + col) = p0;
            *(__half2*)(p16 + base + 8 * 128 + col) = p1;
        }
    }
}

// ---------------- energy: logits fp16 out ------------------------------------
__global__ __launch_bounds__(256, 1) void k_mma_energy(
    const __half* __restrict__ q16, const __half* __restrict__ k16,
    __half* __restrict__ logits)
{
    extern __shared__ char smem[];
    const int z = blockIdx.z;
    const int mb0 = blockIdx.y * 256;    // t
    const int nb0 = blockIdx.x * 128;    // s
    float acc[4][8][4] = {};
    mainloop1(smem,
              q16 + (size_t)z * 131072, k16 + (size_t)z * 131072,
              128, 128, mb0, nb0, 2, acc);
    #pragma unroll
    for (int mt = 0; mt < 4; mt++) {
        EpiIdx e = epi_idx(mb0, mt);
        size_t base = (size_t)z * 1048576 + (size_t)e.r0 * 1024;
        #pragma unroll
        for (int nt = 0; nt < 8; nt++) {
            int col = nb0 + e.wn * 64 + nt * 8 + (e.lane & 3) * 2;
            __half2 p0, p1;
            p0.x = __float2half_rn(acc[mt][nt][0]);
            p0.y = __float2half_rn(acc[mt][nt][1]);
            p1.x = __float2half_rn(acc[mt][nt][2]);
            p1.y = __float2half_rn(acc[mt][nt][3]);
            *(__half2*)(logits + base + col) = p0;
            *(__half2*)(logits + base + 8 * 1024 + col) = p1;
        }
    }
}

// ---------------- v projection: v[z,c,t] single fp16 ------------------------
__global__ __launch_bounds__(256, 1) void k_mma_vconv(
    const __half* __restrict__ wv, const __half* __restrict__ x16,
    const float* __restrict__ bv, __half* __restrict__ v16)
{
    extern __shared__ char smem[];
    const int z = blockIdx.z, h = z & 7, b = z >> 3;
    const int mb0 = blockIdx.y * 256;    // c
    const int nb0 = blockIdx.x * 128;    // t
    float acc[4][8][4] = {};
    mainloop1(smem,
              wv + (size_t)h * 1048576, x16 + (size_t)b * 1048576,
              1024, 1024, mb0, nb0, 16, acc);
    #pragma unroll
    for (int mt = 0; mt < 4; mt++) {
        EpiIdx e = epi_idx(mb0, mt);
        float bias0 = bv[h * Cdim + e.r0];
        float bias1 = bv[h * Cdim + e.r0 + 8];
        size_t base = (size_t)z * 1048576 + (size_t)e.r0 * 1024;
        #pragma unroll
        for (int nt = 0; nt < 8; nt++) {
            int col = nb0 + e.wn * 64 + nt * 8 + (e.lane & 3) * 2;
            __half2 p0, p1;
            p0.x = __float2half_rn(acc[mt][nt][0] + bias0);
            p0.y = __float2half_rn(acc[mt][nt][1] + bias0);
            p1.x = __float2half_rn(acc[mt][nt][2] + bias1);
            p1.y = __float2half_rn(acc[mt][nt][3] + bias1);
            *(__half2*)(v16 + base + col) = p0;
            *(__half2*)(v16 + base + 8 * 1024 + col) = p1;
        }
    }
}

// ---------------- heads: gamma*attn@v^T + x^T, single fp16 ------------------
__global__ __launch_bounds__(256, 1) void k_mma_oheads(
    const __half* __restrict__ a16, const __half* __restrict__ v16,
    const float* __restrict__ gamma, const __half* __restrict__ x16,
    __half* __restrict__ h16)
{
    extern __shared__ char smem[];
    const int z = blockIdx.z, h = z & 7, b = z >> 3;
    const int mb0 = blockIdx.y * 256;    // t
    const int nb0 = blockIdx.x * 128;    // c
    float acc[4][8][4] = {};
    mainloop1(smem,
              a16 + (size_t)z * 1048576, v16 + (size_t)z * 1048576,
              1024, 1024, mb0, nb0, 16, acc);
    const float g = gamma[h];
    #pragma unroll
    for (int mt = 0; mt < 4; mt++) {
        EpiIdx e = epi_idx(mb0, mt);
        size_t hb = (size_t)z * 1048576 + (size_t)e.r0 * 1024;
        size_t xb = (size_t)b * 1048576 + (size_t)e.r0 * 1024;
        #pragma unroll
        for (int nt = 0; nt < 8; nt++) {
            int col = nb0 + e.wn * 64 + nt * 8 + (e.lane & 3) * 2;
            __half2 x0 = *(const __half2*)(x16 + xb + col);
            __half2 x1 = *(const __half2*)(x16 + xb + 8 * 1024 + col);
            __half2 p0, p1;
            p0.x = __float2half_rn(g * acc[mt][nt][0] + __half2float(x0.x));
            p0.y = __float2half_rn(g * acc[mt][nt][1] + __half2float(x0.y));
            p1.x = __float2half_rn(g * acc[mt][nt][2] + __half2float(x1.x));
            p1.y = __float2half_rn(g * acc[mt][nt][3] + __half2float(x1.y));
            *(__half2*)(h16 + hb + col) = p0;
            *(__half2*)(h16 + hb + 8 * 1024 + col) = p1;
        }
    }
}

// ---------------- fc1: y1 = relu(heads.W1^T + b1), single fp16 --------------
__global__ __launch_bounds__(256, 1) void k_mma_fc1(
    const __half* __restrict__ h16, const __half* __restrict__ w1,
    const float* __restrict__ b1, __half* __restrict__ y116)
{
    extern __shared__ char smem[];
    const int mb0 = blockIdx.y * 256;    // r
    float acc[4][8][4] = {};
    mainloop1(smem, h16, w1, 1024, 1024, mb0, 0, 16, acc);
    #pragma unroll
    for (int mt = 0; mt < 4; mt++) {
        EpiIdx e = epi_idx(mb0, mt);
        size_t base = (size_t)e.r0 * 128;
        #pragma unroll
        for (int nt = 0; nt < 8; nt++) {
            int col = e.wn * 64 + nt * 8 + (e.lane & 3) * 2;
            float bc0 = b1[col], bc1 = b1[col + 1];
            __half2 p0, p1;
            p0.x = __float2half_rn(fmaxf(acc[mt][nt][0] + bc0, 0.f));
            p0.y = __float2half_rn(fmaxf(acc[mt][nt][1] + bc1, 0.f));
            p1.x = __float2half_rn(fmaxf(acc[mt][nt][2] + bc0, 0.f));
            p1.y = __float2half_rn(fmaxf(acc[mt][nt][3] + bc1, 0.f));
            *(__half2*)(y116 + base + col) = p0;
            *(__half2*)(y116 + base + 8 * 128 + col) = p1;
        }
    }
}

// ---------------- fc2: out scatter + relu + residual ------------------------
__global__ __launch_bounds__(256, 1) void k_mma_fc2(
    const __half* __restrict__ y116, const __half* __restrict__ w2,
    const float* __restrict__ b2, const float* __restrict__ x,
    float* __restrict__ out)
{
    extern __shared__ char smem[];
    const int mb0 = blockIdx.y * 256;    // r
    float acc[4][8][4] = {};
    mainloop1(smem, y116, w2, 128, 128, mb0, 0, 2, acc);
    #pragma unroll
    for (int mt = 0; mt < 4; mt++) {
        EpiIdx e = epi_idx(mb0, mt);
        #pragma unroll
        for (int rr = 0; rr < 2; rr++) {
            int r = e.r0 + rr * 8;               // r = (b*H + h)*T + t
            int b = r >> 13;
            int h = (r >> 10) & 7;
            int t = r & 1023;
            size_t xbase = (size_t)b * 1048576 + t;
            #pragma unroll
            for (int nt = 0; nt < 8; nt++) {
                int col = e.wn * 64 + nt * 8 + (e.lane & 3) * 2;
                #pragma unroll
                for (int jj = 0; jj < 2; jj++) {
                    int d = col + jj;
                    size_t idx = xbase + (size_t)(d * Hn + h) * 1024;
                    out[idx] = fmaxf(acc[mt][nt][rr * 2 + jj] + b2[d], 0.f) + x[idx];
                }
            }
        }
    }
}

// ---------------- softmax: fp16 logits in, fp16 attn out (in-place) ---------
__global__ __launch_bounds__(256) void k_softmax(__half* __restrict__ a)
{
    __half* row = a + (size_t)blockIdx.x * Tdim;
    const int tid = threadIdx.x;
    __half2 h01 = *(__half2*)&row[tid * 4];
    __half2 h23 = *(__half2*)&row[tid * 4 + 2];
    float v0 = __half2float(h01.x), v1 = __half2float(h01.y);
    float v2 = __half2float(h23.x), v3 = __half2float(h23.y);
    __shared__ float red[256];

    float mx = fmaxf(fmaxf(v0, v1), fmaxf(v2, v3));
    red[tid] = mx; __syncthreads();
    #pragma unroll
    for (int s = 128; s > 0; s >>= 1) {
        if (tid < s) red[tid] = fmaxf(red[tid], red[tid + s]);
        __syncthreads();
    }
    mx = red[0]; __syncthreads();

    v0 = __expf(v0 - mx); v1 = __expf(v1 - mx);
    v2 = __expf(v2 - mx); v3 = __expf(v3 - mx);
    red[tid] = v0 + v1 + v2 + v3; __syncthreads();
    #pragma unroll
    for (int s = 128; s > 0; s >>= 1) {
        if (tid < s) red[tid] += red[tid + s];
        __syncthreads();
    }
    float inv = 1.0f / red[0];

    __half2 p;
    p.x = __float2half_rn(v0 * inv); p.y = __float2half_rn(v1 * inv);
    *(__half2*)&row[tid * 4] = p;
    p.x = __float2half_rn(v2 * inv); p.y = __float2half_rn(v3 * inv);
    *(__half2*)&row[tid * 4 + 2] = p;
}

// ---------------- prep kernels ----------------
__global__ __launch_bounds__(256) void k_wround_h(
    const float* __restrict__ w, __half* __restrict__ o)
{
    size_t i = ((size_t)blockIdx.x * 256 + threadIdx.x) * 4;
    float4 v = *(const float4*)(w + i);
    __half2 p;
    p.x = __float2half_rn(v.x); p.y = __float2half_rn(v.y);
    *(__half2*)(o + i) = p;
    p.x = __float2half_rn(v.z); p.y = __float2half_rn(v.w);
    *(__half2*)(o + i + 2) = p;
}

// transpose x (b,c,t) -> xT (b,t,c) fp16
__global__ void k_xprep(const float* __restrict__ x, __half* __restrict__ x16)
{
    __shared__ float tile[32][33];
    const int b = blockIdx.z;
    const int c0 = blockIdx.y * 32, t0 = blockIdx.x * 32;
    for (int r = threadIdx.y; r < 32; r += 8)
        tile[r][threadIdx.x] = x[(size_t)b * Cdim * Tdim + (size_t)(c0 + r) * Tdim + t0 + threadIdx.x];
    __syncthreads();
    for (int r = threadIdx.y; r < 32; r += 8) {
        float v = tile[threadIdx.x][r];
        size_t o = (size_t)b * Tdim * Cdim + (size_t)(t0 + r) * Cdim + c0 + threadIdx.x;
        x16[o] = __float2half_rn(v);
    }
}

// ============================================================================
// launch
// ============================================================================
extern "C" void kernel_launch(void* const* d_in, const int* in_sizes, int n_in,
                              void* d_out, int out_size)
{
    (void)in_sizes; (void)n_in; (void)out_size;
    const float* x     = (const float*)d_in[0];
    const float* Wq    = (const float*)d_in[1];
    const float* bq    = (const float*)d_in[2];
    const float* Wk    = (const float*)d_in[3];
    const float* bk    = (const float*)d_in[4];
    const float* Wv    = (const float*)d_in[5];
    const float* bv    = (const float*)d_in[6];
    const float* gamma = (const float*)d_in[7];
    const float* W1    = (const float*)d_in[8];
    const float* b1    = (const float*)d_in[9];
    const float* W2    = (const float*)d_in[10];
    const float* b2    = (const float*)d_in[11];
    float* out = (float*)d_out;

    __half *a16, *v16, *wv16, *wq16, *wk16, *w116, *w216, *x16;
    __half *q16, *k16, *h16, *y116;
    cudaGetSymbolAddress((void**)&a16,   g_attn16);
    cudaGetSymbolAddress((void**)&v16,   g_v16);
    cudaGetSymbolAddress((void**)&wv16,  g_wv16);
    cudaGetSymbolAddress((void**)&wq16,  g_wq16);
    cudaGetSymbolAddress((void**)&wk16,  g_wk16);
    cudaGetSymbolAddress((void**)&w116,  g_w116);
    cudaGetSymbolAddress((void**)&w216,  g_w216);
    cudaGetSymbolAddress((void**)&x16,   g_x16);
    cudaGetSymbolAddress((void**)&q16,   g_q16);
    cudaGetSymbolAddress((void**)&k16,   g_k16);
    cudaGetSymbolAddress((void**)&h16,   g_h16);
    cudaGetSymbolAddress((void**)&y116,  g_y116);

    static cudaStream_t s1 = nullptr;
    static cudaEvent_t evFork = nullptr, evV = nullptr;
    static bool init_done = false;
    if (!init_done) {
        cudaFuncSetAttribute(k_mma_proj,   cudaFuncAttributeMaxDynamicSharedMemorySize, MMA_SMEM);
        cudaFuncSetAttribute(k_mma_energy, cudaFuncAttributeMaxDynamicSharedMemorySize, MMA_SMEM);
        cudaFuncSetAttribute(k_mma_vconv,  cudaFuncAttributeMaxDynamicSharedMemorySize, MMA_SMEM);
        cudaFuncSetAttribute(k_mma_oheads, cudaFuncAttributeMaxDynamicSharedMemorySize, MMA_SMEM);
        cudaFuncSetAttribute(k_mma_fc1,    cudaFuncAttributeMaxDynamicSharedMemorySize, MMA_SMEM);
        cudaFuncSetAttribute(k_mma_fc2,    cudaFuncAttributeMaxDynamicSharedMemorySize, MMA_SMEM);
        cudaStreamCreateWithFlags(&s1, cudaStreamNonBlocking);
        cudaEventCreateWithFlags(&evFork, cudaEventDisableTiming);
        cudaEventCreateWithFlags(&evV,    cudaEventDisableTiming);
        init_done = true;
    }

    const dim3 blk(256);
    const int ZB = Bsz * Hn;   // 64

    // -------- stream 0 (default, capture stream): x prep --------
    k_xprep<<<dim3(Tdim/32, Cdim/32, Bsz), dim3(32, 8)>>>(x, x16);
    cudaEventRecord(evFork, 0);

    // -------- stream 1: Wv prep -> vconv -> W2 prep --------
    cudaStreamWaitEvent(s1, evFork, 0);
    k_wround_h<<<(Hn*Cdim*Cdim)/1024, 256, 0, s1>>>(Wv, wv16);
    k_mma_vconv<<<dim3(Tdim/128, Cdim/256, ZB), blk, MMA_SMEM, s1>>>(wv16, x16, bv, v16);
    k_wround_h<<<(DFC1*DFC1)/1024, 256, 0, s1>>>(W2, w216);
    cudaEventRecord(evV, s1);

    // -------- stream 0: q/k chain --------
    k_wround_h<<<(Hn*DQKd*Cdim)/1024, 256>>>(Wq, wq16);
    k_wround_h<<<(Hn*DQKd*Cdim)/1024, 256>>>(Wk, wk16);
    k_wround_h<<<(DFC1*Cdim)/1024,    256>>>(W1, w116);
    k_mma_proj<<<dim3(1, Tdim/256, 2*ZB), blk, MMA_SMEM>>>(x16, wq16, wk16, bq, bk, q16, k16);
    k_mma_energy<<<dim3(Tdim/128, Tdim/256, ZB), blk, MMA_SMEM>>>(q16, k16, a16);
    k_softmax<<<ZB * Tdim, blk>>>(a16);

    // join: oheads needs attn (s0) and v (s1)
    cudaStreamWaitEvent(0, evV, 0);
    k_mma_oheads<<<dim3(Cdim/128, Tdim/256, ZB), blk, MMA_SMEM>>>(
        a16, v16, gamma, x16, h16);

    // MLP (fp16 1-term)
    const int ROWS = Bsz * Hn * Tdim;   // 65536
    k_mma_fc1<<<dim3(1, ROWS/256), blk, MMA_SMEM>>>(h16, w116, b1, y116);
    k_mma_fc2<<<dim3(1, ROWS/256), blk, MMA_SMEM>>>(y116, w216, b2, x, out);
}

// round 12
// speedup vs baseline: 7.1818x; 1.0406x over previous
#include <cuda_runtime.h>
#include <cuda_fp16.h>
#include <cstdint>

// ---------------- problem constants ----------------
#define Bsz  8
#define Cdim 1024
#define Tdim 1024
#define Hn   8
#define DQKd 128
#define DFC1 128

// ---------------- scratch (device globals; no allocs allowed) ----------------
__device__ __half g_attn16[(size_t)Bsz*Hn*Tdim*Tdim];         // logits -> attn (in-place)
__device__ __half g_v16 [(size_t)Bsz*Hn*Cdim*Tdim];           // v (z,c,t)
__device__ __half g_wv16[(size_t)Hn*Cdim*Cdim];
__device__ __half g_wq16[(size_t)Hn*DQKd*Cdim];
__device__ __half g_wk16[(size_t)Hn*DQKd*Cdim];
__device__ __half g_w116[(size_t)DFC1*Cdim];
__device__ __half g_w216[(size_t)DFC1*DFC1];
__device__ __half g_x16 [(size_t)Bsz*Tdim*Cdim];              // x^T (b,t,c)
__device__ __half g_q16[(size_t)Bsz*Hn*Tdim*DQKd];            // q (z,t,o)
__device__ __half g_k16[(size_t)Bsz*Hn*Tdim*DQKd];
__device__ __half g_h16[(size_t)Bsz*Hn*Tdim*Cdim];            // heads (z,t,c)
__device__ __half g_y116[(size_t)Bsz*Hn*Tdim*DFC1];

// ============================================================================
// PTX helpers (sm_80-level — valid on compute_103)
// ============================================================================
__device__ __forceinline__ uint32_t s2u(const void* p) {
    uint32_t a;
    asm("{ .reg .u64 t; cvta.to.shared.u64 t, %1; cvt.u32.u64 %0, t; }"
        : "=r"(a) : "l"(p));
    return a;
}
__device__ __forceinline__ void ldsm_x4(uint32_t* r, uint32_t addr) {
    asm volatile("ldmatrix.sync.aligned.m8n8.x4.shared.b16 {%0,%1,%2,%3}, [%4];"
        : "=r"(r[0]), "=r"(r[1]), "=r"(r[2]), "=r"(r[3]) : "r"(addr));
}
__device__ __forceinline__ void mma_fp(float* c, const uint32_t* a, const uint32_t* b) {
    asm volatile("mma.sync.aligned.m16n8k16.row.col.f32.f16.f16.f32 "
        "{%0,%1,%2,%3}, {%4,%5,%6,%7}, {%8,%9}, {%0,%1,%2,%3};"
        : "+f"(c[0]), "+f"(c[1]), "+f"(c[2]), "+f"(c[3])
        : "r"(a[0]), "r"(a[1]), "r"(a[2]), "r"(a[3]), "r"(b[0]), "r"(b[1]));
}
__device__ __forceinline__ void cpasync16(uint32_t dst, const void* src) {
    asm volatile("cp.async.cg.shared.global [%0], [%1], 16;" :: "r"(dst), "l"(src));
}

// ============================================================================
// fp16 1-term tensor-core GEMM (TN): D[m,n] = sum_k A[m,k]*B[n,k]
// 8 warps as 4M x 2N, warp tile 64x64, CTA tile 256x128.
// Variant A: K-step 128, NPIPE=2 (two syncs/stage)  — for K=1024 GEMMs
// Variant B: K-step 64,  NPIPE=3 (one sync/stage)   — for K=128 GEMMs
// ============================================================================
#define A_ROWS   256
#define B_ROWS   128

// ---- variant A (K-step 128) ----
#define PITCH_A  272                 // 128 fp16 (256 B) + 16 B pad (rows shift 4 banks)
#define A_SB_A   (A_ROWS*PITCH_A)    // 69632
#define B_SB_A   (B_ROWS*PITCH_A)    // 34816
#define STG_A    (A_SB_A + B_SB_A)   // 104448
#define SMEM_A   (2*STG_A)           // 208896

__device__ __forceinline__ void issueA(
    uint32_t sb, int buf, int k0,
    const __half* __restrict__ A, const __half* __restrict__ B,
    int lda, int ldb, int mb0, int nb0)
{
    const int tid  = threadIdx.x;
    const int rgrp = tid >> 4;           // 0..15
    const int cb   = (tid & 15) * 16;    // byte offset within 256-B k-slice
    const uint32_t base = sb + buf * STG_A;
    #pragma unroll
    for (int i = 0; i < 16; i++) {       // 256 A rows
        int row = i * 16 + rgrp;
        cpasync16(base + row * PITCH_A + cb,
                  (const char*)(A + (size_t)(mb0 + row) * lda + k0) + cb);
    }
    #pragma unroll
    for (int i = 0; i < 8; i++) {        // 128 B rows
        int row = i * 16 + rgrp;
        cpasync16(base + A_SB_A + row * PITCH_A + cb,
                  (const char*)(B + (size_t)(nb0 + row) * ldb + k0) + cb);
    }
    asm volatile("cp.async.commit_group;" ::: "memory");
}

__device__ __forceinline__ void computeA(uint32_t sb, int buf, float acc[4][8][4])
{
    const int lane = threadIdx.x & 31, wid = threadIdx.x >> 5;
    const int wm = wid & 3, wn = wid >> 2;
    const uint32_t ab = sb + buf * STG_A;
    const uint32_t bb = ab + A_SB_A;
    #pragma unroll
    for (int k16 = 0; k16 < 8; k16++) {
        const uint32_t acol = k16 * 32 + (lane >> 4) * 16;
        uint32_t ah[4][4];
        #pragma unroll
        for (int mt = 0; mt < 4; mt++) {
            uint32_t arow = wm * 64 + mt * 16 + (lane & 15);
            ldsm_x4(ah[mt], ab + arow * PITCH_A + acol);
        }
        const uint32_t bcol = k16 * 32 + ((lane >> 3) & 1) * 16;
        #pragma unroll
        for (int ntp = 0; ntp < 4; ntp++) {
            uint32_t brow = wn * 64 + ntp * 16 + ((lane >> 4) & 1) * 8 + (lane & 7);
            uint32_t bh[4];
            ldsm_x4(bh, bb + brow * PITCH_A + bcol);
            #pragma unroll
            for (int mt = 0; mt < 4; mt++) {
                mma_fp(acc[mt][2*ntp],   ah[mt], bh);
                mma_fp(acc[mt][2*ntp+1], ah[mt], bh + 2);
            }
        }
    }
}

// double-buffer, two syncs per stage (WAR-safe: issue(st+2) overwrites the
// buffer computed at st, protected by the sync after compute)
__device__ __forceinline__ void mainloopA(
    char* smem,
    const __half* __restrict__ A, const __half* __restrict__ B,
    int lda, int ldb, int mb0, int nb0, int nst, float acc[4][8][4])
{
    uint32_t sb = s2u(smem);
    issueA(sb, 0, 0,   A, B, lda, ldb, mb0, nb0);
    issueA(sb, 1, 128, A, B, lda, ldb, mb0, nb0);
    #pragma unroll 1
    for (int st = 0; st < nst; st++) {
        if (st + 1 < nst) asm volatile("cp.async.wait_group 1;" ::: "memory");
        else              asm volatile("cp.async.wait_group 0;" ::: "memory");
        __syncthreads();
        computeA(sb, st & 1, acc);
        if (st + 2 < nst) {
            __syncthreads();
            issueA(sb, st & 1, (st + 2) * 128, A, B, lda, ldb, mb0, nb0);
        }
    }
}

// ---- variant B (K-step 64, NPIPE=3) ----
#define PITCH_B  144
#define A_SB_B   (A_ROWS*PITCH_B)    // 36864
#define B_SB_B   (B_ROWS*PITCH_B)    // 18432
#define STG_B    (A_SB_B + B_SB_B)   // 55296
#define SMEM_B   (3*STG_B)           // 165888

__device__ __forceinline__ void issueB(
    uint32_t sb, int buf, int k0,
    const __half* __restrict__ A, const __half* __restrict__ B,
    int lda, int ldb, int mb0, int nb0)
{
    const int tid  = threadIdx.x;
    const int rgrp = tid >> 3;
    const int cb   = (tid & 7) * 16;
    const uint32_t base = sb + buf * STG_B;
    #pragma unroll
    for (int i = 0; i < 8; i++) {
        int row = i * 32 + rgrp;
        cpasync16(base + row * PITCH_B + cb,
                  (const char*)(A + (size_t)(mb0 + row) * lda + k0) + cb);
    }
    #pragma unroll
    for (int i = 0; i < 4; i++) {
        int row = i * 32 + rgrp;
        cpasync16(base + A_SB_B + row * PITCH_B + cb,
                  (const char*)(B + (size_t)(nb0 + row) * ldb + k0) + cb);
    }
    asm volatile("cp.async.commit_group;" ::: "memory");
}

__device__ __forceinline__ void computeB(uint32_t sb, int buf, float acc[4][8][4])
{
    const int lane = threadIdx.x & 31, wid = threadIdx.x >> 5;
    const int wm = wid & 3, wn = wid >> 2;
    const uint32_t ab = sb + buf * STG_B;
    const uint32_t bb = ab + A_SB_B;
    #pragma unroll
    for (int k16 = 0; k16 < 4; k16++) {
        const uint32_t acol = k16 * 32 + (lane >> 4) * 16;
        uint32_t ah[4][4];
        #pragma unroll
        for (int mt = 0; mt < 4; mt++) {
            uint32_t arow = wm * 64 + mt * 16 + (lane & 15);
            ldsm_x4(ah[mt], ab + arow * PITCH_B + acol);
        }
        const uint32_t bcol = k16 * 32 + ((lane >> 3) & 1) * 16;
        #pragma unroll
        for (int ntp = 0; ntp < 4; ntp++) {
            uint32_t brow = wn * 64 + ntp * 16 + ((lane >> 4) & 1) * 8 + (lane & 7);
            uint32_t bh[4];
            ldsm_x4(bh, bb + brow * PITCH_B + bcol);
            #pragma unroll
            for (int mt = 0; mt < 4; mt++) {
                mma_fp(acc[mt][2*ntp],   ah[mt], bh);
                mma_fp(acc[mt][2*ntp+1], ah[mt], bh + 2);
            }
        }
    }
}

__device__ __forceinline__ void mainloopB(
    char* smem,
    const __half* __restrict__ A, const __half* __restrict__ B,
    int lda, int ldb, int mb0, int nb0, int nst, float acc[4][8][4])
{
    uint32_t sb = s2u(smem);
    issueB(sb, 0, 0,  A, B, lda, ldb, mb0, nb0);
    issueB(sb, 1, 64, A, B, lda, ldb, mb0, nb0);
    #pragma unroll 1
    for (int st = 0; st < nst; st++) {
        if (st + 1 < nst) asm volatile("cp.async.wait_group 1;" ::: "memory");
        else              asm volatile("cp.async.wait_group 0;" ::: "memory");
        __syncthreads();
        if (st + 2 < nst) {
            int nx = st + 2;
            issueB(sb, nx % 3, nx * 64, A, B, lda, ldb, mb0, nb0);
        }
        computeB(sb, st % 3, acc);
    }
}

// epilogue index helper
struct EpiIdx { int r0; int lane, wm, wn; };
__device__ __forceinline__ EpiIdx epi_idx(int mb0, int mt) {
    EpiIdx e;
    e.lane = threadIdx.x & 31;
    int wid = threadIdx.x >> 5;
    e.wm = wid & 3; e.wn = wid >> 2;
    e.r0 = mb0 + e.wm * 64 + mt * 16 + (e.lane >> 2);
    return e;
}

// ---------------- q+k projection (fused): P[z,t,o] single fp16 --------------
__global__ __launch_bounds__(256, 1) void k_mma_proj(
    const __half* __restrict__ x16,
    const __half* __restrict__ wq16, const __half* __restrict__ wk16,
    const float* __restrict__ bq, const float* __restrict__ bk,
    __half* __restrict__ q16, __half* __restrict__ k16)
{
    extern __shared__ char smem[];
    const int zz = blockIdx.z;            // 0..127; >=64 -> k path
    const int z = zz & 63, h = z & 7, b = z >> 3;
    const bool is_k = zz >= 64;
    const __half* w16 = is_k ? wk16 : wq16;
    const float* bias = is_k ? bk : bq;
    __half* p16 = is_k ? k16 : q16;
    const int mb0 = blockIdx.y * 256;    // t
    float acc[4][8][4] = {};
    mainloopA(smem,
              x16 + (size_t)b * 1048576, w16 + (size_t)h * 131072,
              1024, 1024, mb0, 0, 8, acc);
    #pragma unroll
    for (int mt = 0; mt < 4; mt++) {
        EpiIdx e = epi_idx(mb0, mt);
        size_t base = (size_t)z * 131072 + (size_t)e.r0 * 128;
        #pragma unroll
        for (int nt = 0; nt < 8; nt++) {
            int col = e.wn * 64 + nt * 8 + (e.lane & 3) * 2;
            float bc0 = bias[h * DQKd + col], bc1 = bias[h * DQKd + col + 1];
            __half2 p0, p1;
            p0.x = __float2half_rn(acc[mt][nt][0] + bc0);
            p0.y = __float2half_rn(acc[mt][nt][1] + bc1);
            p1.x = __float2half_rn(acc[mt][nt][2] + bc0);
            p1.y = __float2half_rn(acc[mt][nt][3] + bc1);
            *(__half2*)(p16 + base + col) = p0;
            *(__half2*)(p16 + base + 8 * 128 + col) = p1;
        }
    }
}

// ---------------- energy: logits fp16 out (K=128, variant B) -----------------
__global__ __launch_bounds__(256, 1) void k_mma_energy(
    const __half* __restrict__ q16, const __half* __restrict__ k16,
    __half* __restrict__ logits)
{
    extern __shared__ char smem[];
    const int z = blockIdx.z;
    const int mb0 = blockIdx.y * 256;    // t
    const int nb0 = blockIdx.x * 128;    // s
    float acc[4][8][4] = {};
    mainloopB(smem,
              q16 + (size_t)z * 131072, k16 + (size_t)z * 131072,
              128, 128, mb0, nb0, 2, acc);
    #pragma unroll
    for (int mt = 0; mt < 4; mt++) {
        EpiIdx e = epi_idx(mb0, mt);
        size_t base = (size_t)z * 1048576 + (size_t)e.r0 * 1024;
        #pragma unroll
        for (int nt = 0; nt < 8; nt++) {
            int col = nb0 + e.wn * 64 + nt * 8 + (e.lane & 3) * 2;
            __half2 p0, p1;
            p0.x = __float2half_rn(acc[mt][nt][0]);
            p0.y = __float2half_rn(acc[mt][nt][1]);
            p1.x = __float2half_rn(acc[mt][nt][2]);
            p1.y = __float2half_rn(acc[mt][nt][3]);
            *(__half2*)(logits + base + col) = p0;
            *(__half2*)(logits + base + 8 * 1024 + col) = p1;
        }
    }
}

// ---------------- v projection: v[z,c,t] single fp16 ------------------------
__global__ __launch_bounds__(256, 1) void k_mma_vconv(
    const __half* __restrict__ wv, const __half* __restrict__ x16,
    const float* __restrict__ bv, __half* __restrict__ v16)
{
    extern __shared__ char smem[];
    const int z = blockIdx.z, h = z & 7, b = z >> 3;
    const int mb0 = blockIdx.y * 256;    // c
    const int nb0 = blockIdx.x * 128;    // t
    float acc[4][8][4] = {};
    mainloopA(smem,
              wv + (size_t)h * 1048576, x16 + (size_t)b * 1048576,
              1024, 1024, mb0, nb0, 8, acc);
    #pragma unroll
    for (int mt = 0; mt < 4; mt++) {
        EpiIdx e = epi_idx(mb0, mt);
        float bias0 = bv[h * Cdim + e.r0];
        float bias1 = bv[h * Cdim + e.r0 + 8];
        size_t base = (size_t)z * 1048576 + (size_t)e.r0 * 1024;
        #pragma unroll
        for (int nt = 0; nt < 8; nt++) {
            int col = nb0 + e.wn * 64 + nt * 8 + (e.lane & 3) * 2;
            __half2 p0, p1;
            p0.x = __float2half_rn(acc[mt][nt][0] + bias0);
            p0.y = __float2half_rn(acc[mt][nt][1] + bias0);
            p1.x = __float2half_rn(acc[mt][nt][2] + bias1);
            p1.y = __float2half_rn(acc[mt][nt][3] + bias1);
            *(__half2*)(v16 + base + col) = p0;
            *(__half2*)(v16 + base + 8 * 1024 + col) = p1;
        }
    }
}

// ---------------- heads: gamma*attn@v^T + x^T, single fp16 ------------------
__global__ __launch_bounds__(256, 1) void k_mma_oheads(
    const __half* __restrict__ a16, const __half* __restrict__ v16,
    const float* __restrict__ gamma, const __half* __restrict__ x16,
    __half* __restrict__ h16)
{
    extern __shared__ char smem[];
    const int z = blockIdx.z, h = z & 7, b = z >> 3;
    const int mb0 = blockIdx.y * 256;    // t
    const int nb0 = blockIdx.x * 128;    // c
    float acc[4][8][4] = {};
    mainloopA(smem,
              a16 + (size_t)z * 1048576, v16 + (size_t)z * 1048576,
              1024, 1024, mb0, nb0, 8, acc);
    const float g = gamma[h];
    #pragma unroll
    for (int mt = 0; mt < 4; mt++) {
        EpiIdx e = epi_idx(mb0, mt);
        size_t hb = (size_t)z * 1048576 + (size_t)e.r0 * 1024;
        size_t xb = (size_t)b * 1048576 + (size_t)e.r0 * 1024;
        #pragma unroll
        for (int nt = 0; nt < 8; nt++) {
            int col = nb0 + e.wn * 64 + nt * 8 + (e.lane & 3) * 2;
            __half2 x0 = *(const __half2*)(x16 + xb + col);
            __half2 x1 = *(const __half2*)(x16 + xb + 8 * 1024 + col);
            __half2 p0, p1;
            p0.x = __float2half_rn(g * acc[mt][nt][0] + __half2float(x0.x));
            p0.y = __float2half_rn(g * acc[mt][nt][1] + __half2float(x0.y));
            p1.x = __float2half_rn(g * acc[mt][nt][2] + __half2float(x1.x));
            p1.y = __float2half_rn(g * acc[mt][nt][3] + __half2float(x1.y));
            *(__half2*)(h16 + hb + col) = p0;
            *(__half2*)(h16 + hb + 8 * 1024 + col) = p1;
        }
    }
}

// ---------------- fc1: y1 = relu(heads.W1^T + b1), single fp16 --------------
__global__ __launch_bounds__(256, 1) void k_mma_fc1(
    const __half* __restrict__ h16, const __half* __restrict__ w1,
    const float* __restrict__ b1, __half* __restrict__ y116)
{
    extern __shared__ char smem[];
    const int mb0 = blockIdx.y * 256;    // r
    float acc[4][8][4] = {};
    mainloopA(smem, h16, w1, 1024, 1024, mb0, 0, 8, acc);
    #pragma unroll
    for (int mt = 0; mt < 4; mt++) {
        EpiIdx e = epi_idx(mb0, mt);
        size_t base = (size_t)e.r0 * 128;
        #pragma unroll
        for (int nt = 0; nt < 8; nt++) {
            int col = e.wn * 64 + nt * 8 + (e.lane & 3) * 2;
            float bc0 = b1[col], bc1 = b1[col + 1];
            __half2 p0, p1;
            p0.x = __float2half_rn(fmaxf(acc[mt][nt][0] + bc0, 0.f));
            p0.y = __float2half_rn(fmaxf(acc[mt][nt][1] + bc1, 0.f));
            p1.x = __float2half_rn(fmaxf(acc[mt][nt][2] + bc0, 0.f));
            p1.y = __float2half_rn(fmaxf(acc[mt][nt][3] + bc1, 0.f));
            *(__half2*)(y116 + base + col) = p0;
            *(__half2*)(y116 + base + 8 * 128 + col) = p1;
        }
    }
}

// ---------------- fc2: out scatter + relu + residual (K=128, variant B) -----
__global__ __launch_bounds__(256, 1) void k_mma_fc2(
    const __half* __restrict__ y116, const __half* __restrict__ w2,
    const float* __restrict__ b2, const float* __restrict__ x,
    float* __restrict__ out)
{
    extern __shared__ char smem[];
    const int mb0 = blockIdx.y * 256;    // r
    float acc[4][8][4] = {};
    mainloopB(smem, y116, w2, 128, 128, mb0, 0, 2, acc);
    #pragma unroll
    for (int mt = 0; mt < 4; mt++) {
        EpiIdx e = epi_idx(mb0, mt);
        #pragma unroll
        for (int rr = 0; rr < 2; rr++) {
            int r = e.r0 + rr * 8;               // r = (b*H + h)*T + t
            int b = r >> 13;
            int h = (r >> 10) & 7;
            int t = r & 1023;
            size_t xbase = (size_t)b * 1048576 + t;
            #pragma unroll
            for (int nt = 0; nt < 8; nt++) {
                int col = e.wn * 64 + nt * 8 + (e.lane & 3) * 2;
                #pragma unroll
                for (int jj = 0; jj < 2; jj++) {
                    int d = col + jj;
                    size_t idx = xbase + (size_t)(d * Hn + h) * 1024;
                    out[idx] = fmaxf(acc[mt][nt][rr * 2 + jj] + b2[d], 0.f) + x[idx];
                }
            }
        }
    }
}

// ---------------- softmax: fp16 logits in, fp16 attn out (in-place) ---------
__global__ __launch_bounds__(256) void k_softmax(__half* __restrict__ a)
{
    __half* row = a + (size_t)blockIdx.x * Tdim;
    const int tid = threadIdx.x;
    __half2 h01 = *(__half2*)&row[tid * 4];
    __half2 h23 = *(__half2*)&row[tid * 4 + 2];
    float v0 = __half2float(h01.x), v1 = __half2float(h01.y);
    float v2 = __half2float(h23.x), v3 = __half2float(h23.y);
    __shared__ float red[256];

    float mx = fmaxf(fmaxf(v0, v1), fmaxf(v2, v3));
    red[tid] = mx; __syncthreads();
    #pragma unroll
    for (int s = 128; s > 0; s >>= 1) {
        if (tid < s) red[tid] = fmaxf(red[tid], red[tid + s]);
        __syncthreads();
    }
    mx = red[0]; __syncthreads();

    v0 = __expf(v0 - mx); v1 = __expf(v1 - mx);
    v2 = __expf(v2 - mx); v3 = __expf(v3 - mx);
    red[tid] = v0 + v1 + v2 + v3; __syncthreads();
    #pragma unroll
    for (int s = 128; s > 0; s >>= 1) {
        if (tid < s) red[tid] += red[tid + s];
        __syncthreads();
    }
    float inv = 1.0f / red[0];

    __half2 p;
    p.x = __float2half_rn(v0 * inv); p.y = __float2half_rn(v1 * inv);
    *(__half2*)&row[tid * 4] = p;
    p.x = __float2half_rn(v2 * inv); p.y = __float2half_rn(v3 * inv);
    *(__half2*)&row[tid * 4 + 2] = p;
}

// ---------------- prep kernels ----------------
__global__ __launch_bounds__(256) void k_wround_h(
    const float* __restrict__ w, __half* __restrict__ o)
{
    size_t i = ((size_t)blockIdx.x * 256 + threadIdx.x) * 4;
    float4 v = *(const float4*)(w + i);
    __half2 p;
    p.x = __float2half_rn(v.x); p.y = __float2half_rn(v.y);
    *(__half2*)(o + i) = p;
    p.x = __float2half_rn(v.z); p.y = __float2half_rn(v.w);
    *(__half2*)(o + i + 2) = p;
}

// transpose x (b,c,t) -> xT (b,t,c) fp16
__global__ void k_xprep(const float* __restrict__ x, __half* __restrict__ x16)
{
    __shared__ float tile[32][33];
    const int b = blockIdx.z;
    const int c0 = blockIdx.y * 32, t0 = blockIdx.x * 32;
    for (int r = threadIdx.y; r < 32; r += 8)
        tile[r][threadIdx.x] = x[(size_t)b * Cdim * Tdim + (size_t)(c0 + r) * Tdim + t0 + threadIdx.x];
    __syncthreads();
    for (int r = threadIdx.y; r < 32; r += 8) {
        float v = tile[threadIdx.x][r];
        size_t o = (size_t)b * Tdim * Cdim + (size_t)(t0 + r) * Cdim + c0 + threadIdx.x;
        x16[o] = __float2half_rn(v);
    }
}

// ============================================================================
// launch
// ============================================================================
extern "C" void kernel_launch(void* const* d_in, const int* in_sizes, int n_in,
                              void* d_out, int out_size)
{
    (void)in_sizes; (void)n_in; (void)out_size;
    const float* x     = (const float*)d_in[0];
    const float* Wq    = (const float*)d_in[1];
    const float* bq    = (const float*)d_in[2];
    const float* Wk    = (const float*)d_in[3];
    const float* bk    = (const float*)d_in[4];
    const float* Wv    = (const float*)d_in[5];
    const float* bv    = (const float*)d_in[6];
    const float* gamma = (const float*)d_in[7];
    const float* W1    = (const float*)d_in[8];
    const float* b1    = (const float*)d_in[9];
    const float* W2    = (const float*)d_in[10];
    const float* b2    = (const float*)d_in[11];
    float* out = (float*)d_out;

    __half *a16, *v16, *wv16, *wq16, *wk16, *w116, *w216, *x16;
    __half *q16, *k16, *h16, *y116;
    cudaGetSymbolAddress((void**)&a16,   g_attn16);
    cudaGetSymbolAddress((void**)&v16,   g_v16);
    cudaGetSymbolAddress((void**)&wv16,  g_wv16);
    cudaGetSymbolAddress((void**)&wq16,  g_wq16);
    cudaGetSymbolAddress((void**)&wk16,  g_wk16);
    cudaGetSymbolAddress((void**)&w116,  g_w116);
    cudaGetSymbolAddress((void**)&w216,  g_w216);
    cudaGetSymbolAddress((void**)&x16,   g_x16);
    cudaGetSymbolAddress((void**)&q16,   g_q16);
    cudaGetSymbolAddress((void**)&k16,   g_k16);
    cudaGetSymbolAddress((void**)&h16,   g_h16);
    cudaGetSymbolAddress((void**)&y116,  g_y116);

    static cudaStream_t s1 = nullptr;
    static cudaEvent_t evFork = nullptr, evV = nullptr;
    static bool init_done = false;
    if (!init_done) {
        cudaFuncSetAttribute(k_mma_proj,   cudaFuncAttributeMaxDynamicSharedMemorySize, SMEM_A);
        cudaFuncSetAttribute(k_mma_vconv,  cudaFuncAttributeMaxDynamicSharedMemorySize, SMEM_A);
        cudaFuncSetAttribute(k_mma_oheads, cudaFuncAttributeMaxDynamicSharedMemorySize, SMEM_A);
        cudaFuncSetAttribute(k_mma_fc1,    cudaFuncAttributeMaxDynamicSharedMemorySize, SMEM_A);
        cudaFuncSetAttribute(k_mma_energy, cudaFuncAttributeMaxDynamicSharedMemorySize, SMEM_B);
        cudaFuncSetAttribute(k_mma_fc2,    cudaFuncAttributeMaxDynamicSharedMemorySize, SMEM_B);
        cudaStreamCreateWithFlags(&s1, cudaStreamNonBlocking);
        cudaEventCreateWithFlags(&evFork, cudaEventDisableTiming);
        cudaEventCreateWithFlags(&evV,    cudaEventDisableTiming);
        init_done = true;
    }

    const dim3 blk(256);
    const int ZB = Bsz * Hn;   // 64

    // -------- stream 0 (default, capture stream): x prep --------
    k_xprep<<<dim3(Tdim/32, Cdim/32, Bsz), dim3(32, 8)>>>(x, x16);
    cudaEventRecord(evFork, 0);

    // -------- stream 1: Wv prep -> vconv -> W2 prep --------
    cudaStreamWaitEvent(s1, evFork, 0);
    k_wround_h<<<(Hn*Cdim*Cdim)/1024, 256, 0, s1>>>(Wv, wv16);
    k_mma_vconv<<<dim3(Tdim/128, Cdim/256, ZB), blk, SMEM_A, s1>>>(wv16, x16, bv, v16);
    k_wround_h<<<(DFC1*DFC1)/1024, 256, 0, s1>>>(W2, w216);
    cudaEventRecord(evV, s1);

    // -------- stream 0: q/k chain --------
    k_wround_h<<<(Hn*DQKd*Cdim)/1024, 256>>>(Wq, wq16);
    k_wround_h<<<(Hn*DQKd*Cdim)/1024, 256>>>(Wk, wk16);
    k_wround_h<<<(DFC1*Cdim)/1024,    256>>>(W1, w116);
    k_mma_proj<<<dim3(1, Tdim/256, 2*ZB), blk, SMEM_A>>>(x16, wq16, wk16, bq, bk, q16, k16);
    k_mma_energy<<<dim3(Tdim/128, Tdim/256, ZB), blk, SMEM_B>>>(q16, k16, a16);
    k_softmax<<<ZB * Tdim, blk>>>(a16);

    // join: oheads needs attn (s0) and v (s1)
    cudaStreamWaitEvent(0, evV, 0);
    k_mma_oheads<<<dim3(Cdim/128, Tdim/256, ZB), blk, SMEM_A>>>(
        a16, v16, gamma, x16, h16);

    // MLP (fp16 1-term)
    const int ROWS = Bsz * Hn * Tdim;   // 65536
    k_mma_fc1<<<dim3(1, ROWS/256), blk, SMEM_A>>>(h16, w116, b1, y116);
    k_mma_fc2<<<dim3(1, ROWS/256), blk, SMEM_B>>>(y116, w216, b2, x, out);
}

// round 13
// speedup vs baseline: 7.3833x; 1.0281x over previous
#include <cuda_runtime.h>
#include <cuda_fp16.h>
#include <cstdint>

// ---------------- problem constants ----------------
#define Bsz  8
#define Cdim 1024
#define Tdim 1024
#define Hn   8
#define DQKd 128
#define DFC1 128

// ---------------- scratch (device globals; no allocs allowed) ----------------
__device__ __half g_attn16[(size_t)Bsz*Hn*Tdim*Tdim];         // logits -> attn (in-place)
__device__ __half g_v16 [(size_t)Bsz*Hn*Cdim*Tdim];           // v (z,c,t)
__device__ __half g_wv16[(size_t)Hn*Cdim*Cdim];
__device__ __half g_wq16[(size_t)Hn*DQKd*Cdim];
__device__ __half g_wk16[(size_t)Hn*DQKd*Cdim];
__device__ __half g_w116[(size_t)DFC1*Cdim];
__device__ __half g_w216[(size_t)DFC1*DFC1];
__device__ __half g_x16 [(size_t)Bsz*Tdim*Cdim];              // x^T (b,t,c)
__device__ __half g_q16[(size_t)Bsz*Hn*Tdim*DQKd];            // q (z,t,o)
__device__ __half g_k16[(size_t)Bsz*Hn*Tdim*DQKd];
__device__ __half g_h16[(size_t)Bsz*Hn*Tdim*Cdim];            // heads (z,t,c)
__device__ __half g_y116[(size_t)Bsz*Hn*Tdim*DFC1];

// ============================================================================
// PTX helpers (sm_80-level — valid on compute_103)
// ============================================================================
__device__ __forceinline__ uint32_t s2u(const void* p) {
    uint32_t a;
    asm("{ .reg .u64 t; cvta.to.shared.u64 t, %1; cvt.u32.u64 %0, t; }"
        : "=r"(a) : "l"(p));
    return a;
}
__device__ __forceinline__ void ldsm_x4(uint32_t* r, uint32_t addr) {
    asm volatile("ldmatrix.sync.aligned.m8n8.x4.shared.b16 {%0,%1,%2,%3}, [%4];"
        : "=r"(r[0]), "=r"(r[1]), "=r"(r[2]), "=r"(r[3]) : "r"(addr));
}
__device__ __forceinline__ void mma_fp(float* c, const uint32_t* a, const uint32_t* b) {
    asm volatile("mma.sync.aligned.m16n8k16.row.col.f32.f16.f16.f32 "
        "{%0,%1,%2,%3}, {%4,%5,%6,%7}, {%8,%9}, {%0,%1,%2,%3};"
        : "+f"(c[0]), "+f"(c[1]), "+f"(c[2]), "+f"(c[3])
        : "r"(a[0]), "r"(a[1]), "r"(a[2]), "r"(a[3]), "r"(b[0]), "r"(b[1]));
}
__device__ __forceinline__ void cpasync16(uint32_t dst, const void* src) {
    asm volatile("cp.async.cg.shared.global [%0], [%1], 16;" :: "r"(dst), "l"(src));
}

// ============================================================================
// fp16 1-term tensor-core GEMM (TN): D[m,n] = sum_k A[m,k]*B[n,k]
// CTA tile 128x128, 128 threads (4 warps as 2M x 2N, warp tile 64x64).
// K-step 64, NPIPE=3, single __syncthreads per stage, 2 CTAs/SM.
// ============================================================================
#define A_ROWS   128
#define B_ROWS   128
#define PITCHB   144                 // 64 fp16 (128 B) + 16 B pad (conflict-free)
#define A_SB     (A_ROWS*PITCHB)     // 18432
#define B_SB     (B_ROWS*PITCHB)     // 18432
#define STG_SB   (A_SB + B_SB)       // 36864
#define NPIPE    3
#define MMA_SMEM (NPIPE*STG_SB)      // 110592  (x2 CTAs = 221184 <= 227KB)

__device__ __forceinline__ void issue1(
    uint32_t sb, int buf, int k0,
    const __half* __restrict__ A, const __half* __restrict__ B,
    int lda, int ldb, int mb0, int nb0)
{
    const int tid  = threadIdx.x;        // 0..127
    const int rgrp = tid >> 3;           // 0..15
    const int cb   = (tid & 7) * 16;     // byte offset within 128-B k-slice
    const uint32_t base = sb + buf * STG_SB;
    #pragma unroll
    for (int i = 0; i < 8; i++) {        // 128 A rows
        int row = i * 16 + rgrp;
        cpasync16(base + row * PITCHB + cb,
                  (const char*)(A + (size_t)(mb0 + row) * lda + k0) + cb);
    }
    #pragma unroll
    for (int i = 0; i < 8; i++) {        // 128 B rows
        int row = i * 16 + rgrp;
        cpasync16(base + A_SB + row * PITCHB + cb,
                  (const char*)(B + (size_t)(nb0 + row) * ldb + k0) + cb);
    }
    asm volatile("cp.async.commit_group;" ::: "memory");
}

__device__ __forceinline__ void compute1(uint32_t sb, int buf, float acc[4][8][4])
{
    const int lane = threadIdx.x & 31, wid = threadIdx.x >> 5;   // wid 0..3
    const int wm = wid & 1, wn = wid >> 1;
    const uint32_t ab = sb + buf * STG_SB;
    const uint32_t bb = ab + A_SB;
    #pragma unroll
    for (int k16 = 0; k16 < 4; k16++) {
        const uint32_t acol = k16 * 32 + (lane >> 4) * 16;
        uint32_t ah[4][4];
        #pragma unroll
        for (int mt = 0; mt < 4; mt++) {
            uint32_t arow = wm * 64 + mt * 16 + (lane & 15);
            ldsm_x4(ah[mt], ab + arow * PITCHB + acol);
        }
        const uint32_t bcol = k16 * 32 + ((lane >> 3) & 1) * 16;
        #pragma unroll
        for (int ntp = 0; ntp < 4; ntp++) {
            uint32_t brow = wn * 64 + ntp * 16 + ((lane >> 4) & 1) * 8 + (lane & 7);
            uint32_t bh[4];
            ldsm_x4(bh, bb + brow * PITCHB + bcol);
            #pragma unroll
            for (int mt = 0; mt < 4; mt++) {
                mma_fp(acc[mt][2*ntp],   ah[mt], bh);
                mma_fp(acc[mt][2*ntp+1], ah[mt], bh + 2);
            }
        }
    }
}

__device__ __forceinline__ void mainloop1(
    char* smem,
    const __half* __restrict__ A, const __half* __restrict__ B,
    int lda, int ldb, int mb0, int nb0, int nst, float acc[4][8][4])
{
    uint32_t sb = s2u(smem);
    issue1(sb, 0, 0,  A, B, lda, ldb, mb0, nb0);
    issue1(sb, 1, 64, A, B, lda, ldb, mb0, nb0);
    #pragma unroll 1
    for (int st = 0; st < nst; st++) {
        if (st + 1 < nst) asm volatile("cp.async.wait_group 1;" ::: "memory");
        else              asm volatile("cp.async.wait_group 0;" ::: "memory");
        __syncthreads();
        if (st + 2 < nst) {
            int nx = st + 2;
            issue1(sb, nx % NPIPE, nx * 64, A, B, lda, ldb, mb0, nb0);
        }
        compute1(sb, st % NPIPE, acc);
    }
}

// epilogue index helper (4-warp layout)
struct EpiIdx { int r0; int lane, wm, wn; };
__device__ __forceinline__ EpiIdx epi_idx(int mb0, int mt) {
    EpiIdx e;
    e.lane = threadIdx.x & 31;
    int wid = threadIdx.x >> 5;
    e.wm = wid & 1; e.wn = wid >> 1;
    e.r0 = mb0 + e.wm * 64 + mt * 16 + (e.lane >> 2);
    return e;
}

// ---------------- q+k projection (fused): P[z,t,o] single fp16 --------------
__global__ __launch_bounds__(128, 2) void k_mma_proj(
    const __half* __restrict__ x16,
    const __half* __restrict__ wq16, const __half* __restrict__ wk16,
    const float* __restrict__ bq, const float* __restrict__ bk,
    __half* __restrict__ q16, __half* __restrict__ k16)
{
    extern __shared__ char smem[];
    const int zz = blockIdx.z;            // 0..127; >=64 -> k path
    const int z = zz & 63, h = z & 7, b = z >> 3;
    const bool is_k = zz >= 64;
    const __half* w16 = is_k ? wk16 : wq16;
    const float* bias = is_k ? bk : bq;
    __half* p16 = is_k ? k16 : q16;
    const int mb0 = blockIdx.y * 128;    // t
    float acc[4][8][4] = {};
    mainloop1(smem,
              x16 + (size_t)b * 1048576, w16 + (size_t)h * 131072,
              1024, 1024, mb0, 0, 16, acc);
    #pragma unroll
    for (int mt = 0; mt < 4; mt++) {
        EpiIdx e = epi_idx(mb0, mt);
        size_t base = (size_t)z * 131072 + (size_t)e.r0 * 128;
        #pragma unroll
        for (int nt = 0; nt < 8; nt++) {
            int col = e.wn * 64 + nt * 8 + (e.lane & 3) * 2;
            float bc0 = bias[h * DQKd + col], bc1 = bias[h * DQKd + col + 1];
            __half2 p0, p1;
            p0.x = __float2half_rn(acc[mt][nt][0] + bc0);
            p0.y = __float2half_rn(acc[mt][nt][1] + bc1);
            p1.x = __float2half_rn(acc[mt][nt][2] + bc0);
            p1.y = __float2half_rn(acc[mt][nt][3] + bc1);
            *(__half2*)(p16 + base + col) = p0;
            *(__half2*)(p16 + base + 8 * 128 + col) = p1;
        }
    }
}

// ---------------- energy: logits fp16 out (K=128) ---------------------------
__global__ __launch_bounds__(128, 2) void k_mma_energy(
    const __half* __restrict__ q16, const __half* __restrict__ k16,
    __half* __restrict__ logits)
{
    extern __shared__ char smem[];
    const int z = blockIdx.z;
    const int mb0 = blockIdx.y * 128;    // t
    const int nb0 = blockIdx.x * 128;    // s
    float acc[4][8][4] = {};
    mainloop1(smem,
              q16 + (size_t)z * 131072, k16 + (size_t)z * 131072,
              128, 128, mb0, nb0, 2, acc);
    #pragma unroll
    for (int mt = 0; mt < 4; mt++) {
        EpiIdx e = epi_idx(mb0, mt);
        size_t base = (size_t)z * 1048576 + (size_t)e.r0 * 1024;
        #pragma unroll
        for (int nt = 0; nt < 8; nt++) {
            int col = nb0 + e.wn * 64 + nt * 8 + (e.lane & 3) * 2;
            __half2 p0, p1;
            p0.x = __float2half_rn(acc[mt][nt][0]);
            p0.y = __float2half_rn(acc[mt][nt][1]);
            p1.x = __float2half_rn(acc[mt][nt][2]);
            p1.y = __float2half_rn(acc[mt][nt][3]);
            *(__half2*)(logits + base + col) = p0;
            *(__half2*)(logits + base + 8 * 1024 + col) = p1;
        }
    }
}

// ---------------- v projection: v[z,c,t] single fp16 ------------------------
__global__ __launch_bounds__(128, 2) void k_mma_vconv(
    const __half* __restrict__ wv, const __half* __restrict__ x16,
    const float* __restrict__ bv, __half* __restrict__ v16)
{
    extern __shared__ char smem[];
    const int z = blockIdx.z, h = z & 7, b = z >> 3;
    const int mb0 = blockIdx.y * 128;    // c
    const int nb0 = blockIdx.x * 128;    // t
    float acc[4][8][4] = {};
    mainloop1(smem,
              wv + (size_t)h * 1048576, x16 + (size_t)b * 1048576,
              1024, 1024, mb0, nb0, 16, acc);
    #pragma unroll
    for (int mt = 0; mt < 4; mt++) {
        EpiIdx e = epi_idx(mb0, mt);
        float bias0 = bv[h * Cdim + e.r0];
        float bias1 = bv[h * Cdim + e.r0 + 8];
        size_t base = (size_t)z * 1048576 + (size_t)e.r0 * 1024;
        #pragma unroll
        for (int nt = 0; nt < 8; nt++) {
            int col = nb0 + e.wn * 64 + nt * 8 + (e.lane & 3) * 2;
            __half2 p0, p1;
            p0.x = __float2half_rn(acc[mt][nt][0] + bias0);
            p0.y = __float2half_rn(acc[mt][nt][1] + bias0);
            p1.x = __float2half_rn(acc[mt][nt][2] + bias1);
            p1.y = __float2half_rn(acc[mt][nt][3] + bias1);
            *(__half2*)(v16 + base + col) = p0;
            *(__half2*)(v16 + base + 8 * 1024 + col) = p1;
        }
    }
}

// ---------------- heads: gamma*attn@v^T + x^T, single fp16 ------------------
__global__ __launch_bounds__(128, 2) void k_mma_oheads(
    const __half* __restrict__ a16, const __half* __restrict__ v16,
    const float* __restrict__ gamma, const __half* __restrict__ x16,
    __half* __restrict__ h16)
{
    extern __shared__ char smem[];
    const int z = blockIdx.z, h = z & 7, b = z >> 3;
    const int mb0 = blockIdx.y * 128;    // t
    const int nb0 = blockIdx.x * 128;    // c
    float acc[4][8][4] = {};
    mainloop1(smem,
              a16 + (size_t)z * 1048576, v16 + (size_t)z * 1048576,
              1024, 1024, mb0, nb0, 16, acc);
    const float g = gamma[h];
    #pragma unroll
    for (int mt = 0; mt < 4; mt++) {
        EpiIdx e = epi_idx(mb0, mt);
        size_t hb = (size_t)z * 1048576 + (size_t)e.r0 * 1024;
        size_t xb = (size_t)b * 1048576 + (size_t)e.r0 * 1024;
        #pragma unroll
        for (int nt = 0; nt < 8; nt++) {
            int col = nb0 + e.wn * 64 + nt * 8 + (e.lane & 3) * 2;
            __half2 x0 = *(const __half2*)(x16 + xb + col);
            __half2 x1 = *(const __half2*)(x16 + xb + 8 * 1024 + col);
            __half2 p0, p1;
            p0.x = __float2half_rn(g * acc[mt][nt][0] + __half2float(x0.x));
            p0.y = __float2half_rn(g * acc[mt][nt][1] + __half2float(x0.y));
            p1.x = __float2half_rn(g * acc[mt][nt][2] + __half2float(x1.x));
            p1.y = __float2half_rn(g * acc[mt][nt][3] + __half2float(x1.y));
            *(__half2*)(h16 + hb + col) = p0;
            *(__half2*)(h16 + hb + 8 * 1024 + col) = p1;
        }
    }
}

// ---------------- fc1: y1 = relu(heads.W1^T + b1), single fp16 --------------
__global__ __launch_bounds__(128, 2) void k_mma_fc1(
    const __half* __restrict__ h16, const __half* __restrict__ w1,
    const float* __restrict__ b1, __half* __restrict__ y116)
{
    extern __shared__ char smem[];
    const int mb0 = blockIdx.y * 128;    // r
    float acc[4][8][4] = {};
    mainloop1(smem, h16, w1, 1024, 1024, mb0, 0, 16, acc);
    #pragma unroll
    for (int mt = 0; mt < 4; mt++) {
        EpiIdx e = epi_idx(mb0, mt);
        size_t base = (size_t)e.r0 * 128;
        #pragma unroll
        for (int nt = 0; nt < 8; nt++) {
            int col = e.wn * 64 + nt * 8 + (e.lane & 3) * 2;
            float bc0 = b1[col], bc1 = b1[col + 1];
            __half2 p0, p1;
            p0.x = __float2half_rn(fmaxf(acc[mt][nt][0] + bc0, 0.f));
            p0.y = __float2half_rn(fmaxf(acc[mt][nt][1] + bc1, 0.f));
            p1.x = __float2half_rn(fmaxf(acc[mt][nt][2] + bc0, 0.f));
            p1.y = __float2half_rn(fmaxf(acc[mt][nt][3] + bc1, 0.f));
            *(__half2*)(y116 + base + col) = p0;
            *(__half2*)(y116 + base + 8 * 128 + col) = p1;
        }
    }
}

// ---------------- fc2: out scatter + relu + residual (K=128) ----------------
__global__ __launch_bounds__(128, 2) void k_mma_fc2(
    const __half* __restrict__ y116, const __half* __restrict__ w2,
    const float* __restrict__ b2, const float* __restrict__ x,
    float* __restrict__ out)
{
    extern __shared__ char smem[];
    const int mb0 = blockIdx.y * 128;    // r
    float acc[4][8][4] = {};
    mainloop1(smem, y116, w2, 128, 128, mb0, 0, 2, acc);
    #pragma unroll
    for (int mt = 0; mt < 4; mt++) {
        EpiIdx e = epi_idx(mb0, mt);
        #pragma unroll
        for (int rr = 0; rr < 2; rr++) {
            int r = e.r0 + rr * 8;               // r = (b*H + h)*T + t
            int b = r >> 13;
            int h = (r >> 10) & 7;
            int t = r & 1023;
            size_t xbase = (size_t)b * 1048576 + t;
            #pragma unroll
            for (int nt = 0; nt < 8; nt++) {
                int col = e.wn * 64 + nt * 8 + (e.lane & 3) * 2;
                #pragma unroll
                for (int jj = 0; jj < 2; jj++) {
                    int d = col + jj;
                    size_t idx = xbase + (size_t)(d * Hn + h) * 1024;
                    out[idx] = fmaxf(acc[mt][nt][rr * 2 + jj] + b2[d], 0.f) + x[idx];
                }
            }
        }
    }
}

// ---------------- softmax: fp16 logits in, fp16 attn out (in-place) ---------
__global__ __launch_bounds__(256) void k_softmax(__half* __restrict__ a)
{
    __half* row = a + (size_t)blockIdx.x * Tdim;
    const int tid = threadIdx.x;
    __half2 h01 = *(__half2*)&row[tid * 4];
    __half2 h23 = *(__half2*)&row[tid * 4 + 2];
    float v0 = __half2float(h01.x), v1 = __half2float(h01.y);
    float v2 = __half2float(h23.x), v3 = __half2float(h23.y);
    __shared__ float red[256];

    float mx = fmaxf(fmaxf(v0, v1), fmaxf(v2, v3));
    red[tid] = mx; __syncthreads();
    #pragma unroll
    for (int s = 128; s > 0; s >>= 1) {
        if (tid < s) red[tid] = fmaxf(red[tid], red[tid + s]);
        __syncthreads();
    }
    mx = red[0]; __syncthreads();

    v0 = __expf(v0 - mx); v1 = __expf(v1 - mx);
    v2 = __expf(v2 - mx); v3 = __expf(v3 - mx);
    red[tid] = v0 + v1 + v2 + v3; __syncthreads();
    #pragma unroll
    for (int s = 128; s > 0; s >>= 1) {
        if (tid < s) red[tid] += red[tid + s];
        __syncthreads();
    }
    float inv = 1.0f / red[0];

    __half2 p;
    p.x = __float2half_rn(v0 * inv); p.y = __float2half_rn(v1 * inv);
    *(__half2*)&row[tid * 4] = p;
    p.x = __float2half_rn(v2 * inv); p.y = __float2half_rn(v3 * inv);
    *(__half2*)&row[tid * 4 + 2] = p;
}

// ---------------- prep kernels ----------------
__global__ __launch_bounds__(256) void k_wround_h(
    const float* __restrict__ w, __half* __restrict__ o)
{
    size_t i = ((size_t)blockIdx.x * 256 + threadIdx.x) * 4;
    float4 v = *(const float4*)(w + i);
    __half2 p;
    p.x = __float2half_rn(v.x); p.y = __float2half_rn(v.y);
    *(__half2*)(o + i) = p;
    p.x = __float2half_rn(v.z); p.y = __float2half_rn(v.w);
    *(__half2*)(o + i + 2) = p;
}

// transpose x (b,c,t) -> xT (b,t,c) fp16
__global__ void k_xprep(const float* __restrict__ x, __half* __restrict__ x16)
{
    __shared__ float tile[32][33];
    const int b = blockIdx.z;
    const int c0 = blockIdx.y * 32, t0 = blockIdx.x * 32;
    for (int r = threadIdx.y; r < 32; r += 8)
        tile[r][threadIdx.x] = x[(size_t)b * Cdim * Tdim + (size_t)(c0 + r) * Tdim + t0 + threadIdx.x];
    __syncthreads();
    for (int r = threadIdx.y; r < 32; r += 8) {
        float v = tile[threadIdx.x][r];
        size_t o = (size_t)b * Tdim * Cdim + (size_t)(t0 + r) * Cdim + c0 + threadIdx.x;
        x16[o] = __float2half_rn(v);
    }
}

// ============================================================================
// launch
// ============================================================================
extern "C" void kernel_launch(void* const* d_in, const int* in_sizes, int n_in,
                              void* d_out, int out_size)
{
    (void)in_sizes; (void)n_in; (void)out_size;
    const float* x     = (const float*)d_in[0];
    const float* Wq    = (const float*)d_in[1];
    const float* bq    = (const float*)d_in[2];
    const float* Wk    = (const float*)d_in[3];
    const float* bk    = (const float*)d_in[4];
    const float* Wv    = (const float*)d_in[5];
    const float* bv    = (const float*)d_in[6];
    const float* gamma = (const float*)d_in[7];
    const float* W1    = (const float*)d_in[8];
    const float* b1    = (const float*)d_in[9];
    const float* W2    = (const float*)d_in[10];
    const float* b2    = (const float*)d_in[11];
    float* out = (float*)d_out;

    __half *a16, *v16, *wv16, *wq16, *wk16, *w116, *w216, *x16;
    __half *q16, *k16, *h16, *y116;
    cudaGetSymbolAddress((void**)&a16,   g_attn16);
    cudaGetSymbolAddress((void**)&v16,   g_v16);
    cudaGetSymbolAddress((void**)&wv16,  g_wv16);
    cudaGetSymbolAddress((void**)&wq16,  g_wq16);
    cudaGetSymbolAddress((void**)&wk16,  g_wk16);
    cudaGetSymbolAddress((void**)&w116,  g_w116);
    cudaGetSymbolAddress((void**)&w216,  g_w216);
    cudaGetSymbolAddress((void**)&x16,   g_x16);
    cudaGetSymbolAddress((void**)&q16,   g_q16);
    cudaGetSymbolAddress((void**)&k16,   g_k16);
    cudaGetSymbolAddress((void**)&h16,   g_h16);
    cudaGetSymbolAddress((void**)&y116,  g_y116);

    static cudaStream_t s1 = nullptr;
    static cudaEvent_t evFork = nullptr, evV = nullptr;
    static bool init_done = false;
    if (!init_done) {
        cudaFuncSetAttribute(k_mma_proj,   cudaFuncAttributeMaxDynamicSharedMemorySize, MMA_SMEM);
        cudaFuncSetAttribute(k_mma_energy, cudaFuncAttributeMaxDynamicSharedMemorySize, MMA_SMEM);
        cudaFuncSetAttribute(k_mma_vconv,  cudaFuncAttributeMaxDynamicSharedMemorySize, MMA_SMEM);
        cudaFuncSetAttribute(k_mma_oheads, cudaFuncAttributeMaxDynamicSharedMemorySize, MMA_SMEM);
        cudaFuncSetAttribute(k_mma_fc1,    cudaFuncAttributeMaxDynamicSharedMemorySize, MMA_SMEM);
        cudaFuncSetAttribute(k_mma_fc2,    cudaFuncAttributeMaxDynamicSharedMemorySize, MMA_SMEM);
        cudaStreamCreateWithFlags(&s1, cudaStreamNonBlocking);
        cudaEventCreateWithFlags(&evFork, cudaEventDisableTiming);
        cudaEventCreateWithFlags(&evV,    cudaEventDisableTiming);
        init_done = true;
    }

    const dim3 blk(128);
    const int ZB = Bsz * Hn;   // 64

    // -------- stream 0 (default, capture stream): x prep --------
    k_xprep<<<dim3(Tdim/32, Cdim/32, Bsz), dim3(32, 8)>>>(x, x16);
    cudaEventRecord(evFork, 0);

    // -------- stream 1: Wv prep -> vconv -> W2 prep --------
    cudaStreamWaitEvent(s1, evFork, 0);
    k_wround_h<<<(Hn*Cdim*Cdim)/1024, 256, 0, s1>>>(Wv, wv16);
    k_mma_vconv<<<dim3(Tdim/128, Cdim/128, ZB), blk, MMA_SMEM, s1>>>(wv16, x16, bv, v16);
    k_wround_h<<<(DFC1*DFC1)/1024, 256, 0, s1>>>(W2, w216);
    cudaEventRecord(evV, s1);

    // -------- stream 0: q/k chain --------
    k_wround_h<<<(Hn*DQKd*Cdim)/1024, 256>>>(Wq, wq16);
    k_wround_h<<<(Hn*DQKd*Cdim)/1024, 256>>>(Wk, wk16);
    k_wround_h<<<(DFC1*Cdim)/1024,    256>>>(W1, w116);
    k_mma_proj<<<dim3(1, Tdim/128, 2*ZB), blk, MMA_SMEM>>>(x16, wq16, wk16, bq, bk, q16, k16);
    k_mma_energy<<<dim3(Tdim/128, Tdim/128, ZB), blk, MMA_SMEM>>>(q16, k16, a16);
    k_softmax<<<ZB * Tdim, 256>>>(a16);

    // join: oheads needs attn (s0) and v (s1)
    cudaStreamWaitEvent(0, evV, 0);
    k_mma_oheads<<<dim3(Cdim/128, Tdim/128, ZB), blk, MMA_SMEM>>>(
        a16, v16, gamma, x16, h16);

    // MLP (fp16 1-term)
    const int ROWS = Bsz * Hn * Tdim;   // 65536
    k_mma_fc1<<<dim3(1, ROWS/128), blk, MMA_SMEM>>>(h16, w116, b1, y116);
    k_mma_fc2<<<dim3(1, ROWS/128), blk, MMA_SMEM>>>(y116, w216, b2, x, out);
}

// round 14
// speedup vs baseline: 8.0009x; 1.0837x over previous
#include <cuda_runtime.h>
#include <cuda_fp16.h>
#include <cstdint>

// ---------------- problem constants ----------------
#define Bsz  8
#define Cdim 1024
#define Tdim 1024
#define Hn   8
#define DQKd 128
#define DFC1 128

// ---------------- scratch (device globals; no allocs allowed) ----------------
__device__ __half g_attn16[(size_t)Bsz*Hn*Tdim*Tdim];         // logits -> attn (in-place)
__device__ __half g_v16 [(size_t)Bsz*Hn*Cdim*Tdim];           // v (z,c,t)
__device__ __half g_wv16[(size_t)Hn*Cdim*Cdim];
__device__ __half g_wq16[(size_t)Hn*DQKd*Cdim];
__device__ __half g_wk16[(size_t)Hn*DQKd*Cdim];
__device__ __half g_w116[(size_t)DFC1*Cdim];
__device__ __half g_w216[(size_t)DFC1*DFC1];
__device__ __half g_x16 [(size_t)Bsz*Tdim*Cdim];              // x^T (b,t,c)
__device__ __half g_q16[(size_t)Bsz*Hn*Tdim*DQKd];            // q (z,t,o)
__device__ __half g_k16[(size_t)Bsz*Hn*Tdim*DQKd];
__device__ __half g_h16[(size_t)Bsz*Hn*Tdim*Cdim];            // heads (z,t,c)

// ============================================================================
// PTX helpers (sm_80-level — valid on compute_103)
// ============================================================================
__device__ __forceinline__ uint32_t s2u(const void* p) {
    uint32_t a;
    asm("{ .reg .u64 t; cvta.to.shared.u64 t, %1; cvt.u32.u64 %0, t; }"
        : "=r"(a) : "l"(p));
    return a;
}
__device__ __forceinline__ void ldsm_x4(uint32_t* r, uint32_t addr) {
    asm volatile("ldmatrix.sync.aligned.m8n8.x4.shared.b16 {%0,%1,%2,%3}, [%4];"
        : "=r"(r[0]), "=r"(r[1]), "=r"(r[2]), "=r"(r[3]) : "r"(addr));
}
__device__ __forceinline__ void mma_fp(float* c, const uint32_t* a, const uint32_t* b) {
    asm volatile("mma.sync.aligned.m16n8k16.row.col.f32.f16.f16.f32 "
        "{%0,%1,%2,%3}, {%4,%5,%6,%7}, {%8,%9}, {%0,%1,%2,%3};"
        : "+f"(c[0]), "+f"(c[1]), "+f"(c[2]), "+f"(c[3])
        : "r"(a[0]), "r"(a[1]), "r"(a[2]), "r"(a[3]), "r"(b[0]), "r"(b[1]));
}
__device__ __forceinline__ void cpasync16(uint32_t dst, const void* src) {
    asm volatile("cp.async.cg.shared.global [%0], [%1], 16;" :: "r"(dst), "l"(src));
}

// ============================================================================
// fp16 1-term tensor-core GEMM (TN): D[m,n] = sum_k A[m,k]*B[n,k]
// CTA tile 128x128, 128 threads (4 warps as 2M x 2N, warp tile 64x64).
// K-step 64, NPIPE=3, single __syncthreads per stage, 2 CTAs/SM.
// ============================================================================
#define A_ROWS   128
#define B_ROWS   128
#define PITCHB   144                 // 64 fp16 (128 B) + 16 B pad (conflict-free)
#define A_SB     (A_ROWS*PITCHB)     // 18432
#define B_SB     (B_ROWS*PITCHB)     // 18432
#define STG_SB   (A_SB + B_SB)       // 36864
#define NPIPE    3
#define MMA_SMEM (NPIPE*STG_SB)      // 110592  (x2 CTAs = 221184 <= 227KB)

__device__ __forceinline__ void issue1(
    uint32_t sb, int buf, int k0,
    const __half* __restrict__ A, const __half* __restrict__ B,
    int lda, int ldb, int mb0, int nb0)
{
    const int tid  = threadIdx.x;        // 0..127
    const int rgrp = tid >> 3;           // 0..15
    const int cb   = (tid & 7) * 16;     // byte offset within 128-B k-slice
    const uint32_t base = sb + buf * STG_SB;
    #pragma unroll
    for (int i = 0; i < 8; i++) {        // 128 A rows
        int row = i * 16 + rgrp;
        cpasync16(base + row * PITCHB + cb,
                  (const char*)(A + (size_t)(mb0 + row) * lda + k0) + cb);
    }
    #pragma unroll
    for (int i = 0; i < 8; i++) {        // 128 B rows
        int row = i * 16 + rgrp;
        cpasync16(base + A_SB + row * PITCHB + cb,
                  (const char*)(B + (size_t)(nb0 + row) * ldb + k0) + cb);
    }
    asm volatile("cp.async.commit_group;" ::: "memory");
}

__device__ __forceinline__ void compute1(uint32_t sb, int buf, float acc[4][8][4])
{
    const int lane = threadIdx.x & 31, wid = threadIdx.x >> 5;   // wid 0..3
    const int wm = wid & 1, wn = wid >> 1;
    const uint32_t ab = sb + buf * STG_SB;
    const uint32_t bb = ab + A_SB;
    #pragma unroll
    for (int k16 = 0; k16 < 4; k16++) {
        const uint32_t acol = k16 * 32 + (lane >> 4) * 16;
        uint32_t ah[4][4];
        #pragma unroll
        for (int mt = 0; mt < 4; mt++) {
            uint32_t arow = wm * 64 + mt * 16 + (lane & 15);
            ldsm_x4(ah[mt], ab + arow * PITCHB + acol);
        }
        const uint32_t bcol = k16 * 32 + ((lane >> 3) & 1) * 16;
        #pragma unroll
        for (int ntp = 0; ntp < 4; ntp++) {
            uint32_t brow = wn * 64 + ntp * 16 + ((lane >> 4) & 1) * 8 + (lane & 7);
            uint32_t bh[4];
            ldsm_x4(bh, bb + brow * PITCHB + bcol);
            #pragma unroll
            for (int mt = 0; mt < 4; mt++) {
                mma_fp(acc[mt][2*ntp],   ah[mt], bh);
                mma_fp(acc[mt][2*ntp+1], ah[mt], bh + 2);
            }
        }
    }
}

__device__ __forceinline__ void mainloop1(
    char* smem,
    const __half* __restrict__ A, const __half* __restrict__ B,
    int lda, int ldb, int mb0, int nb0, int nst, float acc[4][8][4])
{
    uint32_t sb = s2u(smem);
    issue1(sb, 0, 0,  A, B, lda, ldb, mb0, nb0);
    issue1(sb, 1, 64, A, B, lda, ldb, mb0, nb0);
    #pragma unroll 1
    for (int st = 0; st < nst; st++) {
        if (st + 1 < nst) asm volatile("cp.async.wait_group 1;" ::: "memory");
        else              asm volatile("cp.async.wait_group 0;" ::: "memory");
        __syncthreads();
        if (st + 2 < nst) {
            int nx = st + 2;
            issue1(sb, nx % NPIPE, nx * 64, A, B, lda, ldb, mb0, nb0);
        }
        compute1(sb, st % NPIPE, acc);
    }
}

// epilogue index helper (4-warp layout)
struct EpiIdx { int r0; int lane, wm, wn; };
__device__ __forceinline__ EpiIdx epi_idx(int mb0, int mt) {
    EpiIdx e;
    e.lane = threadIdx.x & 31;
    int wid = threadIdx.x >> 5;
    e.wm = wid & 1; e.wn = wid >> 1;
    e.r0 = mb0 + e.wm * 64 + mt * 16 + (e.lane >> 2);
    return e;
}

// ---------------- q+k projection (fused): P[z,t,o] single fp16 --------------
__global__ __launch_bounds__(128, 2) void k_mma_proj(
    const __half* __restrict__ x16,
    const __half* __restrict__ wq16, const __half* __restrict__ wk16,
    const float* __restrict__ bq, const float* __restrict__ bk,
    __half* __restrict__ q16, __half* __restrict__ k16)
{
    extern __shared__ char smem[];
    const int zz = blockIdx.z;            // 0..127; >=64 -> k path
    const int z = zz & 63, h = z & 7, b = z >> 3;
    const bool is_k = zz >= 64;
    const __half* w16 = is_k ? wk16 : wq16;
    const float* bias = is_k ? bk : bq;
    __half* p16 = is_k ? k16 : q16;
    const int mb0 = blockIdx.y * 128;    // t
    float acc[4][8][4] = {};
    mainloop1(smem,
              x16 + (size_t)b * 1048576, w16 + (size_t)h * 131072,
              1024, 1024, mb0, 0, 16, acc);
    #pragma unroll
    for (int mt = 0; mt < 4; mt++) {
        EpiIdx e = epi_idx(mb0, mt);
        size_t base = (size_t)z * 131072 + (size_t)e.r0 * 128;
        #pragma unroll
        for (int nt = 0; nt < 8; nt++) {
            int col = e.wn * 64 + nt * 8 + (e.lane & 3) * 2;
            float bc0 = bias[h * DQKd + col], bc1 = bias[h * DQKd + col + 1];
            __half2 p0, p1;
            p0.x = __float2half_rn(acc[mt][nt][0] + bc0);
            p0.y = __float2half_rn(acc[mt][nt][1] + bc1);
            p1.x = __float2half_rn(acc[mt][nt][2] + bc0);
            p1.y = __float2half_rn(acc[mt][nt][3] + bc1);
            *(__half2*)(p16 + base + col) = p0;
            *(__half2*)(p16 + base + 8 * 128 + col) = p1;
        }
    }
}

// ---------------- energy: logits fp16 out (K=128) ---------------------------
__global__ __launch_bounds__(128, 2) void k_mma_energy(
    const __half* __restrict__ q16, const __half* __restrict__ k16,
    __half* __restrict__ logits)
{
    extern __shared__ char smem[];
    const int z = blockIdx.z;
    const int mb0 = blockIdx.y * 128;    // t
    const int nb0 = blockIdx.x * 128;    // s
    float acc[4][8][4] = {};
    mainloop1(smem,
              q16 + (size_t)z * 131072, k16 + (size_t)z * 131072,
              128, 128, mb0, nb0, 2, acc);
    #pragma unroll
    for (int mt = 0; mt < 4; mt++) {
        EpiIdx e = epi_idx(mb0, mt);
        size_t base = (size_t)z * 1048576 + (size_t)e.r0 * 1024;
        #pragma unroll
        for (int nt = 0; nt < 8; nt++) {
            int col = nb0 + e.wn * 64 + nt * 8 + (e.lane & 3) * 2;
            __half2 p0, p1;
            p0.x = __float2half_rn(acc[mt][nt][0]);
            p0.y = __float2half_rn(acc[mt][nt][1]);
            p1.x = __float2half_rn(acc[mt][nt][2]);
            p1.y = __float2half_rn(acc[mt][nt][3]);
            *(__half2*)(logits + base + col) = p0;
            *(__half2*)(logits + base + 8 * 1024 + col) = p1;
        }
    }
}

// ---------------- v projection: v[z,c,t] single fp16 ------------------------
__global__ __launch_bounds__(128, 2) void k_mma_vconv(
    const __half* __restrict__ wv, const __half* __restrict__ x16,
    const float* __restrict__ bv, __half* __restrict__ v16)
{
    extern __shared__ char smem[];
    const int z = blockIdx.z, h = z & 7, b = z >> 3;
    const int mb0 = blockIdx.y * 128;    // c
    const int nb0 = blockIdx.x * 128;    // t
    float acc[4][8][4] = {};
    mainloop1(smem,
              wv + (size_t)h * 1048576, x16 + (size_t)b * 1048576,
              1024, 1024, mb0, nb0, 16, acc);
    #pragma unroll
    for (int mt = 0; mt < 4; mt++) {
        EpiIdx e = epi_idx(mb0, mt);
        float bias0 = bv[h * Cdim + e.r0];
        float bias1 = bv[h * Cdim + e.r0 + 8];
        size_t base = (size_t)z * 1048576 + (size_t)e.r0 * 1024;
        #pragma unroll
        for (int nt = 0; nt < 8; nt++) {
            int col = nb0 + e.wn * 64 + nt * 8 + (e.lane & 3) * 2;
            __half2 p0, p1;
            p0.x = __float2half_rn(acc[mt][nt][0] + bias0);
            p0.y = __float2half_rn(acc[mt][nt][1] + bias0);
            p1.x = __float2half_rn(acc[mt][nt][2] + bias1);
            p1.y = __float2half_rn(acc[mt][nt][3] + bias1);
            *(__half2*)(v16 + base + col) = p0;
            *(__half2*)(v16 + base + 8 * 1024 + col) = p1;
        }
    }
}

// ---------------- heads: gamma*attn@v^T + x^T, single fp16 ------------------
__global__ __launch_bounds__(128, 2) void k_mma_oheads(
    const __half* __restrict__ a16, const __half* __restrict__ v16,
    const float* __restrict__ gamma, const __half* __restrict__ x16,
    __half* __restrict__ h16)
{
    extern __shared__ char smem[];
    const int z = blockIdx.z, h = z & 7, b = z >> 3;
    const int mb0 = blockIdx.y * 128;    // t
    const int nb0 = blockIdx.x * 128;    // c
    float acc[4][8][4] = {};
    mainloop1(smem,
              a16 + (size_t)z * 1048576, v16 + (size_t)z * 1048576,
              1024, 1024, mb0, nb0, 16, acc);
    const float g = gamma[h];
    #pragma unroll
    for (int mt = 0; mt < 4; mt++) {
        EpiIdx e = epi_idx(mb0, mt);
        size_t hb = (size_t)z * 1048576 + (size_t)e.r0 * 1024;
        size_t xb = (size_t)b * 1048576 + (size_t)e.r0 * 1024;
        #pragma unroll
        for (int nt = 0; nt < 8; nt++) {
            int col = nb0 + e.wn * 64 + nt * 8 + (e.lane & 3) * 2;
            __half2 x0 = *(const __half2*)(x16 + xb + col);
            __half2 x1 = *(const __half2*)(x16 + xb + 8 * 1024 + col);
            __half2 p0, p1;
            p0.x = __float2half_rn(g * acc[mt][nt][0] + __half2float(x0.x));
            p0.y = __float2half_rn(g * acc[mt][nt][1] + __half2float(x0.y));
            p1.x = __float2half_rn(g * acc[mt][nt][2] + __half2float(x1.x));
            p1.y = __float2half_rn(g * acc[mt][nt][3] + __half2float(x1.y));
            *(__half2*)(h16 + hb + col) = p0;
            *(__half2*)(h16 + hb + 8 * 1024 + col) = p1;
        }
    }
}

// ---------------- fused MLP: y1 = relu(h.W1^T + b1); out = relu(y1.W2^T + b2)
//                  + scatter + residual. y1 never leaves the CTA. -------------
__global__ __launch_bounds__(128, 2) void k_mma_fcfused(
    const __half* __restrict__ h16, const __half* __restrict__ w1,
    const float* __restrict__ b1, const __half* __restrict__ w2,
    const float* __restrict__ b2, const float* __restrict__ x,
    float* __restrict__ out)
{
    extern __shared__ char smem[];
    uint32_t sb = s2u(smem);
    const int mb0 = blockIdx.y * 128;    // r
    float acc[4][8][4] = {};
    mainloop1(smem, h16, w1, 1024, 1024, mb0, 0, 16, acc);

    // sync: all warps done reading stage buffers before we repurpose them
    __syncthreads();

    // load W2 [128 x 128] into B regions of stages 0 (k 0..63) and 1 (k 64..127)
    {
        const int tid  = threadIdx.x;
        const int rgrp = tid >> 3;
        const int cb   = (tid & 7) * 16;
        #pragma unroll
        for (int ch = 0; ch < 2; ch++) {
            #pragma unroll
            for (int i = 0; i < 8; i++) {
                int row = i * 16 + rgrp;
                cpasync16(sb + ch * STG_SB + A_SB + row * PITCHB + cb,
                          (const char*)(w2 + (size_t)row * 128 + ch * 64) + cb);
            }
        }
        asm volatile("cp.async.commit_group;" ::: "memory");
    }

    // store y1 tile (relu + bias, fp16) into A regions of stages 0/1
    #pragma unroll
    for (int mt = 0; mt < 4; mt++) {
        const int lane = threadIdx.x & 31, wid = threadIdx.x >> 5;
        const int wm = wid & 1, wn = wid >> 1;
        int lr0 = wm * 64 + mt * 16 + (lane >> 2);
        #pragma unroll
        for (int nt = 0; nt < 8; nt++) {
            int col = wn * 64 + nt * 8 + (lane & 3) * 2;
            int ch = col >> 6, cc = col & 63;
            float bc0 = b1[col], bc1 = b1[col + 1];
            __half2 p0, p1;
            p0.x = __float2half_rn(fmaxf(acc[mt][nt][0] + bc0, 0.f));
            p0.y = __float2half_rn(fmaxf(acc[mt][nt][1] + bc1, 0.f));
            p1.x = __float2half_rn(fmaxf(acc[mt][nt][2] + bc0, 0.f));
            p1.y = __float2half_rn(fmaxf(acc[mt][nt][3] + bc1, 0.f));
            uint32_t a0 = sb + ch * STG_SB + lr0 * PITCHB + cc * 2;
            uint32_t a1 = sb + ch * STG_SB + (lr0 + 8) * PITCHB + cc * 2;
            *(__half2*)(smem + (a0 - sb)) = p0;
            *(__half2*)(smem + (a1 - sb)) = p1;
        }
    }
    asm volatile("cp.async.wait_group 0;" ::: "memory");
    __syncthreads();

    // fc2 GEMM from smem (K=128 in two 64-chunks)
    float acc2[4][8][4] = {};
    compute1(sb, 0, acc2);
    compute1(sb, 1, acc2);

    // scatter + relu + residual epilogue
    #pragma unroll
    for (int mt = 0; mt < 4; mt++) {
        EpiIdx e = epi_idx(mb0, mt);
        #pragma unroll
        for (int rr = 0; rr < 2; rr++) {
            int r = e.r0 + rr * 8;               // r = (b*H + h)*T + t
            int b = r >> 13;
            int h = (r >> 10) & 7;
            int t = r & 1023;
            size_t xbase = (size_t)b * 1048576 + t;
            #pragma unroll
            for (int nt = 0; nt < 8; nt++) {
                int col = e.wn * 64 + nt * 8 + (e.lane & 3) * 2;
                #pragma unroll
                for (int jj = 0; jj < 2; jj++) {
                    int d = col + jj;
                    size_t idx = xbase + (size_t)(d * Hn + h) * 1024;
                    out[idx] = fmaxf(acc2[mt][nt][rr * 2 + jj] + b2[d], 0.f) + x[idx];
                }
            }
        }
    }
}

// ---------------- softmax: warp-per-row, shuffle reductions -----------------
__global__ __launch_bounds__(256) void k_softmax(__half* __restrict__ a)
{
    const int warp = threadIdx.x >> 5, lane = threadIdx.x & 31;
    __half* row = a + ((size_t)blockIdx.x * 8 + warp) * Tdim;

    // each lane owns 32 consecutive elements (64 B)
    __half2 v[16];
    #pragma unroll
    for (int i = 0; i < 4; i++)
        *(uint4*)&v[i * 4] = *(const uint4*)(row + lane * 32 + i * 8);

    float mx = -1e30f;
    #pragma unroll
    for (int i = 0; i < 16; i++) {
        float2 f = __half22float2(v[i]);
        mx = fmaxf(mx, fmaxf(f.x, f.y));
    }
    #pragma unroll
    for (int s = 16; s > 0; s >>= 1)
        mx = fmaxf(mx, __shfl_xor_sync(0xFFFFFFFF, mx, s));

    float e[32];
    float sum = 0.f;
    #pragma unroll
    for (int i = 0; i < 16; i++) {
        float2 f = __half22float2(v[i]);
        e[2*i]   = __expf(f.x - mx);
        e[2*i+1] = __expf(f.y - mx);
        sum += e[2*i] + e[2*i+1];
    }
    #pragma unroll
    for (int s = 16; s > 0; s >>= 1)
        sum += __shfl_xor_sync(0xFFFFFFFF, sum, s);
    float inv = 1.0f / sum;

    #pragma unroll
    for (int i = 0; i < 16; i++) {
        v[i].x = __float2half_rn(e[2*i] * inv);
        v[i].y = __float2half_rn(e[2*i+1] * inv);
    }
    #pragma unroll
    for (int i = 0; i < 4; i++)
        *(uint4*)(row + lane * 32 + i * 8) = *(uint4*)&v[i * 4];
}

// ---------------- prep kernels ----------------
__global__ __launch_bounds__(256) void k_wround_h(
    const float* __restrict__ w, __half* __restrict__ o)
{
    size_t i = ((size_t)blockIdx.x * 256 + threadIdx.x) * 4;
    float4 v = *(const float4*)(w + i);
    __half2 p;
    p.x = __float2half_rn(v.x); p.y = __float2half_rn(v.y);
    *(__half2*)(o + i) = p;
    p.x = __float2half_rn(v.z); p.y = __float2half_rn(v.w);
    *(__half2*)(o + i + 2) = p;
}

// transpose x (b,c,t) -> xT (b,t,c) fp16
__global__ void k_xprep(const float* __restrict__ x, __half* __restrict__ x16)
{
    __shared__ float tile[32][33];
    const int b = blockIdx.z;
    const int c0 = blockIdx.y * 32, t0 = blockIdx.x * 32;
    for (int r = threadIdx.y; r < 32; r += 8)
        tile[r][threadIdx.x] = x[(size_t)b * Cdim * Tdim + (size_t)(c0 + r) * Tdim + t0 + threadIdx.x];
    __syncthreads();
    for (int r = threadIdx.y; r < 32; r += 8) {
        float v = tile[threadIdx.x][r];
        size_t o = (size_t)b * Tdim * Cdim + (size_t)(t0 + r) * Cdim + c0 + threadIdx.x;
        x16[o] = __float2half_rn(v);
    }
}

// ============================================================================
// launch
// ============================================================================
extern "C" void kernel_launch(void* const* d_in, const int* in_sizes, int n_in,
                              void* d_out, int out_size)
{
    (void)in_sizes; (void)n_in; (void)out_size;
    const float* x     = (const float*)d_in[0];
    const float* Wq    = (const float*)d_in[1];
    const float* bq    = (const float*)d_in[2];
    const float* Wk    = (const float*)d_in[3];
    const float* bk    = (const float*)d_in[4];
    const float* Wv    = (const float*)d_in[5];
    const float* bv    = (const float*)d_in[6];
    const float* gamma = (const float*)d_in[7];
    const float* W1    = (const float*)d_in[8];
    const float* b1    = (const float*)d_in[9];
    const float* W2    = (const float*)d_in[10];
    const float* b2    = (const float*)d_in[11];
    float* out = (float*)d_out;

    __half *a16, *v16, *wv16, *wq16, *wk16, *w116, *w216, *x16;
    __half *q16, *k16, *h16;
    cudaGetSymbolAddress((void**)&a16,   g_attn16);
    cudaGetSymbolAddress((void**)&v16,   g_v16);
    cudaGetSymbolAddress((void**)&wv16,  g_wv16);
    cudaGetSymbolAddress((void**)&wq16,  g_wq16);
    cudaGetSymbolAddress((void**)&wk16,  g_wk16);
    cudaGetSymbolAddress((void**)&w116,  g_w116);
    cudaGetSymbolAddress((void**)&w216,  g_w216);
    cudaGetSymbolAddress((void**)&x16,   g_x16);
    cudaGetSymbolAddress((void**)&q16,   g_q16);
    cudaGetSymbolAddress((void**)&k16,   g_k16);
    cudaGetSymbolAddress((void**)&h16,   g_h16);

    static cudaStream_t s1 = nullptr;
    static cudaEvent_t evFork = nullptr, evV = nullptr;
    static bool init_done = false;
    if (!init_done) {
        cudaFuncSetAttribute(k_mma_proj,    cudaFuncAttributeMaxDynamicSharedMemorySize, MMA_SMEM);
        cudaFuncSetAttribute(k_mma_energy,  cudaFuncAttributeMaxDynamicSharedMemorySize, MMA_SMEM);
        cudaFuncSetAttribute(k_mma_vconv,   cudaFuncAttributeMaxDynamicSharedMemorySize, MMA_SMEM);
        cudaFuncSetAttribute(k_mma_oheads,  cudaFuncAttributeMaxDynamicSharedMemorySize, MMA_SMEM);
        cudaFuncSetAttribute(k_mma_fcfused, cudaFuncAttributeMaxDynamicSharedMemorySize, MMA_SMEM);
        cudaStreamCreateWithFlags(&s1, cudaStreamNonBlocking);
        cudaEventCreateWithFlags(&evFork, cudaEventDisableTiming);
        cudaEventCreateWithFlags(&evV,    cudaEventDisableTiming);
        init_done = true;
    }

    const dim3 blk(128);
    const int ZB = Bsz * Hn;   // 64

    // -------- stream 0 (default, capture stream): x prep --------
    k_xprep<<<dim3(Tdim/32, Cdim/32, Bsz), dim3(32, 8)>>>(x, x16);
    cudaEventRecord(evFork, 0);

    // -------- stream 1: Wv prep -> vconv -> W2 prep --------
    cudaStreamWaitEvent(s1, evFork, 0);
    k_wround_h<<<(Hn*Cdim*Cdim)/1024, 256, 0, s1>>>(Wv, wv16);
    k_mma_vconv<<<dim3(Tdim/128, Cdim/128, ZB), blk, MMA_SMEM, s1>>>(wv16, x16, bv, v16);
    k_wround_h<<<(DFC1*DFC1)/1024, 256, 0, s1>>>(W2, w216);
    cudaEventRecord(evV, s1);

    // -------- stream 0: q/k chain --------
    k_wround_h<<<(Hn*DQKd*Cdim)/1024, 256>>>(Wq, wq16);
    k_wround_h<<<(Hn*DQKd*Cdim)/1024, 256>>>(Wk, wk16);
    k_wround_h<<<(DFC1*Cdim)/1024,    256>>>(W1, w116);
    k_mma_proj<<<dim3(1, Tdim/128, 2*ZB), blk, MMA_SMEM>>>(x16, wq16, wk16, bq, bk, q16, k16);
    k_mma_energy<<<dim3(Tdim/128, Tdim/128, ZB), blk, MMA_SMEM>>>(q16, k16, a16);
    k_softmax<<<ZB * Tdim / 8, 256>>>(a16);

    // join: oheads needs attn (s0) and v (s1)
    cudaStreamWaitEvent(0, evV, 0);
    k_mma_oheads<<<dim3(Cdim/128, Tdim/128, ZB), blk, MMA_SMEM>>>(
        a16, v16, gamma, x16, h16);

    // fused MLP (fc1 + fc2, y1 stays in smem)
    const int ROWS = Bsz * Hn * Tdim;   // 65536
    k_mma_fcfused<<<dim3(1, ROWS/128), blk, MMA_SMEM>>>(h16, w116, b1, w216, b2, x, out);
}

// round 16
// speedup vs baseline: 20.5735x; 2.5714x over previous
#include <cuda_runtime.h>
#include <cuda_fp16.h>
#include <cstdint>

// ---------------- problem constants ----------------
#define Bsz  8
#define Cdim 1024
#define Tdim 1024
#define Hn   8
#define DQKd 128
#define DFC1 128

// ---------------- scratch (device globals; no allocs allowed) ----------------
__device__ __half g_attn16[(size_t)Bsz*Hn*Tdim*Tdim];         // logits -> attn (in-place)
__device__ __half g_wvT16[(size_t)Hn*Cdim*Cdim];              // Wv^T per head (c, o)
__device__ __half g_wq16[(size_t)Hn*DQKd*Cdim];
__device__ __half g_wk16[(size_t)Hn*DQKd*Cdim];
__device__ __half g_w116[(size_t)DFC1*Cdim];
__device__ __half g_w216[(size_t)DFC1*DFC1];
__device__ __half g_x16 [(size_t)Bsz*Tdim*Cdim];              // x^T (b,t,c)
__device__ __half g_q16[(size_t)Bsz*Hn*Tdim*DQKd];            // q (z,t,o)
__device__ __half g_k16[(size_t)Bsz*Hn*Tdim*DQKd];
__device__ __half g_m16[(size_t)Hn*DFC1*Cdim];                // M[h,f,c] = sum_o W1[f,o] Wv[h,o,c]
__device__ __half g_vw16[(size_t)Bsz*Hn*DFC1*Tdim];           // vw (z,f,s)
__device__ float  g_c1[(size_t)Hn*DFC1];                      // c1 = W1 @ bv[h]
__device__ float  g_xw32[(size_t)Bsz*Tdim*DFC1];              // xw = x^T @ W1^T (fp32)

// ============================================================================
// PTX helpers (sm_80-level — valid on compute_103)
// ============================================================================
__device__ __forceinline__ uint32_t s2u(const void* p) {
    uint32_t a;
    asm("{ .reg .u64 t; cvta.to.shared.u64 t, %1; cvt.u32.u64 %0, t; }"
        : "=r"(a) : "l"(p));
    return a;
}
__device__ __forceinline__ void ldsm_x4(uint32_t* r, uint32_t addr) {
    asm volatile("ldmatrix.sync.aligned.m8n8.x4.shared.b16 {%0,%1,%2,%3}, [%4];"
        : "=r"(r[0]), "=r"(r[1]), "=r"(r[2]), "=r"(r[3]) : "r"(addr));
}
__device__ __forceinline__ void mma_fp(float* c, const uint32_t* a, const uint32_t* b) {
    asm volatile("mma.sync.aligned.m16n8k16.row.col.f32.f16.f16.f32 "
        "{%0,%1,%2,%3}, {%4,%5,%6,%7}, {%8,%9}, {%0,%1,%2,%3};"
        : "+f"(c[0]), "+f"(c[1]), "+f"(c[2]), "+f"(c[3])
        : "r"(a[0]), "r"(a[1]), "r"(a[2]), "r"(a[3]), "r"(b[0]), "r"(b[1]));
}
__device__ __forceinline__ void cpasync16(uint32_t dst, const void* src) {
    asm volatile("cp.async.cg.shared.global [%0], [%1], 16;" :: "r"(dst), "l"(src));
}

// ============================================================================
// fp16 1-term tensor-core GEMM (TN): D[m,n] = sum_k A[m,k]*B[n,k]
// CTA tile 128x128, 128 threads (4 warps as 2M x 2N, warp tile 64x64).
// K-step 64, NPIPE=3, single __syncthreads per stage, 2 CTAs/SM.
// ============================================================================
#define A_ROWS   128
#define B_ROWS   128
#define PITCHB   144                 // 64 fp16 (128 B) + 16 B pad (conflict-free)
#define A_SB     (A_ROWS*PITCHB)     // 18432
#define B_SB     (B_ROWS*PITCHB)     // 18432
#define STG_SB   (A_SB + B_SB)       // 36864
#define NPIPE    3
#define MMA_SMEM (NPIPE*STG_SB)      // 110592  (x2 CTAs = 221184 <= 227KB)

__device__ __forceinline__ void issue1(
    uint32_t sb, int buf, int k0,
    const __half* __restrict__ A, const __half* __restrict__ B,
    int lda, int ldb, int mb0, int nb0)
{
    const int tid  = threadIdx.x;        // 0..127
    const int rgrp = tid >> 3;           // 0..15
    const int cb   = (tid & 7) * 16;     // byte offset within 128-B k-slice
    const uint32_t base = sb + buf * STG_SB;
    #pragma unroll
    for (int i = 0; i < 8; i++) {        // 128 A rows
        int row = i * 16 + rgrp;
        cpasync16(base + row * PITCHB + cb,
                  (const char*)(A + (size_t)(mb0 + row) * lda + k0) + cb);
    }
    #pragma unroll
    for (int i = 0; i < 8; i++) {        // 128 B rows
        int row = i * 16 + rgrp;
        cpasync16(base + A_SB + row * PITCHB + cb,
                  (const char*)(B + (size_t)(nb0 + row) * ldb + k0) + cb);
    }
    asm volatile("cp.async.commit_group;" ::: "memory");
}

__device__ __forceinline__ void compute1(uint32_t sb, int buf, float acc[4][8][4])
{
    const int lane = threadIdx.x & 31, wid = threadIdx.x >> 5;   // wid 0..3
    const int wm = wid & 1, wn = wid >> 1;
    const uint32_t ab = sb + buf * STG_SB;
    const uint32_t bb = ab + A_SB;
    #pragma unroll
    for (int k16 = 0; k16 < 4; k16++) {
        const uint32_t acol = k16 * 32 + (lane >> 4) * 16;
        uint32_t ah[4][4];
        #pragma unroll
        for (int mt = 0; mt < 4; mt++) {
            uint32_t arow = wm * 64 + mt * 16 + (lane & 15);
            ldsm_x4(ah[mt], ab + arow * PITCHB + acol);
        }
        const uint32_t bcol = k16 * 32 + ((lane >> 3) & 1) * 16;
        #pragma unroll
        for (int ntp = 0; ntp < 4; ntp++) {
            uint32_t brow = wn * 64 + ntp * 16 + ((lane >> 4) & 1) * 8 + (lane & 7);
            uint32_t bh[4];
            ldsm_x4(bh, bb + brow * PITCHB + bcol);
            #pragma unroll
            for (int mt = 0; mt < 4; mt++) {
                mma_fp(acc[mt][2*ntp],   ah[mt], bh);
                mma_fp(acc[mt][2*ntp+1], ah[mt], bh + 2);
            }
        }
    }
}

__device__ __forceinline__ void mainloop1(
    char* smem,
    const __half* __restrict__ A, const __half* __restrict__ B,
    int lda, int ldb, int mb0, int nb0, int nst, float acc[4][8][4])
{
    uint32_t sb = s2u(smem);
    issue1(sb, 0, 0,  A, B, lda, ldb, mb0, nb0);
    issue1(sb, 1, 64, A, B, lda, ldb, mb0, nb0);
    #pragma unroll 1
    for (int st = 0; st < nst; st++) {
        if (st + 1 < nst) asm volatile("cp.async.wait_group 1;" ::: "memory");
        else              asm volatile("cp.async.wait_group 0;" ::: "memory");
        __syncthreads();
        if (st + 2 < nst) {
            int nx = st + 2;
            issue1(sb, nx % NPIPE, nx * 64, A, B, lda, ldb, mb0, nb0);
        }
        compute1(sb, st % NPIPE, acc);
    }
}

// epilogue index helper (4-warp layout)
struct EpiIdx { int r0; int lane, wm, wn; };
__device__ __forceinline__ EpiIdx epi_idx(int mb0, int mt) {
    EpiIdx e;
    e.lane = threadIdx.x & 31;
    int wid = threadIdx.x >> 5;
    e.wm = wid & 1; e.wn = wid >> 1;
    e.r0 = mb0 + e.wm * 64 + mt * 16 + (e.lane >> 2);
    return e;
}

// ---------------- q+k projection (fused): P[z,t,o] single fp16 --------------
__global__ __launch_bounds__(128, 2) void k_mma_proj(
    const __half* __restrict__ x16,
    const __half* __restrict__ wq16, const __half* __restrict__ wk16,
    const float* __restrict__ bq, const float* __restrict__ bk,
    __half* __restrict__ q16, __half* __restrict__ k16)
{
    extern __shared__ char smem[];
    const int zz = blockIdx.z;            // 0..127; >=64 -> k path
    const int z = zz & 63, h = z & 7, b = z >> 3;
    const bool is_k = zz >= 64;
    const __half* w16 = is_k ? wk16 : wq16;
    const float* bias = is_k ? bk : bq;
    __half* p16 = is_k ? k16 : q16;
    const int mb0 = blockIdx.y * 128;    // t
    float acc[4][8][4] = {};
    mainloop1(smem,
              x16 + (size_t)b * 1048576, w16 + (size_t)h * 131072,
              1024, 1024, mb0, 0, 16, acc);
    #pragma unroll
    for (int mt = 0; mt < 4; mt++) {
        EpiIdx e = epi_idx(mb0, mt);
        size_t base = (size_t)z * 131072 + (size_t)e.r0 * 128;
        #pragma unroll
        for (int nt = 0; nt < 8; nt++) {
            int col = e.wn * 64 + nt * 8 + (e.lane & 3) * 2;
            float bc0 = bias[h * DQKd + col], bc1 = bias[h * DQKd + col + 1];
            __half2 p0, p1;
            p0.x = __float2half_rn(acc[mt][nt][0] + bc0);
            p0.y = __float2half_rn(acc[mt][nt][1] + bc1);
            p1.x = __float2half_rn(acc[mt][nt][2] + bc0);
            p1.y = __float2half_rn(acc[mt][nt][3] + bc1);
            *(__half2*)(p16 + base + col) = p0;
            *(__half2*)(p16 + base + 8 * 128 + col) = p1;
        }
    }
}

// ---------------- energy: logits fp16 out (K=128) ---------------------------
__global__ __launch_bounds__(128, 2) void k_mma_energy(
    const __half* __restrict__ q16, const __half* __restrict__ k16,
    __half* __restrict__ logits)
{
    extern __shared__ char smem[];
    const int z = blockIdx.z;
    const int mb0 = blockIdx.y * 128;    // t
    const int nb0 = blockIdx.x * 128;    // s
    float acc[4][8][4] = {};
    mainloop1(smem,
              q16 + (size_t)z * 131072, k16 + (size_t)z * 131072,
              128, 128, mb0, nb0, 2, acc);
    #pragma unroll
    for (int mt = 0; mt < 4; mt++) {
        EpiIdx e = epi_idx(mb0, mt);
        size_t base = (size_t)z * 1048576 + (size_t)e.r0 * 1024;
        #pragma unroll
        for (int nt = 0; nt < 8; nt++) {
            int col = nb0 + e.wn * 64 + nt * 8 + (e.lane & 3) * 2;
            __half2 p0, p1;
            p0.x = __float2half_rn(acc[mt][nt][0]);
            p0.y = __float2half_rn(acc[mt][nt][1]);
            p1.x = __float2half_rn(acc[mt][nt][2]);
            p1.y = __float2half_rn(acc[mt][nt][3]);
            *(__half2*)(logits + base + col) = p0;
            *(__half2*)(logits + base + 8 * 1024 + col) = p1;
        }
    }
}

// ---------------- mprep: M[h,f,c] = sum_o W1[f,o] WvT[h,c,o] ----------------
__global__ __launch_bounds__(128, 2) void k_mma_mprep(
    const __half* __restrict__ w116, const __half* __restrict__ wvT16,
    __half* __restrict__ m16)
{
    extern __shared__ char smem[];
    const int h = blockIdx.z;
    const int nb0 = blockIdx.x * 128;    // c
    float acc[4][8][4] = {};
    mainloop1(smem, w116, wvT16 + (size_t)h * 1048576, 1024, 1024, 0, nb0, 16, acc);
    #pragma unroll
    for (int mt = 0; mt < 4; mt++) {
        EpiIdx e = epi_idx(0, mt);       // f
        size_t base = (size_t)h * 131072 + (size_t)e.r0 * 1024;
        #pragma unroll
        for (int nt = 0; nt < 8; nt++) {
            int col = nb0 + e.wn * 64 + nt * 8 + (e.lane & 3) * 2;
            __half2 p0, p1;
            p0.x = __float2half_rn(acc[mt][nt][0]);
            p0.y = __float2half_rn(acc[mt][nt][1]);
            p1.x = __float2half_rn(acc[mt][nt][2]);
            p1.y = __float2half_rn(acc[mt][nt][3]);
            *(__half2*)(m16 + base + col) = p0;
            *(__half2*)(m16 + base + 8 * 1024 + col) = p1;
        }
    }
}

// ---------------- vw[z,f,s] = M[h] @ x16[b] + c1[h,f], fp16 -----------------
__global__ __launch_bounds__(128, 2) void k_mma_vw(
    const __half* __restrict__ m16, const __half* __restrict__ x16,
    const float* __restrict__ c1, __half* __restrict__ vw16)
{
    extern __shared__ char smem[];
    const int z = blockIdx.z, h = z & 7, b = z >> 3;
    const int nb0 = blockIdx.x * 128;    // s
    float acc[4][8][4] = {};
    mainloop1(smem, m16 + (size_t)h * 131072, x16 + (size_t)b * 1048576,
              1024, 1024, 0, nb0, 16, acc);
    #pragma unroll
    for (int mt = 0; mt < 4; mt++) {
        EpiIdx e = epi_idx(0, mt);       // f
        float cc0 = c1[h * DFC1 + e.r0];
        float cc1 = c1[h * DFC1 + e.r0 + 8];
        size_t base = (size_t)z * 131072 + (size_t)e.r0 * 1024;
        #pragma unroll
        for (int nt = 0; nt < 8; nt++) {
            int col = nb0 + e.wn * 64 + nt * 8 + (e.lane & 3) * 2;
            __half2 p0, p1;
            p0.x = __float2half_rn(acc[mt][nt][0] + cc0);
            p0.y = __float2half_rn(acc[mt][nt][1] + cc0);
            p1.x = __float2half_rn(acc[mt][nt][2] + cc1);
            p1.y = __float2half_rn(acc[mt][nt][3] + cc1);
            *(__half2*)(vw16 + base + col) = p0;
            *(__half2*)(vw16 + base + 8 * 1024 + col) = p1;
        }
    }
}

// ---------------- xw[(b,t),f] = x16 @ W1^T, fp32 ----------------------------
__global__ __launch_bounds__(128, 2) void k_mma_xw(
    const __half* __restrict__ x16, const __half* __restrict__ w116,
    float* __restrict__ xw32)
{
    extern __shared__ char smem[];
    const int mb0 = blockIdx.y * 128;    // row (b,t)
    float acc[4][8][4] = {};
    mainloop1(smem, x16, w116, 1024, 1024, mb0, 0, 16, acc);
    #pragma unroll
    for (int mt = 0; mt < 4; mt++) {
        EpiIdx e = epi_idx(mb0, mt);
        size_t base = (size_t)e.r0 * 128;
        #pragma unroll
        for (int nt = 0; nt < 8; nt++) {
            int col = e.wn * 64 + nt * 8 + (e.lane & 3) * 2;
            *(float2*)(xw32 + base + col) = make_float2(acc[mt][nt][0], acc[mt][nt][1]);
            *(float2*)(xw32 + base + 8 * 128 + col) = make_float2(acc[mt][nt][2], acc[mt][nt][3]);
        }
    }
}

// ---------------- final: ow = attn@vw^T; y1 = relu(g*ow + xw + b1);
//                  out = relu(y1@W2^T + b2) scatter + residual ---------------
__global__ __launch_bounds__(128, 2) void k_mma_final(
    const __half* __restrict__ a16, const __half* __restrict__ vw16,
    const float* __restrict__ gamma, const float* __restrict__ xw32,
    const float* __restrict__ b1, const __half* __restrict__ w2,
    const float* __restrict__ b2, const float* __restrict__ x,
    float* __restrict__ out)
{
    extern __shared__ char smem[];
    uint32_t sb = s2u(smem);
    const int r0 = blockIdx.y * 128;     // global row (z,t); one z per CTA
    const int z = r0 >> 10, h = z & 7;
    const int t0 = r0 & 1023;
    float acc[4][8][4] = {};
    mainloop1(smem, a16 + (size_t)z * 1048576, vw16 + (size_t)z * 131072,
              1024, 1024, t0, 0, 16, acc);
    const float g = gamma[h];

    __syncthreads();   // all warps done with stage buffers

    // load W2 [128 x 128] into B regions of stages 0 (k 0..63) and 1 (k 64..127)
    {
        const int tid  = threadIdx.x;
        const int rgrp = tid >> 3;
        const int cb   = (tid & 7) * 16;
        #pragma unroll
        for (int ch = 0; ch < 2; ch++) {
            #pragma unroll
            for (int i = 0; i < 8; i++) {
                int row = i * 16 + rgrp;
                cpasync16(sb + ch * STG_SB + A_SB + row * PITCHB + cb,
                          (const char*)(w2 + (size_t)row * 128 + ch * 64) + cb);
            }
        }
        asm volatile("cp.async.commit_group;" ::: "memory");
    }

    // y1 = relu(g*ow + xw + b1) -> fp16 into A regions of stages 0/1
    #pragma unroll
    for (int mt = 0; mt < 4; mt++) {
        const int lane = threadIdx.x & 31, wid = threadIdx.x >> 5;
        const int wm = wid & 1, wn = wid >> 1;
        int lr0 = wm * 64 + mt * 16 + (lane >> 2);
        int gr0 = r0 + lr0;                      // global row
        int b0 = gr0 >> 13, tt0 = gr0 & 1023;
        int gr1 = gr0 + 8;
        int b1i = gr1 >> 13, tt1 = gr1 & 1023;
        size_t xwr0 = ((size_t)b0 * 1024 + tt0) * 128;
        size_t xwr1 = ((size_t)b1i * 1024 + tt1) * 128;
        #pragma unroll
        for (int nt = 0; nt < 8; nt++) {
            int col = wn * 64 + nt * 8 + (lane & 3) * 2;
            int ch = col >> 6, cc = col & 63;
            float bc0 = b1[col], bc1 = b1[col + 1];
            __half2 p0, p1;
            p0.x = __float2half_rn(fmaxf(g * acc[mt][nt][0] + xw32[xwr0 + col]     + bc0, 0.f));
            p0.y = __float2half_rn(fmaxf(g * acc[mt][nt][1] + xw32[xwr0 + col + 1] + bc1, 0.f));
            p1.x = __float2half_rn(fmaxf(g * acc[mt][nt][2] + xw32[xwr1 + col]     + bc0, 0.f));
            p1.y = __float2half_rn(fmaxf(g * acc[mt][nt][3] + xw32[xwr1 + col + 1] + bc1, 0.f));
            *(__half2*)(smem + ch * STG_SB + lr0 * PITCHB + cc * 2) = p0;
            *(__half2*)(smem + ch * STG_SB + (lr0 + 8) * PITCHB + cc * 2) = p1;
        }
    }
    asm volatile("cp.async.wait_group 0;" ::: "memory");
    __syncthreads();

    // fc2 GEMM from smem (K=128 in two 64-chunks)
    float acc2[4][8][4] = {};
    compute1(sb, 0, acc2);
    compute1(sb, 1, acc2);

    // scatter + relu + residual epilogue
    #pragma unroll
    for (int mt = 0; mt < 4; mt++) {
        EpiIdx e = epi_idx(r0, mt);
        #pragma unroll
        for (int rr = 0; rr < 2; rr++) {
            int r = e.r0 + rr * 8;               // r = (b*H + h)*T + t
            int b = r >> 13;
            int hh = (r >> 10) & 7;
            int t = r & 1023;
            size_t xbase = (size_t)b * 1048576 + t;
            #pragma unroll
            for (int nt = 0; nt < 8; nt++) {
                int col = e.wn * 64 + nt * 8 + (e.lane & 3) * 2;
                #pragma unroll
                for (int jj = 0; jj < 2; jj++) {
                    int d = col + jj;
                    size_t idx = xbase + (size_t)(d * Hn + hh) * 1024;
                    out[idx] = fmaxf(acc2[mt][nt][rr * 2 + jj] + b2[d], 0.f) + x[idx];
                }
            }
        }
    }
}

// ---------------- softmax: warp-per-row, shuffle reductions -----------------
__global__ __launch_bounds__(256) void k_softmax(__half* __restrict__ a)
{
    const int warp = threadIdx.x >> 5, lane = threadIdx.x & 31;
    __half* row = a + ((size_t)blockIdx.x * 8 + warp) * Tdim;

    __half2 v[16];
    #pragma unroll
    for (int i = 0; i < 4; i++)
        *(uint4*)&v[i * 4] = *(const uint4*)(row + lane * 32 + i * 8);

    float mx = -1e30f;
    #pragma unroll
    for (int i = 0; i < 16; i++) {
        float2 f = __half22float2(v[i]);
        mx = fmaxf(mx, fmaxf(f.x, f.y));
    }
    #pragma unroll
    for (int s = 16; s > 0; s >>= 1)
        mx = fmaxf(mx, __shfl_xor_sync(0xFFFFFFFF, mx, s));

    float e[32];
    float sum = 0.f;
    #pragma unroll
    for (int i = 0; i < 16; i++) {
        float2 f = __half22float2(v[i]);
        e[2*i]   = __expf(f.x - mx);
        e[2*i+1] = __expf(f.y - mx);
        sum += e[2*i] + e[2*i+1];
    }
    #pragma unroll
    for (int s = 16; s > 0; s >>= 1)
        sum += __shfl_xor_sync(0xFFFFFFFF, sum, s);
    float inv = 1.0f / sum;

    #pragma unroll
    for (int i = 0; i < 16; i++) {
        v[i].x = __float2half_rn(e[2*i] * inv);
        v[i].y = __float2half_rn(e[2*i+1] * inv);
    }
    #pragma unroll
    for (int i = 0; i < 4; i++)
        *(uint4*)(row + lane * 32 + i * 8) = *(uint4*)&v[i * 4];
}

// ---------------- prep kernels ----------------
__global__ __launch_bounds__(256) void k_wround_h(
    const float* __restrict__ w, __half* __restrict__ o)
{
    size_t i = ((size_t)blockIdx.x * 256 + threadIdx.x) * 4;
    float4 v = *(const float4*)(w + i);
    __half2 p;
    p.x = __float2half_rn(v.x); p.y = __float2half_rn(v.y);
    *(__half2*)(o + i) = p;
    p.x = __float2half_rn(v.z); p.y = __float2half_rn(v.w);
    *(__half2*)(o + i + 2) = p;
}

// transpose Wv per head: wvT[h][c*1024 + o] = Wv[h][o*1024 + c], fp32 -> fp16
__global__ void k_wvtrans(const float* __restrict__ w, __half* __restrict__ ot)
{
    __shared__ float tile[32][33];
    const int h = blockIdx.z;
    const int o0 = blockIdx.y * 32, c0 = blockIdx.x * 32;
    const size_t base = (size_t)h * 1048576;
    for (int r = threadIdx.y; r < 32; r += 8)
        tile[r][threadIdx.x] = w[base + (size_t)(o0 + r) * 1024 + c0 + threadIdx.x];
    __syncthreads();
    for (int r = threadIdx.y; r < 32; r += 8)
        ot[base + (size_t)(c0 + r) * 1024 + o0 + threadIdx.x] =
            __float2half_rn(tile[threadIdx.x][r]);
}

// c1[h,f] = dot(W1[f,:], bv[h,:]) in fp32
__global__ __launch_bounds__(128) void k_c1(
    const float* __restrict__ w1, const float* __restrict__ bv,
    float* __restrict__ c1)
{
    const int h = blockIdx.x, f = threadIdx.x;
    float acc = 0.f;
    for (int c = 0; c < Cdim; c++)
        acc += w1[(size_t)f * Cdim + c] * bv[(size_t)h * Cdim + c];
    c1[h * DFC1 + f] = acc;
}

// transpose x (b,c,t) -> xT (b,t,c) fp16
__global__ void k_xprep(const float* __restrict__ x, __half* __restrict__ x16)
{
    __shared__ float tile[32][33];
    const int b = blockIdx.z;
    const int c0 = blockIdx.y * 32, t0 = blockIdx.x * 32;
    for (int r = threadIdx.y; r < 32; r += 8)
        tile[r][threadIdx.x] = x[(size_t)b * Cdim * Tdim + (size_t)(c0 + r) * Tdim + t0 + threadIdx.x];
    __syncthreads();
    for (int r = threadIdx.y; r < 32; r += 8) {
        float v = tile[threadIdx.x][r];
        size_t o = (size_t)b * Tdim * Cdim + (size_t)(t0 + r) * Cdim + c0 + threadIdx.x;
        x16[o] = __float2half_rn(v);
    }
}

// ============================================================================
// launch
// ============================================================================
extern "C" void kernel_launch(void* const* d_in, const int* in_sizes, int n_in,
                              void* d_out, int out_size)
{
    (void)in_sizes; (void)n_in; (void)out_size;
    const float* x     = (const float*)d_in[0];
    const float* Wq    = (const float*)d_in[1];
    const float* bq    = (const float*)d_in[2];
    const float* Wk    = (const float*)d_in[3];
    const float* bk    = (const float*)d_in[4];
    const float* Wv    = (const float*)d_in[5];
    const float* bv    = (const float*)d_in[6];
    const float* gamma = (const float*)d_in[7];
    const float* W1    = (const float*)d_in[8];
    const float* b1    = (const float*)d_in[9];
    const float* W2    = (const float*)d_in[10];
    const float* b2    = (const float*)d_in[11];
    float* out = (float*)d_out;

    __half *a16, *wvT16, *wq16, *wk16, *w116, *w216, *x16, *q16, *k16, *m16, *vw16;
    float *c1f, *xw32;
    cudaGetSymbolAddress((void**)&a16,   g_attn16);
    cudaGetSymbolAddress((void**)&wvT16, g_wvT16);
    cudaGetSymbolAddress((void**)&wq16,  g_wq16);
    cudaGetSymbolAddress((void**)&wk16,  g_wk16);
    cudaGetSymbolAddress((void**)&w116,  g_w116);
    cudaGetSymbolAddress((void**)&w216,  g_w216);
    cudaGetSymbolAddress((void**)&x16,   g_x16);
    cudaGetSymbolAddress((void**)&q16,   g_q16);
    cudaGetSymbolAddress((void**)&k16,   g_k16);
    cudaGetSymbolAddress((void**)&m16,   g_m16);
    cudaGetSymbolAddress((void**)&vw16,  g_vw16);
    cudaGetSymbolAddress((void**)&c1f,   g_c1);
    cudaGetSymbolAddress((void**)&xw32,  g_xw32);

    static cudaStream_t s1 = nullptr;
    static cudaEvent_t evFork = nullptr, evV = nullptr;
    static bool init_done = false;
    if (!init_done) {
        cudaFuncSetAttribute(k_mma_proj,   cudaFuncAttributeMaxDynamicSharedMemorySize, MMA_SMEM);
        cudaFuncSetAttribute(k_mma_energy, cudaFuncAttributeMaxDynamicSharedMemorySize, MMA_SMEM);
        cudaFuncSetAttribute(k_mma_mprep,  cudaFuncAttributeMaxDynamicSharedMemorySize, MMA_SMEM);
        cudaFuncSetAttribute(k_mma_vw,     cudaFuncAttributeMaxDynamicSharedMemorySize, MMA_SMEM);
        cudaFuncSetAttribute(k_mma_xw,     cudaFuncAttributeMaxDynamicSharedMemorySize, MMA_SMEM);
        cudaFuncSetAttribute(k_mma_final,  cudaFuncAttributeMaxDynamicSharedMemorySize, MMA_SMEM);
        cudaStreamCreateWithFlags(&s1, cudaStreamNonBlocking);
        cudaEventCreateWithFlags(&evFork, cudaEventDisableTiming);
        cudaEventCreateWithFlags(&evV,    cudaEventDisableTiming);
        init_done = true;
    }

    const dim3 blk(128);
    const int ZB = Bsz * Hn;   // 64

    // -------- stream 0 (default, capture stream): x prep --------
    k_xprep<<<dim3(Tdim/32, Cdim/32, Bsz), dim3(32, 8)>>>(x, x16);
    cudaEventRecord(evFork, 0);

    // -------- stream 1: v-path (collapsed) --------
    cudaStreamWaitEvent(s1, evFork, 0);
    k_wvtrans<<<dim3(Cdim/32, Cdim/32, Hn), dim3(32, 8), 0, s1>>>(Wv, wvT16);
    k_wround_h<<<(DFC1*Cdim)/1024, 256, 0, s1>>>(W1, w116);
    k_c1<<<Hn, 128, 0, s1>>>(W1, bv, c1f);
    k_mma_mprep<<<dim3(Cdim/128, 1, Hn), blk, MMA_SMEM, s1>>>(w116, wvT16, m16);
    k_mma_vw<<<dim3(Tdim/128, 1, ZB), blk, MMA_SMEM, s1>>>(m16, x16, c1f, vw16);
    k_mma_xw<<<dim3(1, (Bsz*Tdim)/128), blk, MMA_SMEM, s1>>>(x16, w116, xw32);
    k_wround_h<<<(DFC1*DFC1)/1024, 256, 0, s1>>>(W2, w216);
    cudaEventRecord(evV, s1);

    // -------- stream 0: q/k chain --------
    k_wround_h<<<(Hn*DQKd*Cdim)/1024, 256>>>(Wq, wq16);
    k_wround_h<<<(Hn*DQKd*Cdim)/1024, 256>>>(Wk, wk16);
    k_mma_proj<<<dim3(1, Tdim/128, 2*ZB), blk, MMA_SMEM>>>(x16, wq16, wk16, bq, bk, q16, k16);
    k_mma_energy<<<dim3(Tdim/128, Tdim/128, ZB), blk, MMA_SMEM>>>(q16, k16, a16);
    k_softmax<<<ZB * Tdim / 8, 256>>>(a16);

    // join: final needs attn (s0) and vw/xw/W2 (s1)
    cudaStreamWaitEvent(0, evV, 0);
    const int ROWS = Bsz * Hn * Tdim;   // 65536
    k_mma_final<<<dim3(1, ROWS/128), blk, MMA_SMEM>>>(
        a16, vw16, gamma, xw32, b1, w216, b2, x, out);
}

// round 17
// speedup vs baseline: 23.1819x; 1.1268x over previous
#include <cuda_runtime.h>
#include <cuda_fp16.h>
#include <cstdint>

// ---------------- problem constants ----------------
#define Bsz  8
#define Cdim 1024
#define Tdim 1024
#define Hn   8
#define DQKd 128
#define DFC1 128

// ---------------- scratch (device globals; no allocs allowed) ----------------
__device__ __half g_attn16[(size_t)Bsz*Hn*Tdim*Tdim];         // logits -> attn (in-place)
__device__ __half g_wvT16[(size_t)Hn*Cdim*Cdim];              // Wv^T per head (c, o)
__device__ __half g_wq16[(size_t)Hn*DQKd*Cdim];
__device__ __half g_wk16[(size_t)Hn*DQKd*Cdim];
__device__ __half g_w116[(size_t)DFC1*Cdim];
__device__ __half g_w216[(size_t)DFC1*DFC1];
__device__ __half g_x16 [(size_t)Bsz*Tdim*Cdim];              // x^T (b,t,c)
__device__ __half g_q16[(size_t)Bsz*Hn*Tdim*DQKd];            // q (z,t,o)
__device__ __half g_k16[(size_t)Bsz*Hn*Tdim*DQKd];
__device__ __half g_m16[(size_t)Hn*DFC1*Cdim];                // M[h,f,c] = sum_o W1[f,o] Wv[h,o,c]
__device__ __half g_vw16[(size_t)Bsz*Hn*DFC1*Tdim];           // vw (z,f,s)
__device__ float  g_c1[(size_t)Hn*DFC1];                      // c1 = W1 @ bv[h]
__device__ float  g_xw32[(size_t)Bsz*Tdim*DFC1];              // xw = x^T @ W1^T (fp32)

// ============================================================================
// PTX helpers (sm_80-level — valid on compute_103)
// ============================================================================
__device__ __forceinline__ uint32_t s2u(const void* p) {
    uint32_t a;
    asm("{ .reg .u64 t; cvta.to.shared.u64 t, %1; cvt.u32.u64 %0, t; }"
        : "=r"(a) : "l"(p));
    return a;
}
__device__ __forceinline__ void ldsm_x4(uint32_t* r, uint32_t addr) {
    asm volatile("ldmatrix.sync.aligned.m8n8.x4.shared.b16 {%0,%1,%2,%3}, [%4];"
        : "=r"(r[0]), "=r"(r[1]), "=r"(r[2]), "=r"(r[3]) : "r"(addr));
}
__device__ __forceinline__ void mma_fp(float* c, const uint32_t* a, const uint32_t* b) {
    asm volatile("mma.sync.aligned.m16n8k16.row.col.f32.f16.f16.f32 "
        "{%0,%1,%2,%3}, {%4,%5,%6,%7}, {%8,%9}, {%0,%1,%2,%3};"
        : "+f"(c[0]), "+f"(c[1]), "+f"(c[2]), "+f"(c[3])
        : "r"(a[0]), "r"(a[1]), "r"(a[2]), "r"(a[3]), "r"(b[0]), "r"(b[1]));
}
__device__ __forceinline__ void cpasync16(uint32_t dst, const void* src) {
    asm volatile("cp.async.cg.shared.global [%0], [%1], 16;" :: "r"(dst), "l"(src));
}

// ============================================================================
// fp16 1-term tensor-core GEMM (TN): D[m,n] = sum_k A[m,k]*B[n,k]
// CTA tile 128x128, 128 threads (4 warps as 2M x 2N, warp tile 64x64).
// K-step 64, NPIPE=3, single __syncthreads per stage, 2 CTAs/SM.
// ============================================================================
#define A_ROWS   128
#define B_ROWS   128
#define PITCHB   144                 // 64 fp16 (128 B) + 16 B pad (conflict-free)
#define A_SB     (A_ROWS*PITCHB)     // 18432
#define B_SB     (B_ROWS*PITCHB)     // 18432
#define STG_SB   (A_SB + B_SB)       // 36864
#define NPIPE    3
#define MMA_SMEM (NPIPE*STG_SB)      // 110592  (x2 CTAs = 221184 <= 227KB)

__device__ __forceinline__ void issue1(
    uint32_t sb, int buf, int k0,
    const __half* __restrict__ A, const __half* __restrict__ B,
    int lda, int ldb, int mb0, int nb0)
{
    const int tid  = threadIdx.x;        // 0..127
    const int rgrp = tid >> 3;           // 0..15
    const int cb   = (tid & 7) * 16;     // byte offset within 128-B k-slice
    const uint32_t base = sb + buf * STG_SB;
    #pragma unroll
    for (int i = 0; i < 8; i++) {        // 128 A rows
        int row = i * 16 + rgrp;
        cpasync16(base + row * PITCHB + cb,
                  (const char*)(A + (size_t)(mb0 + row) * lda + k0) + cb);
    }
    #pragma unroll
    for (int i = 0; i < 8; i++) {        // 128 B rows
        int row = i * 16 + rgrp;
        cpasync16(base + A_SB + row * PITCHB + cb,
                  (const char*)(B + (size_t)(nb0 + row) * ldb + k0) + cb);
    }
    asm volatile("cp.async.commit_group;" ::: "memory");
}

__device__ __forceinline__ void compute1(uint32_t sb, int buf, float acc[4][8][4])
{
    const int lane = threadIdx.x & 31, wid = threadIdx.x >> 5;   // wid 0..3
    const int wm = wid & 1, wn = wid >> 1;
    const uint32_t ab = sb + buf * STG_SB;
    const uint32_t bb = ab + A_SB;
    #pragma unroll
    for (int k16 = 0; k16 < 4; k16++) {
        const uint32_t acol = k16 * 32 + (lane >> 4) * 16;
        uint32_t ah[4][4];
        #pragma unroll
        for (int mt = 0; mt < 4; mt++) {
            uint32_t arow = wm * 64 + mt * 16 + (lane & 15);
            ldsm_x4(ah[mt], ab + arow * PITCHB + acol);
        }
        const uint32_t bcol = k16 * 32 + ((lane >> 3) & 1) * 16;
        #pragma unroll
        for (int ntp = 0; ntp < 4; ntp++) {
            uint32_t brow = wn * 64 + ntp * 16 + ((lane >> 4) & 1) * 8 + (lane & 7);
            uint32_t bh[4];
            ldsm_x4(bh, bb + brow * PITCHB + bcol);
            #pragma unroll
            for (int mt = 0; mt < 4; mt++) {
                mma_fp(acc[mt][2*ntp],   ah[mt], bh);
                mma_fp(acc[mt][2*ntp+1], ah[mt], bh + 2);
            }
        }
    }
}

__device__ __forceinline__ void mainloop1(
    char* smem,
    const __half* __restrict__ A, const __half* __restrict__ B,
    int lda, int ldb, int mb0, int nb0, int nst, float acc[4][8][4])
{
    uint32_t sb = s2u(smem);
    issue1(sb, 0, 0,  A, B, lda, ldb, mb0, nb0);
    issue1(sb, 1, 64, A, B, lda, ldb, mb0, nb0);
    #pragma unroll 1
    for (int st = 0; st < nst; st++) {
        if (st + 1 < nst) asm volatile("cp.async.wait_group 1;" ::: "memory");
        else              asm volatile("cp.async.wait_group 0;" ::: "memory");
        __syncthreads();
        if (st + 2 < nst) {
            int nx = st + 2;
            issue1(sb, nx % NPIPE, nx * 64, A, B, lda, ldb, mb0, nb0);
        }
        compute1(sb, st % NPIPE, acc);
    }
}

// epilogue index helper (4-warp layout)
struct EpiIdx { int r0; int lane, wm, wn; };
__device__ __forceinline__ EpiIdx epi_idx(int mb0, int mt) {
    EpiIdx e;
    e.lane = threadIdx.x & 31;
    int wid = threadIdx.x >> 5;
    e.wm = wid & 1; e.wn = wid >> 1;
    e.r0 = mb0 + e.wm * 64 + mt * 16 + (e.lane >> 2);
    return e;
}

// ---------------- q+k projection (fused): P[z,t,o] single fp16 --------------
__global__ __launch_bounds__(128, 2) void k_mma_proj(
    const __half* __restrict__ x16,
    const __half* __restrict__ wq16, const __half* __restrict__ wk16,
    const float* __restrict__ bq, const float* __restrict__ bk,
    __half* __restrict__ q16, __half* __restrict__ k16)
{
    extern __shared__ char smem[];
    const int zz = blockIdx.z;            // 0..127; >=64 -> k path
    const int z = zz & 63, h = z & 7, b = z >> 3;
    const bool is_k = zz >= 64;
    const __half* w16 = is_k ? wk16 : wq16;
    const float* bias = is_k ? bk : bq;
    __half* p16 = is_k ? k16 : q16;
    const int mb0 = blockIdx.y * 128;    // t
    float acc[4][8][4] = {};
    mainloop1(smem,
              x16 + (size_t)b * 1048576, w16 + (size_t)h * 131072,
              1024, 1024, mb0, 0, 16, acc);
    #pragma unroll
    for (int mt = 0; mt < 4; mt++) {
        EpiIdx e = epi_idx(mb0, mt);
        size_t base = (size_t)z * 131072 + (size_t)e.r0 * 128;
        #pragma unroll
        for (int nt = 0; nt < 8; nt++) {
            int col = e.wn * 64 + nt * 8 + (e.lane & 3) * 2;
            float bc0 = bias[h * DQKd + col], bc1 = bias[h * DQKd + col + 1];
            __half2 p0, p1;
            p0.x = __float2half_rn(acc[mt][nt][0] + bc0);
            p0.y = __float2half_rn(acc[mt][nt][1] + bc1);
            p1.x = __float2half_rn(acc[mt][nt][2] + bc0);
            p1.y = __float2half_rn(acc[mt][nt][3] + bc1);
            *(__half2*)(p16 + base + col) = p0;
            *(__half2*)(p16 + base + 8 * 128 + col) = p1;
        }
    }
}

// ---------------- energy: logits fp16 out (K=128) ---------------------------
__global__ __launch_bounds__(128, 2) void k_mma_energy(
    const __half* __restrict__ q16, const __half* __restrict__ k16,
    __half* __restrict__ logits)
{
    extern __shared__ char smem[];
    const int z = blockIdx.z;
    const int mb0 = blockIdx.y * 128;    // t
    const int nb0 = blockIdx.x * 128;    // s
    float acc[4][8][4] = {};
    mainloop1(smem,
              q16 + (size_t)z * 131072, k16 + (size_t)z * 131072,
              128, 128, mb0, nb0, 2, acc);
    #pragma unroll
    for (int mt = 0; mt < 4; mt++) {
        EpiIdx e = epi_idx(mb0, mt);
        size_t base = (size_t)z * 1048576 + (size_t)e.r0 * 1024;
        #pragma unroll
        for (int nt = 0; nt < 8; nt++) {
            int col = nb0 + e.wn * 64 + nt * 8 + (e.lane & 3) * 2;
            __half2 p0, p1;
            p0.x = __float2half_rn(acc[mt][nt][0]);
            p0.y = __float2half_rn(acc[mt][nt][1]);
            p1.x = __float2half_rn(acc[mt][nt][2]);
            p1.y = __float2half_rn(acc[mt][nt][3]);
            *(__half2*)(logits + base + col) = p0;
            *(__half2*)(logits + base + 8 * 1024 + col) = p1;
        }
    }
}

// ---------------- mprep: M[h,f,c] = sum_o W1[f,o] WvT[h,c,o] ----------------
__global__ __launch_bounds__(128, 2) void k_mma_mprep(
    const __half* __restrict__ w116, const __half* __restrict__ wvT16,
    __half* __restrict__ m16)
{
    extern __shared__ char smem[];
    const int h = blockIdx.z;
    const int nb0 = blockIdx.x * 128;    // c
    float acc[4][8][4] = {};
    mainloop1(smem, w116, wvT16 + (size_t)h * 1048576, 1024, 1024, 0, nb0, 16, acc);
    #pragma unroll
    for (int mt = 0; mt < 4; mt++) {
        EpiIdx e = epi_idx(0, mt);       // f
        size_t base = (size_t)h * 131072 + (size_t)e.r0 * 1024;
        #pragma unroll
        for (int nt = 0; nt < 8; nt++) {
            int col = nb0 + e.wn * 64 + nt * 8 + (e.lane & 3) * 2;
            __half2 p0, p1;
            p0.x = __float2half_rn(acc[mt][nt][0]);
            p0.y = __float2half_rn(acc[mt][nt][1]);
            p1.x = __float2half_rn(acc[mt][nt][2]);
            p1.y = __float2half_rn(acc[mt][nt][3]);
            *(__half2*)(m16 + base + col) = p0;
            *(__half2*)(m16 + base + 8 * 1024 + col) = p1;
        }
    }
}

// ---------------- vw[z,f,s] = M[h] @ x16[b] + c1[h,f], fp16 -----------------
__global__ __launch_bounds__(128, 2) void k_mma_vw(
    const __half* __restrict__ m16, const __half* __restrict__ x16,
    const float* __restrict__ c1, __half* __restrict__ vw16)
{
    extern __shared__ char smem[];
    const int z = blockIdx.z, h = z & 7, b = z >> 3;
    const int nb0 = blockIdx.x * 128;    // s
    float acc[4][8][4] = {};
    mainloop1(smem, m16 + (size_t)h * 131072, x16 + (size_t)b * 1048576,
              1024, 1024, 0, nb0, 16, acc);
    #pragma unroll
    for (int mt = 0; mt < 4; mt++) {
        EpiIdx e = epi_idx(0, mt);       // f
        float cc0 = c1[h * DFC1 + e.r0];
        float cc1 = c1[h * DFC1 + e.r0 + 8];
        size_t base = (size_t)z * 131072 + (size_t)e.r0 * 1024;
        #pragma unroll
        for (int nt = 0; nt < 8; nt++) {
            int col = nb0 + e.wn * 64 + nt * 8 + (e.lane & 3) * 2;
            __half2 p0, p1;
            p0.x = __float2half_rn(acc[mt][nt][0] + cc0);
            p0.y = __float2half_rn(acc[mt][nt][1] + cc0);
            p1.x = __float2half_rn(acc[mt][nt][2] + cc1);
            p1.y = __float2half_rn(acc[mt][nt][3] + cc1);
            *(__half2*)(vw16 + base + col) = p0;
            *(__half2*)(vw16 + base + 8 * 1024 + col) = p1;
        }
    }
}

// ---------------- xw[(b,t),f] = x16 @ W1^T, fp32 ----------------------------
__global__ __launch_bounds__(128, 2) void k_mma_xw(
    const __half* __restrict__ x16, const __half* __restrict__ w116,
    float* __restrict__ xw32)
{
    extern __shared__ char smem[];
    const int mb0 = blockIdx.y * 128;    // row (b,t)
    float acc[4][8][4] = {};
    mainloop1(smem, x16, w116, 1024, 1024, mb0, 0, 16, acc);
    #pragma unroll
    for (int mt = 0; mt < 4; mt++) {
        EpiIdx e = epi_idx(mb0, mt);
        size_t base = (size_t)e.r0 * 128;
        #pragma unroll
        for (int nt = 0; nt < 8; nt++) {
            int col = e.wn * 64 + nt * 8 + (e.lane & 3) * 2;
            *(float2*)(xw32 + base + col) = make_float2(acc[mt][nt][0], acc[mt][nt][1]);
            *(float2*)(xw32 + base + 8 * 128 + col) = make_float2(acc[mt][nt][2], acc[mt][nt][3]);
        }
    }
}

// ---------------- final: ow = attn@vw^T; y1 = relu(g*ow + xw + b1);
//                  out = relu(y1@W2^T + b2) scatter + residual ---------------
__global__ __launch_bounds__(128, 2) void k_mma_final(
    const __half* __restrict__ a16, const __half* __restrict__ vw16,
    const float* __restrict__ gamma, const float* __restrict__ xw32,
    const float* __restrict__ b1, const __half* __restrict__ w2,
    const float* __restrict__ b2, const float* __restrict__ x,
    float* __restrict__ out)
{
    extern __shared__ char smem[];
    uint32_t sb = s2u(smem);
    const int r0 = blockIdx.y * 128;     // global row (z,t); one z per CTA
    const int z = r0 >> 10, h = z & 7;
    const int t0 = r0 & 1023;
    float acc[4][8][4] = {};
    mainloop1(smem, a16 + (size_t)z * 1048576, vw16 + (size_t)z * 131072,
              1024, 1024, t0, 0, 16, acc);
    const float g = gamma[h];

    __syncthreads();   // all warps done with stage buffers

    // load W2 [128 x 128] into B regions of stages 0 (k 0..63) and 1 (k 64..127)
    {
        const int tid  = threadIdx.x;
        const int rgrp = tid >> 3;
        const int cb   = (tid & 7) * 16;
        #pragma unroll
        for (int ch = 0; ch < 2; ch++) {
            #pragma unroll
            for (int i = 0; i < 8; i++) {
                int row = i * 16 + rgrp;
                cpasync16(sb + ch * STG_SB + A_SB + row * PITCHB + cb,
                          (const char*)(w2 + (size_t)row * 128 + ch * 64) + cb);
            }
        }
        asm volatile("cp.async.commit_group;" ::: "memory");
    }

    // y1 = relu(g*ow + xw + b1) -> fp16 into A regions of stages 0/1
    #pragma unroll
    for (int mt = 0; mt < 4; mt++) {
        const int lane = threadIdx.x & 31, wid = threadIdx.x >> 5;
        const int wm = wid & 1, wn = wid >> 1;
        int lr0 = wm * 64 + mt * 16 + (lane >> 2);
        int gr0 = r0 + lr0;                      // global row
        int b0 = gr0 >> 13, tt0 = gr0 & 1023;
        int gr1 = gr0 + 8;
        int b1i = gr1 >> 13, tt1 = gr1 & 1023;
        size_t xwr0 = ((size_t)b0 * 1024 + tt0) * 128;
        size_t xwr1 = ((size_t)b1i * 1024 + tt1) * 128;
        #pragma unroll
        for (int nt = 0; nt < 8; nt++) {
            int col = wn * 64 + nt * 8 + (lane & 3) * 2;
            int ch = col >> 6, cc = col & 63;
            float bc0 = b1[col], bc1 = b1[col + 1];
            __half2 p0, p1;
            p0.x = __float2half_rn(fmaxf(g * acc[mt][nt][0] + xw32[xwr0 + col]     + bc0, 0.f));
            p0.y = __float2half_rn(fmaxf(g * acc[mt][nt][1] + xw32[xwr0 + col + 1] + bc1, 0.f));
            p1.x = __float2half_rn(fmaxf(g * acc[mt][nt][2] + xw32[xwr1 + col]     + bc0, 0.f));
            p1.y = __float2half_rn(fmaxf(g * acc[mt][nt][3] + xw32[xwr1 + col + 1] + bc1, 0.f));
            *(__half2*)(smem + ch * STG_SB + lr0 * PITCHB + cc * 2) = p0;
            *(__half2*)(smem + ch * STG_SB + (lr0 + 8) * PITCHB + cc * 2) = p1;
        }
    }
    asm volatile("cp.async.wait_group 0;" ::: "memory");
    __syncthreads();

    // fc2 GEMM from smem (K=128 in two 64-chunks)
    float acc2[4][8][4] = {};
    compute1(sb, 0, acc2);
    compute1(sb, 1, acc2);

    // scatter + relu + residual epilogue
    #pragma unroll
    for (int mt = 0; mt < 4; mt++) {
        EpiIdx e = epi_idx(r0, mt);
        #pragma unroll
        for (int rr = 0; rr < 2; rr++) {
            int r = e.r0 + rr * 8;               // r = (b*H + h)*T + t
            int b = r >> 13;
            int hh = (r >> 10) & 7;
            int t = r & 1023;
            size_t xbase = (size_t)b * 1048576 + t;
            #pragma unroll
            for (int nt = 0; nt < 8; nt++) {
                int col = e.wn * 64 + nt * 8 + (e.lane & 3) * 2;
                #pragma unroll
                for (int jj = 0; jj < 2; jj++) {
                    int d = col + jj;
                    size_t idx = xbase + (size_t)(d * Hn + hh) * 1024;
                    out[idx] = fmaxf(acc2[mt][nt][rr * 2 + jj] + b2[d], 0.f) + x[idx];
                }
            }
        }
    }
}

// ---------------- softmax: warp-per-row, shuffle reductions -----------------
__global__ __launch_bounds__(256) void k_softmax(__half* __restrict__ a)
{
    const int warp = threadIdx.x >> 5, lane = threadIdx.x & 31;
    __half* row = a + ((size_t)blockIdx.x * 8 + warp) * Tdim;

    __half2 v[16];
    #pragma unroll
    for (int i = 0; i < 4; i++)
        *(uint4*)&v[i * 4] = *(const uint4*)(row + lane * 32 + i * 8);

    float mx = -1e30f;
    #pragma unroll
    for (int i = 0; i < 16; i++) {
        float2 f = __half22float2(v[i]);
        mx = fmaxf(mx, fmaxf(f.x, f.y));
    }
    #pragma unroll
    for (int s = 16; s > 0; s >>= 1)
        mx = fmaxf(mx, __shfl_xor_sync(0xFFFFFFFF, mx, s));

    float e[32];
    float sum = 0.f;
    #pragma unroll
    for (int i = 0; i < 16; i++) {
        float2 f = __half22float2(v[i]);
        e[2*i]   = __expf(f.x - mx);
        e[2*i+1] = __expf(f.y - mx);
        sum += e[2*i] + e[2*i+1];
    }
    #pragma unroll
    for (int s = 16; s > 0; s >>= 1)
        sum += __shfl_xor_sync(0xFFFFFFFF, sum, s);
    float inv = 1.0f / sum;

    #pragma unroll
    for (int i = 0; i < 16; i++) {
        v[i].x = __float2half_rn(e[2*i] * inv);
        v[i].y = __float2half_rn(e[2*i+1] * inv);
    }
    #pragma unroll
    for (int i = 0; i < 4; i++)
        *(uint4*)(row + lane * 32 + i * 8) = *(uint4*)&v[i * 4];
}

// ---------------- prep kernels ----------------
__global__ __launch_bounds__(256) void k_wround_h(
    const float* __restrict__ w, __half* __restrict__ o)
{
    size_t i = ((size_t)blockIdx.x * 256 + threadIdx.x) * 4;
    float4 v = *(const float4*)(w + i);
    __half2 p;
    p.x = __float2half_rn(v.x); p.y = __float2half_rn(v.y);
    *(__half2*)(o + i) = p;
    p.x = __float2half_rn(v.z); p.y = __float2half_rn(v.w);
    *(__half2*)(o + i + 2) = p;
}

// transpose Wv per head: wvT[h][c*1024 + o] = Wv[h][o*1024 + c], fp32 -> fp16
__global__ void k_wvtrans(const float* __restrict__ w, __half* __restrict__ ot)
{
    __shared__ float tile[32][33];
    const int h = blockIdx.z;
    const int o0 = blockIdx.y * 32, c0 = blockIdx.x * 32;
    const size_t base = (size_t)h * 1048576;
    for (int r = threadIdx.y; r < 32; r += 8)
        tile[r][threadIdx.x] = w[base + (size_t)(o0 + r) * 1024 + c0 + threadIdx.x];
    __syncthreads();
    for (int r = threadIdx.y; r < 32; r += 8)
        ot[base + (size_t)(c0 + r) * 1024 + o0 + threadIdx.x] =
            __float2half_rn(tile[threadIdx.x][r]);
}

// c1[h,f] = dot(W1[f,:], bv[h,:]) — warp per output, float4 + shfl reduce
__global__ __launch_bounds__(256) void k_c1(
    const float* __restrict__ w1, const float* __restrict__ bv,
    float* __restrict__ c1)
{
    const int warp = (blockIdx.x * 256 + threadIdx.x) >> 5;   // 0..1023
    const int lane = threadIdx.x & 31;
    const int h = warp >> 7, f = warp & 127;
    const float4* wrow = (const float4*)(w1 + (size_t)f * Cdim);
    const float4* brow = (const float4*)(bv + (size_t)h * Cdim);
    float acc = 0.f;
    #pragma unroll
    for (int i = 0; i < 8; i++) {
        float4 wv = wrow[i * 32 + lane];
        float4 bb = brow[i * 32 + lane];
        acc += wv.x * bb.x + wv.y * bb.y + wv.z * bb.z + wv.w * bb.w;
    }
    #pragma unroll
    for (int s = 16; s > 0; s >>= 1)
        acc += __shfl_xor_sync(0xFFFFFFFF, acc, s);
    if (lane == 0) c1[h * DFC1 + f] = acc;
}

// transpose x (b,c,t) -> xT (b,t,c) fp16
__global__ void k_xprep(const float* __restrict__ x, __half* __restrict__ x16)
{
    __shared__ float tile[32][33];
    const int b = blockIdx.z;
    const int c0 = blockIdx.y * 32, t0 = blockIdx.x * 32;
    for (int r = threadIdx.y; r < 32; r += 8)
        tile[r][threadIdx.x] = x[(size_t)b * Cdim * Tdim + (size_t)(c0 + r) * Tdim + t0 + threadIdx.x];
    __syncthreads();
    for (int r = threadIdx.y; r < 32; r += 8) {
        float v = tile[threadIdx.x][r];
        size_t o = (size_t)b * Tdim * Cdim + (size_t)(t0 + r) * Cdim + c0 + threadIdx.x;
        x16[o] = __float2half_rn(v);
    }
}

// ============================================================================
// launch
// ============================================================================
extern "C" void kernel_launch(void* const* d_in, const int* in_sizes, int n_in,
                              void* d_out, int out_size)
{
    (void)in_sizes; (void)n_in; (void)out_size;
    const float* x     = (const float*)d_in[0];
    const float* Wq    = (const float*)d_in[1];
    const float* bq    = (const float*)d_in[2];
    const float* Wk    = (const float*)d_in[3];
    const float* bk    = (const float*)d_in[4];
    const float* Wv    = (const float*)d_in[5];
    const float* bv    = (const float*)d_in[6];
    const float* gamma = (const float*)d_in[7];
    const float* W1    = (const float*)d_in[8];
    const float* b1    = (const float*)d_in[9];
    const float* W2    = (const float*)d_in[10];
    const float* b2    = (const float*)d_in[11];
    float* out = (float*)d_out;

    __half *a16, *wvT16, *wq16, *wk16, *w116, *w216, *x16, *q16, *k16, *m16, *vw16;
    float *c1f, *xw32;
    cudaGetSymbolAddress((void**)&a16,   g_attn16);
    cudaGetSymbolAddress((void**)&wvT16, g_wvT16);
    cudaGetSymbolAddress((void**)&wq16,  g_wq16);
    cudaGetSymbolAddress((void**)&wk16,  g_wk16);
    cudaGetSymbolAddress((void**)&w116,  g_w116);
    cudaGetSymbolAddress((void**)&w216,  g_w216);
    cudaGetSymbolAddress((void**)&x16,   g_x16);
    cudaGetSymbolAddress((void**)&q16,   g_q16);
    cudaGetSymbolAddress((void**)&k16,   g_k16);
    cudaGetSymbolAddress((void**)&m16,   g_m16);
    cudaGetSymbolAddress((void**)&vw16,  g_vw16);
    cudaGetSymbolAddress((void**)&c1f,   g_c1);
    cudaGetSymbolAddress((void**)&xw32,  g_xw32);

    static cudaStream_t s1 = nullptr;
    static cudaEvent_t evFork = nullptr, evV = nullptr;
    static bool init_done = false;
    if (!init_done) {
        cudaFuncSetAttribute(k_mma_proj,   cudaFuncAttributeMaxDynamicSharedMemorySize, MMA_SMEM);
        cudaFuncSetAttribute(k_mma_energy, cudaFuncAttributeMaxDynamicSharedMemorySize, MMA_SMEM);
        cudaFuncSetAttribute(k_mma_mprep,  cudaFuncAttributeMaxDynamicSharedMemorySize, MMA_SMEM);
        cudaFuncSetAttribute(k_mma_vw,     cudaFuncAttributeMaxDynamicSharedMemorySize, MMA_SMEM);
        cudaFuncSetAttribute(k_mma_xw,     cudaFuncAttributeMaxDynamicSharedMemorySize, MMA_SMEM);
        cudaFuncSetAttribute(k_mma_final,  cudaFuncAttributeMaxDynamicSharedMemorySize, MMA_SMEM);
        cudaStreamCreateWithFlags(&s1, cudaStreamNonBlocking);
        cudaEventCreateWithFlags(&evFork, cudaEventDisableTiming);
        cudaEventCreateWithFlags(&evV,    cudaEventDisableTiming);
        init_done = true;
    }

    const dim3 blk(128);
    const int ZB = Bsz * Hn;   // 64

    // -------- stream 1: weight-only chain first (no x dependency) --------
    k_wvtrans<<<dim3(Cdim/32, Cdim/32, Hn), dim3(32, 8), 0, s1>>>(Wv, wvT16);
    k_wround_h<<<(DFC1*Cdim)/1024, 256, 0, s1>>>(W1, w116);
    k_c1<<<(Hn*DFC1)/8, 256, 0, s1>>>(W1, bv, c1f);
    k_wround_h<<<(DFC1*DFC1)/1024, 256, 0, s1>>>(W2, w216);
    k_mma_mprep<<<dim3(Cdim/128, 1, Hn), blk, MMA_SMEM, s1>>>(w116, wvT16, m16);

    // -------- stream 0 (default, capture stream): x prep --------
    k_xprep<<<dim3(Tdim/32, Cdim/32, Bsz), dim3(32, 8)>>>(x, x16);
    cudaEventRecord(evFork, 0);

    // -------- stream 1: x-dependent v-path --------
    cudaStreamWaitEvent(s1, evFork, 0);
    k_mma_vw<<<dim3(Tdim/128, 1, ZB), blk, MMA_SMEM, s1>>>(m16, x16, c1f, vw16);
    k_mma_xw<<<dim3(1, (Bsz*Tdim)/128), blk, MMA_SMEM, s1>>>(x16, w116, xw32);
    cudaEventRecord(evV, s1);

    // -------- stream 0: q/k chain --------
    k_wround_h<<<(Hn*DQKd*Cdim)/1024, 256>>>(Wq, wq16);
    k_wround_h<<<(Hn*DQKd*Cdim)/1024, 256>>>(Wk, wk16);
    k_mma_proj<<<dim3(1, Tdim/128, 2*ZB), blk, MMA_SMEM>>>(x16, wq16, wk16, bq, bk, q16, k16);
    k_mma_energy<<<dim3(Tdim/128, Tdim/128, ZB), blk, MMA_SMEM>>>(q16, k16, a16);
    k_softmax<<<ZB * Tdim / 8, 256>>>(a16);

    // join: final needs attn (s0) and vw/xw/W2 (s1)
    cudaStreamWaitEvent(0, evV, 0);
    const int ROWS = Bsz * Hn * Tdim;   // 65536
    k_mma_final<<<dim3(1, ROWS/128), blk, MMA_SMEM>>>(
        a16, vw16, gamma, xw32, b1, w216, b2, x, out);
}